// round 6
// baseline (speedup 1.0000x reference)
#include <cuda_runtime.h>
#include <cuda_bf16.h>
#include <math.h>
#include <stdint.h>

// ---------------- problem constants ----------------
#define BB   2
#define TT   2048
#define DD   2048
#define NHH  16
#define HDD  128
#define RR   64
#define CQQ  1536
#define CKVV 512
#define BT   (BB*TT)       // 4096
#define DQK  192           // HD + R
#define DVV  128
#define HALFW 256          // WINDOW/2
#define RSCALE 0.07216878364870323f  // 1/sqrt(192)

typedef __nv_bfloat16 bf16;

// ---------------- scratch (device globals; no runtime alloc) ----------------
__device__ float g_qlat [(size_t)BT*CQQ];
__device__ float g_kvlat[(size_t)BT*CKVV];
__device__ float g_qcr  [(size_t)BT*3072];   // [qc(2048) | qr(1024)]
__device__ float g_kcv  [(size_t)BT*4096];   // [kc(2048) | vv(2048)]
__device__ float g_kr   [(size_t)BT*NHH*RR];
__device__ float g_alpha[BT];

// attention operands, pre-split bf16, head-major: [bh][t][d]
__device__ bf16 g_Qh[(size_t)BB*NHH*TT*DQK], g_Ql[(size_t)BB*NHH*TT*DQK];
__device__ bf16 g_Kh[(size_t)BB*NHH*TT*DQK], g_Kl[(size_t)BB*NHH*TT*DQK];
__device__ bf16 g_Vh[(size_t)BB*NHH*TT*DVV], g_Vl[(size_t)BB*NHH*TT*DVV];

// bf16 split buffers (hi/lo) for GEMMs ([K,N] layout)
__device__ bf16 g_xh [(size_t)BT*DD],    g_xl [(size_t)BT*DD];
__device__ bf16 g_qlh[(size_t)BT*CQQ],   g_qll[(size_t)BT*CQQ];
__device__ bf16 g_kvh[(size_t)BT*CKVV],  g_kvl[(size_t)BT*CKVV];
__device__ bf16 g_mgh[(size_t)BT*NHH*HDD], g_mgl[(size_t)BT*NHH*HDD];
__device__ bf16 g_wqd_h [(size_t)DD*CQQ],    g_wqd_l [(size_t)DD*CQQ];
__device__ bf16 g_wqup_h[(size_t)CQQ*3072],  g_wqup_l[(size_t)CQQ*3072];
__device__ bf16 g_wkd_h [(size_t)DD*CKVV],   g_wkd_l [(size_t)DD*CKVV];
__device__ bf16 g_wkvu_h[(size_t)CKVV*4096], g_wkvu_l[(size_t)CKVV*4096];
__device__ bf16 g_wkr_h [(size_t)DD*1024],   g_wkr_l [(size_t)DD*1024];
__device__ bf16 g_wo_h  [(size_t)2048*DD],   g_wo_l  [(size_t)2048*DD];

// ---------------- ptx helpers ----------------
__device__ __forceinline__ uint32_t smem_u32(const void* p) {
    return (uint32_t)__cvta_generic_to_shared(p);
}
__device__ __forceinline__ void ldsm_x4(uint32_t* r, const void* p) {
    uint32_t a = smem_u32(p);
    asm volatile("ldmatrix.sync.aligned.m8n8.x4.shared.b16 {%0,%1,%2,%3}, [%4];"
                 : "=r"(r[0]), "=r"(r[1]), "=r"(r[2]), "=r"(r[3]) : "r"(a));
}
__device__ __forceinline__ void ldsm_x4t(uint32_t* r, const void* p) {
    uint32_t a = smem_u32(p);
    asm volatile("ldmatrix.sync.aligned.m8n8.x4.trans.shared.b16 {%0,%1,%2,%3}, [%4];"
                 : "=r"(r[0]), "=r"(r[1]), "=r"(r[2]), "=r"(r[3]) : "r"(a));
}
__device__ __forceinline__ void ldsm_x2t(uint32_t &r0, uint32_t &r1,
                                         const void* p) {
    uint32_t a = smem_u32(p);
    asm volatile("ldmatrix.sync.aligned.m8n8.x2.trans.shared.b16 {%0,%1}, [%2];"
                 : "=r"(r0), "=r"(r1) : "r"(a));
}
__device__ __forceinline__ void mma_bf16(float* c, const uint32_t* a,
                                         const uint32_t* b) {
    asm volatile(
        "mma.sync.aligned.m16n8k16.row.col.f32.bf16.bf16.f32 "
        "{%0,%1,%2,%3}, {%4,%5,%6,%7}, {%8,%9}, {%0,%1,%2,%3};"
        : "+f"(c[0]), "+f"(c[1]), "+f"(c[2]), "+f"(c[3])
        : "r"(a[0]), "r"(a[1]), "r"(a[2]), "r"(a[3]), "r"(b[0]), "r"(b[1]));
}
__device__ __forceinline__ void cpa16(void* s, const void* g) {
    asm volatile("cp.async.cg.shared.global [%0], [%1], 16;"
                 :: "r"(smem_u32(s)), "l"(g));
}
#define CP_COMMIT asm volatile("cp.async.commit_group;")
#define CP_WAIT1  asm volatile("cp.async.wait_group 1;")
#define CP_WAIT0  asm volatile("cp.async.wait_group 0;")

__device__ __forceinline__ uint32_t pk(bf16 a, bf16 b) {
    __nv_bfloat162 t(a, b);
    return *reinterpret_cast<uint32_t*>(&t);
}

// ---------------- split fp32 -> (hi, lo) bf16 ----------------
__global__ __launch_bounds__(256) void split_kernel(
    const float* __restrict__ s, bf16* __restrict__ h,
    bf16* __restrict__ l, int n)
{
    int i = (blockIdx.x * 256 + threadIdx.x) * 4;
    if (i >= n) return;
    float4 v = *(const float4*)(s + i);
    bf16 h0 = __float2bfloat16(v.x), h1 = __float2bfloat16(v.y);
    bf16 h2 = __float2bfloat16(v.z), h3 = __float2bfloat16(v.w);
    *(__nv_bfloat162*)(h + i)     = __nv_bfloat162(h0, h1);
    *(__nv_bfloat162*)(h + i + 2) = __nv_bfloat162(h2, h3);
    *(__nv_bfloat162*)(l + i) = __nv_bfloat162(
        __float2bfloat16(v.x - __bfloat162float(h0)),
        __float2bfloat16(v.y - __bfloat162float(h1)));
    *(__nv_bfloat162*)(l + i + 2) = __nv_bfloat162(
        __float2bfloat16(v.z - __bfloat162float(h2)),
        __float2bfloat16(v.w - __bfloat162float(h3)));
}

// ---------------- merge two [K,N*] weights into one split [K,N1+N2] --------
__global__ __launch_bounds__(256) void merge_split_kernel(
    const float* __restrict__ W1, const float* __restrict__ W2,
    bf16* __restrict__ h, bf16* __restrict__ l, int N1, int N2, int total)
{
    int i = (blockIdx.x * 256 + threadIdx.x) * 4;
    if (i >= total) return;
    int Nt = N1 + N2;
    int k = i / Nt, n = i % Nt;
    const float* src = (n < N1) ? (W1 + (size_t)k * N1 + n)
                                : (W2 + (size_t)k * N2 + (n - N1));
    float4 v = *(const float4*)src;
    bf16 h0 = __float2bfloat16(v.x), h1 = __float2bfloat16(v.y);
    bf16 h2 = __float2bfloat16(v.z), h3 = __float2bfloat16(v.w);
    *(__nv_bfloat162*)(h + i)     = __nv_bfloat162(h0, h1);
    *(__nv_bfloat162*)(h + i + 2) = __nv_bfloat162(h2, h3);
    *(__nv_bfloat162*)(l + i) = __nv_bfloat162(
        __float2bfloat16(v.x - __bfloat162float(h0)),
        __float2bfloat16(v.y - __bfloat162float(h1)));
    *(__nv_bfloat162*)(l + i + 2) = __nv_bfloat162(
        __float2bfloat16(v.z - __bfloat162float(h2)),
        __float2bfloat16(v.w - __bfloat162float(h3)));
}

// ---------------- split-bf16 TC GEMM, 2-stage cp.async pipeline ------------
#define GS_A   (128*40)
#define GS_B   (32*136)
#define GS_STG (2*GS_A + 2*GS_B)
#define GS_SMEM (2*GS_STG*2)

__global__ __launch_bounds__(256) void gemm_split(
    const bf16* __restrict__ Ah, const bf16* __restrict__ Al,
    const bf16* __restrict__ Bh, const bf16* __restrict__ Bl,
    float* __restrict__ C, int M, int N, int K)
{
    extern __shared__ __align__(16) bf16 gsm[];

    int tid = threadIdx.x;
    int bm = blockIdx.y, bn = blockIdx.x;
    int warp = tid >> 5, lane = tid & 31;
    int wm = warp >> 2, wn = warp & 3;

    int arow = tid >> 2, ac = (tid & 3) * 8;
    int brow = tid >> 4, bc = (tid & 15) * 8;

    float acc[4][4][4];
#pragma unroll
    for (int a = 0; a < 4; a++)
#pragma unroll
        for (int b = 0; b < 4; b++)
#pragma unroll
            for (int c = 0; c < 4; c++) acc[a][b][c] = 0.f;

    int nk = K >> 5;

    auto issue = [&](int stage, int k0) {
        bf16* sAh = gsm + stage * GS_STG;
        bf16* sAl = sAh + GS_A;
        bf16* sBh = sAl + GS_A;
        bf16* sBl = sBh + GS_B;
#pragma unroll
        for (int i = 0; i < 2; i++) {
            int r = arow + i * 64;
            size_t g = (size_t)(bm * 128 + r) * K + k0 + ac;
            cpa16(&sAh[r * 40 + ac], Ah + g);
            cpa16(&sAl[r * 40 + ac], Al + g);
        }
#pragma unroll
        for (int i = 0; i < 2; i++) {
            int r = brow + i * 16;
            size_t g = (size_t)(k0 + r) * N + bn * 128 + bc;
            cpa16(&sBh[r * 136 + bc], Bh + g);
            cpa16(&sBl[r * 136 + bc], Bl + g);
        }
    };

    issue(0, 0);
    CP_COMMIT;

    for (int it = 0; it < nk; it++) {
        if (it + 1 < nk) {
            issue((it + 1) & 1, (it + 1) << 5);
            CP_COMMIT;
            CP_WAIT1;
        } else {
            CP_WAIT0;
        }
        __syncthreads();

        bf16* sAh = gsm + (it & 1) * GS_STG;
        bf16* sAl = sAh + GS_A;
        bf16* sBh = sAl + GS_A;
        bf16* sBl = sBh + GS_B;

#pragma unroll
        for (int kh = 0; kh < 2; kh++) {
            uint32_t bhf[4][2], blf[4][2];
#pragma unroll
            for (int nt = 0; nt < 4; nt++) {
                int br = kh * 16 + (lane & 15);
                int bcl = wn * 32 + nt * 8;
                ldsm_x2t(bhf[nt][0], bhf[nt][1], &sBh[br * 136 + bcl]);
                ldsm_x2t(blf[nt][0], blf[nt][1], &sBl[br * 136 + bcl]);
            }
#pragma unroll
            for (int mt = 0; mt < 4; mt++) {
                int ar = wm * 64 + mt * 16 + (lane & 15);
                int acl = kh * 16 + (lane >> 4) * 8;
                uint32_t ah[4], al[4];
                ldsm_x4(ah, &sAh[ar * 40 + acl]);
                ldsm_x4(al, &sAl[ar * 40 + acl]);
#pragma unroll
                for (int nt = 0; nt < 4; nt++) {
                    mma_bf16(acc[mt][nt], ah, bhf[nt]);
                    mma_bf16(acc[mt][nt], ah, blf[nt]);
                    mma_bf16(acc[mt][nt], al, bhf[nt]);
                }
            }
        }
        __syncthreads();
    }

#pragma unroll
    for (int mt = 0; mt < 4; mt++) {
#pragma unroll
        for (int nt = 0; nt < 4; nt++) {
            int r0 = bm * 128 + wm * 64 + mt * 16 + (lane >> 2);
            int c0 = bn * 128 + wn * 32 + nt * 8 + (lane & 3) * 2;
            *(float2*)&C[(size_t)r0 * N + c0] =
                make_float2(acc[mt][nt][0], acc[mt][nt][1]);
            *(float2*)&C[(size_t)(r0 + 8) * N + c0] =
                make_float2(acc[mt][nt][2], acc[mt][nt][3]);
        }
    }
}

// ---------------- RMSNorm -> split bf16 outputs ----------------
__global__ __launch_bounds__(256) void rmsnorm_split_kernel(
    const float* __restrict__ x, const float* __restrict__ w,
    bf16* __restrict__ hi, bf16* __restrict__ lo, int n)
{
    const float* row = x + (size_t)blockIdx.x * n;
    float ss = 0.f;
    for (int i = threadIdx.x; i < n; i += 256) { float v = row[i]; ss += v*v; }
    __shared__ float sh[8];
    __shared__ float tot;
    int lane = threadIdx.x & 31, wp = threadIdx.x >> 5;
#pragma unroll
    for (int o = 16; o; o >>= 1) ss += __shfl_xor_sync(0xffffffffu, ss, o);
    if (lane == 0) sh[wp] = ss;
    __syncthreads();
    if (threadIdx.x == 0) {
        float s = 0.f;
        for (int i = 0; i < 8; i++) s += sh[i];
        tot = rsqrtf(s / n + 1e-6f);
    }
    __syncthreads();
    float rs = tot;
    bf16* hrow = hi + (size_t)blockIdx.x * n;
    bf16* lrow = lo + (size_t)blockIdx.x * n;
    for (int i = threadIdx.x; i < n; i += 256) {
        float y = row[i] * rs * w[i];
        bf16 h = __float2bfloat16(y);
        hrow[i] = h;
        lrow[i] = __float2bfloat16(y - __bfloat162float(h));
    }
}

// ---------------- gate alpha ----------------
__global__ __launch_bounds__(256) void alpha_kernel(
    const float* __restrict__ x, const float* __restrict__ wg,
    const float* __restrict__ bg, float* __restrict__ alpha,
    float* __restrict__ out_alpha)
{
    const float* row = x + (size_t)blockIdx.x * DD;
    float s = 0.f;
    for (int i = threadIdx.x; i < DD; i += 256) s += row[i] * wg[i];
    __shared__ float sh[8];
    int lane = threadIdx.x & 31, wp = threadIdx.x >> 5;
#pragma unroll
    for (int o = 16; o; o >>= 1) s += __shfl_xor_sync(0xffffffffu, s, o);
    if (lane == 0) sh[wp] = s;
    __syncthreads();
    if (threadIdx.x == 0) {
        float t = 0.f;
        for (int i = 0; i < 8; i++) t += sh[i];
        float z = t + bg[0];
        float a = 1.f / (1.f + expf(-z));
        alpha[blockIdx.x] = a;
        if (out_alpha) out_alpha[blockIdx.x] = a;
    }
}

// ---------------- assemble Q/K/V with EPE-RoPE (emit split bf16) -----------
__global__ __launch_bounds__(128) void assemble_kernel(
    const float* __restrict__ qcr, const float* __restrict__ kcv,
    const float* __restrict__ kr, const float* __restrict__ unc,
    bf16* __restrict__ Qh, bf16* __restrict__ Ql,
    bf16* __restrict__ Kh, bf16* __restrict__ Kl,
    bf16* __restrict__ Vh, bf16* __restrict__ Vl)
{
    int idx = blockIdx.x;
    int h  = idx % NHH;
    int bt = idx / NHH;
    int t  = bt % TT;
    int b  = bt / TT;
    __shared__ float cs[32], sn[32];
    int d = threadIdx.x;
    if (d < 32) {
        float u = unc[bt];
        u = fminf(fmaxf(u, 0.f), 1.f);
        float scale = 0.5f + 1.5f * u;
        float fi = (float)d / 32.0f;
        float theta = expf(-fi * logf(500000.0f));
        float fr = (float)t * theta * scale;
        cs[d] = cosf(fr);
        sn[d] = sinf(fr);
    }
    __syncthreads();
    size_t qkrow = ((size_t)(b*NHH + h))*TT + t;

    float qv0 = qcr[(size_t)bt*3072 + h*128 + d];
    float kv0 = kcv[(size_t)bt*4096 + h*128 + d];
    float vv0 = kcv[(size_t)bt*4096 + 2048 + h*128 + d];
    bf16 hh;
    hh = __float2bfloat16(qv0);
    Qh[qkrow*DQK + d] = hh; Ql[qkrow*DQK + d] = __float2bfloat16(qv0 - __bfloat162float(hh));
    hh = __float2bfloat16(kv0);
    Kh[qkrow*DQK + d] = hh; Kl[qkrow*DQK + d] = __float2bfloat16(kv0 - __bfloat162float(hh));
    hh = __float2bfloat16(vv0);
    Vh[qkrow*DVV + d] = hh; Vl[qkrow*DVV + d] = __float2bfloat16(vv0 - __bfloat162float(hh));

    if (d < 64) {
        const float* qrp = qcr + (size_t)bt*3072 + 2048 + h*64;
        const float* krp = kr  + (size_t)bt*1024 + h*64;
        float qv, kv;
        if (d < 32) {
            float c = cs[d], s = sn[d];
            qv = qrp[d]*c - qrp[d+32]*s;
            kv = krp[d]*c - krp[d+32]*s;
        } else {
            int j = d - 32;
            float c = cs[j], s = sn[j];
            qv = qrp[j+32]*c + qrp[j]*s;
            kv = krp[j+32]*c + krp[j]*s;
        }
        hh = __float2bfloat16(qv);
        Qh[qkrow*DQK + 128 + d] = hh;
        Ql[qkrow*DQK + 128 + d] = __float2bfloat16(qv - __bfloat162float(hh));
        hh = __float2bfloat16(kv);
        Kh[qkrow*DQK + 128 + d] = hh;
        Kl[qkrow*DQK + 128 + d] = __float2bfloat16(kv - __bfloat162float(hh));
    }
}

// ---------------- tensor-core fused dual attention ----------------
// Streams: oR = bidir-only keys, oW = window keys; bidir = oR + oW.
#define KSTR 200
#define VSTR 136
#define ATTN_SMEM ((64*KSTR*2 + 2*64*KSTR*2 + 2*64*VSTR*2) * 2)

__global__ void __launch_bounds__(128, 1) attn_tc_kernel(
    const bf16* __restrict__ Qh, const bf16* __restrict__ Ql,
    const bf16* __restrict__ Kh, const bf16* __restrict__ Kl,
    const bf16* __restrict__ Vh, const bf16* __restrict__ Vl,
    const float* __restrict__ alpha,
    bf16* __restrict__ mgh, bf16* __restrict__ mgl)
{
    extern __shared__ __align__(16) bf16 smem[];
    bf16* sQh = smem;
    bf16* sQl = sQh + 64*KSTR;
    bf16* sKh = sQl + 64*KSTR;
    bf16* sKl = sKh + 2*64*KSTR;
    bf16* sVh = sKl + 2*64*KSTR;
    bf16* sVl = sVh + 2*64*VSTR;

    int tid = threadIdx.x, lane = tid & 31, warp = tid >> 5;
    int qt = blockIdx.x * 64;
    int bh = blockIdx.y;
    int b = bh >> 4, h = bh & 15;
    size_t base = (size_t)bh * TT;

    for (int i = tid; i < 64*24; i += 128) {
        int r = i / 24, c = (i % 24) * 8;
        size_t g = (base + qt + r) * DQK + c;
        cpa16(&sQh[r*KSTR + c], Qh + g);
        cpa16(&sQl[r*KSTR + c], Ql + g);
    }
    for (int i = tid; i < 64*24; i += 128) {
        int r = i / 24, c = (i % 24) * 8;
        size_t g = (base + r) * DQK + c;
        cpa16(&sKh[r*KSTR + c], Kh + g);
        cpa16(&sKl[r*KSTR + c], Kl + g);
    }
    for (int i = tid; i < 64*16; i += 128) {
        int r = i / 16, c = (i % 16) * 8;
        size_t g = (base + r) * DVV + c;
        cpa16(&sVh[r*VSTR + c], Vh + g);
        cpa16(&sVl[r*VSTR + c], Vl + g);
    }
    CP_COMMIT;

    int q0 = qt + 16*warp + (lane >> 2);
    int q1 = q0 + 8;
    int winlo = ((qt >> 8) << 8) - HALFW;
    if (winlo < 0) winlo = 0;

    float ob[16][4], ow[16][4];
#pragma unroll
    for (int n = 0; n < 16; n++)
#pragma unroll
        for (int j = 0; j < 4; j++) { ob[n][j] = 0.f; ow[n][j] = 0.f; }
    float m0 = -1e30f, m1 = -1e30f;
    float lb0 = 0.f, lb1 = 0.f, lw0 = 0.f, lw1 = 0.f;

    for (int t = 0; t < 32; t++) {
        int kt = t * 64;
        int nb = (t + 1) & 1;
        if (t + 1 < 32) {
            int kn = kt + 64;
            for (int i = tid; i < 64*24; i += 128) {
                int r = i / 24, c = (i % 24) * 8;
                size_t g = (base + kn + r) * DQK + c;
                cpa16(&sKh[nb*64*KSTR + r*KSTR + c], Kh + g);
                cpa16(&sKl[nb*64*KSTR + r*KSTR + c], Kl + g);
            }
            for (int i = tid; i < 64*16; i += 128) {
                int r = i / 16, c = (i % 16) * 8;
                size_t g = (base + kn + r) * DVV + c;
                cpa16(&sVh[nb*64*VSTR + r*VSTR + c], Vh + g);
                cpa16(&sVl[nb*64*VSTR + r*VSTR + c], Vl + g);
            }
        }
        CP_COMMIT;
        CP_WAIT1;
        __syncthreads();

        const bf16* bKh = sKh + (t & 1) * 64 * KSTR;
        const bf16* bVh = sVh + (t & 1) * 64 * VSTR;

        bool diag    = (kt == qt);
        bool fullwin = (kt >= winlo) && (kt < qt);

        // ---- S = Q K^T (3 split chains) ----
        float sacc[8][4];
#pragma unroll
        for (int n = 0; n < 8; n++)
#pragma unroll
            for (int j = 0; j < 4; j++) sacc[n][j] = 0.f;

#pragma unroll
        for (int ks = 0; ks < 12; ks++) {
            uint32_t qhf[4], qlf[4];
            const bf16* ap = &sQh[(16*warp + (lane & 15))*KSTR + ks*16 + (lane >> 4)*8];
            ldsm_x4(qhf, ap);
            ldsm_x4(qlf, ap + 64*KSTR);
#pragma unroll
            for (int np = 0; np < 4; np++) {
                int g2 = lane >> 3;
                int krow = np*16 + (g2 >> 1)*8 + (lane & 7);
                int kcol = ks*16 + (g2 & 1)*8;
                const bf16* bp = &bKh[krow*KSTR + kcol];
                uint32_t khf[4], klf[4];
                ldsm_x4(khf, bp);
                ldsm_x4(klf, bp + 2*64*KSTR);
                mma_bf16(sacc[2*np],   qhf, khf);
                mma_bf16(sacc[2*np],   qhf, klf);
                mma_bf16(sacc[2*np],   qlf, khf);
                mma_bf16(sacc[2*np+1], qhf, khf + 2);
                mma_bf16(sacc[2*np+1], qhf, klf + 2);
                mma_bf16(sacc[2*np+1], qlf, khf + 2);
            }
        }

        // ---- online softmax ----
        float tm0 = -1e30f, tm1 = -1e30f;
#pragma unroll
        for (int n = 0; n < 8; n++) {
            tm0 = fmaxf(tm0, fmaxf(sacc[n][0], sacc[n][1]));
            tm1 = fmaxf(tm1, fmaxf(sacc[n][2], sacc[n][3]));
        }
        tm0 *= RSCALE; tm1 *= RSCALE;
        tm0 = fmaxf(tm0, __shfl_xor_sync(0xffffffffu, tm0, 1));
        tm0 = fmaxf(tm0, __shfl_xor_sync(0xffffffffu, tm0, 2));
        tm1 = fmaxf(tm1, __shfl_xor_sync(0xffffffffu, tm1, 1));
        tm1 = fmaxf(tm1, __shfl_xor_sync(0xffffffffu, tm1, 2));
        float mn0 = fmaxf(m0, tm0), mn1 = fmaxf(m1, tm1);
        float c0 = __expf(m0 - mn0), c1 = __expf(m1 - mn1);
        m0 = mn0; m1 = mn1;
        lb0 *= c0; lb1 *= c1; lw0 *= c0; lw1 *= c1;
        if (c0 < 1.f || c1 < 1.f) {
#pragma unroll
            for (int n = 0; n < 16; n++) {
                ob[n][0] *= c0; ob[n][1] *= c0; ob[n][2] *= c1; ob[n][3] *= c1;
                ow[n][0] *= c0; ow[n][1] *= c0; ow[n][2] *= c1; ow[n][3] *= c1;
            }
        }

        float sb0 = 0.f, sb1 = 0.f, sw0 = 0.f, sw1 = 0.f;
#pragma unroll
        for (int n = 0; n < 8; n++) {
            float p0 = __expf(sacc[n][0]*RSCALE - mn0);
            float p1 = __expf(sacc[n][1]*RSCALE - mn0);
            float p2 = __expf(sacc[n][2]*RSCALE - mn1);
            float p3 = __expf(sacc[n][3]*RSCALE - mn1);
            sacc[n][0] = p0; sacc[n][1] = p1; sacc[n][2] = p2; sacc[n][3] = p3;
            sb0 += p0 + p1; sb1 += p2 + p3;
            if (diag) {
                int keyc = kt + 8*n + 2*(lane & 3);
                sw0 += ((keyc   <= q0) ? p0 : 0.f) + ((keyc+1 <= q0) ? p1 : 0.f);
                sw1 += ((keyc   <= q1) ? p2 : 0.f) + ((keyc+1 <= q1) ? p3 : 0.f);
            }
        }
        sb0 += __shfl_xor_sync(0xffffffffu, sb0, 1); sb0 += __shfl_xor_sync(0xffffffffu, sb0, 2);
        sb1 += __shfl_xor_sync(0xffffffffu, sb1, 1); sb1 += __shfl_xor_sync(0xffffffffu, sb1, 2);
        lb0 += sb0; lb1 += sb1;
        if (fullwin) { lw0 += sb0; lw1 += sb1; }
        if (diag) {
            sw0 += __shfl_xor_sync(0xffffffffu, sw0, 1); sw0 += __shfl_xor_sync(0xffffffffu, sw0, 2);
            sw1 += __shfl_xor_sync(0xffffffffu, sw1, 1); sw1 += __shfl_xor_sync(0xffffffffu, sw1, 2);
            lw0 += sw0; lw1 += sw1;
        }

        // ---- P V: route each tile to exactly one stream (diag -> both) ----
        float (*dst)[4] = fullwin ? ow : ob;
#pragma unroll
        for (int j = 0; j < 4; j++) {
            float v0 = sacc[2*j][0],   v1 = sacc[2*j][1];
            float v2 = sacc[2*j][2],   v3 = sacc[2*j][3];
            float v4 = sacc[2*j+1][0], v5 = sacc[2*j+1][1];
            float v6 = sacc[2*j+1][2], v7 = sacc[2*j+1][3];
            bf16 h0 = __float2bfloat16(v0), h1 = __float2bfloat16(v1);
            bf16 h2 = __float2bfloat16(v2), h3 = __float2bfloat16(v3);
            bf16 h4 = __float2bfloat16(v4), h5 = __float2bfloat16(v5);
            bf16 h6 = __float2bfloat16(v6), h7 = __float2bfloat16(v7);
            bf16 e0 = __float2bfloat16(v0 - __bfloat162float(h0));
            bf16 e1 = __float2bfloat16(v1 - __bfloat162float(h1));
            bf16 e2 = __float2bfloat16(v2 - __bfloat162float(h2));
            bf16 e3 = __float2bfloat16(v3 - __bfloat162float(h3));
            bf16 e4 = __float2bfloat16(v4 - __bfloat162float(h4));
            bf16 e5 = __float2bfloat16(v5 - __bfloat162float(h5));
            bf16 e6 = __float2bfloat16(v6 - __bfloat162float(h6));
            bf16 e7 = __float2bfloat16(v7 - __bfloat162float(h7));
            uint32_t ph2[4] = { pk(h0,h1), pk(h2,h3), pk(h4,h5), pk(h6,h7) };
            uint32_t pl2[4] = { pk(e0,e1), pk(e2,e3), pk(e4,e5), pk(e6,e7) };
            uint32_t wh[4], wl[4], xh2[4], xl2[4];
            if (diag) {
                bf16 z = __float2bfloat16(0.f);
                int kc = kt + 16*j + 2*(lane & 3);
                bool a0 = kc   <= q0, a1 = kc+1 <= q0;
                bool b0m = kc  <= q1, b1m = kc+1 <= q1;
                bool a2 = kc+8 <= q0, a3 = kc+9 <= q0;
                bool b2m = kc+8 <= q1, b3m = kc+9 <= q1;
                wh[0] = pk(a0?h0:z, a1?h1:z);   wl[0] = pk(a0?e0:z, a1?e1:z);
                wh[1] = pk(b0m?h2:z, b1m?h3:z); wl[1] = pk(b0m?e2:z, b1m?e3:z);
                wh[2] = pk(a2?h4:z, a3?h5:z);   wl[2] = pk(a2?e4:z, a3?e5:z);
                wh[3] = pk(b2m?h6:z, b3m?h7:z); wl[3] = pk(b2m?e6:z, b3m?e7:z);
                xh2[0] = pk(a0?z:h0, a1?z:h1);   xl2[0] = pk(a0?z:e0, a1?z:e1);
                xh2[1] = pk(b0m?z:h2, b1m?z:h3); xl2[1] = pk(b0m?z:e2, b1m?z:e3);
                xh2[2] = pk(a2?z:h4, a3?z:h5);   xl2[2] = pk(a2?z:e4, a3?z:e5);
                xh2[3] = pk(b2m?z:h6, b3m?z:h7); xl2[3] = pk(b2m?z:e6, b3m?z:e7);
            }
#pragma unroll
            for (int np = 0; np < 8; np++) {
                int g2 = lane >> 3;
                int vrow = 16*j + (g2 & 1)*8 + (lane & 7);
                int vcol = np*16 + (g2 >> 1)*8;
                const bf16* vp = &bVh[vrow*VSTR + vcol];
                uint32_t vhf[4], vlf[4];
                ldsm_x4t(vhf, vp);
                ldsm_x4t(vlf, vp + 2*64*VSTR);
                if (diag) {
                    mma_bf16(ow[2*np],   wh, vhf);
                    mma_bf16(ow[2*np],   wh, vlf);
                    mma_bf16(ow[2*np],   wl, vhf);
                    mma_bf16(ow[2*np+1], wh, vhf + 2);
                    mma_bf16(ow[2*np+1], wh, vlf + 2);
                    mma_bf16(ow[2*np+1], wl, vhf + 2);
                    mma_bf16(ob[2*np],   xh2, vhf);
                    mma_bf16(ob[2*np],   xh2, vlf);
                    mma_bf16(ob[2*np],   xl2, vhf);
                    mma_bf16(ob[2*np+1], xh2, vhf + 2);
                    mma_bf16(ob[2*np+1], xh2, vlf + 2);
                    mma_bf16(ob[2*np+1], xl2, vhf + 2);
                } else {
                    mma_bf16(dst[2*np],   ph2, vhf);
                    mma_bf16(dst[2*np],   ph2, vlf);
                    mma_bf16(dst[2*np],   pl2, vhf);
                    mma_bf16(dst[2*np+1], ph2, vhf + 2);
                    mma_bf16(dst[2*np+1], ph2, vlf + 2);
                    mma_bf16(dst[2*np+1], pl2, vhf + 2);
                }
            }
        }
        __syncthreads();
    }

    // ---- epilogue: bidir = oR + oW; gate-merge; split-bf16 store ----
    float a0 = alpha[(size_t)b*TT + q0];
    float a1 = alpha[(size_t)b*TT + q1];
    float ilb0 = 1.f/lb0, ilb1 = 1.f/lb1, ilw0 = 1.f/lw0, ilw1 = 1.f/lw1;
    size_t r0o = ((size_t)b*TT + q0)*2048 + (size_t)h*128;
    size_t r1o = ((size_t)b*TT + q1)*2048 + (size_t)h*128;
#pragma unroll
    for (int n = 0; n < 16; n++) {
        int d = 8*n + 2*(lane & 3);
        float b00 = ob[n][0] + ow[n][0], b01 = ob[n][1] + ow[n][1];
        float b10 = ob[n][2] + ow[n][2], b11 = ob[n][3] + ow[n][3];
        float o00 = a0*b00*ilb0 + (1.f-a0)*ow[n][0]*ilw0;
        float o01 = a0*b01*ilb0 + (1.f-a0)*ow[n][1]*ilw0;
        float o10 = a1*b10*ilb1 + (1.f-a1)*ow[n][2]*ilw1;
        float o11 = a1*b11*ilb1 + (1.f-a1)*ow[n][3]*ilw1;
        bf16 h00 = __float2bfloat16(o00), h01 = __float2bfloat16(o01);
        bf16 h10 = __float2bfloat16(o10), h11 = __float2bfloat16(o11);
        *(uint32_t*)(mgh + r0o + d) = pk(h00, h01);
        *(uint32_t*)(mgh + r1o + d) = pk(h10, h11);
        *(uint32_t*)(mgl + r0o + d) = pk(
            __float2bfloat16(o00 - __bfloat162float(h00)),
            __float2bfloat16(o01 - __bfloat162float(h01)));
        *(uint32_t*)(mgl + r1o + d) = pk(
            __float2bfloat16(o10 - __bfloat162float(h10)),
            __float2bfloat16(o11 - __bfloat162float(h11)));
    }
}

// ---------------- launcher ----------------
extern "C" void kernel_launch(void* const* d_in, const int* in_sizes, int n_in,
                              void* d_out, int out_size)
{
    (void)in_sizes; (void)n_in;
    const float* x        = (const float*)d_in[0];
    const float* unc      = (const float*)d_in[1];
    const float* Wq_down  = (const float*)d_in[2];
    const float* q_norm_w = (const float*)d_in[3];
    const float* Wq_up    = (const float*)d_in[4];
    const float* Wq_rope  = (const float*)d_in[5];
    const float* Wkv_down = (const float*)d_in[6];
    const float* kv_norm_w= (const float*)d_in[7];
    const float* Wk_up    = (const float*)d_in[8];
    const float* Wv_up    = (const float*)d_in[9];
    const float* Wk_rope  = (const float*)d_in[10];
    const float* Wout     = (const float*)d_in[11];
    const float* Wgate    = (const float*)d_in[12];
    const float* bgate    = (const float*)d_in[13];
    float* out = (float*)d_out;

    float *qlat, *kvlat, *qcr, *kcv, *kr, *al;
    bf16 *Qh,*Ql,*Kh,*Kl,*Vh,*Vl;
    bf16 *xh,*xl,*qlh,*qll,*kvh,*kvl,*mgh,*mgl;
    bf16 *wqdh,*wqdl,*wquph,*wqupl,*wkdh,*wkdl;
    bf16 *wkvuh,*wkvul,*wkrh,*wkrl,*woh,*wol;
    cudaGetSymbolAddress((void**)&qlat,  g_qlat);
    cudaGetSymbolAddress((void**)&kvlat, g_kvlat);
    cudaGetSymbolAddress((void**)&qcr,   g_qcr);
    cudaGetSymbolAddress((void**)&kcv,   g_kcv);
    cudaGetSymbolAddress((void**)&kr,    g_kr);
    cudaGetSymbolAddress((void**)&al,    g_alpha);
    cudaGetSymbolAddress((void**)&Qh,    g_Qh);
    cudaGetSymbolAddress((void**)&Ql,    g_Ql);
    cudaGetSymbolAddress((void**)&Kh,    g_Kh);
    cudaGetSymbolAddress((void**)&Kl,    g_Kl);
    cudaGetSymbolAddress((void**)&Vh,    g_Vh);
    cudaGetSymbolAddress((void**)&Vl,    g_Vl);
    cudaGetSymbolAddress((void**)&xh,    g_xh);
    cudaGetSymbolAddress((void**)&xl,    g_xl);
    cudaGetSymbolAddress((void**)&qlh,   g_qlh);
    cudaGetSymbolAddress((void**)&qll,   g_qll);
    cudaGetSymbolAddress((void**)&kvh,   g_kvh);
    cudaGetSymbolAddress((void**)&kvl,   g_kvl);
    cudaGetSymbolAddress((void**)&mgh,   g_mgh);
    cudaGetSymbolAddress((void**)&mgl,   g_mgl);
    cudaGetSymbolAddress((void**)&wqdh,  g_wqd_h);
    cudaGetSymbolAddress((void**)&wqdl,  g_wqd_l);
    cudaGetSymbolAddress((void**)&wquph, g_wqup_h);
    cudaGetSymbolAddress((void**)&wqupl, g_wqup_l);
    cudaGetSymbolAddress((void**)&wkdh,  g_wkd_h);
    cudaGetSymbolAddress((void**)&wkdl,  g_wkd_l);
    cudaGetSymbolAddress((void**)&wkvuh, g_wkvu_h);
    cudaGetSymbolAddress((void**)&wkvul, g_wkvu_l);
    cudaGetSymbolAddress((void**)&wkrh,  g_wkr_h);
    cudaGetSymbolAddress((void**)&wkrl,  g_wkr_l);
    cudaGetSymbolAddress((void**)&woh,   g_wo_h);
    cudaGetSymbolAddress((void**)&wol,   g_wo_l);

    cudaFuncSetAttribute(attn_tc_kernel,
                         cudaFuncAttributeMaxDynamicSharedMemorySize, ATTN_SMEM);
    cudaFuncSetAttribute(gemm_split,
                         cudaFuncAttributeMaxDynamicSharedMemorySize, GS_SMEM);

    auto split = [&](const float* s, bf16* h, bf16* l, size_t n) {
        split_kernel<<<(int)(n / 1024), 256>>>(s, h, l, (int)n);
    };
    auto gemm = [&](const bf16* Ah, const bf16* Al, const bf16* Bh,
                    const bf16* Bl, float* C, int M, int N, int K) {
        gemm_split<<<dim3(N/128, M/128), 256, GS_SMEM>>>(Ah, Al, Bh, Bl, C, M, N, K);
    };

    // --- q path (ordered so launch index 5 = big merged q-up GEMM for ncu) ---
    split(x, xh, xl, (size_t)BT*DD);                                   // 0
    split(Wq_down, wqdh, wqdl, (size_t)DD*CQQ);                        // 1
    gemm(xh, xl, wqdh, wqdl, qlat, BT, CQQ, DD);                       // 2
    rmsnorm_split_kernel<<<BT, 256>>>(qlat, q_norm_w, qlh, qll, CQQ);  // 3
    merge_split_kernel<<<(CQQ*3072)/1024, 256>>>(Wq_up, Wq_rope,
        wquph, wqupl, 2048, 1024, CQQ*3072);                           // 4
    gemm(qlh, qll, wquph, wqupl, qcr, BT, 3072, CQQ);                  // 5 <- ncu

    // --- kv path ---
    split(Wkv_down, wkdh, wkdl, (size_t)DD*CKVV);
    gemm(xh, xl, wkdh, wkdl, kvlat, BT, CKVV, DD);
    rmsnorm_split_kernel<<<BT, 256>>>(kvlat, kv_norm_w, kvh, kvl, CKVV);
    merge_split_kernel<<<(CKVV*4096)/1024, 256>>>(Wk_up, Wv_up,
        wkvuh, wkvul, 2048, 2048, CKVV*4096);
    gemm(kvh, kvl, wkvuh, wkvul, kcv, BT, 4096, CKVV);

    split(Wk_rope, wkrh, wkrl, (size_t)DD*1024);
    gemm(xh, xl, wkrh, wkrl, kr, BT, 1024, DD);

    split(Wout, woh, wol, (size_t)2048*DD);

    float* out_alpha = (out_size >= BB*TT*DD + BB*TT) ? (out + (size_t)BB*TT*DD)
                                                      : nullptr;
    alpha_kernel<<<BT, 256>>>(x, Wgate, bgate, al, out_alpha);

    assemble_kernel<<<BT*NHH, 128>>>(qcr, kcv, kr, unc,
                                     Qh, Ql, Kh, Kl, Vh, Vl);

    attn_tc_kernel<<<dim3(TT/64, BB*NHH), 128, ATTN_SMEM>>>(
        Qh, Ql, Kh, Kl, Vh, Vl, al, mgh, mgl);

    gemm(mgh, mgl, woh, wol, out, BT, DD, 2048);
}

// round 8
// speedup vs baseline: 1.2044x; 1.2044x over previous
#include <cuda_runtime.h>
#include <cuda_bf16.h>
#include <math.h>
#include <stdint.h>

// ---------------- problem constants ----------------
#define BB   2
#define TT   2048
#define DD   2048
#define NHH  16
#define HDD  128
#define RR   64
#define CQQ  1536
#define CKVV 512
#define BT   (BB*TT)       // 4096
#define DQK  192           // HD + R
#define DVV  128
#define HALFW 256          // WINDOW/2
#define RSCALE 0.07216878364870323f  // 1/sqrt(192)

typedef __nv_bfloat16 bf16;

// ---------------- scratch (device globals; no runtime alloc) ----------------
__device__ float g_qlat [(size_t)BT*CQQ];
__device__ float g_kvlat[(size_t)BT*CKVV];
__device__ float g_qcr  [(size_t)BT*3072];   // [qc(2048) | qr(1024)]
__device__ float g_kcv  [(size_t)BT*4096];   // [kc(2048) | vv(2048)]
__device__ float g_kr   [(size_t)BT*NHH*RR];
__device__ float g_alpha[BT];

// attention operands, pre-split bf16, head-major: [bh][t][d]
__device__ bf16 g_Qh[(size_t)BB*NHH*TT*DQK], g_Ql[(size_t)BB*NHH*TT*DQK];
__device__ bf16 g_Kh[(size_t)BB*NHH*TT*DQK], g_Kl[(size_t)BB*NHH*TT*DQK];
__device__ bf16 g_Vh[(size_t)BB*NHH*TT*DVV], g_Vl[(size_t)BB*NHH*TT*DVV];

// bf16 split buffers (hi/lo) for GEMMs ([K,N] layout)
__device__ bf16 g_xh [(size_t)BT*DD],    g_xl [(size_t)BT*DD];
__device__ bf16 g_qlh[(size_t)BT*CQQ],   g_qll[(size_t)BT*CQQ];
__device__ bf16 g_kvh[(size_t)BT*CKVV],  g_kvl[(size_t)BT*CKVV];
__device__ bf16 g_mgh[(size_t)BT*NHH*HDD], g_mgl[(size_t)BT*NHH*HDD];
__device__ bf16 g_wqd_h [(size_t)DD*CQQ],    g_wqd_l [(size_t)DD*CQQ];
__device__ bf16 g_wqup_h[(size_t)CQQ*3072],  g_wqup_l[(size_t)CQQ*3072];
__device__ bf16 g_wkd_h [(size_t)DD*CKVV],   g_wkd_l [(size_t)DD*CKVV];
__device__ bf16 g_wkvu_h[(size_t)CKVV*4096], g_wkvu_l[(size_t)CKVV*4096];
__device__ bf16 g_wkr_h [(size_t)DD*1024],   g_wkr_l [(size_t)DD*1024];
__device__ bf16 g_wo_h  [(size_t)2048*DD],   g_wo_l  [(size_t)2048*DD];

// ---------------- ptx helpers ----------------
__device__ __forceinline__ uint32_t smem_u32(const void* p) {
    return (uint32_t)__cvta_generic_to_shared(p);
}
__device__ __forceinline__ void ldsm_x4(uint32_t* r, const void* p) {
    uint32_t a = smem_u32(p);
    asm volatile("ldmatrix.sync.aligned.m8n8.x4.shared.b16 {%0,%1,%2,%3}, [%4];"
                 : "=r"(r[0]), "=r"(r[1]), "=r"(r[2]), "=r"(r[3]) : "r"(a));
}
__device__ __forceinline__ void ldsm_x4t(uint32_t* r, const void* p) {
    uint32_t a = smem_u32(p);
    asm volatile("ldmatrix.sync.aligned.m8n8.x4.trans.shared.b16 {%0,%1,%2,%3}, [%4];"
                 : "=r"(r[0]), "=r"(r[1]), "=r"(r[2]), "=r"(r[3]) : "r"(a));
}
__device__ __forceinline__ void ldsm_x2t(uint32_t &r0, uint32_t &r1,
                                         const void* p) {
    uint32_t a = smem_u32(p);
    asm volatile("ldmatrix.sync.aligned.m8n8.x2.trans.shared.b16 {%0,%1}, [%2];"
                 : "=r"(r0), "=r"(r1) : "r"(a));
}
__device__ __forceinline__ void mma_bf16(float* c, const uint32_t* a,
                                         const uint32_t* b) {
    asm volatile(
        "mma.sync.aligned.m16n8k16.row.col.f32.bf16.bf16.f32 "
        "{%0,%1,%2,%3}, {%4,%5,%6,%7}, {%8,%9}, {%0,%1,%2,%3};"
        : "+f"(c[0]), "+f"(c[1]), "+f"(c[2]), "+f"(c[3])
        : "r"(a[0]), "r"(a[1]), "r"(a[2]), "r"(a[3]), "r"(b[0]), "r"(b[1]));
}
__device__ __forceinline__ void cpa16(void* s, const void* g) {
    asm volatile("cp.async.cg.shared.global [%0], [%1], 16;"
                 :: "r"(smem_u32(s)), "l"(g));
}
#define CP_COMMIT asm volatile("cp.async.commit_group;")
#define CP_WAIT1  asm volatile("cp.async.wait_group 1;")
#define CP_WAIT0  asm volatile("cp.async.wait_group 0;")

__device__ __forceinline__ uint32_t pk(bf16 a, bf16 b) {
    __nv_bfloat162 t(a, b);
    return *reinterpret_cast<uint32_t*>(&t);
}

// ---------------- split fp32 -> (hi, lo) bf16 ----------------
__global__ __launch_bounds__(256) void split_kernel(
    const float* __restrict__ s, bf16* __restrict__ h,
    bf16* __restrict__ l, int n)
{
    int i = (blockIdx.x * 256 + threadIdx.x) * 4;
    if (i >= n) return;
    float4 v = *(const float4*)(s + i);
    bf16 h0 = __float2bfloat16(v.x), h1 = __float2bfloat16(v.y);
    bf16 h2 = __float2bfloat16(v.z), h3 = __float2bfloat16(v.w);
    *(__nv_bfloat162*)(h + i)     = __nv_bfloat162(h0, h1);
    *(__nv_bfloat162*)(h + i + 2) = __nv_bfloat162(h2, h3);
    *(__nv_bfloat162*)(l + i) = __nv_bfloat162(
        __float2bfloat16(v.x - __bfloat162float(h0)),
        __float2bfloat16(v.y - __bfloat162float(h1)));
    *(__nv_bfloat162*)(l + i + 2) = __nv_bfloat162(
        __float2bfloat16(v.z - __bfloat162float(h2)),
        __float2bfloat16(v.w - __bfloat162float(h3)));
}

// ---------------- merge two [K,N*] weights into one split [K,N1+N2] --------
__global__ __launch_bounds__(256) void merge_split_kernel(
    const float* __restrict__ W1, const float* __restrict__ W2,
    bf16* __restrict__ h, bf16* __restrict__ l, int N1, int N2, int total)
{
    int i = (blockIdx.x * 256 + threadIdx.x) * 4;
    if (i >= total) return;
    int Nt = N1 + N2;
    int k = i / Nt, n = i % Nt;
    const float* src = (n < N1) ? (W1 + (size_t)k * N1 + n)
                                : (W2 + (size_t)k * N2 + (n - N1));
    float4 v = *(const float4*)src;
    bf16 h0 = __float2bfloat16(v.x), h1 = __float2bfloat16(v.y);
    bf16 h2 = __float2bfloat16(v.z), h3 = __float2bfloat16(v.w);
    *(__nv_bfloat162*)(h + i)     = __nv_bfloat162(h0, h1);
    *(__nv_bfloat162*)(h + i + 2) = __nv_bfloat162(h2, h3);
    *(__nv_bfloat162*)(l + i) = __nv_bfloat162(
        __float2bfloat16(v.x - __bfloat162float(h0)),
        __float2bfloat16(v.y - __bfloat162float(h1)));
    *(__nv_bfloat162*)(l + i + 2) = __nv_bfloat162(
        __float2bfloat16(v.z - __bfloat162float(h2)),
        __float2bfloat16(v.w - __bfloat162float(h3)));
}

// ---------------- split-bf16 TC GEMM, 2-stage cp.async pipeline ------------
#define GS_A   (128*40)
#define GS_B   (32*136)
#define GS_STG (2*GS_A + 2*GS_B)
#define GS_SMEM (2*GS_STG*2)

__global__ __launch_bounds__(256) void gemm_split(
    const bf16* __restrict__ Ah, const bf16* __restrict__ Al,
    const bf16* __restrict__ Bh, const bf16* __restrict__ Bl,
    float* __restrict__ C, int M, int N, int K)
{
    extern __shared__ __align__(16) bf16 gsm[];

    int tid = threadIdx.x;
    int bm = blockIdx.y, bn = blockIdx.x;
    int warp = tid >> 5, lane = tid & 31;
    int wm = warp >> 2, wn = warp & 3;

    int arow = tid >> 2, ac = (tid & 3) * 8;
    int brow = tid >> 4, bc = (tid & 15) * 8;

    float acc[4][4][4];
#pragma unroll
    for (int a = 0; a < 4; a++)
#pragma unroll
        for (int b = 0; b < 4; b++)
#pragma unroll
            for (int c = 0; c < 4; c++) acc[a][b][c] = 0.f;

    int nk = K >> 5;

    auto issue = [&](int stage, int k0) {
        bf16* sAh = gsm + stage * GS_STG;
        bf16* sAl = sAh + GS_A;
        bf16* sBh = sAl + GS_A;
        bf16* sBl = sBh + GS_B;
#pragma unroll
        for (int i = 0; i < 2; i++) {
            int r = arow + i * 64;
            size_t g = (size_t)(bm * 128 + r) * K + k0 + ac;
            cpa16(&sAh[r * 40 + ac], Ah + g);
            cpa16(&sAl[r * 40 + ac], Al + g);
        }
#pragma unroll
        for (int i = 0; i < 2; i++) {
            int r = brow + i * 16;
            size_t g = (size_t)(k0 + r) * N + bn * 128 + bc;
            cpa16(&sBh[r * 136 + bc], Bh + g);
            cpa16(&sBl[r * 136 + bc], Bl + g);
        }
    };

    issue(0, 0);
    CP_COMMIT;

    for (int it = 0; it < nk; it++) {
        if (it + 1 < nk) {
            issue((it + 1) & 1, (it + 1) << 5);
            CP_COMMIT;
            CP_WAIT1;
        } else {
            CP_WAIT0;
        }
        __syncthreads();

        bf16* sAh = gsm + (it & 1) * GS_STG;
        bf16* sAl = sAh + GS_A;
        bf16* sBh = sAl + GS_A;
        bf16* sBl = sBh + GS_B;

#pragma unroll
        for (int kh = 0; kh < 2; kh++) {
            uint32_t bhf[4][2], blf[4][2];
#pragma unroll
            for (int nt = 0; nt < 4; nt++) {
                int br = kh * 16 + (lane & 15);
                int bcl = wn * 32 + nt * 8;
                ldsm_x2t(bhf[nt][0], bhf[nt][1], &sBh[br * 136 + bcl]);
                ldsm_x2t(blf[nt][0], blf[nt][1], &sBl[br * 136 + bcl]);
            }
#pragma unroll
            for (int mt = 0; mt < 4; mt++) {
                int ar = wm * 64 + mt * 16 + (lane & 15);
                int acl = kh * 16 + (lane >> 4) * 8;
                uint32_t ah[4], al[4];
                ldsm_x4(ah, &sAh[ar * 40 + acl]);
                ldsm_x4(al, &sAl[ar * 40 + acl]);
#pragma unroll
                for (int nt = 0; nt < 4; nt++) {
                    mma_bf16(acc[mt][nt], ah, bhf[nt]);
                    mma_bf16(acc[mt][nt], ah, blf[nt]);
                    mma_bf16(acc[mt][nt], al, bhf[nt]);
                }
            }
        }
        __syncthreads();
    }

#pragma unroll
    for (int mt = 0; mt < 4; mt++) {
#pragma unroll
        for (int nt = 0; nt < 4; nt++) {
            int r0 = bm * 128 + wm * 64 + mt * 16 + (lane >> 2);
            int c0 = bn * 128 + wn * 32 + nt * 8 + (lane & 3) * 2;
            *(float2*)&C[(size_t)r0 * N + c0] =
                make_float2(acc[mt][nt][0], acc[mt][nt][1]);
            *(float2*)&C[(size_t)(r0 + 8) * N + c0] =
                make_float2(acc[mt][nt][2], acc[mt][nt][3]);
        }
    }
}

// ---------------- RMSNorm -> split bf16 outputs ----------------
__global__ __launch_bounds__(256) void rmsnorm_split_kernel(
    const float* __restrict__ x, const float* __restrict__ w,
    bf16* __restrict__ hi, bf16* __restrict__ lo, int n)
{
    const float* row = x + (size_t)blockIdx.x * n;
    float ss = 0.f;
    for (int i = threadIdx.x; i < n; i += 256) { float v = row[i]; ss += v*v; }
    __shared__ float sh[8];
    __shared__ float tot;
    int lane = threadIdx.x & 31, wp = threadIdx.x >> 5;
#pragma unroll
    for (int o = 16; o; o >>= 1) ss += __shfl_xor_sync(0xffffffffu, ss, o);
    if (lane == 0) sh[wp] = ss;
    __syncthreads();
    if (threadIdx.x == 0) {
        float s = 0.f;
        for (int i = 0; i < 8; i++) s += sh[i];
        tot = rsqrtf(s / n + 1e-6f);
    }
    __syncthreads();
    float rs = tot;
    bf16* hrow = hi + (size_t)blockIdx.x * n;
    bf16* lrow = lo + (size_t)blockIdx.x * n;
    for (int i = threadIdx.x; i < n; i += 256) {
        float y = row[i] * rs * w[i];
        bf16 h = __float2bfloat16(y);
        hrow[i] = h;
        lrow[i] = __float2bfloat16(y - __bfloat162float(h));
    }
}

// ---------------- gate alpha ----------------
__global__ __launch_bounds__(256) void alpha_kernel(
    const float* __restrict__ x, const float* __restrict__ wg,
    const float* __restrict__ bg, float* __restrict__ alpha,
    float* __restrict__ out_alpha)
{
    const float* row = x + (size_t)blockIdx.x * DD;
    float s = 0.f;
    for (int i = threadIdx.x; i < DD; i += 256) s += row[i] * wg[i];
    __shared__ float sh[8];
    int lane = threadIdx.x & 31, wp = threadIdx.x >> 5;
#pragma unroll
    for (int o = 16; o; o >>= 1) s += __shfl_xor_sync(0xffffffffu, s, o);
    if (lane == 0) sh[wp] = s;
    __syncthreads();
    if (threadIdx.x == 0) {
        float t = 0.f;
        for (int i = 0; i < 8; i++) t += sh[i];
        float z = t + bg[0];
        float a = 1.f / (1.f + expf(-z));
        alpha[blockIdx.x] = a;
        if (out_alpha) out_alpha[blockIdx.x] = a;
    }
}

// ---------------- assemble Q/K/V with EPE-RoPE (emit split bf16) -----------
__global__ __launch_bounds__(128) void assemble_kernel(
    const float* __restrict__ qcr, const float* __restrict__ kcv,
    const float* __restrict__ kr, const float* __restrict__ unc,
    bf16* __restrict__ Qh, bf16* __restrict__ Ql,
    bf16* __restrict__ Kh, bf16* __restrict__ Kl,
    bf16* __restrict__ Vh, bf16* __restrict__ Vl)
{
    int idx = blockIdx.x;
    int h  = idx % NHH;
    int bt = idx / NHH;
    int t  = bt % TT;
    int b  = bt / TT;
    __shared__ float cs[32], sn[32];
    int d = threadIdx.x;
    if (d < 32) {
        float u = unc[bt];
        u = fminf(fmaxf(u, 0.f), 1.f);
        float scale = 0.5f + 1.5f * u;
        float fi = (float)d / 32.0f;
        float theta = expf(-fi * logf(500000.0f));
        float fr = (float)t * theta * scale;
        cs[d] = cosf(fr);
        sn[d] = sinf(fr);
    }
    __syncthreads();
    size_t qkrow = ((size_t)(b*NHH + h))*TT + t;

    float qv0 = qcr[(size_t)bt*3072 + h*128 + d];
    float kv0 = kcv[(size_t)bt*4096 + h*128 + d];
    float vv0 = kcv[(size_t)bt*4096 + 2048 + h*128 + d];
    bf16 hh;
    hh = __float2bfloat16(qv0);
    Qh[qkrow*DQK + d] = hh; Ql[qkrow*DQK + d] = __float2bfloat16(qv0 - __bfloat162float(hh));
    hh = __float2bfloat16(kv0);
    Kh[qkrow*DQK + d] = hh; Kl[qkrow*DQK + d] = __float2bfloat16(kv0 - __bfloat162float(hh));
    hh = __float2bfloat16(vv0);
    Vh[qkrow*DVV + d] = hh; Vl[qkrow*DVV + d] = __float2bfloat16(vv0 - __bfloat162float(hh));

    if (d < 64) {
        const float* qrp = qcr + (size_t)bt*3072 + 2048 + h*64;
        const float* krp = kr  + (size_t)bt*1024 + h*64;
        float qv, kv;
        if (d < 32) {
            float c = cs[d], s = sn[d];
            qv = qrp[d]*c - qrp[d+32]*s;
            kv = krp[d]*c - krp[d+32]*s;
        } else {
            int j = d - 32;
            float c = cs[j], s = sn[j];
            qv = qrp[j+32]*c + qrp[j]*s;
            kv = krp[j+32]*c + krp[j]*s;
        }
        hh = __float2bfloat16(qv);
        Qh[qkrow*DQK + 128 + d] = hh;
        Ql[qkrow*DQK + 128 + d] = __float2bfloat16(qv - __bfloat162float(hh));
        hh = __float2bfloat16(kv);
        Kh[qkrow*DQK + 128 + d] = hh;
        Kl[qkrow*DQK + 128 + d] = __float2bfloat16(kv - __bfloat162float(hh));
    }
}

// ---------------- tensor-core fused dual attention ----------------
// Streams: oR(ob) = bidir-only keys, oW(ow) = window keys; bidir = ob + ow.
// All accumulator writes name ob/ow DIRECTLY (block-uniform branches, no
// pointer indirection -> arrays stay in registers).
#define KSTR 200
#define VSTR 136
#define ATTN_SMEM ((64*KSTR*2 + 2*64*KSTR*2 + 2*64*VSTR*2) * 2)

__global__ void __launch_bounds__(128, 1) attn_tc_kernel(
    const bf16* __restrict__ Qh, const bf16* __restrict__ Ql,
    const bf16* __restrict__ Kh, const bf16* __restrict__ Kl,
    const bf16* __restrict__ Vh, const bf16* __restrict__ Vl,
    const float* __restrict__ alpha,
    bf16* __restrict__ mgh, bf16* __restrict__ mgl)
{
    extern __shared__ __align__(16) bf16 smem[];
    bf16* sQh = smem;
    bf16* sQl = sQh + 64*KSTR;
    bf16* sKh = sQl + 64*KSTR;
    bf16* sKl = sKh + 2*64*KSTR;
    bf16* sVh = sKl + 2*64*KSTR;
    bf16* sVl = sVh + 2*64*VSTR;

    int tid = threadIdx.x, lane = tid & 31, warp = tid >> 5;
    int qt = blockIdx.x * 64;
    int bh = blockIdx.y;
    int b = bh >> 4, h = bh & 15;
    size_t base = (size_t)bh * TT;

    for (int i = tid; i < 64*24; i += 128) {
        int r = i / 24, c = (i % 24) * 8;
        size_t g = (base + qt + r) * DQK + c;
        cpa16(&sQh[r*KSTR + c], Qh + g);
        cpa16(&sQl[r*KSTR + c], Ql + g);
    }
    for (int i = tid; i < 64*24; i += 128) {
        int r = i / 24, c = (i % 24) * 8;
        size_t g = (base + r) * DQK + c;
        cpa16(&sKh[r*KSTR + c], Kh + g);
        cpa16(&sKl[r*KSTR + c], Kl + g);
    }
    for (int i = tid; i < 64*16; i += 128) {
        int r = i / 16, c = (i % 16) * 8;
        size_t g = (base + r) * DVV + c;
        cpa16(&sVh[r*VSTR + c], Vh + g);
        cpa16(&sVl[r*VSTR + c], Vl + g);
    }
    CP_COMMIT;

    int q0 = qt + 16*warp + (lane >> 2);
    int q1 = q0 + 8;
    int winlo = ((qt >> 8) << 8) - HALFW;
    if (winlo < 0) winlo = 0;

    float ob[16][4], ow[16][4];
#pragma unroll
    for (int n = 0; n < 16; n++)
#pragma unroll
        for (int j = 0; j < 4; j++) { ob[n][j] = 0.f; ow[n][j] = 0.f; }
    float m0 = -1e30f, m1 = -1e30f;
    float lb0 = 0.f, lb1 = 0.f, lw0 = 0.f, lw1 = 0.f;

    for (int t = 0; t < 32; t++) {
        int kt = t * 64;
        int nb = (t + 1) & 1;
        if (t + 1 < 32) {
            int kn = kt + 64;
            for (int i = tid; i < 64*24; i += 128) {
                int r = i / 24, c = (i % 24) * 8;
                size_t g = (base + kn + r) * DQK + c;
                cpa16(&sKh[nb*64*KSTR + r*KSTR + c], Kh + g);
                cpa16(&sKl[nb*64*KSTR + r*KSTR + c], Kl + g);
            }
            for (int i = tid; i < 64*16; i += 128) {
                int r = i / 16, c = (i % 16) * 8;
                size_t g = (base + kn + r) * DVV + c;
                cpa16(&sVh[nb*64*VSTR + r*VSTR + c], Vh + g);
                cpa16(&sVl[nb*64*VSTR + r*VSTR + c], Vl + g);
            }
        }
        CP_COMMIT;
        CP_WAIT1;
        __syncthreads();

        const bf16* bKh = sKh + (t & 1) * 64 * KSTR;
        const bf16* bVh = sVh + (t & 1) * 64 * VSTR;

        bool diag    = (kt == qt);
        bool fullwin = (kt >= winlo) && (kt < qt);

        // ---- S = Q K^T (3 split chains) ----
        float sacc[8][4];
#pragma unroll
        for (int n = 0; n < 8; n++)
#pragma unroll
            for (int j = 0; j < 4; j++) sacc[n][j] = 0.f;

#pragma unroll
        for (int ks = 0; ks < 12; ks++) {
            uint32_t qhf[4], qlf[4];
            const bf16* ap = &sQh[(16*warp + (lane & 15))*KSTR + ks*16 + (lane >> 4)*8];
            ldsm_x4(qhf, ap);
            ldsm_x4(qlf, ap + 64*KSTR);
#pragma unroll
            for (int np = 0; np < 4; np++) {
                int g2 = lane >> 3;
                int krow = np*16 + (g2 >> 1)*8 + (lane & 7);
                int kcol = ks*16 + (g2 & 1)*8;
                const bf16* bp = &bKh[krow*KSTR + kcol];
                uint32_t khf[4], klf[4];
                ldsm_x4(khf, bp);
                ldsm_x4(klf, bp + 2*64*KSTR);
                mma_bf16(sacc[2*np],   qhf, khf);
                mma_bf16(sacc[2*np],   qhf, klf);
                mma_bf16(sacc[2*np],   qlf, khf);
                mma_bf16(sacc[2*np+1], qhf, khf + 2);
                mma_bf16(sacc[2*np+1], qhf, klf + 2);
                mma_bf16(sacc[2*np+1], qlf, khf + 2);
            }
        }

        // ---- online softmax ----
        float tm0 = -1e30f, tm1 = -1e30f;
#pragma unroll
        for (int n = 0; n < 8; n++) {
            tm0 = fmaxf(tm0, fmaxf(sacc[n][0], sacc[n][1]));
            tm1 = fmaxf(tm1, fmaxf(sacc[n][2], sacc[n][3]));
        }
        tm0 *= RSCALE; tm1 *= RSCALE;
        tm0 = fmaxf(tm0, __shfl_xor_sync(0xffffffffu, tm0, 1));
        tm0 = fmaxf(tm0, __shfl_xor_sync(0xffffffffu, tm0, 2));
        tm1 = fmaxf(tm1, __shfl_xor_sync(0xffffffffu, tm1, 1));
        tm1 = fmaxf(tm1, __shfl_xor_sync(0xffffffffu, tm1, 2));
        float mn0 = fmaxf(m0, tm0), mn1 = fmaxf(m1, tm1);
        float c0 = __expf(m0 - mn0), c1 = __expf(m1 - mn1);
        m0 = mn0; m1 = mn1;
        lb0 *= c0; lb1 *= c1; lw0 *= c0; lw1 *= c1;
        if (c0 < 1.f || c1 < 1.f) {
#pragma unroll
            for (int n = 0; n < 16; n++) {
                ob[n][0] *= c0; ob[n][1] *= c0; ob[n][2] *= c1; ob[n][3] *= c1;
                ow[n][0] *= c0; ow[n][1] *= c0; ow[n][2] *= c1; ow[n][3] *= c1;
            }
        }

        float sb0 = 0.f, sb1 = 0.f, sw0 = 0.f, sw1 = 0.f;
#pragma unroll
        for (int n = 0; n < 8; n++) {
            float p0 = __expf(sacc[n][0]*RSCALE - mn0);
            float p1 = __expf(sacc[n][1]*RSCALE - mn0);
            float p2 = __expf(sacc[n][2]*RSCALE - mn1);
            float p3 = __expf(sacc[n][3]*RSCALE - mn1);
            sacc[n][0] = p0; sacc[n][1] = p1; sacc[n][2] = p2; sacc[n][3] = p3;
            sb0 += p0 + p1; sb1 += p2 + p3;
            if (diag) {
                int keyc = kt + 8*n + 2*(lane & 3);
                sw0 += ((keyc   <= q0) ? p0 : 0.f) + ((keyc+1 <= q0) ? p1 : 0.f);
                sw1 += ((keyc   <= q1) ? p2 : 0.f) + ((keyc+1 <= q1) ? p3 : 0.f);
            }
        }
        sb0 += __shfl_xor_sync(0xffffffffu, sb0, 1); sb0 += __shfl_xor_sync(0xffffffffu, sb0, 2);
        sb1 += __shfl_xor_sync(0xffffffffu, sb1, 1); sb1 += __shfl_xor_sync(0xffffffffu, sb1, 2);
        lb0 += sb0; lb1 += sb1;
        if (fullwin) { lw0 += sb0; lw1 += sb1; }
        if (diag) {
            sw0 += __shfl_xor_sync(0xffffffffu, sw0, 1); sw0 += __shfl_xor_sync(0xffffffffu, sw0, 2);
            sw1 += __shfl_xor_sync(0xffffffffu, sw1, 1); sw1 += __shfl_xor_sync(0xffffffffu, sw1, 2);
            lw0 += sw0; lw1 += sw1;
        }

        // ---- P V: tile routed by block-uniform branch; direct reg arrays ----
#pragma unroll
        for (int j = 0; j < 4; j++) {
            float v0 = sacc[2*j][0],   v1 = sacc[2*j][1];
            float v2 = sacc[2*j][2],   v3 = sacc[2*j][3];
            float v4 = sacc[2*j+1][0], v5 = sacc[2*j+1][1];
            float v6 = sacc[2*j+1][2], v7 = sacc[2*j+1][3];
            bf16 h0 = __float2bfloat16(v0), h1 = __float2bfloat16(v1);
            bf16 h2 = __float2bfloat16(v2), h3 = __float2bfloat16(v3);
            bf16 h4 = __float2bfloat16(v4), h5 = __float2bfloat16(v5);
            bf16 h6 = __float2bfloat16(v6), h7 = __float2bfloat16(v7);
            bf16 e0 = __float2bfloat16(v0 - __bfloat162float(h0));
            bf16 e1 = __float2bfloat16(v1 - __bfloat162float(h1));
            bf16 e2 = __float2bfloat16(v2 - __bfloat162float(h2));
            bf16 e3 = __float2bfloat16(v3 - __bfloat162float(h3));
            bf16 e4 = __float2bfloat16(v4 - __bfloat162float(h4));
            bf16 e5 = __float2bfloat16(v5 - __bfloat162float(h5));
            bf16 e6 = __float2bfloat16(v6 - __bfloat162float(h6));
            bf16 e7 = __float2bfloat16(v7 - __bfloat162float(h7));
            uint32_t ph2[4] = { pk(h0,h1), pk(h2,h3), pk(h4,h5), pk(h6,h7) };
            uint32_t pl2[4] = { pk(e0,e1), pk(e2,e3), pk(e4,e5), pk(e6,e7) };

            if (diag) {
                bf16 z = __float2bfloat16(0.f);
                int kc = kt + 16*j + 2*(lane & 3);
                bool a0 = kc   <= q0, a1 = kc+1 <= q0;
                bool b0m = kc  <= q1, b1m = kc+1 <= q1;
                bool a2 = kc+8 <= q0, a3 = kc+9 <= q0;
                bool b2m = kc+8 <= q1, b3m = kc+9 <= q1;
                uint32_t wh[4], wl[4], xh2[4], xl2[4];
                wh[0] = pk(a0?h0:z, a1?h1:z);   wl[0] = pk(a0?e0:z, a1?e1:z);
                wh[1] = pk(b0m?h2:z, b1m?h3:z); wl[1] = pk(b0m?e2:z, b1m?e3:z);
                wh[2] = pk(a2?h4:z, a3?h5:z);   wl[2] = pk(a2?e4:z, a3?e5:z);
                wh[3] = pk(b2m?h6:z, b3m?h7:z); wl[3] = pk(b2m?e6:z, b3m?e7:z);
                xh2[0] = pk(a0?z:h0, a1?z:h1);   xl2[0] = pk(a0?z:e0, a1?z:e1);
                xh2[1] = pk(b0m?z:h2, b1m?z:h3); xl2[1] = pk(b0m?z:e2, b1m?z:e3);
                xh2[2] = pk(a2?z:h4, a3?z:h5);   xl2[2] = pk(a2?z:e4, a3?z:e5);
                xh2[3] = pk(b2m?z:h6, b3m?z:h7); xl2[3] = pk(b2m?z:e6, b3m?z:e7);
#pragma unroll
                for (int np = 0; np < 8; np++) {
                    int g2 = lane >> 3;
                    int vrow = 16*j + (g2 & 1)*8 + (lane & 7);
                    int vcol = np*16 + (g2 >> 1)*8;
                    const bf16* vp = &bVh[vrow*VSTR + vcol];
                    uint32_t vhf[4], vlf[4];
                    ldsm_x4t(vhf, vp);
                    ldsm_x4t(vlf, vp + 2*64*VSTR);
                    mma_bf16(ow[2*np],   wh, vhf);
                    mma_bf16(ow[2*np],   wh, vlf);
                    mma_bf16(ow[2*np],   wl, vhf);
                    mma_bf16(ow[2*np+1], wh, vhf + 2);
                    mma_bf16(ow[2*np+1], wh, vlf + 2);
                    mma_bf16(ow[2*np+1], wl, vhf + 2);
                    mma_bf16(ob[2*np],   xh2, vhf);
                    mma_bf16(ob[2*np],   xh2, vlf);
                    mma_bf16(ob[2*np],   xl2, vhf);
                    mma_bf16(ob[2*np+1], xh2, vhf + 2);
                    mma_bf16(ob[2*np+1], xh2, vlf + 2);
                    mma_bf16(ob[2*np+1], xl2, vhf + 2);
                }
            } else if (fullwin) {
#pragma unroll
                for (int np = 0; np < 8; np++) {
                    int g2 = lane >> 3;
                    int vrow = 16*j + (g2 & 1)*8 + (lane & 7);
                    int vcol = np*16 + (g2 >> 1)*8;
                    const bf16* vp = &bVh[vrow*VSTR + vcol];
                    uint32_t vhf[4], vlf[4];
                    ldsm_x4t(vhf, vp);
                    ldsm_x4t(vlf, vp + 2*64*VSTR);
                    mma_bf16(ow[2*np],   ph2, vhf);
                    mma_bf16(ow[2*np],   ph2, vlf);
                    mma_bf16(ow[2*np],   pl2, vhf);
                    mma_bf16(ow[2*np+1], ph2, vhf + 2);
                    mma_bf16(ow[2*np+1], ph2, vlf + 2);
                    mma_bf16(ow[2*np+1], pl2, vhf + 2);
                }
            } else {
#pragma unroll
                for (int np = 0; np < 8; np++) {
                    int g2 = lane >> 3;
                    int vrow = 16*j + (g2 & 1)*8 + (lane & 7);
                    int vcol = np*16 + (g2 >> 1)*8;
                    const bf16* vp = &bVh[vrow*VSTR + vcol];
                    uint32_t vhf[4], vlf[4];
                    ldsm_x4t(vhf, vp);
                    ldsm_x4t(vlf, vp + 2*64*VSTR);
                    mma_bf16(ob[2*np],   ph2, vhf);
                    mma_bf16(ob[2*np],   ph2, vlf);
                    mma_bf16(ob[2*np],   pl2, vhf);
                    mma_bf16(ob[2*np+1], ph2, vhf + 2);
                    mma_bf16(ob[2*np+1], ph2, vlf + 2);
                    mma_bf16(ob[2*np+1], pl2, vhf + 2);
                }
            }
        }
        __syncthreads();
    }

    // ---- epilogue: bidir = ob + ow; gate-merge; split-bf16 store ----
    float a0 = alpha[(size_t)b*TT + q0];
    float a1 = alpha[(size_t)b*TT + q1];
    float ilb0 = 1.f/lb0, ilb1 = 1.f/lb1, ilw0 = 1.f/lw0, ilw1 = 1.f/lw1;
    size_t r0o = ((size_t)b*TT + q0)*2048 + (size_t)h*128;
    size_t r1o = ((size_t)b*TT + q1)*2048 + (size_t)h*128;
#pragma unroll
    for (int n = 0; n < 16; n++) {
        int d = 8*n + 2*(lane & 3);
        float b00 = ob[n][0] + ow[n][0], b01 = ob[n][1] + ow[n][1];
        float b10 = ob[n][2] + ow[n][2], b11 = ob[n][3] + ow[n][3];
        float o00 = a0*b00*ilb0 + (1.f-a0)*ow[n][0]*ilw0;
        float o01 = a0*b01*ilb0 + (1.f-a0)*ow[n][1]*ilw0;
        float o10 = a1*b10*ilb1 + (1.f-a1)*ow[n][2]*ilw1;
        float o11 = a1*b11*ilb1 + (1.f-a1)*ow[n][3]*ilw1;
        bf16 h00 = __float2bfloat16(o00), h01 = __float2bfloat16(o01);
        bf16 h10 = __float2bfloat16(o10), h11 = __float2bfloat16(o11);
        *(uint32_t*)(mgh + r0o + d) = pk(h00, h01);
        *(uint32_t*)(mgh + r1o + d) = pk(h10, h11);
        *(uint32_t*)(mgl + r0o + d) = pk(
            __float2bfloat16(o00 - __bfloat162float(h00)),
            __float2bfloat16(o01 - __bfloat162float(h01)));
        *(uint32_t*)(mgl + r1o + d) = pk(
            __float2bfloat16(o10 - __bfloat162float(h10)),
            __float2bfloat16(o11 - __bfloat162float(h11)));
    }
}

// ---------------- launcher ----------------
extern "C" void kernel_launch(void* const* d_in, const int* in_sizes, int n_in,
                              void* d_out, int out_size)
{
    (void)in_sizes; (void)n_in;
    const float* x        = (const float*)d_in[0];
    const float* unc      = (const float*)d_in[1];
    const float* Wq_down  = (const float*)d_in[2];
    const float* q_norm_w = (const float*)d_in[3];
    const float* Wq_up    = (const float*)d_in[4];
    const float* Wq_rope  = (const float*)d_in[5];
    const float* Wkv_down = (const float*)d_in[6];
    const float* kv_norm_w= (const float*)d_in[7];
    const float* Wk_up    = (const float*)d_in[8];
    const float* Wv_up    = (const float*)d_in[9];
    const float* Wk_rope  = (const float*)d_in[10];
    const float* Wout     = (const float*)d_in[11];
    const float* Wgate    = (const float*)d_in[12];
    const float* bgate    = (const float*)d_in[13];
    float* out = (float*)d_out;

    float *qlat, *kvlat, *qcr, *kcv, *kr, *al;
    bf16 *Qh,*Ql,*Kh,*Kl,*Vh,*Vl;
    bf16 *xh,*xl,*qlh,*qll,*kvh,*kvl,*mgh,*mgl;
    bf16 *wqdh,*wqdl,*wquph,*wqupl,*wkdh,*wkdl;
    bf16 *wkvuh,*wkvul,*wkrh,*wkrl,*woh,*wol;
    cudaGetSymbolAddress((void**)&qlat,  g_qlat);
    cudaGetSymbolAddress((void**)&kvlat, g_kvlat);
    cudaGetSymbolAddress((void**)&qcr,   g_qcr);
    cudaGetSymbolAddress((void**)&kcv,   g_kcv);
    cudaGetSymbolAddress((void**)&kr,    g_kr);
    cudaGetSymbolAddress((void**)&al,    g_alpha);
    cudaGetSymbolAddress((void**)&Qh,    g_Qh);
    cudaGetSymbolAddress((void**)&Ql,    g_Ql);
    cudaGetSymbolAddress((void**)&Kh,    g_Kh);
    cudaGetSymbolAddress((void**)&Kl,    g_Kl);
    cudaGetSymbolAddress((void**)&Vh,    g_Vh);
    cudaGetSymbolAddress((void**)&Vl,    g_Vl);
    cudaGetSymbolAddress((void**)&xh,    g_xh);
    cudaGetSymbolAddress((void**)&xl,    g_xl);
    cudaGetSymbolAddress((void**)&qlh,   g_qlh);
    cudaGetSymbolAddress((void**)&qll,   g_qll);
    cudaGetSymbolAddress((void**)&kvh,   g_kvh);
    cudaGetSymbolAddress((void**)&kvl,   g_kvl);
    cudaGetSymbolAddress((void**)&mgh,   g_mgh);
    cudaGetSymbolAddress((void**)&mgl,   g_mgl);
    cudaGetSymbolAddress((void**)&wqdh,  g_wqd_h);
    cudaGetSymbolAddress((void**)&wqdl,  g_wqd_l);
    cudaGetSymbolAddress((void**)&wquph, g_wqup_h);
    cudaGetSymbolAddress((void**)&wqupl, g_wqup_l);
    cudaGetSymbolAddress((void**)&wkdh,  g_wkd_h);
    cudaGetSymbolAddress((void**)&wkdl,  g_wkd_l);
    cudaGetSymbolAddress((void**)&wkvuh, g_wkvu_h);
    cudaGetSymbolAddress((void**)&wkvul, g_wkvu_l);
    cudaGetSymbolAddress((void**)&wkrh,  g_wkr_h);
    cudaGetSymbolAddress((void**)&wkrl,  g_wkr_l);
    cudaGetSymbolAddress((void**)&woh,   g_wo_h);
    cudaGetSymbolAddress((void**)&wol,   g_wo_l);

    cudaFuncSetAttribute(attn_tc_kernel,
                         cudaFuncAttributeMaxDynamicSharedMemorySize, ATTN_SMEM);
    cudaFuncSetAttribute(gemm_split,
                         cudaFuncAttributeMaxDynamicSharedMemorySize, GS_SMEM);

    auto split = [&](const float* s, bf16* h, bf16* l, size_t n) {
        split_kernel<<<(int)(n / 1024), 256>>>(s, h, l, (int)n);
    };
    auto gemm = [&](const bf16* Ah, const bf16* Al, const bf16* Bh,
                    const bf16* Bl, float* C, int M, int N, int K) {
        gemm_split<<<dim3(N/128, M/128), 256, GS_SMEM>>>(Ah, Al, Bh, Bl, C, M, N, K);
    };

    split(x, xh, xl, (size_t)BT*DD);
    split(Wq_down, wqdh, wqdl, (size_t)DD*CQQ);
    gemm(xh, xl, wqdh, wqdl, qlat, BT, CQQ, DD);
    rmsnorm_split_kernel<<<BT, 256>>>(qlat, q_norm_w, qlh, qll, CQQ);
    merge_split_kernel<<<(CQQ*3072)/1024, 256>>>(Wq_up, Wq_rope,
        wquph, wqupl, 2048, 1024, CQQ*3072);
    gemm(qlh, qll, wquph, wqupl, qcr, BT, 3072, CQQ);

    split(Wkv_down, wkdh, wkdl, (size_t)DD*CKVV);
    gemm(xh, xl, wkdh, wkdl, kvlat, BT, CKVV, DD);
    rmsnorm_split_kernel<<<BT, 256>>>(kvlat, kv_norm_w, kvh, kvl, CKVV);
    merge_split_kernel<<<(CKVV*4096)/1024, 256>>>(Wk_up, Wv_up,
        wkvuh, wkvul, 2048, 2048, CKVV*4096);
    gemm(kvh, kvl, wkvuh, wkvul, kcv, BT, 4096, CKVV);

    split(Wk_rope, wkrh, wkrl, (size_t)DD*1024);
    gemm(xh, xl, wkrh, wkrl, kr, BT, 1024, DD);

    split(Wout, woh, wol, (size_t)2048*DD);

    float* out_alpha = (out_size >= BB*TT*DD + BB*TT) ? (out + (size_t)BB*TT*DD)
                                                      : nullptr;
    alpha_kernel<<<BT, 256>>>(x, Wgate, bgate, al, out_alpha);

    assemble_kernel<<<BT*NHH, 128>>>(qcr, kcv, kr, unc,
                                     Qh, Ql, Kh, Kl, Vh, Vl);

    attn_tc_kernel<<<dim3(TT/64, BB*NHH), 128, ATTN_SMEM>>>(
        Qh, Ql, Kh, Kl, Vh, Vl, al, mgh, mgl);

    gemm(mgh, mgl, woh, wol, out, BT, DD, 2048);
}

// round 9
// speedup vs baseline: 1.2126x; 1.0068x over previous
#include <cuda_runtime.h>
#include <cuda_bf16.h>
#include <math.h>
#include <stdint.h>

// ---------------- problem constants ----------------
#define BB   2
#define TT   2048
#define DD   2048
#define NHH  16
#define HDD  128
#define RR   64
#define CQQ  1536
#define CKVV 512
#define BT   (BB*TT)       // 4096
#define DQK  192           // HD + R
#define DVV  128
#define HALFW 256          // WINDOW/2
#define RSCALE 0.07216878364870323f  // 1/sqrt(192)

typedef __nv_bfloat16 bf16;

// ---------------- scratch (device globals; no runtime alloc) ----------------
__device__ float g_lat3 [(size_t)BT*3072];   // [qlat(1536) | kvlat(512) | kr(1024)]
__device__ float g_qcr  [(size_t)BT*3072];   // [qc(2048) | qr(1024)]
__device__ float g_kcv  [(size_t)BT*4096];   // [kc(2048) | vv(2048)]
__device__ float g_alpha[BT];

// attention operands, pre-split bf16, head-major: [bh][t][d]
__device__ bf16 g_Qh[(size_t)BB*NHH*TT*DQK], g_Ql[(size_t)BB*NHH*TT*DQK];
__device__ bf16 g_Kh[(size_t)BB*NHH*TT*DQK], g_Kl[(size_t)BB*NHH*TT*DQK];
__device__ bf16 g_Vh[(size_t)BB*NHH*TT*DVV], g_Vl[(size_t)BB*NHH*TT*DVV];

// bf16 split buffers (hi/lo) for GEMMs ([K,N] layout)
__device__ bf16 g_xh [(size_t)BT*DD],    g_xl [(size_t)BT*DD];
__device__ bf16 g_qlh[(size_t)BT*CQQ],   g_qll[(size_t)BT*CQQ];
__device__ bf16 g_kvh[(size_t)BT*CKVV],  g_kvl[(size_t)BT*CKVV];
__device__ bf16 g_mgh[(size_t)BT*NHH*HDD], g_mgl[(size_t)BT*NHH*HDD];
__device__ bf16 g_wdn_h [(size_t)DD*3072],   g_wdn_l [(size_t)DD*3072];   // [Wqd|Wkd|Wkr]
__device__ bf16 g_wqup_h[(size_t)CQQ*3072],  g_wqup_l[(size_t)CQQ*3072];
__device__ bf16 g_wkvu_h[(size_t)CKVV*4096], g_wkvu_l[(size_t)CKVV*4096];
__device__ bf16 g_wo_h  [(size_t)2048*DD],   g_wo_l  [(size_t)2048*DD];

// ---------------- ptx helpers ----------------
__device__ __forceinline__ uint32_t smem_u32(const void* p) {
    return (uint32_t)__cvta_generic_to_shared(p);
}
__device__ __forceinline__ void ldsm_x4(uint32_t* r, const void* p) {
    uint32_t a = smem_u32(p);
    asm volatile("ldmatrix.sync.aligned.m8n8.x4.shared.b16 {%0,%1,%2,%3}, [%4];"
                 : "=r"(r[0]), "=r"(r[1]), "=r"(r[2]), "=r"(r[3]) : "r"(a));
}
__device__ __forceinline__ void ldsm_x4t(uint32_t* r, const void* p) {
    uint32_t a = smem_u32(p);
    asm volatile("ldmatrix.sync.aligned.m8n8.x4.trans.shared.b16 {%0,%1,%2,%3}, [%4];"
                 : "=r"(r[0]), "=r"(r[1]), "=r"(r[2]), "=r"(r[3]) : "r"(a));
}
__device__ __forceinline__ void ldsm_x2t(uint32_t &r0, uint32_t &r1,
                                         const void* p) {
    uint32_t a = smem_u32(p);
    asm volatile("ldmatrix.sync.aligned.m8n8.x2.trans.shared.b16 {%0,%1}, [%2];"
                 : "=r"(r0), "=r"(r1) : "r"(a));
}
__device__ __forceinline__ void mma_bf16(float* c, const uint32_t* a,
                                         const uint32_t* b) {
    asm volatile(
        "mma.sync.aligned.m16n8k16.row.col.f32.bf16.bf16.f32 "
        "{%0,%1,%2,%3}, {%4,%5,%6,%7}, {%8,%9}, {%0,%1,%2,%3};"
        : "+f"(c[0]), "+f"(c[1]), "+f"(c[2]), "+f"(c[3])
        : "r"(a[0]), "r"(a[1]), "r"(a[2]), "r"(a[3]), "r"(b[0]), "r"(b[1]));
}
__device__ __forceinline__ void cpa16(void* s, const void* g) {
    asm volatile("cp.async.cg.shared.global [%0], [%1], 16;"
                 :: "r"(smem_u32(s)), "l"(g));
}
#define CP_COMMIT asm volatile("cp.async.commit_group;")
#define CP_WAIT1  asm volatile("cp.async.wait_group 1;")
#define CP_WAIT0  asm volatile("cp.async.wait_group 0;")

__device__ __forceinline__ uint32_t pk(bf16 a, bf16 b) {
    __nv_bfloat162 t(a, b);
    return *reinterpret_cast<uint32_t*>(&t);
}

// ---------------- split fp32 -> (hi, lo) bf16 ----------------
__global__ __launch_bounds__(256) void split_kernel(
    const float* __restrict__ s, bf16* __restrict__ h,
    bf16* __restrict__ l, int n)
{
    int i = (blockIdx.x * 256 + threadIdx.x) * 4;
    if (i >= n) return;
    float4 v = *(const float4*)(s + i);
    bf16 h0 = __float2bfloat16(v.x), h1 = __float2bfloat16(v.y);
    bf16 h2 = __float2bfloat16(v.z), h3 = __float2bfloat16(v.w);
    *(__nv_bfloat162*)(h + i)     = __nv_bfloat162(h0, h1);
    *(__nv_bfloat162*)(h + i + 2) = __nv_bfloat162(h2, h3);
    *(__nv_bfloat162*)(l + i) = __nv_bfloat162(
        __float2bfloat16(v.x - __bfloat162float(h0)),
        __float2bfloat16(v.y - __bfloat162float(h1)));
    *(__nv_bfloat162*)(l + i + 2) = __nv_bfloat162(
        __float2bfloat16(v.z - __bfloat162float(h2)),
        __float2bfloat16(v.w - __bfloat162float(h3)));
}

// ---------------- merge two [K,N*] weights into one split [K,N1+N2] --------
__global__ __launch_bounds__(256) void merge_split_kernel(
    const float* __restrict__ W1, const float* __restrict__ W2,
    bf16* __restrict__ h, bf16* __restrict__ l, int N1, int N2, int total)
{
    int i = (blockIdx.x * 256 + threadIdx.x) * 4;
    if (i >= total) return;
    int Nt = N1 + N2;
    int k = i / Nt, n = i % Nt;
    const float* src = (n < N1) ? (W1 + (size_t)k * N1 + n)
                                : (W2 + (size_t)k * N2 + (n - N1));
    float4 v = *(const float4*)src;
    bf16 h0 = __float2bfloat16(v.x), h1 = __float2bfloat16(v.y);
    bf16 h2 = __float2bfloat16(v.z), h3 = __float2bfloat16(v.w);
    *(__nv_bfloat162*)(h + i)     = __nv_bfloat162(h0, h1);
    *(__nv_bfloat162*)(h + i + 2) = __nv_bfloat162(h2, h3);
    *(__nv_bfloat162*)(l + i) = __nv_bfloat162(
        __float2bfloat16(v.x - __bfloat162float(h0)),
        __float2bfloat16(v.y - __bfloat162float(h1)));
    *(__nv_bfloat162*)(l + i + 2) = __nv_bfloat162(
        __float2bfloat16(v.z - __bfloat162float(h2)),
        __float2bfloat16(v.w - __bfloat162float(h3)));
}

// ---------------- merge three [K,N*] weights into one split [K,N1+N2+N3] ---
__global__ __launch_bounds__(256) void merge3_split_kernel(
    const float* __restrict__ W1, const float* __restrict__ W2,
    const float* __restrict__ W3,
    bf16* __restrict__ h, bf16* __restrict__ l,
    int N1, int N2, int N3, int total)
{
    int i = (blockIdx.x * 256 + threadIdx.x) * 4;
    if (i >= total) return;
    int Nt = N1 + N2 + N3;
    int k = i / Nt, n = i % Nt;
    const float* src;
    if (n < N1)            src = W1 + (size_t)k * N1 + n;
    else if (n < N1 + N2)  src = W2 + (size_t)k * N2 + (n - N1);
    else                   src = W3 + (size_t)k * N3 + (n - N1 - N2);
    float4 v = *(const float4*)src;
    bf16 h0 = __float2bfloat16(v.x), h1 = __float2bfloat16(v.y);
    bf16 h2 = __float2bfloat16(v.z), h3 = __float2bfloat16(v.w);
    *(__nv_bfloat162*)(h + i)     = __nv_bfloat162(h0, h1);
    *(__nv_bfloat162*)(h + i + 2) = __nv_bfloat162(h2, h3);
    *(__nv_bfloat162*)(l + i) = __nv_bfloat162(
        __float2bfloat16(v.x - __bfloat162float(h0)),
        __float2bfloat16(v.y - __bfloat162float(h1)));
    *(__nv_bfloat162*)(l + i + 2) = __nv_bfloat162(
        __float2bfloat16(v.z - __bfloat162float(h2)),
        __float2bfloat16(v.w - __bfloat162float(h3)));
}

// ---------------- split-bf16 TC GEMM, 2-stage cp.async pipeline ------------
#define GS_A   (128*40)
#define GS_B   (32*136)
#define GS_STG (2*GS_A + 2*GS_B)
#define GS_SMEM (2*GS_STG*2)

__global__ __launch_bounds__(256) void gemm_split(
    const bf16* __restrict__ Ah, const bf16* __restrict__ Al,
    const bf16* __restrict__ Bh, const bf16* __restrict__ Bl,
    float* __restrict__ C, int M, int N, int K)
{
    extern __shared__ __align__(16) bf16 gsm[];

    int tid = threadIdx.x;
    int bm = blockIdx.y, bn = blockIdx.x;
    int warp = tid >> 5, lane = tid & 31;
    int wm = warp >> 2, wn = warp & 3;

    int arow = tid >> 2, ac = (tid & 3) * 8;
    int brow = tid >> 4, bc = (tid & 15) * 8;

    float acc[4][4][4];
#pragma unroll
    for (int a = 0; a < 4; a++)
#pragma unroll
        for (int b = 0; b < 4; b++)
#pragma unroll
            for (int c = 0; c < 4; c++) acc[a][b][c] = 0.f;

    int nk = K >> 5;

    auto issue = [&](int stage, int k0) {
        bf16* sAh = gsm + stage * GS_STG;
        bf16* sAl = sAh + GS_A;
        bf16* sBh = sAl + GS_A;
        bf16* sBl = sBh + GS_B;
#pragma unroll
        for (int i = 0; i < 2; i++) {
            int r = arow + i * 64;
            size_t g = (size_t)(bm * 128 + r) * K + k0 + ac;
            cpa16(&sAh[r * 40 + ac], Ah + g);
            cpa16(&sAl[r * 40 + ac], Al + g);
        }
#pragma unroll
        for (int i = 0; i < 2; i++) {
            int r = brow + i * 16;
            size_t g = (size_t)(k0 + r) * N + bn * 128 + bc;
            cpa16(&sBh[r * 136 + bc], Bh + g);
            cpa16(&sBl[r * 136 + bc], Bl + g);
        }
    };

    issue(0, 0);
    CP_COMMIT;

    for (int it = 0; it < nk; it++) {
        if (it + 1 < nk) {
            issue((it + 1) & 1, (it + 1) << 5);
            CP_COMMIT;
            CP_WAIT1;
        } else {
            CP_WAIT0;
        }
        __syncthreads();

        bf16* sAh = gsm + (it & 1) * GS_STG;
        bf16* sAl = sAh + GS_A;
        bf16* sBh = sAl + GS_A;
        bf16* sBl = sBh + GS_B;

#pragma unroll
        for (int kh = 0; kh < 2; kh++) {
            uint32_t bhf[4][2], blf[4][2];
#pragma unroll
            for (int nt = 0; nt < 4; nt++) {
                int br = kh * 16 + (lane & 15);
                int bcl = wn * 32 + nt * 8;
                ldsm_x2t(bhf[nt][0], bhf[nt][1], &sBh[br * 136 + bcl]);
                ldsm_x2t(blf[nt][0], blf[nt][1], &sBl[br * 136 + bcl]);
            }
#pragma unroll
            for (int mt = 0; mt < 4; mt++) {
                int ar = wm * 64 + mt * 16 + (lane & 15);
                int acl = kh * 16 + (lane >> 4) * 8;
                uint32_t ah[4], al[4];
                ldsm_x4(ah, &sAh[ar * 40 + acl]);
                ldsm_x4(al, &sAl[ar * 40 + acl]);
#pragma unroll
                for (int nt = 0; nt < 4; nt++) {
                    mma_bf16(acc[mt][nt], ah, bhf[nt]);
                    mma_bf16(acc[mt][nt], ah, blf[nt]);
                    mma_bf16(acc[mt][nt], al, bhf[nt]);
                }
            }
        }
        __syncthreads();
    }

#pragma unroll
    for (int mt = 0; mt < 4; mt++) {
#pragma unroll
        for (int nt = 0; nt < 4; nt++) {
            int r0 = bm * 128 + wm * 64 + mt * 16 + (lane >> 2);
            int c0 = bn * 128 + wn * 32 + nt * 8 + (lane & 3) * 2;
            *(float2*)&C[(size_t)r0 * N + c0] =
                make_float2(acc[mt][nt][0], acc[mt][nt][1]);
            *(float2*)&C[(size_t)(r0 + 8) * N + c0] =
                make_float2(acc[mt][nt][2], acc[mt][nt][3]);
        }
    }
}

// ---------------- RMSNorm slice -> split bf16 outputs ----------------
// row = x + blockIdx.x*rowstride + off, length n; outputs contiguous [BT,n].
__global__ __launch_bounds__(256) void rmsnorm_split_kernel(
    const float* __restrict__ x, int rowstride, int off,
    const float* __restrict__ w,
    bf16* __restrict__ hi, bf16* __restrict__ lo, int n)
{
    const float* row = x + (size_t)blockIdx.x * rowstride + off;
    float ss = 0.f;
    for (int i = threadIdx.x; i < n; i += 256) { float v = row[i]; ss += v*v; }
    __shared__ float sh[8];
    __shared__ float tot;
    int lane = threadIdx.x & 31, wp = threadIdx.x >> 5;
#pragma unroll
    for (int o = 16; o; o >>= 1) ss += __shfl_xor_sync(0xffffffffu, ss, o);
    if (lane == 0) sh[wp] = ss;
    __syncthreads();
    if (threadIdx.x == 0) {
        float s = 0.f;
        for (int i = 0; i < 8; i++) s += sh[i];
        tot = rsqrtf(s / n + 1e-6f);
    }
    __syncthreads();
    float rs = tot;
    bf16* hrow = hi + (size_t)blockIdx.x * n;
    bf16* lrow = lo + (size_t)blockIdx.x * n;
    for (int i = threadIdx.x; i < n; i += 256) {
        float y = row[i] * rs * w[i];
        bf16 h = __float2bfloat16(y);
        hrow[i] = h;
        lrow[i] = __float2bfloat16(y - __bfloat162float(h));
    }
}

// ---------------- gate alpha ----------------
__global__ __launch_bounds__(256) void alpha_kernel(
    const float* __restrict__ x, const float* __restrict__ wg,
    const float* __restrict__ bg, float* __restrict__ alpha,
    float* __restrict__ out_alpha)
{
    const float* row = x + (size_t)blockIdx.x * DD;
    float s = 0.f;
    for (int i = threadIdx.x; i < DD; i += 256) s += row[i] * wg[i];
    __shared__ float sh[8];
    int lane = threadIdx.x & 31, wp = threadIdx.x >> 5;
#pragma unroll
    for (int o = 16; o; o >>= 1) s += __shfl_xor_sync(0xffffffffu, s, o);
    if (lane == 0) sh[wp] = s;
    __syncthreads();
    if (threadIdx.x == 0) {
        float t = 0.f;
        for (int i = 0; i < 8; i++) t += sh[i];
        float z = t + bg[0];
        float a = 1.f / (1.f + expf(-z));
        alpha[blockIdx.x] = a;
        if (out_alpha) out_alpha[blockIdx.x] = a;
    }
}

// ---------------- assemble Q/K/V with EPE-RoPE (emit split bf16) -----------
__global__ __launch_bounds__(128) void assemble_kernel(
    const float* __restrict__ qcr, const float* __restrict__ kcv,
    const float* __restrict__ lat3, const float* __restrict__ unc,
    bf16* __restrict__ Qh, bf16* __restrict__ Ql,
    bf16* __restrict__ Kh, bf16* __restrict__ Kl,
    bf16* __restrict__ Vh, bf16* __restrict__ Vl)
{
    int idx = blockIdx.x;
    int h  = idx % NHH;
    int bt = idx / NHH;
    int t  = bt % TT;
    int b  = bt / TT;
    __shared__ float cs[32], sn[32];
    int d = threadIdx.x;
    if (d < 32) {
        float u = unc[bt];
        u = fminf(fmaxf(u, 0.f), 1.f);
        float scale = 0.5f + 1.5f * u;
        float fi = (float)d / 32.0f;
        float theta = expf(-fi * logf(500000.0f));
        float fr = (float)t * theta * scale;
        cs[d] = cosf(fr);
        sn[d] = sinf(fr);
    }
    __syncthreads();
    size_t qkrow = ((size_t)(b*NHH + h))*TT + t;

    float qv0 = qcr[(size_t)bt*3072 + h*128 + d];
    float kv0 = kcv[(size_t)bt*4096 + h*128 + d];
    float vv0 = kcv[(size_t)bt*4096 + 2048 + h*128 + d];
    bf16 hh;
    hh = __float2bfloat16(qv0);
    Qh[qkrow*DQK + d] = hh; Ql[qkrow*DQK + d] = __float2bfloat16(qv0 - __bfloat162float(hh));
    hh = __float2bfloat16(kv0);
    Kh[qkrow*DQK + d] = hh; Kl[qkrow*DQK + d] = __float2bfloat16(kv0 - __bfloat162float(hh));
    hh = __float2bfloat16(vv0);
    Vh[qkrow*DVV + d] = hh; Vl[qkrow*DVV + d] = __float2bfloat16(vv0 - __bfloat162float(hh));

    if (d < 64) {
        const float* qrp = qcr  + (size_t)bt*3072 + 2048 + h*64;
        const float* krp = lat3 + (size_t)bt*3072 + 2048 + h*64;
        float qv, kv;
        if (d < 32) {
            float c = cs[d], s = sn[d];
            qv = qrp[d]*c - qrp[d+32]*s;
            kv = krp[d]*c - krp[d+32]*s;
        } else {
            int j = d - 32;
            float c = cs[j], s = sn[j];
            qv = qrp[j+32]*c + qrp[j]*s;
            kv = krp[j+32]*c + krp[j]*s;
        }
        hh = __float2bfloat16(qv);
        Qh[qkrow*DQK + 128 + d] = hh;
        Ql[qkrow*DQK + 128 + d] = __float2bfloat16(qv - __bfloat162float(hh));
        hh = __float2bfloat16(kv);
        Kh[qkrow*DQK + 128 + d] = hh;
        Kl[qkrow*DQK + 128 + d] = __float2bfloat16(kv - __bfloat162float(hh));
    }
}

// ---------------- tensor-core fused dual attention ----------------
// Streams: oR(ob) = bidir-only keys, oW(ow) = window keys; bidir = ob + ow.
#define KSTR 200
#define VSTR 136
#define ATTN_SMEM ((64*KSTR*2 + 2*64*KSTR*2 + 2*64*VSTR*2) * 2)

__global__ void __launch_bounds__(128, 1) attn_tc_kernel(
    const bf16* __restrict__ Qh, const bf16* __restrict__ Ql,
    const bf16* __restrict__ Kh, const bf16* __restrict__ Kl,
    const bf16* __restrict__ Vh, const bf16* __restrict__ Vl,
    const float* __restrict__ alpha,
    bf16* __restrict__ mgh, bf16* __restrict__ mgl)
{
    extern __shared__ __align__(16) bf16 smem[];
    bf16* sQh = smem;
    bf16* sQl = sQh + 64*KSTR;
    bf16* sKh = sQl + 64*KSTR;
    bf16* sKl = sKh + 2*64*KSTR;
    bf16* sVh = sKl + 2*64*KSTR;
    bf16* sVl = sVh + 2*64*VSTR;

    int tid = threadIdx.x, lane = tid & 31, warp = tid >> 5;
    int qt = blockIdx.x * 64;
    int bh = blockIdx.y;
    int b = bh >> 4, h = bh & 15;
    size_t base = (size_t)bh * TT;

    for (int i = tid; i < 64*24; i += 128) {
        int r = i / 24, c = (i % 24) * 8;
        size_t g = (base + qt + r) * DQK + c;
        cpa16(&sQh[r*KSTR + c], Qh + g);
        cpa16(&sQl[r*KSTR + c], Ql + g);
    }
    for (int i = tid; i < 64*24; i += 128) {
        int r = i / 24, c = (i % 24) * 8;
        size_t g = (base + r) * DQK + c;
        cpa16(&sKh[r*KSTR + c], Kh + g);
        cpa16(&sKl[r*KSTR + c], Kl + g);
    }
    for (int i = tid; i < 64*16; i += 128) {
        int r = i / 16, c = (i % 16) * 8;
        size_t g = (base + r) * DVV + c;
        cpa16(&sVh[r*VSTR + c], Vh + g);
        cpa16(&sVl[r*VSTR + c], Vl + g);
    }
    CP_COMMIT;

    int q0 = qt + 16*warp + (lane >> 2);
    int q1 = q0 + 8;
    int winlo = ((qt >> 8) << 8) - HALFW;
    if (winlo < 0) winlo = 0;

    float ob[16][4], ow[16][4];
#pragma unroll
    for (int n = 0; n < 16; n++)
#pragma unroll
        for (int j = 0; j < 4; j++) { ob[n][j] = 0.f; ow[n][j] = 0.f; }
    float m0 = -1e30f, m1 = -1e30f;
    float lb0 = 0.f, lb1 = 0.f, lw0 = 0.f, lw1 = 0.f;

    for (int t = 0; t < 32; t++) {
        int kt = t * 64;
        int nb = (t + 1) & 1;
        if (t + 1 < 32) {
            int kn = kt + 64;
            for (int i = tid; i < 64*24; i += 128) {
                int r = i / 24, c = (i % 24) * 8;
                size_t g = (base + kn + r) * DQK + c;
                cpa16(&sKh[nb*64*KSTR + r*KSTR + c], Kh + g);
                cpa16(&sKl[nb*64*KSTR + r*KSTR + c], Kl + g);
            }
            for (int i = tid; i < 64*16; i += 128) {
                int r = i / 16, c = (i % 16) * 8;
                size_t g = (base + kn + r) * DVV + c;
                cpa16(&sVh[nb*64*VSTR + r*VSTR + c], Vh + g);
                cpa16(&sVl[nb*64*VSTR + r*VSTR + c], Vl + g);
            }
        }
        CP_COMMIT;
        CP_WAIT1;
        __syncthreads();

        const bf16* bKh = sKh + (t & 1) * 64 * KSTR;
        const bf16* bVh = sVh + (t & 1) * 64 * VSTR;

        bool diag    = (kt == qt);
        bool fullwin = (kt >= winlo) && (kt < qt);

        float sacc[8][4];
#pragma unroll
        for (int n = 0; n < 8; n++)
#pragma unroll
            for (int j = 0; j < 4; j++) sacc[n][j] = 0.f;

#pragma unroll
        for (int ks = 0; ks < 12; ks++) {
            uint32_t qhf[4], qlf[4];
            const bf16* ap = &sQh[(16*warp + (lane & 15))*KSTR + ks*16 + (lane >> 4)*8];
            ldsm_x4(qhf, ap);
            ldsm_x4(qlf, ap + 64*KSTR);
#pragma unroll
            for (int np = 0; np < 4; np++) {
                int g2 = lane >> 3;
                int krow = np*16 + (g2 >> 1)*8 + (lane & 7);
                int kcol = ks*16 + (g2 & 1)*8;
                const bf16* bp = &bKh[krow*KSTR + kcol];
                uint32_t khf[4], klf[4];
                ldsm_x4(khf, bp);
                ldsm_x4(klf, bp + 2*64*KSTR);
                mma_bf16(sacc[2*np],   qhf, khf);
                mma_bf16(sacc[2*np],   qhf, klf);
                mma_bf16(sacc[2*np],   qlf, khf);
                mma_bf16(sacc[2*np+1], qhf, khf + 2);
                mma_bf16(sacc[2*np+1], qhf, klf + 2);
                mma_bf16(sacc[2*np+1], qlf, khf + 2);
            }
        }

        float tm0 = -1e30f, tm1 = -1e30f;
#pragma unroll
        for (int n = 0; n < 8; n++) {
            tm0 = fmaxf(tm0, fmaxf(sacc[n][0], sacc[n][1]));
            tm1 = fmaxf(tm1, fmaxf(sacc[n][2], sacc[n][3]));
        }
        tm0 *= RSCALE; tm1 *= RSCALE;
        tm0 = fmaxf(tm0, __shfl_xor_sync(0xffffffffu, tm0, 1));
        tm0 = fmaxf(tm0, __shfl_xor_sync(0xffffffffu, tm0, 2));
        tm1 = fmaxf(tm1, __shfl_xor_sync(0xffffffffu, tm1, 1));
        tm1 = fmaxf(tm1, __shfl_xor_sync(0xffffffffu, tm1, 2));
        float mn0 = fmaxf(m0, tm0), mn1 = fmaxf(m1, tm1);
        float c0 = __expf(m0 - mn0), c1 = __expf(m1 - mn1);
        m0 = mn0; m1 = mn1;
        lb0 *= c0; lb1 *= c1; lw0 *= c0; lw1 *= c1;
        if (c0 < 1.f || c1 < 1.f) {
#pragma unroll
            for (int n = 0; n < 16; n++) {
                ob[n][0] *= c0; ob[n][1] *= c0; ob[n][2] *= c1; ob[n][3] *= c1;
                ow[n][0] *= c0; ow[n][1] *= c0; ow[n][2] *= c1; ow[n][3] *= c1;
            }
        }

        float sb0 = 0.f, sb1 = 0.f, sw0 = 0.f, sw1 = 0.f;
#pragma unroll
        for (int n = 0; n < 8; n++) {
            float p0 = __expf(sacc[n][0]*RSCALE - mn0);
            float p1 = __expf(sacc[n][1]*RSCALE - mn0);
            float p2 = __expf(sacc[n][2]*RSCALE - mn1);
            float p3 = __expf(sacc[n][3]*RSCALE - mn1);
            sacc[n][0] = p0; sacc[n][1] = p1; sacc[n][2] = p2; sacc[n][3] = p3;
            sb0 += p0 + p1; sb1 += p2 + p3;
            if (diag) {
                int keyc = kt + 8*n + 2*(lane & 3);
                sw0 += ((keyc   <= q0) ? p0 : 0.f) + ((keyc+1 <= q0) ? p1 : 0.f);
                sw1 += ((keyc   <= q1) ? p2 : 0.f) + ((keyc+1 <= q1) ? p3 : 0.f);
            }
        }
        sb0 += __shfl_xor_sync(0xffffffffu, sb0, 1); sb0 += __shfl_xor_sync(0xffffffffu, sb0, 2);
        sb1 += __shfl_xor_sync(0xffffffffu, sb1, 1); sb1 += __shfl_xor_sync(0xffffffffu, sb1, 2);
        lb0 += sb0; lb1 += sb1;
        if (fullwin) { lw0 += sb0; lw1 += sb1; }
        if (diag) {
            sw0 += __shfl_xor_sync(0xffffffffu, sw0, 1); sw0 += __shfl_xor_sync(0xffffffffu, sw0, 2);
            sw1 += __shfl_xor_sync(0xffffffffu, sw1, 1); sw1 += __shfl_xor_sync(0xffffffffu, sw1, 2);
            lw0 += sw0; lw1 += sw1;
        }

#pragma unroll
        for (int j = 0; j < 4; j++) {
            float v0 = sacc[2*j][0],   v1 = sacc[2*j][1];
            float v2 = sacc[2*j][2],   v3 = sacc[2*j][3];
            float v4 = sacc[2*j+1][0], v5 = sacc[2*j+1][1];
            float v6 = sacc[2*j+1][2], v7 = sacc[2*j+1][3];
            bf16 h0 = __float2bfloat16(v0), h1 = __float2bfloat16(v1);
            bf16 h2 = __float2bfloat16(v2), h3 = __float2bfloat16(v3);
            bf16 h4 = __float2bfloat16(v4), h5 = __float2bfloat16(v5);
            bf16 h6 = __float2bfloat16(v6), h7 = __float2bfloat16(v7);
            bf16 e0 = __float2bfloat16(v0 - __bfloat162float(h0));
            bf16 e1 = __float2bfloat16(v1 - __bfloat162float(h1));
            bf16 e2 = __float2bfloat16(v2 - __bfloat162float(h2));
            bf16 e3 = __float2bfloat16(v3 - __bfloat162float(h3));
            bf16 e4 = __float2bfloat16(v4 - __bfloat162float(h4));
            bf16 e5 = __float2bfloat16(v5 - __bfloat162float(h5));
            bf16 e6 = __float2bfloat16(v6 - __bfloat162float(h6));
            bf16 e7 = __float2bfloat16(v7 - __bfloat162float(h7));
            uint32_t ph2[4] = { pk(h0,h1), pk(h2,h3), pk(h4,h5), pk(h6,h7) };
            uint32_t pl2[4] = { pk(e0,e1), pk(e2,e3), pk(e4,e5), pk(e6,e7) };

            if (diag) {
                bf16 z = __float2bfloat16(0.f);
                int kc = kt + 16*j + 2*(lane & 3);
                bool a0 = kc   <= q0, a1 = kc+1 <= q0;
                bool b0m = kc  <= q1, b1m = kc+1 <= q1;
                bool a2 = kc+8 <= q0, a3 = kc+9 <= q0;
                bool b2m = kc+8 <= q1, b3m = kc+9 <= q1;
                uint32_t wh[4], wl[4], xh2[4], xl2[4];
                wh[0] = pk(a0?h0:z, a1?h1:z);   wl[0] = pk(a0?e0:z, a1?e1:z);
                wh[1] = pk(b0m?h2:z, b1m?h3:z); wl[1] = pk(b0m?e2:z, b1m?e3:z);
                wh[2] = pk(a2?h4:z, a3?h5:z);   wl[2] = pk(a2?e4:z, a3?e5:z);
                wh[3] = pk(b2m?h6:z, b3m?h7:z); wl[3] = pk(b2m?e6:z, b3m?e7:z);
                xh2[0] = pk(a0?z:h0, a1?z:h1);   xl2[0] = pk(a0?z:e0, a1?z:e1);
                xh2[1] = pk(b0m?z:h2, b1m?z:h3); xl2[1] = pk(b0m?z:e2, b1m?z:e3);
                xh2[2] = pk(a2?z:h4, a3?z:h5);   xl2[2] = pk(a2?z:e4, a3?z:e5);
                xh2[3] = pk(b2m?z:h6, b3m?z:h7); xl2[3] = pk(b2m?z:e6, b3m?z:e7);
#pragma unroll
                for (int np = 0; np < 8; np++) {
                    int g2 = lane >> 3;
                    int vrow = 16*j + (g2 & 1)*8 + (lane & 7);
                    int vcol = np*16 + (g2 >> 1)*8;
                    const bf16* vp = &bVh[vrow*VSTR + vcol];
                    uint32_t vhf[4], vlf[4];
                    ldsm_x4t(vhf, vp);
                    ldsm_x4t(vlf, vp + 2*64*VSTR);
                    mma_bf16(ow[2*np],   wh, vhf);
                    mma_bf16(ow[2*np],   wh, vlf);
                    mma_bf16(ow[2*np],   wl, vhf);
                    mma_bf16(ow[2*np+1], wh, vhf + 2);
                    mma_bf16(ow[2*np+1], wh, vlf + 2);
                    mma_bf16(ow[2*np+1], wl, vhf + 2);
                    mma_bf16(ob[2*np],   xh2, vhf);
                    mma_bf16(ob[2*np],   xh2, vlf);
                    mma_bf16(ob[2*np],   xl2, vhf);
                    mma_bf16(ob[2*np+1], xh2, vhf + 2);
                    mma_bf16(ob[2*np+1], xh2, vlf + 2);
                    mma_bf16(ob[2*np+1], xl2, vhf + 2);
                }
            } else if (fullwin) {
#pragma unroll
                for (int np = 0; np < 8; np++) {
                    int g2 = lane >> 3;
                    int vrow = 16*j + (g2 & 1)*8 + (lane & 7);
                    int vcol = np*16 + (g2 >> 1)*8;
                    const bf16* vp = &bVh[vrow*VSTR + vcol];
                    uint32_t vhf[4], vlf[4];
                    ldsm_x4t(vhf, vp);
                    ldsm_x4t(vlf, vp + 2*64*VSTR);
                    mma_bf16(ow[2*np],   ph2, vhf);
                    mma_bf16(ow[2*np],   ph2, vlf);
                    mma_bf16(ow[2*np],   pl2, vhf);
                    mma_bf16(ow[2*np+1], ph2, vhf + 2);
                    mma_bf16(ow[2*np+1], ph2, vlf + 2);
                    mma_bf16(ow[2*np+1], pl2, vhf + 2);
                }
            } else {
#pragma unroll
                for (int np = 0; np < 8; np++) {
                    int g2 = lane >> 3;
                    int vrow = 16*j + (g2 & 1)*8 + (lane & 7);
                    int vcol = np*16 + (g2 >> 1)*8;
                    const bf16* vp = &bVh[vrow*VSTR + vcol];
                    uint32_t vhf[4], vlf[4];
                    ldsm_x4t(vhf, vp);
                    ldsm_x4t(vlf, vp + 2*64*VSTR);
                    mma_bf16(ob[2*np],   ph2, vhf);
                    mma_bf16(ob[2*np],   ph2, vlf);
                    mma_bf16(ob[2*np],   pl2, vhf);
                    mma_bf16(ob[2*np+1], ph2, vhf + 2);
                    mma_bf16(ob[2*np+1], ph2, vlf + 2);
                    mma_bf16(ob[2*np+1], pl2, vhf + 2);
                }
            }
        }
        __syncthreads();
    }

    float a0 = alpha[(size_t)b*TT + q0];
    float a1 = alpha[(size_t)b*TT + q1];
    float ilb0 = 1.f/lb0, ilb1 = 1.f/lb1, ilw0 = 1.f/lw0, ilw1 = 1.f/lw1;
    size_t r0o = ((size_t)b*TT + q0)*2048 + (size_t)h*128;
    size_t r1o = ((size_t)b*TT + q1)*2048 + (size_t)h*128;
#pragma unroll
    for (int n = 0; n < 16; n++) {
        int d = 8*n + 2*(lane & 3);
        float b00 = ob[n][0] + ow[n][0], b01 = ob[n][1] + ow[n][1];
        float b10 = ob[n][2] + ow[n][2], b11 = ob[n][3] + ow[n][3];
        float o00 = a0*b00*ilb0 + (1.f-a0)*ow[n][0]*ilw0;
        float o01 = a0*b01*ilb0 + (1.f-a0)*ow[n][1]*ilw0;
        float o10 = a1*b10*ilb1 + (1.f-a1)*ow[n][2]*ilw1;
        float o11 = a1*b11*ilb1 + (1.f-a1)*ow[n][3]*ilw1;
        bf16 h00 = __float2bfloat16(o00), h01 = __float2bfloat16(o01);
        bf16 h10 = __float2bfloat16(o10), h11 = __float2bfloat16(o11);
        *(uint32_t*)(mgh + r0o + d) = pk(h00, h01);
        *(uint32_t*)(mgh + r1o + d) = pk(h10, h11);
        *(uint32_t*)(mgl + r0o + d) = pk(
            __float2bfloat16(o00 - __bfloat162float(h00)),
            __float2bfloat16(o01 - __bfloat162float(h01)));
        *(uint32_t*)(mgl + r1o + d) = pk(
            __float2bfloat16(o10 - __bfloat162float(h10)),
            __float2bfloat16(o11 - __bfloat162float(h11)));
    }
}

// ---------------- launcher ----------------
extern "C" void kernel_launch(void* const* d_in, const int* in_sizes, int n_in,
                              void* d_out, int out_size)
{
    (void)in_sizes; (void)n_in;
    const float* x        = (const float*)d_in[0];
    const float* unc      = (const float*)d_in[1];
    const float* Wq_down  = (const float*)d_in[2];
    const float* q_norm_w = (const float*)d_in[3];
    const float* Wq_up    = (const float*)d_in[4];
    const float* Wq_rope  = (const float*)d_in[5];
    const float* Wkv_down = (const float*)d_in[6];
    const float* kv_norm_w= (const float*)d_in[7];
    const float* Wk_up    = (const float*)d_in[8];
    const float* Wv_up    = (const float*)d_in[9];
    const float* Wk_rope  = (const float*)d_in[10];
    const float* Wout     = (const float*)d_in[11];
    const float* Wgate    = (const float*)d_in[12];
    const float* bgate    = (const float*)d_in[13];
    float* out = (float*)d_out;

    float *lat3, *qcr, *kcv, *al;
    bf16 *Qh,*Ql,*Kh,*Kl,*Vh,*Vl;
    bf16 *xh,*xl,*qlh,*qll,*kvh,*kvl,*mgh,*mgl;
    bf16 *wdnh,*wdnl,*wquph,*wqupl,*wkvuh,*wkvul,*woh,*wol;
    cudaGetSymbolAddress((void**)&lat3,  g_lat3);
    cudaGetSymbolAddress((void**)&qcr,   g_qcr);
    cudaGetSymbolAddress((void**)&kcv,   g_kcv);
    cudaGetSymbolAddress((void**)&al,    g_alpha);
    cudaGetSymbolAddress((void**)&Qh,    g_Qh);
    cudaGetSymbolAddress((void**)&Ql,    g_Ql);
    cudaGetSymbolAddress((void**)&Kh,    g_Kh);
    cudaGetSymbolAddress((void**)&Kl,    g_Kl);
    cudaGetSymbolAddress((void**)&Vh,    g_Vh);
    cudaGetSymbolAddress((void**)&Vl,    g_Vl);
    cudaGetSymbolAddress((void**)&xh,    g_xh);
    cudaGetSymbolAddress((void**)&xl,    g_xl);
    cudaGetSymbolAddress((void**)&qlh,   g_qlh);
    cudaGetSymbolAddress((void**)&qll,   g_qll);
    cudaGetSymbolAddress((void**)&kvh,   g_kvh);
    cudaGetSymbolAddress((void**)&kvl,   g_kvl);
    cudaGetSymbolAddress((void**)&mgh,   g_mgh);
    cudaGetSymbolAddress((void**)&mgl,   g_mgl);
    cudaGetSymbolAddress((void**)&wdnh,  g_wdn_h);
    cudaGetSymbolAddress((void**)&wdnl,  g_wdn_l);
    cudaGetSymbolAddress((void**)&wquph, g_wqup_h);
    cudaGetSymbolAddress((void**)&wqupl, g_wqup_l);
    cudaGetSymbolAddress((void**)&wkvuh, g_wkvu_h);
    cudaGetSymbolAddress((void**)&wkvul, g_wkvu_l);
    cudaGetSymbolAddress((void**)&woh,   g_wo_h);
    cudaGetSymbolAddress((void**)&wol,   g_wo_l);

    cudaFuncSetAttribute(attn_tc_kernel,
                         cudaFuncAttributeMaxDynamicSharedMemorySize, ATTN_SMEM);
    cudaFuncSetAttribute(gemm_split,
                         cudaFuncAttributeMaxDynamicSharedMemorySize, GS_SMEM);

    auto split = [&](const float* s, bf16* h, bf16* l, size_t n) {
        split_kernel<<<(int)(n / 1024), 256>>>(s, h, l, (int)n);
    };
    auto gemm = [&](const bf16* Ah, const bf16* Al, const bf16* Bh,
                    const bf16* Bl, float* C, int M, int N, int K) {
        gemm_split<<<dim3(N/128, M/128), 256, GS_SMEM>>>(Ah, Al, Bh, Bl, C, M, N, K);
    };

    // launch order: index 3 (ncu capture slot) = merged down-projection GEMM
    split(x, xh, xl, (size_t)BT*DD);                                   // 0
    merge3_split_kernel<<<(DD*3072)/1024, 256>>>(Wq_down, Wkv_down,
        Wk_rope, wdnh, wdnl, CQQ, CKVV, 1024, DD*3072);                // 1
    merge_split_kernel<<<(CQQ*3072)/1024, 256>>>(Wq_up, Wq_rope,
        wquph, wqupl, 2048, 1024, CQQ*3072);                           // 2
    gemm(xh, xl, wdnh, wdnl, lat3, BT, 3072, DD);                      // 3 <- ncu

    rmsnorm_split_kernel<<<BT, 256>>>(lat3, 3072, 0,    q_norm_w,  qlh, qll, CQQ);
    rmsnorm_split_kernel<<<BT, 256>>>(lat3, 3072, CQQ,  kv_norm_w, kvh, kvl, CKVV);

    gemm(qlh, qll, wquph, wqupl, qcr, BT, 3072, CQQ);

    merge_split_kernel<<<(CKVV*4096)/1024, 256>>>(Wk_up, Wv_up,
        wkvuh, wkvul, 2048, 2048, CKVV*4096);
    gemm(kvh, kvl, wkvuh, wkvul, kcv, BT, 4096, CKVV);

    split(Wout, woh, wol, (size_t)2048*DD);

    float* out_alpha = (out_size >= BB*TT*DD + BB*TT) ? (out + (size_t)BB*TT*DD)
                                                      : nullptr;
    alpha_kernel<<<BT, 256>>>(x, Wgate, bgate, al, out_alpha);

    assemble_kernel<<<BT*NHH, 128>>>(qcr, kcv, lat3, unc,
                                     Qh, Ql, Kh, Kl, Vh, Vl);

    attn_tc_kernel<<<dim3(TT/64, BB*NHH), 128, ATTN_SMEM>>>(
        Qh, Ql, Kh, Kl, Vh, Vl, al, mgh, mgl);

    gemm(mgh, mgl, woh, wol, out, BT, DD, 2048);
}

// round 10
// speedup vs baseline: 1.2339x; 1.0175x over previous
#include <cuda_runtime.h>
#include <cuda_bf16.h>
#include <math.h>
#include <stdint.h>

// ---------------- problem constants ----------------
#define BB   2
#define TT   2048
#define DD   2048
#define NHH  16
#define HDD  128
#define RR   64
#define CQQ  1536
#define CKVV 512
#define BT   (BB*TT)       // 4096
#define DQK  192           // HD + R
#define DVV  128
#define HALFW 256          // WINDOW/2
#define RSCALE 0.07216878364870323f  // 1/sqrt(192)

typedef __nv_bfloat16 bf16;

// ---------------- scratch (device globals; no runtime alloc) ----------------
__device__ float g_lat3 [(size_t)BT*3072];   // [qlat(1536) | kvlat(512) | kr(1024)]
__device__ float g_qcr  [(size_t)BT*3072];   // [qc(2048) | qr(1024)]
__device__ float g_kcv  [(size_t)BT*4096];   // [kc(2048) | vv(2048)]
__device__ float g_alpha[BT];

// attention operands, pre-split bf16, head-major: [bh][t][d]
__device__ bf16 g_Qh[(size_t)BB*NHH*TT*DQK], g_Ql[(size_t)BB*NHH*TT*DQK];
__device__ bf16 g_Kh[(size_t)BB*NHH*TT*DQK], g_Kl[(size_t)BB*NHH*TT*DQK];
__device__ bf16 g_Vh[(size_t)BB*NHH*TT*DVV], g_Vl[(size_t)BB*NHH*TT*DVV];

// bf16 split buffers (hi/lo) for GEMMs ([K,N] layout)
__device__ bf16 g_xh [(size_t)BT*DD],    g_xl [(size_t)BT*DD];
__device__ bf16 g_qlh[(size_t)BT*CQQ],   g_qll[(size_t)BT*CQQ];
__device__ bf16 g_kvh[(size_t)BT*CKVV],  g_kvl[(size_t)BT*CKVV];
__device__ bf16 g_mgh[(size_t)BT*NHH*HDD], g_mgl[(size_t)BT*NHH*HDD];
__device__ bf16 g_wdn_h [(size_t)DD*3072],   g_wdn_l [(size_t)DD*3072];   // [Wqd|Wkd|Wkr]
__device__ bf16 g_wqup_h[(size_t)CQQ*3072],  g_wqup_l[(size_t)CQQ*3072];
__device__ bf16 g_wkvu_h[(size_t)CKVV*4096], g_wkvu_l[(size_t)CKVV*4096];
__device__ bf16 g_wo_h  [(size_t)2048*DD],   g_wo_l  [(size_t)2048*DD];

// ---------------- ptx helpers ----------------
__device__ __forceinline__ uint32_t smem_u32(const void* p) {
    return (uint32_t)__cvta_generic_to_shared(p);
}
__device__ __forceinline__ void ldsm_x4(uint32_t* r, const void* p) {
    uint32_t a = smem_u32(p);
    asm volatile("ldmatrix.sync.aligned.m8n8.x4.shared.b16 {%0,%1,%2,%3}, [%4];"
                 : "=r"(r[0]), "=r"(r[1]), "=r"(r[2]), "=r"(r[3]) : "r"(a));
}
__device__ __forceinline__ void ldsm_x4t(uint32_t* r, const void* p) {
    uint32_t a = smem_u32(p);
    asm volatile("ldmatrix.sync.aligned.m8n8.x4.trans.shared.b16 {%0,%1,%2,%3}, [%4];"
                 : "=r"(r[0]), "=r"(r[1]), "=r"(r[2]), "=r"(r[3]) : "r"(a));
}
__device__ __forceinline__ void ldsm_x2t(uint32_t &r0, uint32_t &r1,
                                         const void* p) {
    uint32_t a = smem_u32(p);
    asm volatile("ldmatrix.sync.aligned.m8n8.x2.trans.shared.b16 {%0,%1}, [%2];"
                 : "=r"(r0), "=r"(r1) : "r"(a));
}
__device__ __forceinline__ void mma_bf16(float* c, const uint32_t* a,
                                         const uint32_t* b) {
    asm volatile(
        "mma.sync.aligned.m16n8k16.row.col.f32.bf16.bf16.f32 "
        "{%0,%1,%2,%3}, {%4,%5,%6,%7}, {%8,%9}, {%0,%1,%2,%3};"
        : "+f"(c[0]), "+f"(c[1]), "+f"(c[2]), "+f"(c[3])
        : "r"(a[0]), "r"(a[1]), "r"(a[2]), "r"(a[3]), "r"(b[0]), "r"(b[1]));
}
__device__ __forceinline__ void cpa16(void* s, const void* g) {
    asm volatile("cp.async.cg.shared.global [%0], [%1], 16;"
                 :: "r"(smem_u32(s)), "l"(g));
}
#define CP_COMMIT asm volatile("cp.async.commit_group;")
#define CP_WAIT0  asm volatile("cp.async.wait_group 0;")

__device__ __forceinline__ uint32_t pk(bf16 a, bf16 b) {
    __nv_bfloat162 t(a, b);
    return *reinterpret_cast<uint32_t*>(&t);
}

// ---------------- split fp32 -> (hi, lo) bf16 ----------------
__global__ __launch_bounds__(256) void split_kernel(
    const float* __restrict__ s, bf16* __restrict__ h,
    bf16* __restrict__ l, int n)
{
    int i = (blockIdx.x * 256 + threadIdx.x) * 4;
    if (i >= n) return;
    float4 v = *(const float4*)(s + i);
    bf16 h0 = __float2bfloat16(v.x), h1 = __float2bfloat16(v.y);
    bf16 h2 = __float2bfloat16(v.z), h3 = __float2bfloat16(v.w);
    *(__nv_bfloat162*)(h + i)     = __nv_bfloat162(h0, h1);
    *(__nv_bfloat162*)(h + i + 2) = __nv_bfloat162(h2, h3);
    *(__nv_bfloat162*)(l + i) = __nv_bfloat162(
        __float2bfloat16(v.x - __bfloat162float(h0)),
        __float2bfloat16(v.y - __bfloat162float(h1)));
    *(__nv_bfloat162*)(l + i + 2) = __nv_bfloat162(
        __float2bfloat16(v.z - __bfloat162float(h2)),
        __float2bfloat16(v.w - __bfloat162float(h3)));
}

// ---------------- merge two [K,N*] weights into one split [K,N1+N2] --------
__global__ __launch_bounds__(256) void merge_split_kernel(
    const float* __restrict__ W1, const float* __restrict__ W2,
    bf16* __restrict__ h, bf16* __restrict__ l, int N1, int N2, int total)
{
    int i = (blockIdx.x * 256 + threadIdx.x) * 4;
    if (i >= total) return;
    int Nt = N1 + N2;
    int k = i / Nt, n = i % Nt;
    const float* src = (n < N1) ? (W1 + (size_t)k * N1 + n)
                                : (W2 + (size_t)k * N2 + (n - N1));
    float4 v = *(const float4*)src;
    bf16 h0 = __float2bfloat16(v.x), h1 = __float2bfloat16(v.y);
    bf16 h2 = __float2bfloat16(v.z), h3 = __float2bfloat16(v.w);
    *(__nv_bfloat162*)(h + i)     = __nv_bfloat162(h0, h1);
    *(__nv_bfloat162*)(h + i + 2) = __nv_bfloat162(h2, h3);
    *(__nv_bfloat162*)(l + i) = __nv_bfloat162(
        __float2bfloat16(v.x - __bfloat162float(h0)),
        __float2bfloat16(v.y - __bfloat162float(h1)));
    *(__nv_bfloat162*)(l + i + 2) = __nv_bfloat162(
        __float2bfloat16(v.z - __bfloat162float(h2)),
        __float2bfloat16(v.w - __bfloat162float(h3)));
}

// ---------------- merge three [K,N*] weights into one split [K,N1+N2+N3] ---
__global__ __launch_bounds__(256) void merge3_split_kernel(
    const float* __restrict__ W1, const float* __restrict__ W2,
    const float* __restrict__ W3,
    bf16* __restrict__ h, bf16* __restrict__ l,
    int N1, int N2, int N3, int total)
{
    int i = (blockIdx.x * 256 + threadIdx.x) * 4;
    if (i >= total) return;
    int Nt = N1 + N2 + N3;
    int k = i / Nt, n = i % Nt;
    const float* src;
    if (n < N1)            src = W1 + (size_t)k * N1 + n;
    else if (n < N1 + N2)  src = W2 + (size_t)k * N2 + (n - N1);
    else                   src = W3 + (size_t)k * N3 + (n - N1 - N2);
    float4 v = *(const float4*)src;
    bf16 h0 = __float2bfloat16(v.x), h1 = __float2bfloat16(v.y);
    bf16 h2 = __float2bfloat16(v.z), h3 = __float2bfloat16(v.w);
    *(__nv_bfloat162*)(h + i)     = __nv_bfloat162(h0, h1);
    *(__nv_bfloat162*)(h + i + 2) = __nv_bfloat162(h2, h3);
    *(__nv_bfloat162*)(l + i) = __nv_bfloat162(
        __float2bfloat16(v.x - __bfloat162float(h0)),
        __float2bfloat16(v.y - __bfloat162float(h1)));
    *(__nv_bfloat162*)(l + i + 2) = __nv_bfloat162(
        __float2bfloat16(v.z - __bfloat162float(h2)),
        __float2bfloat16(v.w - __bfloat162float(h3)));
}

// ---------------- split-bf16 TC GEMM, 2-stage cp.async, 1 sync/iter --------
#define GS_A   (128*40)
#define GS_B   (32*136)
#define GS_STG (2*GS_A + 2*GS_B)
#define GS_SMEM (2*GS_STG*2)

__global__ __launch_bounds__(256) void gemm_split(
    const bf16* __restrict__ Ah, const bf16* __restrict__ Al,
    const bf16* __restrict__ Bh, const bf16* __restrict__ Bl,
    float* __restrict__ C, int M, int N, int K)
{
    extern __shared__ __align__(16) bf16 gsm[];

    int tid = threadIdx.x;
    int bm = blockIdx.y, bn = blockIdx.x;
    int warp = tid >> 5, lane = tid & 31;
    int wm = warp >> 2, wn = warp & 3;

    int arow = tid >> 2, ac = (tid & 3) * 8;
    int brow = tid >> 4, bc = (tid & 15) * 8;

    float acc[4][4][4];
#pragma unroll
    for (int a = 0; a < 4; a++)
#pragma unroll
        for (int b = 0; b < 4; b++)
#pragma unroll
            for (int c = 0; c < 4; c++) acc[a][b][c] = 0.f;

    int nk = K >> 5;

    auto issue = [&](int stage, int k0) {
        bf16* sAh = gsm + stage * GS_STG;
        bf16* sAl = sAh + GS_A;
        bf16* sBh = sAl + GS_A;
        bf16* sBl = sBh + GS_B;
#pragma unroll
        for (int i = 0; i < 2; i++) {
            int r = arow + i * 64;
            size_t g = (size_t)(bm * 128 + r) * K + k0 + ac;
            cpa16(&sAh[r * 40 + ac], Ah + g);
            cpa16(&sAl[r * 40 + ac], Al + g);
        }
#pragma unroll
        for (int i = 0; i < 2; i++) {
            int r = brow + i * 16;
            size_t g = (size_t)(k0 + r) * N + bn * 128 + bc;
            cpa16(&sBh[r * 136 + bc], Bh + g);
            cpa16(&sBl[r * 136 + bc], Bl + g);
        }
    };

    issue(0, 0);
    CP_COMMIT;

    for (int it = 0; it < nk; it++) {
        CP_WAIT0;              // exactly one group outstanding: buffer 'it'
        __syncthreads();       // also fences prior compute before reissue
        if (it + 1 < nk) {
            issue((it + 1) & 1, (it + 1) << 5);
            CP_COMMIT;
        }

        bf16* sAh = gsm + (it & 1) * GS_STG;
        bf16* sAl = sAh + GS_A;
        bf16* sBh = sAl + GS_A;
        bf16* sBl = sBh + GS_B;

#pragma unroll
        for (int kh = 0; kh < 2; kh++) {
            uint32_t bhf[4][2], blf[4][2];
#pragma unroll
            for (int nt = 0; nt < 4; nt++) {
                int br = kh * 16 + (lane & 15);
                int bcl = wn * 32 + nt * 8;
                ldsm_x2t(bhf[nt][0], bhf[nt][1], &sBh[br * 136 + bcl]);
                ldsm_x2t(blf[nt][0], blf[nt][1], &sBl[br * 136 + bcl]);
            }
#pragma unroll
            for (int mt = 0; mt < 4; mt++) {
                int ar = wm * 64 + mt * 16 + (lane & 15);
                int acl = kh * 16 + (lane >> 4) * 8;
                uint32_t ah[4], al[4];
                ldsm_x4(ah, &sAh[ar * 40 + acl]);
                ldsm_x4(al, &sAl[ar * 40 + acl]);
#pragma unroll
                for (int nt = 0; nt < 4; nt++) {
                    mma_bf16(acc[mt][nt], ah, bhf[nt]);
                    mma_bf16(acc[mt][nt], ah, blf[nt]);
                    mma_bf16(acc[mt][nt], al, bhf[nt]);
                }
            }
        }
    }

#pragma unroll
    for (int mt = 0; mt < 4; mt++) {
#pragma unroll
        for (int nt = 0; nt < 4; nt++) {
            int r0 = bm * 128 + wm * 64 + mt * 16 + (lane >> 2);
            int c0 = bn * 128 + wn * 32 + nt * 8 + (lane & 3) * 2;
            *(float2*)&C[(size_t)r0 * N + c0] =
                make_float2(acc[mt][nt][0], acc[mt][nt][1]);
            *(float2*)&C[(size_t)(r0 + 8) * N + c0] =
                make_float2(acc[mt][nt][2], acc[mt][nt][3]);
        }
    }
}

// ---------------- RMSNorm slice -> split bf16 outputs ----------------
__global__ __launch_bounds__(256) void rmsnorm_split_kernel(
    const float* __restrict__ x, int rowstride, int off,
    const float* __restrict__ w,
    bf16* __restrict__ hi, bf16* __restrict__ lo, int n)
{
    const float* row = x + (size_t)blockIdx.x * rowstride + off;
    float ss = 0.f;
    for (int i = threadIdx.x; i < n; i += 256) { float v = row[i]; ss += v*v; }
    __shared__ float sh[8];
    __shared__ float tot;
    int lane = threadIdx.x & 31, wp = threadIdx.x >> 5;
#pragma unroll
    for (int o = 16; o; o >>= 1) ss += __shfl_xor_sync(0xffffffffu, ss, o);
    if (lane == 0) sh[wp] = ss;
    __syncthreads();
    if (threadIdx.x == 0) {
        float s = 0.f;
        for (int i = 0; i < 8; i++) s += sh[i];
        tot = rsqrtf(s / n + 1e-6f);
    }
    __syncthreads();
    float rs = tot;
    bf16* hrow = hi + (size_t)blockIdx.x * n;
    bf16* lrow = lo + (size_t)blockIdx.x * n;
    for (int i = threadIdx.x; i < n; i += 256) {
        float y = row[i] * rs * w[i];
        bf16 h = __float2bfloat16(y);
        hrow[i] = h;
        lrow[i] = __float2bfloat16(y - __bfloat162float(h));
    }
}

// ---------------- gate alpha ----------------
__global__ __launch_bounds__(256) void alpha_kernel(
    const float* __restrict__ x, const float* __restrict__ wg,
    const float* __restrict__ bg, float* __restrict__ alpha,
    float* __restrict__ out_alpha)
{
    const float* row = x + (size_t)blockIdx.x * DD;
    float s = 0.f;
    for (int i = threadIdx.x; i < DD; i += 256) s += row[i] * wg[i];
    __shared__ float sh[8];
    int lane = threadIdx.x & 31, wp = threadIdx.x >> 5;
#pragma unroll
    for (int o = 16; o; o >>= 1) s += __shfl_xor_sync(0xffffffffu, s, o);
    if (lane == 0) sh[wp] = s;
    __syncthreads();
    if (threadIdx.x == 0) {
        float t = 0.f;
        for (int i = 0; i < 8; i++) t += sh[i];
        float z = t + bg[0];
        float a = 1.f / (1.f + expf(-z));
        alpha[blockIdx.x] = a;
        if (out_alpha) out_alpha[blockIdx.x] = a;
    }
}

// ---------------- assemble Q/K/V with EPE-RoPE (emit split bf16) -----------
__global__ __launch_bounds__(128) void assemble_kernel(
    const float* __restrict__ qcr, const float* __restrict__ kcv,
    const float* __restrict__ lat3, const float* __restrict__ unc,
    bf16* __restrict__ Qh, bf16* __restrict__ Ql,
    bf16* __restrict__ Kh, bf16* __restrict__ Kl,
    bf16* __restrict__ Vh, bf16* __restrict__ Vl)
{
    int idx = blockIdx.x;
    int h  = idx % NHH;
    int bt = idx / NHH;
    int t  = bt % TT;
    int b  = bt / TT;
    __shared__ float cs[32], sn[32];
    int d = threadIdx.x;
    if (d < 32) {
        float u = unc[bt];
        u = fminf(fmaxf(u, 0.f), 1.f);
        float scale = 0.5f + 1.5f * u;
        float fi = (float)d / 32.0f;
        float theta = expf(-fi * logf(500000.0f));
        float fr = (float)t * theta * scale;
        cs[d] = cosf(fr);
        sn[d] = sinf(fr);
    }
    __syncthreads();
    size_t qkrow = ((size_t)(b*NHH + h))*TT + t;

    float qv0 = qcr[(size_t)bt*3072 + h*128 + d];
    float kv0 = kcv[(size_t)bt*4096 + h*128 + d];
    float vv0 = kcv[(size_t)bt*4096 + 2048 + h*128 + d];
    bf16 hh;
    hh = __float2bfloat16(qv0);
    Qh[qkrow*DQK + d] = hh; Ql[qkrow*DQK + d] = __float2bfloat16(qv0 - __bfloat162float(hh));
    hh = __float2bfloat16(kv0);
    Kh[qkrow*DQK + d] = hh; Kl[qkrow*DQK + d] = __float2bfloat16(kv0 - __bfloat162float(hh));
    hh = __float2bfloat16(vv0);
    Vh[qkrow*DVV + d] = hh; Vl[qkrow*DVV + d] = __float2bfloat16(vv0 - __bfloat162float(hh));

    if (d < 64) {
        const float* qrp = qcr  + (size_t)bt*3072 + 2048 + h*64;
        const float* krp = lat3 + (size_t)bt*3072 + 2048 + h*64;
        float qv, kv;
        if (d < 32) {
            float c = cs[d], s = sn[d];
            qv = qrp[d]*c - qrp[d+32]*s;
            kv = krp[d]*c - krp[d+32]*s;
        } else {
            int j = d - 32;
            float c = cs[j], s = sn[j];
            qv = qrp[j+32]*c + qrp[j]*s;
            kv = krp[j+32]*c + krp[j]*s;
        }
        hh = __float2bfloat16(qv);
        Qh[qkrow*DQK + 128 + d] = hh;
        Ql[qkrow*DQK + 128 + d] = __float2bfloat16(qv - __bfloat162float(hh));
        hh = __float2bfloat16(kv);
        Kh[qkrow*DQK + 128 + d] = hh;
        Kl[qkrow*DQK + 128 + d] = __float2bfloat16(kv - __bfloat162float(hh));
    }
}

// ---------------- tensor-core fused dual attention (1 sync/tile) -----------
// Streams: oR(ob) = bidir-only keys, oW(ow) = window keys; bidir = ob + ow.
#define KSTR 200
#define VSTR 136
#define ATTN_SMEM ((64*KSTR*2 + 2*64*KSTR*2 + 2*64*VSTR*2) * 2)

__global__ void __launch_bounds__(128, 1) attn_tc_kernel(
    const bf16* __restrict__ Qh, const bf16* __restrict__ Ql,
    const bf16* __restrict__ Kh, const bf16* __restrict__ Kl,
    const bf16* __restrict__ Vh, const bf16* __restrict__ Vl,
    const float* __restrict__ alpha,
    bf16* __restrict__ mgh, bf16* __restrict__ mgl)
{
    extern __shared__ __align__(16) bf16 smem[];
    bf16* sQh = smem;
    bf16* sQl = sQh + 64*KSTR;
    bf16* sKh = sQl + 64*KSTR;
    bf16* sKl = sKh + 2*64*KSTR;
    bf16* sVh = sKl + 2*64*KSTR;
    bf16* sVl = sVh + 2*64*VSTR;

    int tid = threadIdx.x, lane = tid & 31, warp = tid >> 5;
    int qt = blockIdx.x * 64;
    int bh = blockIdx.y;
    int b = bh >> 4, h = bh & 15;
    size_t base = (size_t)bh * TT;

    // prologue: Q tile + K/V tile 0 in one group
    for (int i = tid; i < 64*24; i += 128) {
        int r = i / 24, c = (i % 24) * 8;
        size_t g = (base + qt + r) * DQK + c;
        cpa16(&sQh[r*KSTR + c], Qh + g);
        cpa16(&sQl[r*KSTR + c], Ql + g);
    }
    for (int i = tid; i < 64*24; i += 128) {
        int r = i / 24, c = (i % 24) * 8;
        size_t g = (base + r) * DQK + c;
        cpa16(&sKh[r*KSTR + c], Kh + g);
        cpa16(&sKl[r*KSTR + c], Kl + g);
    }
    for (int i = tid; i < 64*16; i += 128) {
        int r = i / 16, c = (i % 16) * 8;
        size_t g = (base + r) * DVV + c;
        cpa16(&sVh[r*VSTR + c], Vh + g);
        cpa16(&sVl[r*VSTR + c], Vl + g);
    }
    CP_COMMIT;

    int q0 = qt + 16*warp + (lane >> 2);
    int q1 = q0 + 8;
    int winlo = ((qt >> 8) << 8) - HALFW;
    if (winlo < 0) winlo = 0;

    float ob[16][4], ow[16][4];
#pragma unroll
    for (int n = 0; n < 16; n++)
#pragma unroll
        for (int j = 0; j < 4; j++) { ob[n][j] = 0.f; ow[n][j] = 0.f; }
    float m0 = -1e30f, m1 = -1e30f;
    float lb0 = 0.f, lb1 = 0.f, lw0 = 0.f, lw1 = 0.f;

    for (int t = 0; t < 32; t++) {
        int kt = t * 64;

        CP_WAIT0;              // tile t resident
        __syncthreads();       // fences prior tile's compute before reissue
        if (t + 1 < 32) {
            int nb = (t + 1) & 1;
            int kn = kt + 64;
            for (int i = tid; i < 64*24; i += 128) {
                int r = i / 24, c = (i % 24) * 8;
                size_t g = (base + kn + r) * DQK + c;
                cpa16(&sKh[nb*64*KSTR + r*KSTR + c], Kh + g);
                cpa16(&sKl[nb*64*KSTR + r*KSTR + c], Kl + g);
            }
            for (int i = tid; i < 64*16; i += 128) {
                int r = i / 16, c = (i % 16) * 8;
                size_t g = (base + kn + r) * DVV + c;
                cpa16(&sVh[nb*64*VSTR + r*VSTR + c], Vh + g);
                cpa16(&sVl[nb*64*VSTR + r*VSTR + c], Vl + g);
            }
            CP_COMMIT;
        }

        const bf16* bKh = sKh + (t & 1) * 64 * KSTR;
        const bf16* bVh = sVh + (t & 1) * 64 * VSTR;

        bool diag    = (kt == qt);
        bool fullwin = (kt >= winlo) && (kt < qt);

        float sacc[8][4];
#pragma unroll
        for (int n = 0; n < 8; n++)
#pragma unroll
            for (int j = 0; j < 4; j++) sacc[n][j] = 0.f;

#pragma unroll
        for (int ks = 0; ks < 12; ks++) {
            uint32_t qhf[4], qlf[4];
            const bf16* ap = &sQh[(16*warp + (lane & 15))*KSTR + ks*16 + (lane >> 4)*8];
            ldsm_x4(qhf, ap);
            ldsm_x4(qlf, ap + 64*KSTR);
#pragma unroll
            for (int np = 0; np < 4; np++) {
                int g2 = lane >> 3;
                int krow = np*16 + (g2 >> 1)*8 + (lane & 7);
                int kcol = ks*16 + (g2 & 1)*8;
                const bf16* bp = &bKh[krow*KSTR + kcol];
                uint32_t khf[4], klf[4];
                ldsm_x4(khf, bp);
                ldsm_x4(klf, bp + 2*64*KSTR);
                mma_bf16(sacc[2*np],   qhf, khf);
                mma_bf16(sacc[2*np],   qhf, klf);
                mma_bf16(sacc[2*np],   qlf, khf);
                mma_bf16(sacc[2*np+1], qhf, khf + 2);
                mma_bf16(sacc[2*np+1], qhf, klf + 2);
                mma_bf16(sacc[2*np+1], qlf, khf + 2);
            }
        }

        float tm0 = -1e30f, tm1 = -1e30f;
#pragma unroll
        for (int n = 0; n < 8; n++) {
            tm0 = fmaxf(tm0, fmaxf(sacc[n][0], sacc[n][1]));
            tm1 = fmaxf(tm1, fmaxf(sacc[n][2], sacc[n][3]));
        }
        tm0 *= RSCALE; tm1 *= RSCALE;
        tm0 = fmaxf(tm0, __shfl_xor_sync(0xffffffffu, tm0, 1));
        tm0 = fmaxf(tm0, __shfl_xor_sync(0xffffffffu, tm0, 2));
        tm1 = fmaxf(tm1, __shfl_xor_sync(0xffffffffu, tm1, 1));
        tm1 = fmaxf(tm1, __shfl_xor_sync(0xffffffffu, tm1, 2));
        float mn0 = fmaxf(m0, tm0), mn1 = fmaxf(m1, tm1);
        float c0 = __expf(m0 - mn0), c1 = __expf(m1 - mn1);
        m0 = mn0; m1 = mn1;
        lb0 *= c0; lb1 *= c1; lw0 *= c0; lw1 *= c1;
        if (c0 < 1.f || c1 < 1.f) {
#pragma unroll
            for (int n = 0; n < 16; n++) {
                ob[n][0] *= c0; ob[n][1] *= c0; ob[n][2] *= c1; ob[n][3] *= c1;
                ow[n][0] *= c0; ow[n][1] *= c0; ow[n][2] *= c1; ow[n][3] *= c1;
            }
        }

        float sb0 = 0.f, sb1 = 0.f, sw0 = 0.f, sw1 = 0.f;
#pragma unroll
        for (int n = 0; n < 8; n++) {
            float p0 = __expf(sacc[n][0]*RSCALE - mn0);
            float p1 = __expf(sacc[n][1]*RSCALE - mn0);
            float p2 = __expf(sacc[n][2]*RSCALE - mn1);
            float p3 = __expf(sacc[n][3]*RSCALE - mn1);
            sacc[n][0] = p0; sacc[n][1] = p1; sacc[n][2] = p2; sacc[n][3] = p3;
            sb0 += p0 + p1; sb1 += p2 + p3;
            if (diag) {
                int keyc = kt + 8*n + 2*(lane & 3);
                sw0 += ((keyc   <= q0) ? p0 : 0.f) + ((keyc+1 <= q0) ? p1 : 0.f);
                sw1 += ((keyc   <= q1) ? p2 : 0.f) + ((keyc+1 <= q1) ? p3 : 0.f);
            }
        }
        sb0 += __shfl_xor_sync(0xffffffffu, sb0, 1); sb0 += __shfl_xor_sync(0xffffffffu, sb0, 2);
        sb1 += __shfl_xor_sync(0xffffffffu, sb1, 1); sb1 += __shfl_xor_sync(0xffffffffu, sb1, 2);
        lb0 += sb0; lb1 += sb1;
        if (fullwin) { lw0 += sb0; lw1 += sb1; }
        if (diag) {
            sw0 += __shfl_xor_sync(0xffffffffu, sw0, 1); sw0 += __shfl_xor_sync(0xffffffffu, sw0, 2);
            sw1 += __shfl_xor_sync(0xffffffffu, sw1, 1); sw1 += __shfl_xor_sync(0xffffffffu, sw1, 2);
            lw0 += sw0; lw1 += sw1;
        }

#pragma unroll
        for (int j = 0; j < 4; j++) {
            float v0 = sacc[2*j][0],   v1 = sacc[2*j][1];
            float v2 = sacc[2*j][2],   v3 = sacc[2*j][3];
            float v4 = sacc[2*j+1][0], v5 = sacc[2*j+1][1];
            float v6 = sacc[2*j+1][2], v7 = sacc[2*j+1][3];
            bf16 h0 = __float2bfloat16(v0), h1 = __float2bfloat16(v1);
            bf16 h2 = __float2bfloat16(v2), h3 = __float2bfloat16(v3);
            bf16 h4 = __float2bfloat16(v4), h5 = __float2bfloat16(v5);
            bf16 h6 = __float2bfloat16(v6), h7 = __float2bfloat16(v7);
            bf16 e0 = __float2bfloat16(v0 - __bfloat162float(h0));
            bf16 e1 = __float2bfloat16(v1 - __bfloat162float(h1));
            bf16 e2 = __float2bfloat16(v2 - __bfloat162float(h2));
            bf16 e3 = __float2bfloat16(v3 - __bfloat162float(h3));
            bf16 e4 = __float2bfloat16(v4 - __bfloat162float(h4));
            bf16 e5 = __float2bfloat16(v5 - __bfloat162float(h5));
            bf16 e6 = __float2bfloat16(v6 - __bfloat162float(h6));
            bf16 e7 = __float2bfloat16(v7 - __bfloat162float(h7));
            uint32_t ph2[4] = { pk(h0,h1), pk(h2,h3), pk(h4,h5), pk(h6,h7) };
            uint32_t pl2[4] = { pk(e0,e1), pk(e2,e3), pk(e4,e5), pk(e6,e7) };

            if (diag) {
                bf16 z = __float2bfloat16(0.f);
                int kc = kt + 16*j + 2*(lane & 3);
                bool a0 = kc   <= q0, a1 = kc+1 <= q0;
                bool b0m = kc  <= q1, b1m = kc+1 <= q1;
                bool a2 = kc+8 <= q0, a3 = kc+9 <= q0;
                bool b2m = kc+8 <= q1, b3m = kc+9 <= q1;
                uint32_t wh[4], wl[4], xh2[4], xl2[4];
                wh[0] = pk(a0?h0:z, a1?h1:z);   wl[0] = pk(a0?e0:z, a1?e1:z);
                wh[1] = pk(b0m?h2:z, b1m?h3:z); wl[1] = pk(b0m?e2:z, b1m?e3:z);
                wh[2] = pk(a2?h4:z, a3?h5:z);   wl[2] = pk(a2?e4:z, a3?e5:z);
                wh[3] = pk(b2m?h6:z, b3m?h7:z); wl[3] = pk(b2m?e6:z, b3m?e7:z);
                xh2[0] = pk(a0?z:h0, a1?z:h1);   xl2[0] = pk(a0?z:e0, a1?z:e1);
                xh2[1] = pk(b0m?z:h2, b1m?z:h3); xl2[1] = pk(b0m?z:e2, b1m?z:e3);
                xh2[2] = pk(a2?z:h4, a3?z:h5);   xl2[2] = pk(a2?z:e4, a3?z:e5);
                xh2[3] = pk(b2m?z:h6, b3m?z:h7); xl2[3] = pk(b2m?z:e6, b3m?z:e7);
#pragma unroll
                for (int np = 0; np < 8; np++) {
                    int g2 = lane >> 3;
                    int vrow = 16*j + (g2 & 1)*8 + (lane & 7);
                    int vcol = np*16 + (g2 >> 1)*8;
                    const bf16* vp = &bVh[vrow*VSTR + vcol];
                    uint32_t vhf[4], vlf[4];
                    ldsm_x4t(vhf, vp);
                    ldsm_x4t(vlf, vp + 2*64*VSTR);
                    mma_bf16(ow[2*np],   wh, vhf);
                    mma_bf16(ow[2*np],   wh, vlf);
                    mma_bf16(ow[2*np],   wl, vhf);
                    mma_bf16(ow[2*np+1], wh, vhf + 2);
                    mma_bf16(ow[2*np+1], wh, vlf + 2);
                    mma_bf16(ow[2*np+1], wl, vhf + 2);
                    mma_bf16(ob[2*np],   xh2, vhf);
                    mma_bf16(ob[2*np],   xh2, vlf);
                    mma_bf16(ob[2*np],   xl2, vhf);
                    mma_bf16(ob[2*np+1], xh2, vhf + 2);
                    mma_bf16(ob[2*np+1], xh2, vlf + 2);
                    mma_bf16(ob[2*np+1], xl2, vhf + 2);
                }
            } else if (fullwin) {
#pragma unroll
                for (int np = 0; np < 8; np++) {
                    int g2 = lane >> 3;
                    int vrow = 16*j + (g2 & 1)*8 + (lane & 7);
                    int vcol = np*16 + (g2 >> 1)*8;
                    const bf16* vp = &bVh[vrow*VSTR + vcol];
                    uint32_t vhf[4], vlf[4];
                    ldsm_x4t(vhf, vp);
                    ldsm_x4t(vlf, vp + 2*64*VSTR);
                    mma_bf16(ow[2*np],   ph2, vhf);
                    mma_bf16(ow[2*np],   ph2, vlf);
                    mma_bf16(ow[2*np],   pl2, vhf);
                    mma_bf16(ow[2*np+1], ph2, vhf + 2);
                    mma_bf16(ow[2*np+1], ph2, vlf + 2);
                    mma_bf16(ow[2*np+1], pl2, vhf + 2);
                }
            } else {
#pragma unroll
                for (int np = 0; np < 8; np++) {
                    int g2 = lane >> 3;
                    int vrow = 16*j + (g2 & 1)*8 + (lane & 7);
                    int vcol = np*16 + (g2 >> 1)*8;
                    const bf16* vp = &bVh[vrow*VSTR + vcol];
                    uint32_t vhf[4], vlf[4];
                    ldsm_x4t(vhf, vp);
                    ldsm_x4t(vlf, vp + 2*64*VSTR);
                    mma_bf16(ob[2*np],   ph2, vhf);
                    mma_bf16(ob[2*np],   ph2, vlf);
                    mma_bf16(ob[2*np],   pl2, vhf);
                    mma_bf16(ob[2*np+1], ph2, vhf + 2);
                    mma_bf16(ob[2*np+1], ph2, vlf + 2);
                    mma_bf16(ob[2*np+1], pl2, vhf + 2);
                }
            }
        }
    }

    float a0 = alpha[(size_t)b*TT + q0];
    float a1 = alpha[(size_t)b*TT + q1];
    float ilb0 = 1.f/lb0, ilb1 = 1.f/lb1, ilw0 = 1.f/lw0, ilw1 = 1.f/lw1;
    size_t r0o = ((size_t)b*TT + q0)*2048 + (size_t)h*128;
    size_t r1o = ((size_t)b*TT + q1)*2048 + (size_t)h*128;
#pragma unroll
    for (int n = 0; n < 16; n++) {
        int d = 8*n + 2*(lane & 3);
        float b00 = ob[n][0] + ow[n][0], b01 = ob[n][1] + ow[n][1];
        float b10 = ob[n][2] + ow[n][2], b11 = ob[n][3] + ow[n][3];
        float o00 = a0*b00*ilb0 + (1.f-a0)*ow[n][0]*ilw0;
        float o01 = a0*b01*ilb0 + (1.f-a0)*ow[n][1]*ilw0;
        float o10 = a1*b10*ilb1 + (1.f-a1)*ow[n][2]*ilw1;
        float o11 = a1*b11*ilb1 + (1.f-a1)*ow[n][3]*ilw1;
        bf16 h00 = __float2bfloat16(o00), h01 = __float2bfloat16(o01);
        bf16 h10 = __float2bfloat16(o10), h11 = __float2bfloat16(o11);
        *(uint32_t*)(mgh + r0o + d) = pk(h00, h01);
        *(uint32_t*)(mgh + r1o + d) = pk(h10, h11);
        *(uint32_t*)(mgl + r0o + d) = pk(
            __float2bfloat16(o00 - __bfloat162float(h00)),
            __float2bfloat16(o01 - __bfloat162float(h01)));
        *(uint32_t*)(mgl + r1o + d) = pk(
            __float2bfloat16(o10 - __bfloat162float(h10)),
            __float2bfloat16(o11 - __bfloat162float(h11)));
    }
}

// ---------------- launcher ----------------
extern "C" void kernel_launch(void* const* d_in, const int* in_sizes, int n_in,
                              void* d_out, int out_size)
{
    (void)in_sizes; (void)n_in;
    const float* x        = (const float*)d_in[0];
    const float* unc      = (const float*)d_in[1];
    const float* Wq_down  = (const float*)d_in[2];
    const float* q_norm_w = (const float*)d_in[3];
    const float* Wq_up    = (const float*)d_in[4];
    const float* Wq_rope  = (const float*)d_in[5];
    const float* Wkv_down = (const float*)d_in[6];
    const float* kv_norm_w= (const float*)d_in[7];
    const float* Wk_up    = (const float*)d_in[8];
    const float* Wv_up    = (const float*)d_in[9];
    const float* Wk_rope  = (const float*)d_in[10];
    const float* Wout     = (const float*)d_in[11];
    const float* Wgate    = (const float*)d_in[12];
    const float* bgate    = (const float*)d_in[13];
    float* out = (float*)d_out;

    float *lat3, *qcr, *kcv, *al;
    bf16 *Qh,*Ql,*Kh,*Kl,*Vh,*Vl;
    bf16 *xh,*xl,*qlh,*qll,*kvh,*kvl,*mgh,*mgl;
    bf16 *wdnh,*wdnl,*wquph,*wqupl,*wkvuh,*wkvul,*woh,*wol;
    cudaGetSymbolAddress((void**)&lat3,  g_lat3);
    cudaGetSymbolAddress((void**)&qcr,   g_qcr);
    cudaGetSymbolAddress((void**)&kcv,   g_kcv);
    cudaGetSymbolAddress((void**)&al,    g_alpha);
    cudaGetSymbolAddress((void**)&Qh,    g_Qh);
    cudaGetSymbolAddress((void**)&Ql,    g_Ql);
    cudaGetSymbolAddress((void**)&Kh,    g_Kh);
    cudaGetSymbolAddress((void**)&Kl,    g_Kl);
    cudaGetSymbolAddress((void**)&Vh,    g_Vh);
    cudaGetSymbolAddress((void**)&Vl,    g_Vl);
    cudaGetSymbolAddress((void**)&xh,    g_xh);
    cudaGetSymbolAddress((void**)&xl,    g_xl);
    cudaGetSymbolAddress((void**)&qlh,   g_qlh);
    cudaGetSymbolAddress((void**)&qll,   g_qll);
    cudaGetSymbolAddress((void**)&kvh,   g_kvh);
    cudaGetSymbolAddress((void**)&kvl,   g_kvl);
    cudaGetSymbolAddress((void**)&mgh,   g_mgh);
    cudaGetSymbolAddress((void**)&mgl,   g_mgl);
    cudaGetSymbolAddress((void**)&wdnh,  g_wdn_h);
    cudaGetSymbolAddress((void**)&wdnl,  g_wdn_l);
    cudaGetSymbolAddress((void**)&wquph, g_wqup_h);
    cudaGetSymbolAddress((void**)&wqupl, g_wqup_l);
    cudaGetSymbolAddress((void**)&wkvuh, g_wkvu_h);
    cudaGetSymbolAddress((void**)&wkvul, g_wkvu_l);
    cudaGetSymbolAddress((void**)&woh,   g_wo_h);
    cudaGetSymbolAddress((void**)&wol,   g_wo_l);

    cudaFuncSetAttribute(attn_tc_kernel,
                         cudaFuncAttributeMaxDynamicSharedMemorySize, ATTN_SMEM);
    cudaFuncSetAttribute(gemm_split,
                         cudaFuncAttributeMaxDynamicSharedMemorySize, GS_SMEM);

    auto split = [&](const float* s, bf16* h, bf16* l, size_t n) {
        split_kernel<<<(int)(n / 1024), 256>>>(s, h, l, (int)n);
    };
    auto gemm = [&](const bf16* Ah, const bf16* Al, const bf16* Bh,
                    const bf16* Bl, float* C, int M, int N, int K) {
        gemm_split<<<dim3(N/128, M/128), 256, GS_SMEM>>>(Ah, Al, Bh, Bl, C, M, N, K);
    };

    // launch order: index 3 (ncu capture slot) = merged down-projection GEMM
    split(x, xh, xl, (size_t)BT*DD);                                   // 0
    merge3_split_kernel<<<(DD*3072)/1024, 256>>>(Wq_down, Wkv_down,
        Wk_rope, wdnh, wdnl, CQQ, CKVV, 1024, DD*3072);                // 1
    merge_split_kernel<<<(CQQ*3072)/1024, 256>>>(Wq_up, Wq_rope,
        wquph, wqupl, 2048, 1024, CQQ*3072);                           // 2
    gemm(xh, xl, wdnh, wdnl, lat3, BT, 3072, DD);                      // 3 <- ncu

    rmsnorm_split_kernel<<<BT, 256>>>(lat3, 3072, 0,    q_norm_w,  qlh, qll, CQQ);
    rmsnorm_split_kernel<<<BT, 256>>>(lat3, 3072, CQQ,  kv_norm_w, kvh, kvl, CKVV);

    gemm(qlh, qll, wquph, wqupl, qcr, BT, 3072, CQQ);

    merge_split_kernel<<<(CKVV*4096)/1024, 256>>>(Wk_up, Wv_up,
        wkvuh, wkvul, 2048, 2048, CKVV*4096);
    gemm(kvh, kvl, wkvuh, wkvul, kcv, BT, 4096, CKVV);

    split(Wout, woh, wol, (size_t)2048*DD);

    float* out_alpha = (out_size >= BB*TT*DD + BB*TT) ? (out + (size_t)BB*TT*DD)
                                                      : nullptr;
    alpha_kernel<<<BT, 256>>>(x, Wgate, bgate, al, out_alpha);

    assemble_kernel<<<BT*NHH, 128>>>(qcr, kcv, lat3, unc,
                                     Qh, Ql, Kh, Kl, Vh, Vl);

    attn_tc_kernel<<<dim3(TT/64, BB*NHH), 128, ATTN_SMEM>>>(
        Qh, Ql, Kh, Kl, Vh, Vl, al, mgh, mgl);

    gemm(mgh, mgl, woh, wol, out, BT, DD, 2048);
}

// round 11
// speedup vs baseline: 1.2388x; 1.0040x over previous
#include <cuda_runtime.h>
#include <cuda_bf16.h>
#include <math.h>
#include <stdint.h>

// ---------------- problem constants ----------------
#define BB   2
#define TT   2048
#define DD   2048
#define NHH  16
#define HDD  128
#define RR   64
#define CQQ  1536
#define CKVV 512
#define BT   (BB*TT)       // 4096
#define DQK  192           // HD + R
#define DVV  128
#define HALFW 256          // WINDOW/2
#define RSCALE 0.07216878364870323f  // 1/sqrt(192)

typedef __nv_bfloat16 bf16;

// ---------------- scratch (device globals; no runtime alloc) ----------------
__device__ float g_lat3 [(size_t)BT*3072];   // [qlat(1536) | kvlat(512) | kr(1024)]
__device__ float g_qcr  [(size_t)BT*3072];   // [qc(2048) | qr(1024)]
__device__ float g_kcv  [(size_t)BT*4096];   // [kc(2048) | vv(2048)]
__device__ float g_alpha[BT];

// attention operands, pre-split bf16, head-major: [bh][t][d]
__device__ bf16 g_Qh[(size_t)BB*NHH*TT*DQK], g_Ql[(size_t)BB*NHH*TT*DQK];
__device__ bf16 g_Kh[(size_t)BB*NHH*TT*DQK], g_Kl[(size_t)BB*NHH*TT*DQK];
__device__ bf16 g_Vh[(size_t)BB*NHH*TT*DVV], g_Vl[(size_t)BB*NHH*TT*DVV];

// bf16 split buffers (hi/lo) for GEMMs ([K,N] layout)
__device__ bf16 g_xh [(size_t)BT*DD],    g_xl [(size_t)BT*DD];
__device__ bf16 g_qlh[(size_t)BT*CQQ],   g_qll[(size_t)BT*CQQ];
__device__ bf16 g_kvh[(size_t)BT*CKVV],  g_kvl[(size_t)BT*CKVV];
__device__ bf16 g_mgh[(size_t)BT*NHH*HDD], g_mgl[(size_t)BT*NHH*HDD];
__device__ bf16 g_wdn_h [(size_t)DD*3072],   g_wdn_l [(size_t)DD*3072];   // [Wqd|Wkd|Wkr]
__device__ bf16 g_wqup_h[(size_t)CQQ*3072],  g_wqup_l[(size_t)CQQ*3072];
__device__ bf16 g_wkvu_h[(size_t)CKVV*4096], g_wkvu_l[(size_t)CKVV*4096];
__device__ bf16 g_wo_h  [(size_t)2048*DD],   g_wo_l  [(size_t)2048*DD];

// ---------------- ptx helpers ----------------
__device__ __forceinline__ uint32_t smem_u32(const void* p) {
    return (uint32_t)__cvta_generic_to_shared(p);
}
__device__ __forceinline__ void ldsm_x4(uint32_t* r, const void* p) {
    uint32_t a = smem_u32(p);
    asm volatile("ldmatrix.sync.aligned.m8n8.x4.shared.b16 {%0,%1,%2,%3}, [%4];"
                 : "=r"(r[0]), "=r"(r[1]), "=r"(r[2]), "=r"(r[3]) : "r"(a));
}
__device__ __forceinline__ void ldsm_x4t(uint32_t* r, const void* p) {
    uint32_t a = smem_u32(p);
    asm volatile("ldmatrix.sync.aligned.m8n8.x4.trans.shared.b16 {%0,%1,%2,%3}, [%4];"
                 : "=r"(r[0]), "=r"(r[1]), "=r"(r[2]), "=r"(r[3]) : "r"(a));
}
__device__ __forceinline__ void ldsm_x2t(uint32_t &r0, uint32_t &r1,
                                         const void* p) {
    uint32_t a = smem_u32(p);
    asm volatile("ldmatrix.sync.aligned.m8n8.x2.trans.shared.b16 {%0,%1}, [%2];"
                 : "=r"(r0), "=r"(r1) : "r"(a));
}
__device__ __forceinline__ void mma_bf16(float* c, const uint32_t* a,
                                         const uint32_t* b) {
    asm volatile(
        "mma.sync.aligned.m16n8k16.row.col.f32.bf16.bf16.f32 "
        "{%0,%1,%2,%3}, {%4,%5,%6,%7}, {%8,%9}, {%0,%1,%2,%3};"
        : "+f"(c[0]), "+f"(c[1]), "+f"(c[2]), "+f"(c[3])
        : "r"(a[0]), "r"(a[1]), "r"(a[2]), "r"(a[3]), "r"(b[0]), "r"(b[1]));
}
__device__ __forceinline__ void cpa16(void* s, const void* g) {
    asm volatile("cp.async.cg.shared.global [%0], [%1], 16;"
                 :: "r"(smem_u32(s)), "l"(g));
}
#define CP_COMMIT asm volatile("cp.async.commit_group;")
#define CP_WAIT0  asm volatile("cp.async.wait_group 0;")

__device__ __forceinline__ uint32_t pk(bf16 a, bf16 b) {
    __nv_bfloat162 t(a, b);
    return *reinterpret_cast<uint32_t*>(&t);
}

// ---------------- split fp32 -> (hi, lo) bf16 ----------------
__global__ __launch_bounds__(256) void split_kernel(
    const float* __restrict__ s, bf16* __restrict__ h,
    bf16* __restrict__ l, int n)
{
    int i = (blockIdx.x * 256 + threadIdx.x) * 4;
    if (i >= n) return;
    float4 v = *(const float4*)(s + i);
    bf16 h0 = __float2bfloat16(v.x), h1 = __float2bfloat16(v.y);
    bf16 h2 = __float2bfloat16(v.z), h3 = __float2bfloat16(v.w);
    *(__nv_bfloat162*)(h + i)     = __nv_bfloat162(h0, h1);
    *(__nv_bfloat162*)(h + i + 2) = __nv_bfloat162(h2, h3);
    *(__nv_bfloat162*)(l + i) = __nv_bfloat162(
        __float2bfloat16(v.x - __bfloat162float(h0)),
        __float2bfloat16(v.y - __bfloat162float(h1)));
    *(__nv_bfloat162*)(l + i + 2) = __nv_bfloat162(
        __float2bfloat16(v.z - __bfloat162float(h2)),
        __float2bfloat16(v.w - __bfloat162float(h3)));
}

// ---------------- merge two [K,N*] weights into one split [K,N1+N2] --------
__global__ __launch_bounds__(256) void merge_split_kernel(
    const float* __restrict__ W1, const float* __restrict__ W2,
    bf16* __restrict__ h, bf16* __restrict__ l, int N1, int N2, int total)
{
    int i = (blockIdx.x * 256 + threadIdx.x) * 4;
    if (i >= total) return;
    int Nt = N1 + N2;
    int k = i / Nt, n = i % Nt;
    const float* src = (n < N1) ? (W1 + (size_t)k * N1 + n)
                                : (W2 + (size_t)k * N2 + (n - N1));
    float4 v = *(const float4*)src;
    bf16 h0 = __float2bfloat16(v.x), h1 = __float2bfloat16(v.y);
    bf16 h2 = __float2bfloat16(v.z), h3 = __float2bfloat16(v.w);
    *(__nv_bfloat162*)(h + i)     = __nv_bfloat162(h0, h1);
    *(__nv_bfloat162*)(h + i + 2) = __nv_bfloat162(h2, h3);
    *(__nv_bfloat162*)(l + i) = __nv_bfloat162(
        __float2bfloat16(v.x - __bfloat162float(h0)),
        __float2bfloat16(v.y - __bfloat162float(h1)));
    *(__nv_bfloat162*)(l + i + 2) = __nv_bfloat162(
        __float2bfloat16(v.z - __bfloat162float(h2)),
        __float2bfloat16(v.w - __bfloat162float(h3)));
}

// ---------------- merge three [K,N*] weights into one split [K,N1+N2+N3] ---
__global__ __launch_bounds__(256) void merge3_split_kernel(
    const float* __restrict__ W1, const float* __restrict__ W2,
    const float* __restrict__ W3,
    bf16* __restrict__ h, bf16* __restrict__ l,
    int N1, int N2, int N3, int total)
{
    int i = (blockIdx.x * 256 + threadIdx.x) * 4;
    if (i >= total) return;
    int Nt = N1 + N2 + N3;
    int k = i / Nt, n = i % Nt;
    const float* src;
    if (n < N1)            src = W1 + (size_t)k * N1 + n;
    else if (n < N1 + N2)  src = W2 + (size_t)k * N2 + (n - N1);
    else                   src = W3 + (size_t)k * N3 + (n - N1 - N2);
    float4 v = *(const float4*)src;
    bf16 h0 = __float2bfloat16(v.x), h1 = __float2bfloat16(v.y);
    bf16 h2 = __float2bfloat16(v.z), h3 = __float2bfloat16(v.w);
    *(__nv_bfloat162*)(h + i)     = __nv_bfloat162(h0, h1);
    *(__nv_bfloat162*)(h + i + 2) = __nv_bfloat162(h2, h3);
    *(__nv_bfloat162*)(l + i) = __nv_bfloat162(
        __float2bfloat16(v.x - __bfloat162float(h0)),
        __float2bfloat16(v.y - __bfloat162float(h1)));
    *(__nv_bfloat162*)(l + i + 2) = __nv_bfloat162(
        __float2bfloat16(v.z - __bfloat162float(h2)),
        __float2bfloat16(v.w - __bfloat162float(h3)));
}

// ---------------- split-bf16 TC GEMM, 2-stage cp.async, 1 sync/iter --------
// MMA issue order: three passes (hh, hl, lh) per mt -> dependency distance 4
// per accumulator; per-acc accumulation order unchanged (bit-identical).
#define GS_A   (128*40)
#define GS_B   (32*136)
#define GS_STG (2*GS_A + 2*GS_B)
#define GS_SMEM (2*GS_STG*2)

__global__ __launch_bounds__(256) void gemm_split(
    const bf16* __restrict__ Ah, const bf16* __restrict__ Al,
    const bf16* __restrict__ Bh, const bf16* __restrict__ Bl,
    float* __restrict__ C, int M, int N, int K)
{
    extern __shared__ __align__(16) bf16 gsm[];

    int tid = threadIdx.x;
    int bm = blockIdx.y, bn = blockIdx.x;
    int warp = tid >> 5, lane = tid & 31;
    int wm = warp >> 2, wn = warp & 3;

    int arow = tid >> 2, ac = (tid & 3) * 8;
    int brow = tid >> 4, bc = (tid & 15) * 8;

    float acc[4][4][4];
#pragma unroll
    for (int a = 0; a < 4; a++)
#pragma unroll
        for (int b = 0; b < 4; b++)
#pragma unroll
            for (int c = 0; c < 4; c++) acc[a][b][c] = 0.f;

    int nk = K >> 5;

    auto issue = [&](int stage, int k0) {
        bf16* sAh = gsm + stage * GS_STG;
        bf16* sAl = sAh + GS_A;
        bf16* sBh = sAl + GS_A;
        bf16* sBl = sBh + GS_B;
#pragma unroll
        for (int i = 0; i < 2; i++) {
            int r = arow + i * 64;
            size_t g = (size_t)(bm * 128 + r) * K + k0 + ac;
            cpa16(&sAh[r * 40 + ac], Ah + g);
            cpa16(&sAl[r * 40 + ac], Al + g);
        }
#pragma unroll
        for (int i = 0; i < 2; i++) {
            int r = brow + i * 16;
            size_t g = (size_t)(k0 + r) * N + bn * 128 + bc;
            cpa16(&sBh[r * 136 + bc], Bh + g);
            cpa16(&sBl[r * 136 + bc], Bl + g);
        }
    };

    issue(0, 0);
    CP_COMMIT;

    for (int it = 0; it < nk; it++) {
        CP_WAIT0;
        __syncthreads();
        if (it + 1 < nk) {
            issue((it + 1) & 1, (it + 1) << 5);
            CP_COMMIT;
        }

        bf16* sAh = gsm + (it & 1) * GS_STG;
        bf16* sAl = sAh + GS_A;
        bf16* sBh = sAl + GS_A;
        bf16* sBl = sBh + GS_B;

#pragma unroll
        for (int kh = 0; kh < 2; kh++) {
            uint32_t bhf[4][2], blf[4][2];
#pragma unroll
            for (int nt = 0; nt < 4; nt++) {
                int br = kh * 16 + (lane & 15);
                int bcl = wn * 32 + nt * 8;
                ldsm_x2t(bhf[nt][0], bhf[nt][1], &sBh[br * 136 + bcl]);
                ldsm_x2t(blf[nt][0], blf[nt][1], &sBl[br * 136 + bcl]);
            }
#pragma unroll
            for (int mt = 0; mt < 4; mt++) {
                int ar = wm * 64 + mt * 16 + (lane & 15);
                int acl = kh * 16 + (lane >> 4) * 8;
                uint32_t ah[4], al[4];
                ldsm_x4(ah, &sAh[ar * 40 + acl]);
                ldsm_x4(al, &sAl[ar * 40 + acl]);
                // three passes: dependency distance 4 per accumulator
#pragma unroll
                for (int nt = 0; nt < 4; nt++) mma_bf16(acc[mt][nt], ah, bhf[nt]);
#pragma unroll
                for (int nt = 0; nt < 4; nt++) mma_bf16(acc[mt][nt], ah, blf[nt]);
#pragma unroll
                for (int nt = 0; nt < 4; nt++) mma_bf16(acc[mt][nt], al, bhf[nt]);
            }
        }
    }

#pragma unroll
    for (int mt = 0; mt < 4; mt++) {
#pragma unroll
        for (int nt = 0; nt < 4; nt++) {
            int r0 = bm * 128 + wm * 64 + mt * 16 + (lane >> 2);
            int c0 = bn * 128 + wn * 32 + nt * 8 + (lane & 3) * 2;
            *(float2*)&C[(size_t)r0 * N + c0] =
                make_float2(acc[mt][nt][0], acc[mt][nt][1]);
            *(float2*)&C[(size_t)(r0 + 8) * N + c0] =
                make_float2(acc[mt][nt][2], acc[mt][nt][3]);
        }
    }
}

// ---------------- RMSNorm slice -> split bf16 outputs ----------------
__global__ __launch_bounds__(256) void rmsnorm_split_kernel(
    const float* __restrict__ x, int rowstride, int off,
    const float* __restrict__ w,
    bf16* __restrict__ hi, bf16* __restrict__ lo, int n)
{
    const float* row = x + (size_t)blockIdx.x * rowstride + off;
    float ss = 0.f;
    for (int i = threadIdx.x; i < n; i += 256) { float v = row[i]; ss += v*v; }
    __shared__ float sh[8];
    __shared__ float tot;
    int lane = threadIdx.x & 31, wp = threadIdx.x >> 5;
#pragma unroll
    for (int o = 16; o; o >>= 1) ss += __shfl_xor_sync(0xffffffffu, ss, o);
    if (lane == 0) sh[wp] = ss;
    __syncthreads();
    if (threadIdx.x == 0) {
        float s = 0.f;
        for (int i = 0; i < 8; i++) s += sh[i];
        tot = rsqrtf(s / n + 1e-6f);
    }
    __syncthreads();
    float rs = tot;
    bf16* hrow = hi + (size_t)blockIdx.x * n;
    bf16* lrow = lo + (size_t)blockIdx.x * n;
    for (int i = threadIdx.x; i < n; i += 256) {
        float y = row[i] * rs * w[i];
        bf16 h = __float2bfloat16(y);
        hrow[i] = h;
        lrow[i] = __float2bfloat16(y - __bfloat162float(h));
    }
}

// ---------------- gate alpha ----------------
__global__ __launch_bounds__(256) void alpha_kernel(
    const float* __restrict__ x, const float* __restrict__ wg,
    const float* __restrict__ bg, float* __restrict__ alpha,
    float* __restrict__ out_alpha)
{
    const float* row = x + (size_t)blockIdx.x * DD;
    float s = 0.f;
    for (int i = threadIdx.x; i < DD; i += 256) s += row[i] * wg[i];
    __shared__ float sh[8];
    int lane = threadIdx.x & 31, wp = threadIdx.x >> 5;
#pragma unroll
    for (int o = 16; o; o >>= 1) s += __shfl_xor_sync(0xffffffffu, s, o);
    if (lane == 0) sh[wp] = s;
    __syncthreads();
    if (threadIdx.x == 0) {
        float t = 0.f;
        for (int i = 0; i < 8; i++) t += sh[i];
        float z = t + bg[0];
        float a = 1.f / (1.f + expf(-z));
        alpha[blockIdx.x] = a;
        if (out_alpha) out_alpha[blockIdx.x] = a;
    }
}

// ---------------- assemble Q/K/V with EPE-RoPE (emit split bf16) -----------
__global__ __launch_bounds__(128) void assemble_kernel(
    const float* __restrict__ qcr, const float* __restrict__ kcv,
    const float* __restrict__ lat3, const float* __restrict__ unc,
    bf16* __restrict__ Qh, bf16* __restrict__ Ql,
    bf16* __restrict__ Kh, bf16* __restrict__ Kl,
    bf16* __restrict__ Vh, bf16* __restrict__ Vl)
{
    int idx = blockIdx.x;
    int h  = idx % NHH;
    int bt = idx / NHH;
    int t  = bt % TT;
    int b  = bt / TT;
    __shared__ float cs[32], sn[32];
    int d = threadIdx.x;
    if (d < 32) {
        float u = unc[bt];
        u = fminf(fmaxf(u, 0.f), 1.f);
        float scale = 0.5f + 1.5f * u;
        float fi = (float)d / 32.0f;
        float theta = expf(-fi * logf(500000.0f));
        float fr = (float)t * theta * scale;
        cs[d] = cosf(fr);
        sn[d] = sinf(fr);
    }
    __syncthreads();
    size_t qkrow = ((size_t)(b*NHH + h))*TT + t;

    float qv0 = qcr[(size_t)bt*3072 + h*128 + d];
    float kv0 = kcv[(size_t)bt*4096 + h*128 + d];
    float vv0 = kcv[(size_t)bt*4096 + 2048 + h*128 + d];
    bf16 hh;
    hh = __float2bfloat16(qv0);
    Qh[qkrow*DQK + d] = hh; Ql[qkrow*DQK + d] = __float2bfloat16(qv0 - __bfloat162float(hh));
    hh = __float2bfloat16(kv0);
    Kh[qkrow*DQK + d] = hh; Kl[qkrow*DQK + d] = __float2bfloat16(kv0 - __bfloat162float(hh));
    hh = __float2bfloat16(vv0);
    Vh[qkrow*DVV + d] = hh; Vl[qkrow*DVV + d] = __float2bfloat16(vv0 - __bfloat162float(hh));

    if (d < 64) {
        const float* qrp = qcr  + (size_t)bt*3072 + 2048 + h*64;
        const float* krp = lat3 + (size_t)bt*3072 + 2048 + h*64;
        float qv, kv;
        if (d < 32) {
            float c = cs[d], s = sn[d];
            qv = qrp[d]*c - qrp[d+32]*s;
            kv = krp[d]*c - krp[d+32]*s;
        } else {
            int j = d - 32;
            float c = cs[j], s = sn[j];
            qv = qrp[j+32]*c + qrp[j]*s;
            kv = krp[j+32]*c + krp[j]*s;
        }
        hh = __float2bfloat16(qv);
        Qh[qkrow*DQK + 128 + d] = hh;
        Ql[qkrow*DQK + 128 + d] = __float2bfloat16(qv - __bfloat162float(hh));
        hh = __float2bfloat16(kv);
        Kh[qkrow*DQK + 128 + d] = hh;
        Kl[qkrow*DQK + 128 + d] = __float2bfloat16(kv - __bfloat162float(hh));
    }
}

// ---------------- tensor-core fused dual attention (1 sync/tile) -----------
// Streams: oR(ob) = bidir-only keys, oW(ow) = window keys; bidir = ob + ow.
// MMA issue interleaved across row-pair accumulators (distance >= 2),
// per-accumulator chain order unchanged (bit-identical).
#define KSTR 200
#define VSTR 136
#define ATTN_SMEM ((64*KSTR*2 + 2*64*KSTR*2 + 2*64*VSTR*2) * 2)

__global__ void __launch_bounds__(128, 1) attn_tc_kernel(
    const bf16* __restrict__ Qh, const bf16* __restrict__ Ql,
    const bf16* __restrict__ Kh, const bf16* __restrict__ Kl,
    const bf16* __restrict__ Vh, const bf16* __restrict__ Vl,
    const float* __restrict__ alpha,
    bf16* __restrict__ mgh, bf16* __restrict__ mgl)
{
    extern __shared__ __align__(16) bf16 smem[];
    bf16* sQh = smem;
    bf16* sQl = sQh + 64*KSTR;
    bf16* sKh = sQl + 64*KSTR;
    bf16* sKl = sKh + 2*64*KSTR;
    bf16* sVh = sKl + 2*64*KSTR;
    bf16* sVl = sVh + 2*64*VSTR;

    int tid = threadIdx.x, lane = tid & 31, warp = tid >> 5;
    int qt = blockIdx.x * 64;
    int bh = blockIdx.y;
    int b = bh >> 4, h = bh & 15;
    size_t base = (size_t)bh * TT;

    for (int i = tid; i < 64*24; i += 128) {
        int r = i / 24, c = (i % 24) * 8;
        size_t g = (base + qt + r) * DQK + c;
        cpa16(&sQh[r*KSTR + c], Qh + g);
        cpa16(&sQl[r*KSTR + c], Ql + g);
    }
    for (int i = tid; i < 64*24; i += 128) {
        int r = i / 24, c = (i % 24) * 8;
        size_t g = (base + r) * DQK + c;
        cpa16(&sKh[r*KSTR + c], Kh + g);
        cpa16(&sKl[r*KSTR + c], Kl + g);
    }
    for (int i = tid; i < 64*16; i += 128) {
        int r = i / 16, c = (i % 16) * 8;
        size_t g = (base + r) * DVV + c;
        cpa16(&sVh[r*VSTR + c], Vh + g);
        cpa16(&sVl[r*VSTR + c], Vl + g);
    }
    CP_COMMIT;

    int q0 = qt + 16*warp + (lane >> 2);
    int q1 = q0 + 8;
    int winlo = ((qt >> 8) << 8) - HALFW;
    if (winlo < 0) winlo = 0;

    float ob[16][4], ow[16][4];
#pragma unroll
    for (int n = 0; n < 16; n++)
#pragma unroll
        for (int j = 0; j < 4; j++) { ob[n][j] = 0.f; ow[n][j] = 0.f; }
    float m0 = -1e30f, m1 = -1e30f;
    float lb0 = 0.f, lb1 = 0.f, lw0 = 0.f, lw1 = 0.f;

    for (int t = 0; t < 32; t++) {
        int kt = t * 64;

        CP_WAIT0;
        __syncthreads();
        if (t + 1 < 32) {
            int nb = (t + 1) & 1;
            int kn = kt + 64;
            for (int i = tid; i < 64*24; i += 128) {
                int r = i / 24, c = (i % 24) * 8;
                size_t g = (base + kn + r) * DQK + c;
                cpa16(&sKh[nb*64*KSTR + r*KSTR + c], Kh + g);
                cpa16(&sKl[nb*64*KSTR + r*KSTR + c], Kl + g);
            }
            for (int i = tid; i < 64*16; i += 128) {
                int r = i / 16, c = (i % 16) * 8;
                size_t g = (base + kn + r) * DVV + c;
                cpa16(&sVh[nb*64*VSTR + r*VSTR + c], Vh + g);
                cpa16(&sVl[nb*64*VSTR + r*VSTR + c], Vl + g);
            }
            CP_COMMIT;
        }

        const bf16* bKh = sKh + (t & 1) * 64 * KSTR;
        const bf16* bVh = sVh + (t & 1) * 64 * VSTR;

        bool diag    = (kt == qt);
        bool fullwin = (kt >= winlo) && (kt < qt);

        float sacc[8][4];
#pragma unroll
        for (int n = 0; n < 8; n++)
#pragma unroll
            for (int j = 0; j < 4; j++) sacc[n][j] = 0.f;

#pragma unroll
        for (int ks = 0; ks < 12; ks++) {
            uint32_t qhf[4], qlf[4];
            const bf16* ap = &sQh[(16*warp + (lane & 15))*KSTR + ks*16 + (lane >> 4)*8];
            ldsm_x4(qhf, ap);
            ldsm_x4(qlf, ap + 64*KSTR);
#pragma unroll
            for (int np = 0; np < 4; np++) {
                int g2 = lane >> 3;
                int krow = np*16 + (g2 >> 1)*8 + (lane & 7);
                int kcol = ks*16 + (g2 & 1)*8;
                const bf16* bp = &bKh[krow*KSTR + kcol];
                uint32_t khf[4], klf[4];
                ldsm_x4(khf, bp);
                ldsm_x4(klf, bp + 2*64*KSTR);
                // interleaved: distance 2 per accumulator
                mma_bf16(sacc[2*np],   qhf, khf);
                mma_bf16(sacc[2*np+1], qhf, khf + 2);
                mma_bf16(sacc[2*np],   qhf, klf);
                mma_bf16(sacc[2*np+1], qhf, klf + 2);
                mma_bf16(sacc[2*np],   qlf, khf);
                mma_bf16(sacc[2*np+1], qlf, khf + 2);
            }
        }

        float tm0 = -1e30f, tm1 = -1e30f;
#pragma unroll
        for (int n = 0; n < 8; n++) {
            tm0 = fmaxf(tm0, fmaxf(sacc[n][0], sacc[n][1]));
            tm1 = fmaxf(tm1, fmaxf(sacc[n][2], sacc[n][3]));
        }
        tm0 *= RSCALE; tm1 *= RSCALE;
        tm0 = fmaxf(tm0, __shfl_xor_sync(0xffffffffu, tm0, 1));
        tm0 = fmaxf(tm0, __shfl_xor_sync(0xffffffffu, tm0, 2));
        tm1 = fmaxf(tm1, __shfl_xor_sync(0xffffffffu, tm1, 1));
        tm1 = fmaxf(tm1, __shfl_xor_sync(0xffffffffu, tm1, 2));
        float mn0 = fmaxf(m0, tm0), mn1 = fmaxf(m1, tm1);
        float c0 = __expf(m0 - mn0), c1 = __expf(m1 - mn1);
        m0 = mn0; m1 = mn1;
        lb0 *= c0; lb1 *= c1; lw0 *= c0; lw1 *= c1;
        if (c0 < 1.f || c1 < 1.f) {
#pragma unroll
            for (int n = 0; n < 16; n++) {
                ob[n][0] *= c0; ob[n][1] *= c0; ob[n][2] *= c1; ob[n][3] *= c1;
                ow[n][0] *= c0; ow[n][1] *= c0; ow[n][2] *= c1; ow[n][3] *= c1;
            }
        }

        float sb0 = 0.f, sb1 = 0.f, sw0 = 0.f, sw1 = 0.f;
#pragma unroll
        for (int n = 0; n < 8; n++) {
            float p0 = __expf(sacc[n][0]*RSCALE - mn0);
            float p1 = __expf(sacc[n][1]*RSCALE - mn0);
            float p2 = __expf(sacc[n][2]*RSCALE - mn1);
            float p3 = __expf(sacc[n][3]*RSCALE - mn1);
            sacc[n][0] = p0; sacc[n][1] = p1; sacc[n][2] = p2; sacc[n][3] = p3;
            sb0 += p0 + p1; sb1 += p2 + p3;
            if (diag) {
                int keyc = kt + 8*n + 2*(lane & 3);
                sw0 += ((keyc   <= q0) ? p0 : 0.f) + ((keyc+1 <= q0) ? p1 : 0.f);
                sw1 += ((keyc   <= q1) ? p2 : 0.f) + ((keyc+1 <= q1) ? p3 : 0.f);
            }
        }
        sb0 += __shfl_xor_sync(0xffffffffu, sb0, 1); sb0 += __shfl_xor_sync(0xffffffffu, sb0, 2);
        sb1 += __shfl_xor_sync(0xffffffffu, sb1, 1); sb1 += __shfl_xor_sync(0xffffffffu, sb1, 2);
        lb0 += sb0; lb1 += sb1;
        if (fullwin) { lw0 += sb0; lw1 += sb1; }
        if (diag) {
            sw0 += __shfl_xor_sync(0xffffffffu, sw0, 1); sw0 += __shfl_xor_sync(0xffffffffu, sw0, 2);
            sw1 += __shfl_xor_sync(0xffffffffu, sw1, 1); sw1 += __shfl_xor_sync(0xffffffffu, sw1, 2);
            lw0 += sw0; lw1 += sw1;
        }

#pragma unroll
        for (int j = 0; j < 4; j++) {
            float v0 = sacc[2*j][0],   v1 = sacc[2*j][1];
            float v2 = sacc[2*j][2],   v3 = sacc[2*j][3];
            float v4 = sacc[2*j+1][0], v5 = sacc[2*j+1][1];
            float v6 = sacc[2*j+1][2], v7 = sacc[2*j+1][3];
            bf16 h0 = __float2bfloat16(v0), h1 = __float2bfloat16(v1);
            bf16 h2 = __float2bfloat16(v2), h3 = __float2bfloat16(v3);
            bf16 h4 = __float2bfloat16(v4), h5 = __float2bfloat16(v5);
            bf16 h6 = __float2bfloat16(v6), h7 = __float2bfloat16(v7);
            bf16 e0 = __float2bfloat16(v0 - __bfloat162float(h0));
            bf16 e1 = __float2bfloat16(v1 - __bfloat162float(h1));
            bf16 e2 = __float2bfloat16(v2 - __bfloat162float(h2));
            bf16 e3 = __float2bfloat16(v3 - __bfloat162float(h3));
            bf16 e4 = __float2bfloat16(v4 - __bfloat162float(h4));
            bf16 e5 = __float2bfloat16(v5 - __bfloat162float(h5));
            bf16 e6 = __float2bfloat16(v6 - __bfloat162float(h6));
            bf16 e7 = __float2bfloat16(v7 - __bfloat162float(h7));
            uint32_t ph2[4] = { pk(h0,h1), pk(h2,h3), pk(h4,h5), pk(h6,h7) };
            uint32_t pl2[4] = { pk(e0,e1), pk(e2,e3), pk(e4,e5), pk(e6,e7) };

            if (diag) {
                bf16 z = __float2bfloat16(0.f);
                int kc = kt + 16*j + 2*(lane & 3);
                bool a0 = kc   <= q0, a1 = kc+1 <= q0;
                bool b0m = kc  <= q1, b1m = kc+1 <= q1;
                bool a2 = kc+8 <= q0, a3 = kc+9 <= q0;
                bool b2m = kc+8 <= q1, b3m = kc+9 <= q1;
                uint32_t wh[4], wl[4], xh2[4], xl2[4];
                wh[0] = pk(a0?h0:z, a1?h1:z);   wl[0] = pk(a0?e0:z, a1?e1:z);
                wh[1] = pk(b0m?h2:z, b1m?h3:z); wl[1] = pk(b0m?e2:z, b1m?e3:z);
                wh[2] = pk(a2?h4:z, a3?h5:z);   wl[2] = pk(a2?e4:z, a3?e5:z);
                wh[3] = pk(b2m?h6:z, b3m?h7:z); wl[3] = pk(b2m?e6:z, b3m?e7:z);
                xh2[0] = pk(a0?z:h0, a1?z:h1);   xl2[0] = pk(a0?z:e0, a1?z:e1);
                xh2[1] = pk(b0m?z:h2, b1m?z:h3); xl2[1] = pk(b0m?z:e2, b1m?z:e3);
                xh2[2] = pk(a2?z:h4, a3?z:h5);   xl2[2] = pk(a2?z:e4, a3?z:e5);
                xh2[3] = pk(b2m?z:h6, b3m?z:h7); xl2[3] = pk(b2m?z:e6, b3m?z:e7);
#pragma unroll
                for (int np = 0; np < 8; np++) {
                    int g2 = lane >> 3;
                    int vrow = 16*j + (g2 & 1)*8 + (lane & 7);
                    int vcol = np*16 + (g2 >> 1)*8;
                    const bf16* vp = &bVh[vrow*VSTR + vcol];
                    uint32_t vhf[4], vlf[4];
                    ldsm_x4t(vhf, vp);
                    ldsm_x4t(vlf, vp + 2*64*VSTR);
                    // interleaved across 4 accumulators (distance 4)
                    mma_bf16(ow[2*np],   wh, vhf);
                    mma_bf16(ow[2*np+1], wh, vhf + 2);
                    mma_bf16(ob[2*np],   xh2, vhf);
                    mma_bf16(ob[2*np+1], xh2, vhf + 2);
                    mma_bf16(ow[2*np],   wh, vlf);
                    mma_bf16(ow[2*np+1], wh, vlf + 2);
                    mma_bf16(ob[2*np],   xh2, vlf);
                    mma_bf16(ob[2*np+1], xh2, vlf + 2);
                    mma_bf16(ow[2*np],   wl, vhf);
                    mma_bf16(ow[2*np+1], wl, vhf + 2);
                    mma_bf16(ob[2*np],   xl2, vhf);
                    mma_bf16(ob[2*np+1], xl2, vhf + 2);
                }
            } else if (fullwin) {
#pragma unroll
                for (int np = 0; np < 8; np++) {
                    int g2 = lane >> 3;
                    int vrow = 16*j + (g2 & 1)*8 + (lane & 7);
                    int vcol = np*16 + (g2 >> 1)*8;
                    const bf16* vp = &bVh[vrow*VSTR + vcol];
                    uint32_t vhf[4], vlf[4];
                    ldsm_x4t(vhf, vp);
                    ldsm_x4t(vlf, vp + 2*64*VSTR);
                    // interleaved row-pair: distance 2
                    mma_bf16(ow[2*np],   ph2, vhf);
                    mma_bf16(ow[2*np+1], ph2, vhf + 2);
                    mma_bf16(ow[2*np],   ph2, vlf);
                    mma_bf16(ow[2*np+1], ph2, vlf + 2);
                    mma_bf16(ow[2*np],   pl2, vhf);
                    mma_bf16(ow[2*np+1], pl2, vhf + 2);
                }
            } else {
#pragma unroll
                for (int np = 0; np < 8; np++) {
                    int g2 = lane >> 3;
                    int vrow = 16*j + (g2 & 1)*8 + (lane & 7);
                    int vcol = np*16 + (g2 >> 1)*8;
                    const bf16* vp = &bVh[vrow*VSTR + vcol];
                    uint32_t vhf[4], vlf[4];
                    ldsm_x4t(vhf, vp);
                    ldsm_x4t(vlf, vp + 2*64*VSTR);
                    mma_bf16(ob[2*np],   ph2, vhf);
                    mma_bf16(ob[2*np+1], ph2, vhf + 2);
                    mma_bf16(ob[2*np],   ph2, vlf);
                    mma_bf16(ob[2*np+1], ph2, vlf + 2);
                    mma_bf16(ob[2*np],   pl2, vhf);
                    mma_bf16(ob[2*np+1], pl2, vhf + 2);
                }
            }
        }
    }

    float a0 = alpha[(size_t)b*TT + q0];
    float a1 = alpha[(size_t)b*TT + q1];
    float ilb0 = 1.f/lb0, ilb1 = 1.f/lb1, ilw0 = 1.f/lw0, ilw1 = 1.f/lw1;
    size_t r0o = ((size_t)b*TT + q0)*2048 + (size_t)h*128;
    size_t r1o = ((size_t)b*TT + q1)*2048 + (size_t)h*128;
#pragma unroll
    for (int n = 0; n < 16; n++) {
        int d = 8*n + 2*(lane & 3);
        float b00 = ob[n][0] + ow[n][0], b01 = ob[n][1] + ow[n][1];
        float b10 = ob[n][2] + ow[n][2], b11 = ob[n][3] + ow[n][3];
        float o00 = a0*b00*ilb0 + (1.f-a0)*ow[n][0]*ilw0;
        float o01 = a0*b01*ilb0 + (1.f-a0)*ow[n][1]*ilw0;
        float o10 = a1*b10*ilb1 + (1.f-a1)*ow[n][2]*ilw1;
        float o11 = a1*b11*ilb1 + (1.f-a1)*ow[n][3]*ilw1;
        bf16 h00 = __float2bfloat16(o00), h01 = __float2bfloat16(o01);
        bf16 h10 = __float2bfloat16(o10), h11 = __float2bfloat16(o11);
        *(uint32_t*)(mgh + r0o + d) = pk(h00, h01);
        *(uint32_t*)(mgh + r1o + d) = pk(h10, h11);
        *(uint32_t*)(mgl + r0o + d) = pk(
            __float2bfloat16(o00 - __bfloat162float(h00)),
            __float2bfloat16(o01 - __bfloat162float(h01)));
        *(uint32_t*)(mgl + r1o + d) = pk(
            __float2bfloat16(o10 - __bfloat162float(h10)),
            __float2bfloat16(o11 - __bfloat162float(h11)));
    }
}

// ---------------- launcher ----------------
extern "C" void kernel_launch(void* const* d_in, const int* in_sizes, int n_in,
                              void* d_out, int out_size)
{
    (void)in_sizes; (void)n_in;
    const float* x        = (const float*)d_in[0];
    const float* unc      = (const float*)d_in[1];
    const float* Wq_down  = (const float*)d_in[2];
    const float* q_norm_w = (const float*)d_in[3];
    const float* Wq_up    = (const float*)d_in[4];
    const float* Wq_rope  = (const float*)d_in[5];
    const float* Wkv_down = (const float*)d_in[6];
    const float* kv_norm_w= (const float*)d_in[7];
    const float* Wk_up    = (const float*)d_in[8];
    const float* Wv_up    = (const float*)d_in[9];
    const float* Wk_rope  = (const float*)d_in[10];
    const float* Wout     = (const float*)d_in[11];
    const float* Wgate    = (const float*)d_in[12];
    const float* bgate    = (const float*)d_in[13];
    float* out = (float*)d_out;

    float *lat3, *qcr, *kcv, *al;
    bf16 *Qh,*Ql,*Kh,*Kl,*Vh,*Vl;
    bf16 *xh,*xl,*qlh,*qll,*kvh,*kvl,*mgh,*mgl;
    bf16 *wdnh,*wdnl,*wquph,*wqupl,*wkvuh,*wkvul,*woh,*wol;
    cudaGetSymbolAddress((void**)&lat3,  g_lat3);
    cudaGetSymbolAddress((void**)&qcr,   g_qcr);
    cudaGetSymbolAddress((void**)&kcv,   g_kcv);
    cudaGetSymbolAddress((void**)&al,    g_alpha);
    cudaGetSymbolAddress((void**)&Qh,    g_Qh);
    cudaGetSymbolAddress((void**)&Ql,    g_Ql);
    cudaGetSymbolAddress((void**)&Kh,    g_Kh);
    cudaGetSymbolAddress((void**)&Kl,    g_Kl);
    cudaGetSymbolAddress((void**)&Vh,    g_Vh);
    cudaGetSymbolAddress((void**)&Vl,    g_Vl);
    cudaGetSymbolAddress((void**)&xh,    g_xh);
    cudaGetSymbolAddress((void**)&xl,    g_xl);
    cudaGetSymbolAddress((void**)&qlh,   g_qlh);
    cudaGetSymbolAddress((void**)&qll,   g_qll);
    cudaGetSymbolAddress((void**)&kvh,   g_kvh);
    cudaGetSymbolAddress((void**)&kvl,   g_kvl);
    cudaGetSymbolAddress((void**)&mgh,   g_mgh);
    cudaGetSymbolAddress((void**)&mgl,   g_mgl);
    cudaGetSymbolAddress((void**)&wdnh,  g_wdn_h);
    cudaGetSymbolAddress((void**)&wdnl,  g_wdn_l);
    cudaGetSymbolAddress((void**)&wquph, g_wqup_h);
    cudaGetSymbolAddress((void**)&wqupl, g_wqup_l);
    cudaGetSymbolAddress((void**)&wkvuh, g_wkvu_h);
    cudaGetSymbolAddress((void**)&wkvul, g_wkvu_l);
    cudaGetSymbolAddress((void**)&woh,   g_wo_h);
    cudaGetSymbolAddress((void**)&wol,   g_wo_l);

    cudaFuncSetAttribute(attn_tc_kernel,
                         cudaFuncAttributeMaxDynamicSharedMemorySize, ATTN_SMEM);
    cudaFuncSetAttribute(gemm_split,
                         cudaFuncAttributeMaxDynamicSharedMemorySize, GS_SMEM);

    auto split = [&](const float* s, bf16* h, bf16* l, size_t n) {
        split_kernel<<<(int)(n / 1024), 256>>>(s, h, l, (int)n);
    };
    auto gemm = [&](const bf16* Ah, const bf16* Al, const bf16* Bh,
                    const bf16* Bl, float* C, int M, int N, int K) {
        gemm_split<<<dim3(N/128, M/128), 256, GS_SMEM>>>(Ah, Al, Bh, Bl, C, M, N, K);
    };

    // launch order: index 3 (ncu capture slot) = merged down-projection GEMM
    split(x, xh, xl, (size_t)BT*DD);                                   // 0
    merge3_split_kernel<<<(DD*3072)/1024, 256>>>(Wq_down, Wkv_down,
        Wk_rope, wdnh, wdnl, CQQ, CKVV, 1024, DD*3072);                // 1
    merge_split_kernel<<<(CQQ*3072)/1024, 256>>>(Wq_up, Wq_rope,
        wquph, wqupl, 2048, 1024, CQQ*3072);                           // 2
    gemm(xh, xl, wdnh, wdnl, lat3, BT, 3072, DD);                      // 3 <- ncu

    rmsnorm_split_kernel<<<BT, 256>>>(lat3, 3072, 0,    q_norm_w,  qlh, qll, CQQ);
    rmsnorm_split_kernel<<<BT, 256>>>(lat3, 3072, CQQ,  kv_norm_w, kvh, kvl, CKVV);

    gemm(qlh, qll, wquph, wqupl, qcr, BT, 3072, CQQ);

    merge_split_kernel<<<(CKVV*4096)/1024, 256>>>(Wk_up, Wv_up,
        wkvuh, wkvul, 2048, 2048, CKVV*4096);
    gemm(kvh, kvl, wkvuh, wkvul, kcv, BT, 4096, CKVV);

    split(Wout, woh, wol, (size_t)2048*DD);

    float* out_alpha = (out_size >= BB*TT*DD + BB*TT) ? (out + (size_t)BB*TT*DD)
                                                      : nullptr;
    alpha_kernel<<<BT, 256>>>(x, Wgate, bgate, al, out_alpha);

    assemble_kernel<<<BT*NHH, 128>>>(qcr, kcv, lat3, unc,
                                     Qh, Ql, Kh, Kl, Vh, Vl);

    attn_tc_kernel<<<dim3(TT/64, BB*NHH), 128, ATTN_SMEM>>>(
        Qh, Ql, Kh, Kl, Vh, Vl, al, mgh, mgl);

    gemm(mgh, mgl, woh, wol, out, BT, DD, 2048);
}

// round 12
// speedup vs baseline: 1.2658x; 1.0218x over previous
#include <cuda_runtime.h>
#include <cuda_bf16.h>
#include <math.h>
#include <stdint.h>

// ---------------- problem constants ----------------
#define BB   2
#define TT   2048
#define DD   2048
#define NHH  16
#define HDD  128
#define RR   64
#define CQQ  1536
#define CKVV 512
#define BT   (BB*TT)       // 4096
#define DQK  192           // HD + R
#define DVV  128
#define HALFW 256          // WINDOW/2
#define RSCALE 0.07216878364870323f  // 1/sqrt(192)

typedef __nv_bfloat16 bf16;

// ---------------- scratch (device globals; no runtime alloc) ----------------
__device__ float g_lat3 [(size_t)BT*3072];   // [qlat(1536) | kvlat(512) | kr(1024)]
__device__ float g_qcr  [(size_t)BT*3072];   // [qc(2048) | qr(1024)]
__device__ float g_kcv  [(size_t)BT*4096];   // [kc(2048) | vv(2048)]
__device__ float g_alpha[BT];

// attention operands, pre-split bf16, head-major: [bh][t][d]
__device__ bf16 g_Qh[(size_t)BB*NHH*TT*DQK], g_Ql[(size_t)BB*NHH*TT*DQK];
__device__ bf16 g_Kh[(size_t)BB*NHH*TT*DQK], g_Kl[(size_t)BB*NHH*TT*DQK];
__device__ bf16 g_Vh[(size_t)BB*NHH*TT*DVV], g_Vl[(size_t)BB*NHH*TT*DVV];

// bf16 split buffers (hi/lo) for GEMMs ([K,N] layout)
__device__ bf16 g_xh [(size_t)BT*DD],    g_xl [(size_t)BT*DD];
__device__ bf16 g_qlh[(size_t)BT*CQQ],   g_qll[(size_t)BT*CQQ];
__device__ bf16 g_kvh[(size_t)BT*CKVV],  g_kvl[(size_t)BT*CKVV];
__device__ bf16 g_mgh[(size_t)BT*NHH*HDD], g_mgl[(size_t)BT*NHH*HDD];
__device__ bf16 g_wdn_h [(size_t)DD*3072],   g_wdn_l [(size_t)DD*3072];   // [Wqd|Wkd|Wkr]
__device__ bf16 g_wqup_h[(size_t)CQQ*3072],  g_wqup_l[(size_t)CQQ*3072];
__device__ bf16 g_wkvu_h[(size_t)CKVV*4096], g_wkvu_l[(size_t)CKVV*4096];
__device__ bf16 g_wo_h  [(size_t)2048*DD],   g_wo_l  [(size_t)2048*DD];

// ---------------- ptx helpers ----------------
__device__ __forceinline__ uint32_t smem_u32(const void* p) {
    return (uint32_t)__cvta_generic_to_shared(p);
}
__device__ __forceinline__ void ldsm_x4(uint32_t* r, const void* p) {
    uint32_t a = smem_u32(p);
    asm volatile("ldmatrix.sync.aligned.m8n8.x4.shared.b16 {%0,%1,%2,%3}, [%4];"
                 : "=r"(r[0]), "=r"(r[1]), "=r"(r[2]), "=r"(r[3]) : "r"(a));
}
__device__ __forceinline__ void ldsm_x4t(uint32_t* r, const void* p) {
    uint32_t a = smem_u32(p);
    asm volatile("ldmatrix.sync.aligned.m8n8.x4.trans.shared.b16 {%0,%1,%2,%3}, [%4];"
                 : "=r"(r[0]), "=r"(r[1]), "=r"(r[2]), "=r"(r[3]) : "r"(a));
}
__device__ __forceinline__ void ldsm_x2t(uint32_t &r0, uint32_t &r1,
                                         const void* p) {
    uint32_t a = smem_u32(p);
    asm volatile("ldmatrix.sync.aligned.m8n8.x2.trans.shared.b16 {%0,%1}, [%2];"
                 : "=r"(r0), "=r"(r1) : "r"(a));
}
__device__ __forceinline__ void mma_bf16(float* c, const uint32_t* a,
                                         const uint32_t* b) {
    asm volatile(
        "mma.sync.aligned.m16n8k16.row.col.f32.bf16.bf16.f32 "
        "{%0,%1,%2,%3}, {%4,%5,%6,%7}, {%8,%9}, {%0,%1,%2,%3};"
        : "+f"(c[0]), "+f"(c[1]), "+f"(c[2]), "+f"(c[3])
        : "r"(a[0]), "r"(a[1]), "r"(a[2]), "r"(a[3]), "r"(b[0]), "r"(b[1]));
}
__device__ __forceinline__ void cpa16(void* s, const void* g) {
    asm volatile("cp.async.cg.shared.global [%0], [%1], 16;"
                 :: "r"(smem_u32(s)), "l"(g));
}
#define CP_COMMIT asm volatile("cp.async.commit_group;")
#define CP_WAIT0  asm volatile("cp.async.wait_group 0;")

__device__ __forceinline__ uint32_t pk(bf16 a, bf16 b) {
    __nv_bfloat162 t(a, b);
    return *reinterpret_cast<uint32_t*>(&t);
}

// ---------------- split fp32 -> (hi, lo) bf16 ----------------
__global__ __launch_bounds__(256) void split_kernel(
    const float* __restrict__ s, bf16* __restrict__ h,
    bf16* __restrict__ l, int n)
{
    int i = (blockIdx.x * 256 + threadIdx.x) * 4;
    if (i >= n) return;
    float4 v = *(const float4*)(s + i);
    bf16 h0 = __float2bfloat16(v.x), h1 = __float2bfloat16(v.y);
    bf16 h2 = __float2bfloat16(v.z), h3 = __float2bfloat16(v.w);
    *(__nv_bfloat162*)(h + i)     = __nv_bfloat162(h0, h1);
    *(__nv_bfloat162*)(h + i + 2) = __nv_bfloat162(h2, h3);
    *(__nv_bfloat162*)(l + i) = __nv_bfloat162(
        __float2bfloat16(v.x - __bfloat162float(h0)),
        __float2bfloat16(v.y - __bfloat162float(h1)));
    *(__nv_bfloat162*)(l + i + 2) = __nv_bfloat162(
        __float2bfloat16(v.z - __bfloat162float(h2)),
        __float2bfloat16(v.w - __bfloat162float(h3)));
}

// ---------------- merge two [K,N*] weights into one split [K,N1+N2] --------
__global__ __launch_bounds__(256) void merge_split_kernel(
    const float* __restrict__ W1, const float* __restrict__ W2,
    bf16* __restrict__ h, bf16* __restrict__ l, int N1, int N2, int total)
{
    int i = (blockIdx.x * 256 + threadIdx.x) * 4;
    if (i >= total) return;
    int Nt = N1 + N2;
    int k = i / Nt, n = i % Nt;
    const float* src = (n < N1) ? (W1 + (size_t)k * N1 + n)
                                : (W2 + (size_t)k * N2 + (n - N1));
    float4 v = *(const float4*)src;
    bf16 h0 = __float2bfloat16(v.x), h1 = __float2bfloat16(v.y);
    bf16 h2 = __float2bfloat16(v.z), h3 = __float2bfloat16(v.w);
    *(__nv_bfloat162*)(h + i)     = __nv_bfloat162(h0, h1);
    *(__nv_bfloat162*)(h + i + 2) = __nv_bfloat162(h2, h3);
    *(__nv_bfloat162*)(l + i) = __nv_bfloat162(
        __float2bfloat16(v.x - __bfloat162float(h0)),
        __float2bfloat16(v.y - __bfloat162float(h1)));
    *(__nv_bfloat162*)(l + i + 2) = __nv_bfloat162(
        __float2bfloat16(v.z - __bfloat162float(h2)),
        __float2bfloat16(v.w - __bfloat162float(h3)));
}

// ---------------- merge three [K,N*] weights into one split [K,N1+N2+N3] ---
__global__ __launch_bounds__(256) void merge3_split_kernel(
    const float* __restrict__ W1, const float* __restrict__ W2,
    const float* __restrict__ W3,
    bf16* __restrict__ h, bf16* __restrict__ l,
    int N1, int N2, int N3, int total)
{
    int i = (blockIdx.x * 256 + threadIdx.x) * 4;
    if (i >= total) return;
    int Nt = N1 + N2 + N3;
    int k = i / Nt, n = i % Nt;
    const float* src;
    if (n < N1)            src = W1 + (size_t)k * N1 + n;
    else if (n < N1 + N2)  src = W2 + (size_t)k * N2 + (n - N1);
    else                   src = W3 + (size_t)k * N3 + (n - N1 - N2);
    float4 v = *(const float4*)src;
    bf16 h0 = __float2bfloat16(v.x), h1 = __float2bfloat16(v.y);
    bf16 h2 = __float2bfloat16(v.z), h3 = __float2bfloat16(v.w);
    *(__nv_bfloat162*)(h + i)     = __nv_bfloat162(h0, h1);
    *(__nv_bfloat162*)(h + i + 2) = __nv_bfloat162(h2, h3);
    *(__nv_bfloat162*)(l + i) = __nv_bfloat162(
        __float2bfloat16(v.x - __bfloat162float(h0)),
        __float2bfloat16(v.y - __bfloat162float(h1)));
    *(__nv_bfloat162*)(l + i + 2) = __nv_bfloat162(
        __float2bfloat16(v.z - __bfloat162float(h2)),
        __float2bfloat16(v.w - __bfloat162float(h3)));
}

// ---------------- split-bf16 TC GEMM, 2-stage cp.async, 1 sync/iter --------
#define GS_A   (128*40)
#define GS_B   (32*136)
#define GS_STG (2*GS_A + 2*GS_B)
#define GS_SMEM (2*GS_STG*2)

__global__ __launch_bounds__(256) void gemm_split(
    const bf16* __restrict__ Ah, const bf16* __restrict__ Al,
    const bf16* __restrict__ Bh, const bf16* __restrict__ Bl,
    float* __restrict__ C, int M, int N, int K)
{
    extern __shared__ __align__(16) bf16 gsm[];

    int tid = threadIdx.x;
    int bm = blockIdx.y, bn = blockIdx.x;
    int warp = tid >> 5, lane = tid & 31;
    int wm = warp >> 2, wn = warp & 3;

    int arow = tid >> 2, ac = (tid & 3) * 8;
    int brow = tid >> 4, bc = (tid & 15) * 8;

    float acc[4][4][4];
#pragma unroll
    for (int a = 0; a < 4; a++)
#pragma unroll
        for (int b = 0; b < 4; b++)
#pragma unroll
            for (int c = 0; c < 4; c++) acc[a][b][c] = 0.f;

    int nk = K >> 5;

    auto issue = [&](int stage, int k0) {
        bf16* sAh = gsm + stage * GS_STG;
        bf16* sAl = sAh + GS_A;
        bf16* sBh = sAl + GS_A;
        bf16* sBl = sBh + GS_B;
#pragma unroll
        for (int i = 0; i < 2; i++) {
            int r = arow + i * 64;
            size_t g = (size_t)(bm * 128 + r) * K + k0 + ac;
            cpa16(&sAh[r * 40 + ac], Ah + g);
            cpa16(&sAl[r * 40 + ac], Al + g);
        }
#pragma unroll
        for (int i = 0; i < 2; i++) {
            int r = brow + i * 16;
            size_t g = (size_t)(k0 + r) * N + bn * 128 + bc;
            cpa16(&sBh[r * 136 + bc], Bh + g);
            cpa16(&sBl[r * 136 + bc], Bl + g);
        }
    };

    issue(0, 0);
    CP_COMMIT;

    for (int it = 0; it < nk; it++) {
        CP_WAIT0;
        __syncthreads();
        if (it + 1 < nk) {
            issue((it + 1) & 1, (it + 1) << 5);
            CP_COMMIT;
        }

        bf16* sAh = gsm + (it & 1) * GS_STG;
        bf16* sAl = sAh + GS_A;
        bf16* sBh = sAl + GS_A;
        bf16* sBl = sBh + GS_B;

#pragma unroll
        for (int kh = 0; kh < 2; kh++) {
            uint32_t bhf[4][2], blf[4][2];
#pragma unroll
            for (int nt = 0; nt < 4; nt++) {
                int br = kh * 16 + (lane & 15);
                int bcl = wn * 32 + nt * 8;
                ldsm_x2t(bhf[nt][0], bhf[nt][1], &sBh[br * 136 + bcl]);
                ldsm_x2t(blf[nt][0], blf[nt][1], &sBl[br * 136 + bcl]);
            }
#pragma unroll
            for (int mt = 0; mt < 4; mt++) {
                int ar = wm * 64 + mt * 16 + (lane & 15);
                int acl = kh * 16 + (lane >> 4) * 8;
                uint32_t ah[4], al[4];
                ldsm_x4(ah, &sAh[ar * 40 + acl]);
                ldsm_x4(al, &sAl[ar * 40 + acl]);
#pragma unroll
                for (int nt = 0; nt < 4; nt++) mma_bf16(acc[mt][nt], ah, bhf[nt]);
#pragma unroll
                for (int nt = 0; nt < 4; nt++) mma_bf16(acc[mt][nt], ah, blf[nt]);
#pragma unroll
                for (int nt = 0; nt < 4; nt++) mma_bf16(acc[mt][nt], al, bhf[nt]);
            }
        }
    }

#pragma unroll
    for (int mt = 0; mt < 4; mt++) {
#pragma unroll
        for (int nt = 0; nt < 4; nt++) {
            int r0 = bm * 128 + wm * 64 + mt * 16 + (lane >> 2);
            int c0 = bn * 128 + wn * 32 + nt * 8 + (lane & 3) * 2;
            *(float2*)&C[(size_t)r0 * N + c0] =
                make_float2(acc[mt][nt][0], acc[mt][nt][1]);
            *(float2*)&C[(size_t)(r0 + 8) * N + c0] =
                make_float2(acc[mt][nt][2], acc[mt][nt][3]);
        }
    }
}

// ---------------- RMSNorm slice -> split bf16 outputs ----------------
__global__ __launch_bounds__(256) void rmsnorm_split_kernel(
    const float* __restrict__ x, int rowstride, int off,
    const float* __restrict__ w,
    bf16* __restrict__ hi, bf16* __restrict__ lo, int n)
{
    const float* row = x + (size_t)blockIdx.x * rowstride + off;
    float ss = 0.f;
    for (int i = threadIdx.x; i < n; i += 256) { float v = row[i]; ss += v*v; }
    __shared__ float sh[8];
    __shared__ float tot;
    int lane = threadIdx.x & 31, wp = threadIdx.x >> 5;
#pragma unroll
    for (int o = 16; o; o >>= 1) ss += __shfl_xor_sync(0xffffffffu, ss, o);
    if (lane == 0) sh[wp] = ss;
    __syncthreads();
    if (threadIdx.x == 0) {
        float s = 0.f;
        for (int i = 0; i < 8; i++) s += sh[i];
        tot = rsqrtf(s / n + 1e-6f);
    }
    __syncthreads();
    float rs = tot;
    bf16* hrow = hi + (size_t)blockIdx.x * n;
    bf16* lrow = lo + (size_t)blockIdx.x * n;
    for (int i = threadIdx.x; i < n; i += 256) {
        float y = row[i] * rs * w[i];
        bf16 h = __float2bfloat16(y);
        hrow[i] = h;
        lrow[i] = __float2bfloat16(y - __bfloat162float(h));
    }
}

// ---------------- gate alpha ----------------
__global__ __launch_bounds__(256) void alpha_kernel(
    const float* __restrict__ x, const float* __restrict__ wg,
    const float* __restrict__ bg, float* __restrict__ alpha,
    float* __restrict__ out_alpha)
{
    const float* row = x + (size_t)blockIdx.x * DD;
    float s = 0.f;
    for (int i = threadIdx.x; i < DD; i += 256) s += row[i] * wg[i];
    __shared__ float sh[8];
    int lane = threadIdx.x & 31, wp = threadIdx.x >> 5;
#pragma unroll
    for (int o = 16; o; o >>= 1) s += __shfl_xor_sync(0xffffffffu, s, o);
    if (lane == 0) sh[wp] = s;
    __syncthreads();
    if (threadIdx.x == 0) {
        float t = 0.f;
        for (int i = 0; i < 8; i++) t += sh[i];
        float z = t + bg[0];
        float a = 1.f / (1.f + expf(-z));
        alpha[blockIdx.x] = a;
        if (out_alpha) out_alpha[blockIdx.x] = a;
    }
}

// ---------------- assemble Q/K/V with EPE-RoPE (emit split bf16) -----------
__global__ __launch_bounds__(128) void assemble_kernel(
    const float* __restrict__ qcr, const float* __restrict__ kcv,
    const float* __restrict__ lat3, const float* __restrict__ unc,
    bf16* __restrict__ Qh, bf16* __restrict__ Ql,
    bf16* __restrict__ Kh, bf16* __restrict__ Kl,
    bf16* __restrict__ Vh, bf16* __restrict__ Vl)
{
    int idx = blockIdx.x;
    int h  = idx % NHH;
    int bt = idx / NHH;
    int t  = bt % TT;
    int b  = bt / TT;
    __shared__ float cs[32], sn[32];
    int d = threadIdx.x;
    if (d < 32) {
        float u = unc[bt];
        u = fminf(fmaxf(u, 0.f), 1.f);
        float scale = 0.5f + 1.5f * u;
        float fi = (float)d / 32.0f;
        float theta = expf(-fi * logf(500000.0f));
        float fr = (float)t * theta * scale;
        cs[d] = cosf(fr);
        sn[d] = sinf(fr);
    }
    __syncthreads();
    size_t qkrow = ((size_t)(b*NHH + h))*TT + t;

    float qv0 = qcr[(size_t)bt*3072 + h*128 + d];
    float kv0 = kcv[(size_t)bt*4096 + h*128 + d];
    float vv0 = kcv[(size_t)bt*4096 + 2048 + h*128 + d];
    bf16 hh;
    hh = __float2bfloat16(qv0);
    Qh[qkrow*DQK + d] = hh; Ql[qkrow*DQK + d] = __float2bfloat16(qv0 - __bfloat162float(hh));
    hh = __float2bfloat16(kv0);
    Kh[qkrow*DQK + d] = hh; Kl[qkrow*DQK + d] = __float2bfloat16(kv0 - __bfloat162float(hh));
    hh = __float2bfloat16(vv0);
    Vh[qkrow*DVV + d] = hh; Vl[qkrow*DVV + d] = __float2bfloat16(vv0 - __bfloat162float(hh));

    if (d < 64) {
        const float* qrp = qcr  + (size_t)bt*3072 + 2048 + h*64;
        const float* krp = lat3 + (size_t)bt*3072 + 2048 + h*64;
        float qv, kv;
        if (d < 32) {
            float c = cs[d], s = sn[d];
            qv = qrp[d]*c - qrp[d+32]*s;
            kv = krp[d]*c - krp[d+32]*s;
        } else {
            int j = d - 32;
            float c = cs[j], s = sn[j];
            qv = qrp[j+32]*c + qrp[j]*s;
            kv = krp[j+32]*c + krp[j]*s;
        }
        hh = __float2bfloat16(qv);
        Qh[qkrow*DQK + 128 + d] = hh;
        Ql[qkrow*DQK + 128 + d] = __float2bfloat16(qv - __bfloat162float(hh));
        hh = __float2bfloat16(kv);
        Kh[qkrow*DQK + 128 + d] = hh;
        Kl[qkrow*DQK + 128 + d] = __float2bfloat16(kv - __bfloat162float(hh));
    }
}

// ---------------- tensor-core fused dual attention, split-key warps --------
// 256 thr / 8 warps; warp w: query rows 16*(w&3).. +15, keys 32*(w>>2)..+31
// of each 64-key tile. Each warp keeps independent (m, l, acc) softmax state;
// the two key-halves merge once at the epilogue (flash split-K merge).
#define KSTR 200
#define VSTR 136
#define ATTN_SMEM ((64*KSTR*2 + 2*64*KSTR*2 + 2*64*VSTR*2) * 2)

__global__ void __launch_bounds__(256, 1) attn_tc_kernel(
    const bf16* __restrict__ Qh, const bf16* __restrict__ Ql,
    const bf16* __restrict__ Kh, const bf16* __restrict__ Kl,
    const bf16* __restrict__ Vh, const bf16* __restrict__ Vl,
    const float* __restrict__ alpha,
    bf16* __restrict__ mgh, bf16* __restrict__ mgl)
{
    extern __shared__ __align__(16) bf16 smem[];
    bf16* sQh = smem;
    bf16* sQl = sQh + 64*KSTR;
    bf16* sKh = sQl + 64*KSTR;
    bf16* sKl = sKh + 2*64*KSTR;
    bf16* sVh = sKl + 2*64*KSTR;
    bf16* sVl = sVh + 2*64*VSTR;

    int tid = threadIdx.x, lane = tid & 31, warp = tid >> 5;
    int rg = warp & 3;         // query row group (16 rows)
    int ch = warp >> 2;        // key half (0: keys 0-31, 1: keys 32-63)
    int qt = blockIdx.x * 64;
    int bh = blockIdx.y;
    int b = bh >> 4, h = bh & 15;
    size_t base = (size_t)bh * TT;

    for (int i = tid; i < 64*24; i += 256) {
        int r = i / 24, c = (i % 24) * 8;
        size_t g = (base + qt + r) * DQK + c;
        cpa16(&sQh[r*KSTR + c], Qh + g);
        cpa16(&sQl[r*KSTR + c], Ql + g);
    }
    for (int i = tid; i < 64*24; i += 256) {
        int r = i / 24, c = (i % 24) * 8;
        size_t g = (base + r) * DQK + c;
        cpa16(&sKh[r*KSTR + c], Kh + g);
        cpa16(&sKl[r*KSTR + c], Kl + g);
    }
    for (int i = tid; i < 64*16; i += 256) {
        int r = i / 16, c = (i % 16) * 8;
        size_t g = (base + r) * DVV + c;
        cpa16(&sVh[r*VSTR + c], Vh + g);
        cpa16(&sVl[r*VSTR + c], Vl + g);
    }
    CP_COMMIT;

    int q0 = qt + 16*rg + (lane >> 2);
    int q1 = q0 + 8;
    int winlo = ((qt >> 8) << 8) - HALFW;
    if (winlo < 0) winlo = 0;

    float ob[16][4], ow[16][4];
#pragma unroll
    for (int n = 0; n < 16; n++)
#pragma unroll
        for (int j = 0; j < 4; j++) { ob[n][j] = 0.f; ow[n][j] = 0.f; }
    float m0 = -1e30f, m1 = -1e30f;
    float lb0 = 0.f, lb1 = 0.f, lw0 = 0.f, lw1 = 0.f;

    for (int t = 0; t < 32; t++) {
        int kt = t * 64;

        CP_WAIT0;
        __syncthreads();
        if (t + 1 < 32) {
            int nb = (t + 1) & 1;
            int kn = kt + 64;
            for (int i = tid; i < 64*24; i += 256) {
                int r = i / 24, c = (i % 24) * 8;
                size_t g = (base + kn + r) * DQK + c;
                cpa16(&sKh[nb*64*KSTR + r*KSTR + c], Kh + g);
                cpa16(&sKl[nb*64*KSTR + r*KSTR + c], Kl + g);
            }
            for (int i = tid; i < 64*16; i += 256) {
                int r = i / 16, c = (i % 16) * 8;
                size_t g = (base + kn + r) * DVV + c;
                cpa16(&sVh[nb*64*VSTR + r*VSTR + c], Vh + g);
                cpa16(&sVl[nb*64*VSTR + r*VSTR + c], Vl + g);
            }
            CP_COMMIT;
        }

        const bf16* bKh = sKh + (t & 1) * 64 * KSTR;
        const bf16* bVh = sVh + (t & 1) * 64 * VSTR;

        bool diag    = (kt == qt);
        bool fullwin = (kt >= winlo) && (kt < qt);

        // ---- S = Q K^T over this warp's 32-key slice ----
        float sacc[4][4];
#pragma unroll
        for (int n = 0; n < 4; n++)
#pragma unroll
            for (int j = 0; j < 4; j++) sacc[n][j] = 0.f;

#pragma unroll
        for (int ks = 0; ks < 12; ks++) {
            uint32_t qhf[4], qlf[4];
            const bf16* ap = &sQh[(16*rg + (lane & 15))*KSTR + ks*16 + (lane >> 4)*8];
            ldsm_x4(qhf, ap);
            ldsm_x4(qlf, ap + 64*KSTR);
#pragma unroll
            for (int np = 0; np < 2; np++) {
                int g2 = lane >> 3;
                int krow = ch*32 + np*16 + (g2 >> 1)*8 + (lane & 7);
                int kcol = ks*16 + (g2 & 1)*8;
                const bf16* bp = &bKh[krow*KSTR + kcol];
                uint32_t khf[4], klf[4];
                ldsm_x4(khf, bp);
                ldsm_x4(klf, bp + 2*64*KSTR);
                mma_bf16(sacc[2*np],   qhf, khf);
                mma_bf16(sacc[2*np+1], qhf, khf + 2);
                mma_bf16(sacc[2*np],   qhf, klf);
                mma_bf16(sacc[2*np+1], qhf, klf + 2);
                mma_bf16(sacc[2*np],   qlf, khf);
                mma_bf16(sacc[2*np+1], qlf, khf + 2);
            }
        }

        // ---- online softmax (warp-local m/l over its key slice) ----
        float tm0 = -1e30f, tm1 = -1e30f;
#pragma unroll
        for (int n = 0; n < 4; n++) {
            tm0 = fmaxf(tm0, fmaxf(sacc[n][0], sacc[n][1]));
            tm1 = fmaxf(tm1, fmaxf(sacc[n][2], sacc[n][3]));
        }
        tm0 *= RSCALE; tm1 *= RSCALE;
        tm0 = fmaxf(tm0, __shfl_xor_sync(0xffffffffu, tm0, 1));
        tm0 = fmaxf(tm0, __shfl_xor_sync(0xffffffffu, tm0, 2));
        tm1 = fmaxf(tm1, __shfl_xor_sync(0xffffffffu, tm1, 1));
        tm1 = fmaxf(tm1, __shfl_xor_sync(0xffffffffu, tm1, 2));
        float mn0 = fmaxf(m0, tm0), mn1 = fmaxf(m1, tm1);
        float c0 = __expf(m0 - mn0), c1 = __expf(m1 - mn1);
        m0 = mn0; m1 = mn1;
        lb0 *= c0; lb1 *= c1; lw0 *= c0; lw1 *= c1;
        if (c0 < 1.f || c1 < 1.f) {
#pragma unroll
            for (int n = 0; n < 16; n++) {
                ob[n][0] *= c0; ob[n][1] *= c0; ob[n][2] *= c1; ob[n][3] *= c1;
                ow[n][0] *= c0; ow[n][1] *= c0; ow[n][2] *= c1; ow[n][3] *= c1;
            }
        }

        float sb0 = 0.f, sb1 = 0.f, sw0 = 0.f, sw1 = 0.f;
#pragma unroll
        for (int n = 0; n < 4; n++) {
            float p0 = __expf(sacc[n][0]*RSCALE - mn0);
            float p1 = __expf(sacc[n][1]*RSCALE - mn0);
            float p2 = __expf(sacc[n][2]*RSCALE - mn1);
            float p3 = __expf(sacc[n][3]*RSCALE - mn1);
            sacc[n][0] = p0; sacc[n][1] = p1; sacc[n][2] = p2; sacc[n][3] = p3;
            sb0 += p0 + p1; sb1 += p2 + p3;
            if (diag) {
                int keyc = kt + ch*32 + 8*n + 2*(lane & 3);
                sw0 += ((keyc   <= q0) ? p0 : 0.f) + ((keyc+1 <= q0) ? p1 : 0.f);
                sw1 += ((keyc   <= q1) ? p2 : 0.f) + ((keyc+1 <= q1) ? p3 : 0.f);
            }
        }
        sb0 += __shfl_xor_sync(0xffffffffu, sb0, 1); sb0 += __shfl_xor_sync(0xffffffffu, sb0, 2);
        sb1 += __shfl_xor_sync(0xffffffffu, sb1, 1); sb1 += __shfl_xor_sync(0xffffffffu, sb1, 2);
        lb0 += sb0; lb1 += sb1;
        if (fullwin) { lw0 += sb0; lw1 += sb1; }
        if (diag) {
            sw0 += __shfl_xor_sync(0xffffffffu, sw0, 1); sw0 += __shfl_xor_sync(0xffffffffu, sw0, 2);
            sw1 += __shfl_xor_sync(0xffffffffu, sw1, 1); sw1 += __shfl_xor_sync(0xffffffffu, sw1, 2);
            lw0 += sw0; lw1 += sw1;
        }

        // ---- P V over this warp's 32 keys ----
#pragma unroll
        for (int j = 0; j < 2; j++) {
            float v0 = sacc[2*j][0],   v1 = sacc[2*j][1];
            float v2 = sacc[2*j][2],   v3 = sacc[2*j][3];
            float v4 = sacc[2*j+1][0], v5 = sacc[2*j+1][1];
            float v6 = sacc[2*j+1][2], v7 = sacc[2*j+1][3];
            bf16 h0 = __float2bfloat16(v0), h1 = __float2bfloat16(v1);
            bf16 h2 = __float2bfloat16(v2), h3 = __float2bfloat16(v3);
            bf16 h4 = __float2bfloat16(v4), h5 = __float2bfloat16(v5);
            bf16 h6 = __float2bfloat16(v6), h7 = __float2bfloat16(v7);
            bf16 e0 = __float2bfloat16(v0 - __bfloat162float(h0));
            bf16 e1 = __float2bfloat16(v1 - __bfloat162float(h1));
            bf16 e2 = __float2bfloat16(v2 - __bfloat162float(h2));
            bf16 e3 = __float2bfloat16(v3 - __bfloat162float(h3));
            bf16 e4 = __float2bfloat16(v4 - __bfloat162float(h4));
            bf16 e5 = __float2bfloat16(v5 - __bfloat162float(h5));
            bf16 e6 = __float2bfloat16(v6 - __bfloat162float(h6));
            bf16 e7 = __float2bfloat16(v7 - __bfloat162float(h7));
            uint32_t ph2[4] = { pk(h0,h1), pk(h2,h3), pk(h4,h5), pk(h6,h7) };
            uint32_t pl2[4] = { pk(e0,e1), pk(e2,e3), pk(e4,e5), pk(e6,e7) };

            if (diag) {
                bf16 z = __float2bfloat16(0.f);
                int kc = kt + ch*32 + 16*j + 2*(lane & 3);
                bool a0 = kc   <= q0, a1 = kc+1 <= q0;
                bool b0m = kc  <= q1, b1m = kc+1 <= q1;
                bool a2 = kc+8 <= q0, a3 = kc+9 <= q0;
                bool b2m = kc+8 <= q1, b3m = kc+9 <= q1;
                uint32_t wh[4], wl[4], xh2[4], xl2[4];
                wh[0] = pk(a0?h0:z, a1?h1:z);   wl[0] = pk(a0?e0:z, a1?e1:z);
                wh[1] = pk(b0m?h2:z, b1m?h3:z); wl[1] = pk(b0m?e2:z, b1m?e3:z);
                wh[2] = pk(a2?h4:z, a3?h5:z);   wl[2] = pk(a2?e4:z, a3?e5:z);
                wh[3] = pk(b2m?h6:z, b3m?h7:z); wl[3] = pk(b2m?e6:z, b3m?e7:z);
                xh2[0] = pk(a0?z:h0, a1?z:h1);   xl2[0] = pk(a0?z:e0, a1?z:e1);
                xh2[1] = pk(b0m?z:h2, b1m?z:h3); xl2[1] = pk(b0m?z:e2, b1m?z:e3);
                xh2[2] = pk(a2?z:h4, a3?z:h5);   xl2[2] = pk(a2?z:e4, a3?z:e5);
                xh2[3] = pk(b2m?z:h6, b3m?z:h7); xl2[3] = pk(b2m?z:e6, b3m?z:e7);
#pragma unroll
                for (int np = 0; np < 8; np++) {
                    int g2 = lane >> 3;
                    int vrow = ch*32 + 16*j + (g2 & 1)*8 + (lane & 7);
                    int vcol = np*16 + (g2 >> 1)*8;
                    const bf16* vp = &bVh[vrow*VSTR + vcol];
                    uint32_t vhf[4], vlf[4];
                    ldsm_x4t(vhf, vp);
                    ldsm_x4t(vlf, vp + 2*64*VSTR);
                    mma_bf16(ow[2*np],   wh, vhf);
                    mma_bf16(ow[2*np+1], wh, vhf + 2);
                    mma_bf16(ob[2*np],   xh2, vhf);
                    mma_bf16(ob[2*np+1], xh2, vhf + 2);
                    mma_bf16(ow[2*np],   wh, vlf);
                    mma_bf16(ow[2*np+1], wh, vlf + 2);
                    mma_bf16(ob[2*np],   xh2, vlf);
                    mma_bf16(ob[2*np+1], xh2, vlf + 2);
                    mma_bf16(ow[2*np],   wl, vhf);
                    mma_bf16(ow[2*np+1], wl, vhf + 2);
                    mma_bf16(ob[2*np],   xl2, vhf);
                    mma_bf16(ob[2*np+1], xl2, vhf + 2);
                }
            } else if (fullwin) {
#pragma unroll
                for (int np = 0; np < 8; np++) {
                    int g2 = lane >> 3;
                    int vrow = ch*32 + 16*j + (g2 & 1)*8 + (lane & 7);
                    int vcol = np*16 + (g2 >> 1)*8;
                    const bf16* vp = &bVh[vrow*VSTR + vcol];
                    uint32_t vhf[4], vlf[4];
                    ldsm_x4t(vhf, vp);
                    ldsm_x4t(vlf, vp + 2*64*VSTR);
                    mma_bf16(ow[2*np],   ph2, vhf);
                    mma_bf16(ow[2*np+1], ph2, vhf + 2);
                    mma_bf16(ow[2*np],   ph2, vlf);
                    mma_bf16(ow[2*np+1], ph2, vlf + 2);
                    mma_bf16(ow[2*np],   pl2, vhf);
                    mma_bf16(ow[2*np+1], pl2, vhf + 2);
                }
            } else {
#pragma unroll
                for (int np = 0; np < 8; np++) {
                    int g2 = lane >> 3;
                    int vrow = ch*32 + 16*j + (g2 & 1)*8 + (lane & 7);
                    int vcol = np*16 + (g2 >> 1)*8;
                    const bf16* vp = &bVh[vrow*VSTR + vcol];
                    uint32_t vhf[4], vlf[4];
                    ldsm_x4t(vhf, vp);
                    ldsm_x4t(vlf, vp + 2*64*VSTR);
                    mma_bf16(ob[2*np],   ph2, vhf);
                    mma_bf16(ob[2*np+1], ph2, vhf + 2);
                    mma_bf16(ob[2*np],   ph2, vlf);
                    mma_bf16(ob[2*np+1], ph2, vlf + 2);
                    mma_bf16(ob[2*np],   pl2, vhf);
                    mma_bf16(ob[2*np+1], pl2, vhf + 2);
                }
            }
        }
    }

    // ---- split-key merge: ch=1 warps publish, ch=0 warps combine ----
    __syncthreads();               // all compute done; safe to reuse smem
    float* msm = (float*)smem;     // 4 pairs x 32 lanes x 134 floats = 68.6KB
    float* slot = msm + ((size_t)rg * 32 + lane) * 134;
    if (ch == 1) {
        slot[0] = m0; slot[1] = m1;
        slot[2] = lb0; slot[3] = lb1;
        slot[4] = lw0; slot[5] = lw1;
#pragma unroll
        for (int n = 0; n < 16; n++)
#pragma unroll
            for (int j = 0; j < 4; j++) {
                slot[6  + n*4 + j] = ob[n][j];
                slot[70 + n*4 + j] = ow[n][j];
            }
    }
    __syncthreads();
    if (ch == 0) {
        float mB0 = slot[0], mB1 = slot[1];
        float lbB0 = slot[2], lbB1 = slot[3];
        float lwB0 = slot[4], lwB1 = slot[5];
        float M0 = fmaxf(m0, mB0), M1 = fmaxf(m1, mB1);
        float sA0 = __expf(m0 - M0), sB0 = __expf(mB0 - M0);
        float sA1 = __expf(m1 - M1), sB1 = __expf(mB1 - M1);
        lb0 = lb0*sA0 + lbB0*sB0;  lb1 = lb1*sA1 + lbB1*sB1;
        lw0 = lw0*sA0 + lwB0*sB0;  lw1 = lw1*sA1 + lwB1*sB1;
#pragma unroll
        for (int n = 0; n < 16; n++) {
            ob[n][0] = ob[n][0]*sA0 + slot[6 + n*4 + 0]*sB0;
            ob[n][1] = ob[n][1]*sA0 + slot[6 + n*4 + 1]*sB0;
            ob[n][2] = ob[n][2]*sA1 + slot[6 + n*4 + 2]*sB1;
            ob[n][3] = ob[n][3]*sA1 + slot[6 + n*4 + 3]*sB1;
            ow[n][0] = ow[n][0]*sA0 + slot[70 + n*4 + 0]*sB0;
            ow[n][1] = ow[n][1]*sA0 + slot[70 + n*4 + 1]*sB0;
            ow[n][2] = ow[n][2]*sA1 + slot[70 + n*4 + 2]*sB1;
            ow[n][3] = ow[n][3]*sA1 + slot[70 + n*4 + 3]*sB1;
        }

        float a0 = alpha[(size_t)b*TT + q0];
        float a1 = alpha[(size_t)b*TT + q1];
        float ilb0 = 1.f/lb0, ilb1 = 1.f/lb1, ilw0 = 1.f/lw0, ilw1 = 1.f/lw1;
        size_t r0o = ((size_t)b*TT + q0)*2048 + (size_t)h*128;
        size_t r1o = ((size_t)b*TT + q1)*2048 + (size_t)h*128;
#pragma unroll
        for (int n = 0; n < 16; n++) {
            int d = 8*n + 2*(lane & 3);
            float b00 = ob[n][0] + ow[n][0], b01 = ob[n][1] + ow[n][1];
            float b10 = ob[n][2] + ow[n][2], b11 = ob[n][3] + ow[n][3];
            float o00 = a0*b00*ilb0 + (1.f-a0)*ow[n][0]*ilw0;
            float o01 = a0*b01*ilb0 + (1.f-a0)*ow[n][1]*ilw0;
            float o10 = a1*b10*ilb1 + (1.f-a1)*ow[n][2]*ilw1;
            float o11 = a1*b11*ilb1 + (1.f-a1)*ow[n][3]*ilw1;
            bf16 h00 = __float2bfloat16(o00), h01 = __float2bfloat16(o01);
            bf16 h10 = __float2bfloat16(o10), h11 = __float2bfloat16(o11);
            *(uint32_t*)(mgh + r0o + d) = pk(h00, h01);
            *(uint32_t*)(mgh + r1o + d) = pk(h10, h11);
            *(uint32_t*)(mgl + r0o + d) = pk(
                __float2bfloat16(o00 - __bfloat162float(h00)),
                __float2bfloat16(o01 - __bfloat162float(h01)));
            *(uint32_t*)(mgl + r1o + d) = pk(
                __float2bfloat16(o10 - __bfloat162float(h10)),
                __float2bfloat16(o11 - __bfloat162float(h11)));
        }
    }
}

// ---------------- launcher ----------------
extern "C" void kernel_launch(void* const* d_in, const int* in_sizes, int n_in,
                              void* d_out, int out_size)
{
    (void)in_sizes; (void)n_in;
    const float* x        = (const float*)d_in[0];
    const float* unc      = (const float*)d_in[1];
    const float* Wq_down  = (const float*)d_in[2];
    const float* q_norm_w = (const float*)d_in[3];
    const float* Wq_up    = (const float*)d_in[4];
    const float* Wq_rope  = (const float*)d_in[5];
    const float* Wkv_down = (const float*)d_in[6];
    const float* kv_norm_w= (const float*)d_in[7];
    const float* Wk_up    = (const float*)d_in[8];
    const float* Wv_up    = (const float*)d_in[9];
    const float* Wk_rope  = (const float*)d_in[10];
    const float* Wout     = (const float*)d_in[11];
    const float* Wgate    = (const float*)d_in[12];
    const float* bgate    = (const float*)d_in[13];
    float* out = (float*)d_out;

    float *lat3, *qcr, *kcv, *al;
    bf16 *Qh,*Ql,*Kh,*Kl,*Vh,*Vl;
    bf16 *xh,*xl,*qlh,*qll,*kvh,*kvl,*mgh,*mgl;
    bf16 *wdnh,*wdnl,*wquph,*wqupl,*wkvuh,*wkvul,*woh,*wol;
    cudaGetSymbolAddress((void**)&lat3,  g_lat3);
    cudaGetSymbolAddress((void**)&qcr,   g_qcr);
    cudaGetSymbolAddress((void**)&kcv,   g_kcv);
    cudaGetSymbolAddress((void**)&al,    g_alpha);
    cudaGetSymbolAddress((void**)&Qh,    g_Qh);
    cudaGetSymbolAddress((void**)&Ql,    g_Ql);
    cudaGetSymbolAddress((void**)&Kh,    g_Kh);
    cudaGetSymbolAddress((void**)&Kl,    g_Kl);
    cudaGetSymbolAddress((void**)&Vh,    g_Vh);
    cudaGetSymbolAddress((void**)&Vl,    g_Vl);
    cudaGetSymbolAddress((void**)&xh,    g_xh);
    cudaGetSymbolAddress((void**)&xl,    g_xl);
    cudaGetSymbolAddress((void**)&qlh,   g_qlh);
    cudaGetSymbolAddress((void**)&qll,   g_qll);
    cudaGetSymbolAddress((void**)&kvh,   g_kvh);
    cudaGetSymbolAddress((void**)&kvl,   g_kvl);
    cudaGetSymbolAddress((void**)&mgh,   g_mgh);
    cudaGetSymbolAddress((void**)&mgl,   g_mgl);
    cudaGetSymbolAddress((void**)&wdnh,  g_wdn_h);
    cudaGetSymbolAddress((void**)&wdnl,  g_wdn_l);
    cudaGetSymbolAddress((void**)&wquph, g_wqup_h);
    cudaGetSymbolAddress((void**)&wqupl, g_wqup_l);
    cudaGetSymbolAddress((void**)&wkvuh, g_wkvu_h);
    cudaGetSymbolAddress((void**)&wkvul, g_wkvu_l);
    cudaGetSymbolAddress((void**)&woh,   g_wo_h);
    cudaGetSymbolAddress((void**)&wol,   g_wo_l);

    cudaFuncSetAttribute(attn_tc_kernel,
                         cudaFuncAttributeMaxDynamicSharedMemorySize, ATTN_SMEM);
    cudaFuncSetAttribute(gemm_split,
                         cudaFuncAttributeMaxDynamicSharedMemorySize, GS_SMEM);

    auto split = [&](const float* s, bf16* h, bf16* l, size_t n) {
        split_kernel<<<(int)(n / 1024), 256>>>(s, h, l, (int)n);
    };
    auto gemm = [&](const bf16* Ah, const bf16* Al, const bf16* Bh,
                    const bf16* Bl, float* C, int M, int N, int K) {
        gemm_split<<<dim3(N/128, M/128), 256, GS_SMEM>>>(Ah, Al, Bh, Bl, C, M, N, K);
    };

    // launch order: index 3 (ncu capture slot) = merged down-projection GEMM
    split(x, xh, xl, (size_t)BT*DD);                                   // 0
    merge3_split_kernel<<<(DD*3072)/1024, 256>>>(Wq_down, Wkv_down,
        Wk_rope, wdnh, wdnl, CQQ, CKVV, 1024, DD*3072);                // 1
    merge_split_kernel<<<(CQQ*3072)/1024, 256>>>(Wq_up, Wq_rope,
        wquph, wqupl, 2048, 1024, CQQ*3072);                           // 2
    gemm(xh, xl, wdnh, wdnl, lat3, BT, 3072, DD);                      // 3 <- ncu

    rmsnorm_split_kernel<<<BT, 256>>>(lat3, 3072, 0,    q_norm_w,  qlh, qll, CQQ);
    rmsnorm_split_kernel<<<BT, 256>>>(lat3, 3072, CQQ,  kv_norm_w, kvh, kvl, CKVV);

    gemm(qlh, qll, wquph, wqupl, qcr, BT, 3072, CQQ);

    merge_split_kernel<<<(CKVV*4096)/1024, 256>>>(Wk_up, Wv_up,
        wkvuh, wkvul, 2048, 2048, CKVV*4096);
    gemm(kvh, kvl, wkvuh, wkvul, kcv, BT, 4096, CKVV);

    split(Wout, woh, wol, (size_t)2048*DD);

    float* out_alpha = (out_size >= BB*TT*DD + BB*TT) ? (out + (size_t)BB*TT*DD)
                                                      : nullptr;
    alpha_kernel<<<BT, 256>>>(x, Wgate, bgate, al, out_alpha);

    assemble_kernel<<<BT*NHH, 128>>>(qcr, kcv, lat3, unc,
                                     Qh, Ql, Kh, Kl, Vh, Vl);

    attn_tc_kernel<<<dim3(TT/64, BB*NHH), 256, ATTN_SMEM>>>(
        Qh, Ql, Kh, Kl, Vh, Vl, al, mgh, mgl);

    gemm(mgh, mgl, woh, wol, out, BT, DD, 2048);
}

// round 13
// speedup vs baseline: 1.3166x; 1.0402x over previous
#include <cuda_runtime.h>
#include <cuda_bf16.h>
#include <math.h>
#include <stdint.h>

// ---------------- problem constants ----------------
#define BB   2
#define TT   2048
#define DD   2048
#define NHH  16
#define HDD  128
#define RR   64
#define CQQ  1536
#define CKVV 512
#define BT   (BB*TT)       // 4096
#define DQK  192           // HD + R
#define DVV  128
#define HALFW 256          // WINDOW/2
#define RSCALE 0.07216878364870323f  // 1/sqrt(192)

typedef __nv_bfloat16 bf16;

// ---------------- scratch (device globals; no runtime alloc) ----------------
__device__ float g_lat3 [(size_t)BT*3072];   // [qlat(1536) | kvlat(512) | kr(1024)]
__device__ float g_qcr  [(size_t)BT*3072];   // [qc(2048) | qr(1024)]
__device__ float g_kcv  [(size_t)BT*4096];   // [kc(2048) | vv(2048)]
__device__ float g_alpha[BT];

// attention operands, pre-split bf16, head-major: [bh][t][d]
__device__ bf16 g_Qh[(size_t)BB*NHH*TT*DQK], g_Ql[(size_t)BB*NHH*TT*DQK];
__device__ bf16 g_Kh[(size_t)BB*NHH*TT*DQK], g_Kl[(size_t)BB*NHH*TT*DQK];
__device__ bf16 g_Vh[(size_t)BB*NHH*TT*DVV], g_Vl[(size_t)BB*NHH*TT*DVV];

// bf16 split buffers (hi/lo) for GEMMs ([K,N] layout)
__device__ bf16 g_xh [(size_t)BT*DD],    g_xl [(size_t)BT*DD];
__device__ bf16 g_qlh[(size_t)BT*CQQ],   g_qll[(size_t)BT*CQQ];
__device__ bf16 g_kvh[(size_t)BT*CKVV],  g_kvl[(size_t)BT*CKVV];
__device__ bf16 g_mgh[(size_t)BT*NHH*HDD], g_mgl[(size_t)BT*NHH*HDD];
__device__ bf16 g_wdn_h [(size_t)DD*3072],   g_wdn_l [(size_t)DD*3072];   // [Wqd|Wkd|Wkr]
__device__ bf16 g_wqup_h[(size_t)CQQ*3072],  g_wqup_l[(size_t)CQQ*3072];
__device__ bf16 g_wkvu_h[(size_t)CKVV*4096], g_wkvu_l[(size_t)CKVV*4096];
__device__ bf16 g_wo_h  [(size_t)2048*DD],   g_wo_l  [(size_t)2048*DD];

// ---------------- ptx helpers ----------------
__device__ __forceinline__ uint32_t smem_u32(const void* p) {
    return (uint32_t)__cvta_generic_to_shared(p);
}
__device__ __forceinline__ void ldsm_x4(uint32_t* r, const void* p) {
    uint32_t a = smem_u32(p);
    asm volatile("ldmatrix.sync.aligned.m8n8.x4.shared.b16 {%0,%1,%2,%3}, [%4];"
                 : "=r"(r[0]), "=r"(r[1]), "=r"(r[2]), "=r"(r[3]) : "r"(a));
}
__device__ __forceinline__ void ldsm_x4t(uint32_t* r, const void* p) {
    uint32_t a = smem_u32(p);
    asm volatile("ldmatrix.sync.aligned.m8n8.x4.trans.shared.b16 {%0,%1,%2,%3}, [%4];"
                 : "=r"(r[0]), "=r"(r[1]), "=r"(r[2]), "=r"(r[3]) : "r"(a));
}
__device__ __forceinline__ void ldsm_x2t(uint32_t &r0, uint32_t &r1,
                                         const void* p) {
    uint32_t a = smem_u32(p);
    asm volatile("ldmatrix.sync.aligned.m8n8.x2.trans.shared.b16 {%0,%1}, [%2];"
                 : "=r"(r0), "=r"(r1) : "r"(a));
}
__device__ __forceinline__ void mma_bf16(float* c, const uint32_t* a,
                                         const uint32_t* b) {
    asm volatile(
        "mma.sync.aligned.m16n8k16.row.col.f32.bf16.bf16.f32 "
        "{%0,%1,%2,%3}, {%4,%5,%6,%7}, {%8,%9}, {%0,%1,%2,%3};"
        : "+f"(c[0]), "+f"(c[1]), "+f"(c[2]), "+f"(c[3])
        : "r"(a[0]), "r"(a[1]), "r"(a[2]), "r"(a[3]), "r"(b[0]), "r"(b[1]));
}
__device__ __forceinline__ void cpa16(void* s, const void* g) {
    asm volatile("cp.async.cg.shared.global [%0], [%1], 16;"
                 :: "r"(smem_u32(s)), "l"(g));
}
#define CP_COMMIT asm volatile("cp.async.commit_group;")
#define CP_WAIT0  asm volatile("cp.async.wait_group 0;")

__device__ __forceinline__ uint32_t pk(bf16 a, bf16 b) {
    __nv_bfloat162 t(a, b);
    return *reinterpret_cast<uint32_t*>(&t);
}

// ---------------- split helper: store 4 fp32 -> hi/lo bf16 at index i ------
__device__ __forceinline__ void store_split4(float4 v, bf16* h, bf16* l, int i) {
    bf16 h0 = __float2bfloat16(v.x), h1 = __float2bfloat16(v.y);
    bf16 h2 = __float2bfloat16(v.z), h3 = __float2bfloat16(v.w);
    *(__nv_bfloat162*)(h + i)     = __nv_bfloat162(h0, h1);
    *(__nv_bfloat162*)(h + i + 2) = __nv_bfloat162(h2, h3);
    *(__nv_bfloat162*)(l + i) = __nv_bfloat162(
        __float2bfloat16(v.x - __bfloat162float(h0)),
        __float2bfloat16(v.y - __bfloat162float(h1)));
    *(__nv_bfloat162*)(l + i + 2) = __nv_bfloat162(
        __float2bfloat16(v.z - __bfloat162float(h2)),
        __float2bfloat16(v.w - __bfloat162float(h3)));
}

// ---------------- split fp32 -> (hi, lo) bf16 ----------------
__global__ __launch_bounds__(256) void split_kernel(
    const float* __restrict__ s, bf16* __restrict__ h,
    bf16* __restrict__ l, int n)
{
    int i = (blockIdx.x * 256 + threadIdx.x) * 4;
    if (i >= n) return;
    store_split4(*(const float4*)(s + i), h, l, i);
}

// ---------------- fused weight prep: all merges + splits in one launch -----
// ranges: [0,T0) wdn merge3 | [T0,T1) wqup merge | [T1,T2) wkvu merge
//         [T2,T3) wo split
#define PW_T0 (DD*3072)
#define PW_T1 (PW_T0 + CQQ*3072)
#define PW_T2 (PW_T1 + CKVV*4096)
#define PW_T3 (PW_T2 + 2048*DD)

__global__ __launch_bounds__(256) void prep_weights_kernel(
    const float* __restrict__ Wq_down, const float* __restrict__ Wkv_down,
    const float* __restrict__ Wk_rope,
    bf16* __restrict__ wdnh, bf16* __restrict__ wdnl,
    const float* __restrict__ Wq_up, const float* __restrict__ Wq_rope,
    bf16* __restrict__ wquph, bf16* __restrict__ wqupl,
    const float* __restrict__ Wk_up, const float* __restrict__ Wv_up,
    bf16* __restrict__ wkvuh, bf16* __restrict__ wkvul,
    const float* __restrict__ Wout,
    bf16* __restrict__ woh, bf16* __restrict__ wol)
{
    int gi = (blockIdx.x * 256 + threadIdx.x) * 4;
    if (gi >= PW_T3) return;
    if (gi < PW_T0) {
        int i = gi;
        int k = i / 3072, n = i % 3072;
        const float* src;
        if (n < CQQ)             src = Wq_down  + (size_t)k * CQQ  + n;
        else if (n < CQQ + CKVV) src = Wkv_down + (size_t)k * CKVV + (n - CQQ);
        else                     src = Wk_rope  + (size_t)k * 1024 + (n - CQQ - CKVV);
        store_split4(*(const float4*)src, wdnh, wdnl, i);
    } else if (gi < PW_T1) {
        int i = gi - PW_T0;
        int k = i / 3072, n = i % 3072;
        const float* src = (n < 2048) ? (Wq_up + (size_t)k * 2048 + n)
                                      : (Wq_rope + (size_t)k * 1024 + (n - 2048));
        store_split4(*(const float4*)src, wquph, wqupl, i);
    } else if (gi < PW_T2) {
        int i = gi - PW_T1;
        int k = i / 4096, n = i % 4096;
        const float* src = (n < 2048) ? (Wk_up + (size_t)k * 2048 + n)
                                      : (Wv_up + (size_t)k * 2048 + (n - 2048));
        store_split4(*(const float4*)src, wkvuh, wkvul, i);
    } else {
        int i = gi - PW_T2;
        store_split4(*(const float4*)(Wout + i), woh, wol, i);
    }
}

// ---------------- split-bf16 TC GEMM core (2-stage cp.async, 1 sync/iter) --
#define GS_A   (128*40)
#define GS_B   (32*136)
#define GS_STG (2*GS_A + 2*GS_B)
#define GS_SMEM (2*GS_STG*2)

__device__ __forceinline__ void gemm_core(
    const bf16* __restrict__ Ah, const bf16* __restrict__ Al,
    const bf16* __restrict__ Bh, const bf16* __restrict__ Bl,
    float* __restrict__ C, int N, int K, int bm, int bn, bf16* gsm)
{
    int tid = threadIdx.x;
    int warp = tid >> 5, lane = tid & 31;
    int wm = warp >> 2, wn = warp & 3;

    int arow = tid >> 2, ac = (tid & 3) * 8;
    int brow = tid >> 4, bc = (tid & 15) * 8;

    float acc[4][4][4];
#pragma unroll
    for (int a = 0; a < 4; a++)
#pragma unroll
        for (int b = 0; b < 4; b++)
#pragma unroll
            for (int c = 0; c < 4; c++) acc[a][b][c] = 0.f;

    int nk = K >> 5;

    auto issue = [&](int stage, int k0) {
        bf16* sAh = gsm + stage * GS_STG;
        bf16* sAl = sAh + GS_A;
        bf16* sBh = sAl + GS_A;
        bf16* sBl = sBh + GS_B;
#pragma unroll
        for (int i = 0; i < 2; i++) {
            int r = arow + i * 64;
            size_t g = (size_t)(bm * 128 + r) * K + k0 + ac;
            cpa16(&sAh[r * 40 + ac], Ah + g);
            cpa16(&sAl[r * 40 + ac], Al + g);
        }
#pragma unroll
        for (int i = 0; i < 2; i++) {
            int r = brow + i * 16;
            size_t g = (size_t)(k0 + r) * N + bn * 128 + bc;
            cpa16(&sBh[r * 136 + bc], Bh + g);
            cpa16(&sBl[r * 136 + bc], Bl + g);
        }
    };

    issue(0, 0);
    CP_COMMIT;

    for (int it = 0; it < nk; it++) {
        CP_WAIT0;
        __syncthreads();
        if (it + 1 < nk) {
            issue((it + 1) & 1, (it + 1) << 5);
            CP_COMMIT;
        }

        bf16* sAh = gsm + (it & 1) * GS_STG;
        bf16* sAl = sAh + GS_A;
        bf16* sBh = sAl + GS_A;
        bf16* sBl = sBh + GS_B;

#pragma unroll
        for (int kh = 0; kh < 2; kh++) {
            uint32_t bhf[4][2], blf[4][2];
#pragma unroll
            for (int nt = 0; nt < 4; nt++) {
                int br = kh * 16 + (lane & 15);
                int bcl = wn * 32 + nt * 8;
                ldsm_x2t(bhf[nt][0], bhf[nt][1], &sBh[br * 136 + bcl]);
                ldsm_x2t(blf[nt][0], blf[nt][1], &sBl[br * 136 + bcl]);
            }
#pragma unroll
            for (int mt = 0; mt < 4; mt++) {
                int ar = wm * 64 + mt * 16 + (lane & 15);
                int acl = kh * 16 + (lane >> 4) * 8;
                uint32_t ah[4], al[4];
                ldsm_x4(ah, &sAh[ar * 40 + acl]);
                ldsm_x4(al, &sAl[ar * 40 + acl]);
#pragma unroll
                for (int nt = 0; nt < 4; nt++) mma_bf16(acc[mt][nt], ah, bhf[nt]);
#pragma unroll
                for (int nt = 0; nt < 4; nt++) mma_bf16(acc[mt][nt], ah, blf[nt]);
#pragma unroll
                for (int nt = 0; nt < 4; nt++) mma_bf16(acc[mt][nt], al, bhf[nt]);
            }
        }
    }

#pragma unroll
    for (int mt = 0; mt < 4; mt++) {
#pragma unroll
        for (int nt = 0; nt < 4; nt++) {
            int r0 = bm * 128 + wm * 64 + mt * 16 + (lane >> 2);
            int c0 = bn * 128 + wn * 32 + nt * 8 + (lane & 3) * 2;
            *(float2*)&C[(size_t)r0 * N + c0] =
                make_float2(acc[mt][nt][0], acc[mt][nt][1]);
            *(float2*)&C[(size_t)(r0 + 8) * N + c0] =
                make_float2(acc[mt][nt][2], acc[mt][nt][3]);
        }
    }
}

__global__ __launch_bounds__(256) void gemm_split(
    const bf16* __restrict__ Ah, const bf16* __restrict__ Al,
    const bf16* __restrict__ Bh, const bf16* __restrict__ Bl,
    float* __restrict__ C, int M, int N, int K)
{
    extern __shared__ __align__(16) bf16 gsm[];
    gemm_core(Ah, Al, Bh, Bl, C, N, K, blockIdx.y, blockIdx.x, gsm);
}

// merged q-up (768 blocks, N=3072,K=1536) + kv-up (1024 blocks, N=4096,K=512)
__global__ __launch_bounds__(256) void gemm_up2(
    const bf16* __restrict__ qlh, const bf16* __restrict__ qll,
    const bf16* __restrict__ wquph, const bf16* __restrict__ wqupl,
    float* __restrict__ qcr,
    const bf16* __restrict__ kvh, const bf16* __restrict__ kvl,
    const bf16* __restrict__ wkvuh, const bf16* __restrict__ wkvul,
    float* __restrict__ kcv)
{
    extern __shared__ __align__(16) bf16 gsm[];
    int idx = blockIdx.x;
    if (idx < 768) {
        gemm_core(qlh, qll, wquph, wqupl, qcr, 3072, CQQ, idx / 24, idx % 24, gsm);
    } else {
        idx -= 768;
        gemm_core(kvh, kvl, wkvuh, wkvul, kcv, 4096, CKVV, idx / 32, idx % 32, gsm);
    }
}

// ---------------- RMSNorm slice -> split bf16 outputs ----------------
__global__ __launch_bounds__(256) void rmsnorm_split_kernel(
    const float* __restrict__ x, int rowstride, int off,
    const float* __restrict__ w,
    bf16* __restrict__ hi, bf16* __restrict__ lo, int n)
{
    const float* row = x + (size_t)blockIdx.x * rowstride + off;
    float ss = 0.f;
    for (int i = threadIdx.x; i < n; i += 256) { float v = row[i]; ss += v*v; }
    __shared__ float sh[8];
    __shared__ float tot;
    int lane = threadIdx.x & 31, wp = threadIdx.x >> 5;
#pragma unroll
    for (int o = 16; o; o >>= 1) ss += __shfl_xor_sync(0xffffffffu, ss, o);
    if (lane == 0) sh[wp] = ss;
    __syncthreads();
    if (threadIdx.x == 0) {
        float s = 0.f;
        for (int i = 0; i < 8; i++) s += sh[i];
        tot = rsqrtf(s / n + 1e-6f);
    }
    __syncthreads();
    float rs = tot;
    bf16* hrow = hi + (size_t)blockIdx.x * n;
    bf16* lrow = lo + (size_t)blockIdx.x * n;
    for (int i = threadIdx.x; i < n; i += 256) {
        float y = row[i] * rs * w[i];
        bf16 h = __float2bfloat16(y);
        hrow[i] = h;
        lrow[i] = __float2bfloat16(y - __bfloat162float(h));
    }
}

// ---------------- gate alpha ----------------
__global__ __launch_bounds__(256) void alpha_kernel(
    const float* __restrict__ x, const float* __restrict__ wg,
    const float* __restrict__ bg, float* __restrict__ alpha,
    float* __restrict__ out_alpha)
{
    const float* row = x + (size_t)blockIdx.x * DD;
    float s = 0.f;
    for (int i = threadIdx.x; i < DD; i += 256) s += row[i] * wg[i];
    __shared__ float sh[8];
    int lane = threadIdx.x & 31, wp = threadIdx.x >> 5;
#pragma unroll
    for (int o = 16; o; o >>= 1) s += __shfl_xor_sync(0xffffffffu, s, o);
    if (lane == 0) sh[wp] = s;
    __syncthreads();
    if (threadIdx.x == 0) {
        float t = 0.f;
        for (int i = 0; i < 8; i++) t += sh[i];
        float z = t + bg[0];
        float a = 1.f / (1.f + expf(-z));
        alpha[blockIdx.x] = a;
        if (out_alpha) out_alpha[blockIdx.x] = a;
    }
}

// ---------------- assemble Q/K/V with EPE-RoPE (emit split bf16) -----------
__global__ __launch_bounds__(128) void assemble_kernel(
    const float* __restrict__ qcr, const float* __restrict__ kcv,
    const float* __restrict__ lat3, const float* __restrict__ unc,
    bf16* __restrict__ Qh, bf16* __restrict__ Ql,
    bf16* __restrict__ Kh, bf16* __restrict__ Kl,
    bf16* __restrict__ Vh, bf16* __restrict__ Vl)
{
    int idx = blockIdx.x;
    int h  = idx % NHH;
    int bt = idx / NHH;
    int t  = bt % TT;
    int b  = bt / TT;
    __shared__ float cs[32], sn[32];
    int d = threadIdx.x;
    if (d < 32) {
        float u = unc[bt];
        u = fminf(fmaxf(u, 0.f), 1.f);
        float scale = 0.5f + 1.5f * u;
        float fi = (float)d / 32.0f;
        float theta = expf(-fi * logf(500000.0f));
        float fr = (float)t * theta * scale;
        cs[d] = cosf(fr);
        sn[d] = sinf(fr);
    }
    __syncthreads();
    size_t qkrow = ((size_t)(b*NHH + h))*TT + t;

    float qv0 = qcr[(size_t)bt*3072 + h*128 + d];
    float kv0 = kcv[(size_t)bt*4096 + h*128 + d];
    float vv0 = kcv[(size_t)bt*4096 + 2048 + h*128 + d];
    bf16 hh;
    hh = __float2bfloat16(qv0);
    Qh[qkrow*DQK + d] = hh; Ql[qkrow*DQK + d] = __float2bfloat16(qv0 - __bfloat162float(hh));
    hh = __float2bfloat16(kv0);
    Kh[qkrow*DQK + d] = hh; Kl[qkrow*DQK + d] = __float2bfloat16(kv0 - __bfloat162float(hh));
    hh = __float2bfloat16(vv0);
    Vh[qkrow*DVV + d] = hh; Vl[qkrow*DVV + d] = __float2bfloat16(vv0 - __bfloat162float(hh));

    if (d < 64) {
        const float* qrp = qcr  + (size_t)bt*3072 + 2048 + h*64;
        const float* krp = lat3 + (size_t)bt*3072 + 2048 + h*64;
        float qv, kv;
        if (d < 32) {
            float c = cs[d], s = sn[d];
            qv = qrp[d]*c - qrp[d+32]*s;
            kv = krp[d]*c - krp[d+32]*s;
        } else {
            int j = d - 32;
            float c = cs[j], s = sn[j];
            qv = qrp[j+32]*c + qrp[j]*s;
            kv = krp[j+32]*c + krp[j]*s;
        }
        hh = __float2bfloat16(qv);
        Qh[qkrow*DQK + 128 + d] = hh;
        Ql[qkrow*DQK + 128 + d] = __float2bfloat16(qv - __bfloat162float(hh));
        hh = __float2bfloat16(kv);
        Kh[qkrow*DQK + 128 + d] = hh;
        Kl[qkrow*DQK + 128 + d] = __float2bfloat16(kv - __bfloat162float(hh));
    }
}

// ---------------- tensor-core fused dual attention, split-key warps --------
#define KSTR 200
#define VSTR 136
#define ATTN_SMEM ((64*KSTR*2 + 2*64*KSTR*2 + 2*64*VSTR*2) * 2)

__global__ void __launch_bounds__(256, 1) attn_tc_kernel(
    const bf16* __restrict__ Qh, const bf16* __restrict__ Ql,
    const bf16* __restrict__ Kh, const bf16* __restrict__ Kl,
    const bf16* __restrict__ Vh, const bf16* __restrict__ Vl,
    const float* __restrict__ alpha,
    bf16* __restrict__ mgh, bf16* __restrict__ mgl)
{
    extern __shared__ __align__(16) bf16 smem[];
    bf16* sQh = smem;
    bf16* sQl = sQh + 64*KSTR;
    bf16* sKh = sQl + 64*KSTR;
    bf16* sKl = sKh + 2*64*KSTR;
    bf16* sVh = sKl + 2*64*KSTR;
    bf16* sVl = sVh + 2*64*VSTR;

    int tid = threadIdx.x, lane = tid & 31, warp = tid >> 5;
    int rg = warp & 3;
    int ch = warp >> 2;
    int qt = blockIdx.x * 64;
    int bh = blockIdx.y;
    int b = bh >> 4, h = bh & 15;
    size_t base = (size_t)bh * TT;

    for (int i = tid; i < 64*24; i += 256) {
        int r = i / 24, c = (i % 24) * 8;
        size_t g = (base + qt + r) * DQK + c;
        cpa16(&sQh[r*KSTR + c], Qh + g);
        cpa16(&sQl[r*KSTR + c], Ql + g);
    }
    for (int i = tid; i < 64*24; i += 256) {
        int r = i / 24, c = (i % 24) * 8;
        size_t g = (base + r) * DQK + c;
        cpa16(&sKh[r*KSTR + c], Kh + g);
        cpa16(&sKl[r*KSTR + c], Kl + g);
    }
    for (int i = tid; i < 64*16; i += 256) {
        int r = i / 16, c = (i % 16) * 8;
        size_t g = (base + r) * DVV + c;
        cpa16(&sVh[r*VSTR + c], Vh + g);
        cpa16(&sVl[r*VSTR + c], Vl + g);
    }
    CP_COMMIT;

    int q0 = qt + 16*rg + (lane >> 2);
    int q1 = q0 + 8;
    int winlo = ((qt >> 8) << 8) - HALFW;
    if (winlo < 0) winlo = 0;

    float ob[16][4], ow[16][4];
#pragma unroll
    for (int n = 0; n < 16; n++)
#pragma unroll
        for (int j = 0; j < 4; j++) { ob[n][j] = 0.f; ow[n][j] = 0.f; }
    float m0 = -1e30f, m1 = -1e30f;
    float lb0 = 0.f, lb1 = 0.f, lw0 = 0.f, lw1 = 0.f;

    for (int t = 0; t < 32; t++) {
        int kt = t * 64;

        CP_WAIT0;
        __syncthreads();
        if (t + 1 < 32) {
            int nb = (t + 1) & 1;
            int kn = kt + 64;
            for (int i = tid; i < 64*24; i += 256) {
                int r = i / 24, c = (i % 24) * 8;
                size_t g = (base + kn + r) * DQK + c;
                cpa16(&sKh[nb*64*KSTR + r*KSTR + c], Kh + g);
                cpa16(&sKl[nb*64*KSTR + r*KSTR + c], Kl + g);
            }
            for (int i = tid; i < 64*16; i += 256) {
                int r = i / 16, c = (i % 16) * 8;
                size_t g = (base + kn + r) * DVV + c;
                cpa16(&sVh[nb*64*VSTR + r*VSTR + c], Vh + g);
                cpa16(&sVl[nb*64*VSTR + r*VSTR + c], Vl + g);
            }
            CP_COMMIT;
        }

        const bf16* bKh = sKh + (t & 1) * 64 * KSTR;
        const bf16* bVh = sVh + (t & 1) * 64 * VSTR;

        bool diag    = (kt == qt);
        bool fullwin = (kt >= winlo) && (kt < qt);

        float sacc[4][4];
#pragma unroll
        for (int n = 0; n < 4; n++)
#pragma unroll
            for (int j = 0; j < 4; j++) sacc[n][j] = 0.f;

#pragma unroll
        for (int ks = 0; ks < 12; ks++) {
            uint32_t qhf[4], qlf[4];
            const bf16* ap = &sQh[(16*rg + (lane & 15))*KSTR + ks*16 + (lane >> 4)*8];
            ldsm_x4(qhf, ap);
            ldsm_x4(qlf, ap + 64*KSTR);
#pragma unroll
            for (int np = 0; np < 2; np++) {
                int g2 = lane >> 3;
                int krow = ch*32 + np*16 + (g2 >> 1)*8 + (lane & 7);
                int kcol = ks*16 + (g2 & 1)*8;
                const bf16* bp = &bKh[krow*KSTR + kcol];
                uint32_t khf[4], klf[4];
                ldsm_x4(khf, bp);
                ldsm_x4(klf, bp + 2*64*KSTR);
                mma_bf16(sacc[2*np],   qhf, khf);
                mma_bf16(sacc[2*np+1], qhf, khf + 2);
                mma_bf16(sacc[2*np],   qhf, klf);
                mma_bf16(sacc[2*np+1], qhf, klf + 2);
                mma_bf16(sacc[2*np],   qlf, khf);
                mma_bf16(sacc[2*np+1], qlf, khf + 2);
            }
        }

        float tm0 = -1e30f, tm1 = -1e30f;
#pragma unroll
        for (int n = 0; n < 4; n++) {
            tm0 = fmaxf(tm0, fmaxf(sacc[n][0], sacc[n][1]));
            tm1 = fmaxf(tm1, fmaxf(sacc[n][2], sacc[n][3]));
        }
        tm0 *= RSCALE; tm1 *= RSCALE;
        tm0 = fmaxf(tm0, __shfl_xor_sync(0xffffffffu, tm0, 1));
        tm0 = fmaxf(tm0, __shfl_xor_sync(0xffffffffu, tm0, 2));
        tm1 = fmaxf(tm1, __shfl_xor_sync(0xffffffffu, tm1, 1));
        tm1 = fmaxf(tm1, __shfl_xor_sync(0xffffffffu, tm1, 2));
        float mn0 = fmaxf(m0, tm0), mn1 = fmaxf(m1, tm1);
        float c0 = __expf(m0 - mn0), c1 = __expf(m1 - mn1);
        m0 = mn0; m1 = mn1;
        lb0 *= c0; lb1 *= c1; lw0 *= c0; lw1 *= c1;
        if (c0 < 1.f || c1 < 1.f) {
#pragma unroll
            for (int n = 0; n < 16; n++) {
                ob[n][0] *= c0; ob[n][1] *= c0; ob[n][2] *= c1; ob[n][3] *= c1;
                ow[n][0] *= c0; ow[n][1] *= c0; ow[n][2] *= c1; ow[n][3] *= c1;
            }
        }

        float sb0 = 0.f, sb1 = 0.f, sw0 = 0.f, sw1 = 0.f;
#pragma unroll
        for (int n = 0; n < 4; n++) {
            float p0 = __expf(sacc[n][0]*RSCALE - mn0);
            float p1 = __expf(sacc[n][1]*RSCALE - mn0);
            float p2 = __expf(sacc[n][2]*RSCALE - mn1);
            float p3 = __expf(sacc[n][3]*RSCALE - mn1);
            sacc[n][0] = p0; sacc[n][1] = p1; sacc[n][2] = p2; sacc[n][3] = p3;
            sb0 += p0 + p1; sb1 += p2 + p3;
            if (diag) {
                int keyc = kt + ch*32 + 8*n + 2*(lane & 3);
                sw0 += ((keyc   <= q0) ? p0 : 0.f) + ((keyc+1 <= q0) ? p1 : 0.f);
                sw1 += ((keyc   <= q1) ? p2 : 0.f) + ((keyc+1 <= q1) ? p3 : 0.f);
            }
        }
        sb0 += __shfl_xor_sync(0xffffffffu, sb0, 1); sb0 += __shfl_xor_sync(0xffffffffu, sb0, 2);
        sb1 += __shfl_xor_sync(0xffffffffu, sb1, 1); sb1 += __shfl_xor_sync(0xffffffffu, sb1, 2);
        lb0 += sb0; lb1 += sb1;
        if (fullwin) { lw0 += sb0; lw1 += sb1; }
        if (diag) {
            sw0 += __shfl_xor_sync(0xffffffffu, sw0, 1); sw0 += __shfl_xor_sync(0xffffffffu, sw0, 2);
            sw1 += __shfl_xor_sync(0xffffffffu, sw1, 1); sw1 += __shfl_xor_sync(0xffffffffu, sw1, 2);
            lw0 += sw0; lw1 += sw1;
        }

#pragma unroll
        for (int j = 0; j < 2; j++) {
            float v0 = sacc[2*j][0],   v1 = sacc[2*j][1];
            float v2 = sacc[2*j][2],   v3 = sacc[2*j][3];
            float v4 = sacc[2*j+1][0], v5 = sacc[2*j+1][1];
            float v6 = sacc[2*j+1][2], v7 = sacc[2*j+1][3];
            bf16 h0 = __float2bfloat16(v0), h1 = __float2bfloat16(v1);
            bf16 h2 = __float2bfloat16(v2), h3 = __float2bfloat16(v3);
            bf16 h4 = __float2bfloat16(v4), h5 = __float2bfloat16(v5);
            bf16 h6 = __float2bfloat16(v6), h7 = __float2bfloat16(v7);
            bf16 e0 = __float2bfloat16(v0 - __bfloat162float(h0));
            bf16 e1 = __float2bfloat16(v1 - __bfloat162float(h1));
            bf16 e2 = __float2bfloat16(v2 - __bfloat162float(h2));
            bf16 e3 = __float2bfloat16(v3 - __bfloat162float(h3));
            bf16 e4 = __float2bfloat16(v4 - __bfloat162float(h4));
            bf16 e5 = __float2bfloat16(v5 - __bfloat162float(h5));
            bf16 e6 = __float2bfloat16(v6 - __bfloat162float(h6));
            bf16 e7 = __float2bfloat16(v7 - __bfloat162float(h7));
            uint32_t ph2[4] = { pk(h0,h1), pk(h2,h3), pk(h4,h5), pk(h6,h7) };
            uint32_t pl2[4] = { pk(e0,e1), pk(e2,e3), pk(e4,e5), pk(e6,e7) };

            if (diag) {
                bf16 z = __float2bfloat16(0.f);
                int kc = kt + ch*32 + 16*j + 2*(lane & 3);
                bool a0 = kc   <= q0, a1 = kc+1 <= q0;
                bool b0m = kc  <= q1, b1m = kc+1 <= q1;
                bool a2 = kc+8 <= q0, a3 = kc+9 <= q0;
                bool b2m = kc+8 <= q1, b3m = kc+9 <= q1;
                uint32_t wh[4], wl[4], xh2[4], xl2[4];
                wh[0] = pk(a0?h0:z, a1?h1:z);   wl[0] = pk(a0?e0:z, a1?e1:z);
                wh[1] = pk(b0m?h2:z, b1m?h3:z); wl[1] = pk(b0m?e2:z, b1m?e3:z);
                wh[2] = pk(a2?h4:z, a3?h5:z);   wl[2] = pk(a2?e4:z, a3?e5:z);
                wh[3] = pk(b2m?h6:z, b3m?h7:z); wl[3] = pk(b2m?e6:z, b3m?e7:z);
                xh2[0] = pk(a0?z:h0, a1?z:h1);   xl2[0] = pk(a0?z:e0, a1?z:e1);
                xh2[1] = pk(b0m?z:h2, b1m?z:h3); xl2[1] = pk(b0m?z:e2, b1m?z:e3);
                xh2[2] = pk(a2?z:h4, a3?z:h5);   xl2[2] = pk(a2?z:e4, a3?z:e5);
                xh2[3] = pk(b2m?z:h6, b3m?z:h7); xl2[3] = pk(b2m?z:e6, b3m?z:e7);
#pragma unroll
                for (int np = 0; np < 8; np++) {
                    int g2 = lane >> 3;
                    int vrow = ch*32 + 16*j + (g2 & 1)*8 + (lane & 7);
                    int vcol = np*16 + (g2 >> 1)*8;
                    const bf16* vp = &bVh[vrow*VSTR + vcol];
                    uint32_t vhf[4], vlf[4];
                    ldsm_x4t(vhf, vp);
                    ldsm_x4t(vlf, vp + 2*64*VSTR);
                    mma_bf16(ow[2*np],   wh, vhf);
                    mma_bf16(ow[2*np+1], wh, vhf + 2);
                    mma_bf16(ob[2*np],   xh2, vhf);
                    mma_bf16(ob[2*np+1], xh2, vhf + 2);
                    mma_bf16(ow[2*np],   wh, vlf);
                    mma_bf16(ow[2*np+1], wh, vlf + 2);
                    mma_bf16(ob[2*np],   xh2, vlf);
                    mma_bf16(ob[2*np+1], xh2, vlf + 2);
                    mma_bf16(ow[2*np],   wl, vhf);
                    mma_bf16(ow[2*np+1], wl, vhf + 2);
                    mma_bf16(ob[2*np],   xl2, vhf);
                    mma_bf16(ob[2*np+1], xl2, vhf + 2);
                }
            } else if (fullwin) {
#pragma unroll
                for (int np = 0; np < 8; np++) {
                    int g2 = lane >> 3;
                    int vrow = ch*32 + 16*j + (g2 & 1)*8 + (lane & 7);
                    int vcol = np*16 + (g2 >> 1)*8;
                    const bf16* vp = &bVh[vrow*VSTR + vcol];
                    uint32_t vhf[4], vlf[4];
                    ldsm_x4t(vhf, vp);
                    ldsm_x4t(vlf, vp + 2*64*VSTR);
                    mma_bf16(ow[2*np],   ph2, vhf);
                    mma_bf16(ow[2*np+1], ph2, vhf + 2);
                    mma_bf16(ow[2*np],   ph2, vlf);
                    mma_bf16(ow[2*np+1], ph2, vlf + 2);
                    mma_bf16(ow[2*np],   pl2, vhf);
                    mma_bf16(ow[2*np+1], pl2, vhf + 2);
                }
            } else {
#pragma unroll
                for (int np = 0; np < 8; np++) {
                    int g2 = lane >> 3;
                    int vrow = ch*32 + 16*j + (g2 & 1)*8 + (lane & 7);
                    int vcol = np*16 + (g2 >> 1)*8;
                    const bf16* vp = &bVh[vrow*VSTR + vcol];
                    uint32_t vhf[4], vlf[4];
                    ldsm_x4t(vhf, vp);
                    ldsm_x4t(vlf, vp + 2*64*VSTR);
                    mma_bf16(ob[2*np],   ph2, vhf);
                    mma_bf16(ob[2*np+1], ph2, vhf + 2);
                    mma_bf16(ob[2*np],   ph2, vlf);
                    mma_bf16(ob[2*np+1], ph2, vlf + 2);
                    mma_bf16(ob[2*np],   pl2, vhf);
                    mma_bf16(ob[2*np+1], pl2, vhf + 2);
                }
            }
        }
    }

    // ---- split-key merge ----
    __syncthreads();
    float* msm = (float*)smem;
    float* slot = msm + ((size_t)rg * 32 + lane) * 134;
    if (ch == 1) {
        slot[0] = m0; slot[1] = m1;
        slot[2] = lb0; slot[3] = lb1;
        slot[4] = lw0; slot[5] = lw1;
#pragma unroll
        for (int n = 0; n < 16; n++)
#pragma unroll
            for (int j = 0; j < 4; j++) {
                slot[6  + n*4 + j] = ob[n][j];
                slot[70 + n*4 + j] = ow[n][j];
            }
    }
    __syncthreads();
    if (ch == 0) {
        float mB0 = slot[0], mB1 = slot[1];
        float lbB0 = slot[2], lbB1 = slot[3];
        float lwB0 = slot[4], lwB1 = slot[5];
        float M0 = fmaxf(m0, mB0), M1 = fmaxf(m1, mB1);
        float sA0 = __expf(m0 - M0), sB0 = __expf(mB0 - M0);
        float sA1 = __expf(m1 - M1), sB1 = __expf(mB1 - M1);
        lb0 = lb0*sA0 + lbB0*sB0;  lb1 = lb1*sA1 + lbB1*sB1;
        lw0 = lw0*sA0 + lwB0*sB0;  lw1 = lw1*sA1 + lwB1*sB1;
#pragma unroll
        for (int n = 0; n < 16; n++) {
            ob[n][0] = ob[n][0]*sA0 + slot[6 + n*4 + 0]*sB0;
            ob[n][1] = ob[n][1]*sA0 + slot[6 + n*4 + 1]*sB0;
            ob[n][2] = ob[n][2]*sA1 + slot[6 + n*4 + 2]*sB1;
            ob[n][3] = ob[n][3]*sA1 + slot[6 + n*4 + 3]*sB1;
            ow[n][0] = ow[n][0]*sA0 + slot[70 + n*4 + 0]*sB0;
            ow[n][1] = ow[n][1]*sA0 + slot[70 + n*4 + 1]*sB0;
            ow[n][2] = ow[n][2]*sA1 + slot[70 + n*4 + 2]*sB1;
            ow[n][3] = ow[n][3]*sA1 + slot[70 + n*4 + 3]*sB1;
        }

        float a0 = alpha[(size_t)b*TT + q0];
        float a1 = alpha[(size_t)b*TT + q1];
        float ilb0 = 1.f/lb0, ilb1 = 1.f/lb1, ilw0 = 1.f/lw0, ilw1 = 1.f/lw1;
        size_t r0o = ((size_t)b*TT + q0)*2048 + (size_t)h*128;
        size_t r1o = ((size_t)b*TT + q1)*2048 + (size_t)h*128;
#pragma unroll
        for (int n = 0; n < 16; n++) {
            int d = 8*n + 2*(lane & 3);
            float b00 = ob[n][0] + ow[n][0], b01 = ob[n][1] + ow[n][1];
            float b10 = ob[n][2] + ow[n][2], b11 = ob[n][3] + ow[n][3];
            float o00 = a0*b00*ilb0 + (1.f-a0)*ow[n][0]*ilw0;
            float o01 = a0*b01*ilb0 + (1.f-a0)*ow[n][1]*ilw0;
            float o10 = a1*b10*ilb1 + (1.f-a1)*ow[n][2]*ilw1;
            float o11 = a1*b11*ilb1 + (1.f-a1)*ow[n][3]*ilw1;
            bf16 h00 = __float2bfloat16(o00), h01 = __float2bfloat16(o01);
            bf16 h10 = __float2bfloat16(o10), h11 = __float2bfloat16(o11);
            *(uint32_t*)(mgh + r0o + d) = pk(h00, h01);
            *(uint32_t*)(mgh + r1o + d) = pk(h10, h11);
            *(uint32_t*)(mgl + r0o + d) = pk(
                __float2bfloat16(o00 - __bfloat162float(h00)),
                __float2bfloat16(o01 - __bfloat162float(h01)));
            *(uint32_t*)(mgl + r1o + d) = pk(
                __float2bfloat16(o10 - __bfloat162float(h10)),
                __float2bfloat16(o11 - __bfloat162float(h11)));
        }
    }
}

// ---------------- launcher ----------------
extern "C" void kernel_launch(void* const* d_in, const int* in_sizes, int n_in,
                              void* d_out, int out_size)
{
    (void)in_sizes; (void)n_in;
    const float* x        = (const float*)d_in[0];
    const float* unc      = (const float*)d_in[1];
    const float* Wq_down  = (const float*)d_in[2];
    const float* q_norm_w = (const float*)d_in[3];
    const float* Wq_up    = (const float*)d_in[4];
    const float* Wq_rope  = (const float*)d_in[5];
    const float* Wkv_down = (const float*)d_in[6];
    const float* kv_norm_w= (const float*)d_in[7];
    const float* Wk_up    = (const float*)d_in[8];
    const float* Wv_up    = (const float*)d_in[9];
    const float* Wk_rope  = (const float*)d_in[10];
    const float* Wout     = (const float*)d_in[11];
    const float* Wgate    = (const float*)d_in[12];
    const float* bgate    = (const float*)d_in[13];
    float* out = (float*)d_out;

    float *lat3, *qcr, *kcv, *al;
    bf16 *Qh,*Ql,*Kh,*Kl,*Vh,*Vl;
    bf16 *xh,*xl,*qlh,*qll,*kvh,*kvl,*mgh,*mgl;
    bf16 *wdnh,*wdnl,*wquph,*wqupl,*wkvuh,*wkvul,*woh,*wol;
    cudaGetSymbolAddress((void**)&lat3,  g_lat3);
    cudaGetSymbolAddress((void**)&qcr,   g_qcr);
    cudaGetSymbolAddress((void**)&kcv,   g_kcv);
    cudaGetSymbolAddress((void**)&al,    g_alpha);
    cudaGetSymbolAddress((void**)&Qh,    g_Qh);
    cudaGetSymbolAddress((void**)&Ql,    g_Ql);
    cudaGetSymbolAddress((void**)&Kh,    g_Kh);
    cudaGetSymbolAddress((void**)&Kl,    g_Kl);
    cudaGetSymbolAddress((void**)&Vh,    g_Vh);
    cudaGetSymbolAddress((void**)&Vl,    g_Vl);
    cudaGetSymbolAddress((void**)&xh,    g_xh);
    cudaGetSymbolAddress((void**)&xl,    g_xl);
    cudaGetSymbolAddress((void**)&qlh,   g_qlh);
    cudaGetSymbolAddress((void**)&qll,   g_qll);
    cudaGetSymbolAddress((void**)&kvh,   g_kvh);
    cudaGetSymbolAddress((void**)&kvl,   g_kvl);
    cudaGetSymbolAddress((void**)&mgh,   g_mgh);
    cudaGetSymbolAddress((void**)&mgl,   g_mgl);
    cudaGetSymbolAddress((void**)&wdnh,  g_wdn_h);
    cudaGetSymbolAddress((void**)&wdnl,  g_wdn_l);
    cudaGetSymbolAddress((void**)&wquph, g_wqup_h);
    cudaGetSymbolAddress((void**)&wqupl, g_wqup_l);
    cudaGetSymbolAddress((void**)&wkvuh, g_wkvu_h);
    cudaGetSymbolAddress((void**)&wkvul, g_wkvu_l);
    cudaGetSymbolAddress((void**)&woh,   g_wo_h);
    cudaGetSymbolAddress((void**)&wol,   g_wo_l);

    cudaFuncSetAttribute(attn_tc_kernel,
                         cudaFuncAttributeMaxDynamicSharedMemorySize, ATTN_SMEM);
    cudaFuncSetAttribute(gemm_split,
                         cudaFuncAttributeMaxDynamicSharedMemorySize, GS_SMEM);
    cudaFuncSetAttribute(gemm_up2,
                         cudaFuncAttributeMaxDynamicSharedMemorySize, GS_SMEM);

    // 0: split input activations
    split_kernel<<<(BT*DD)/1024, 256>>>(x, xh, xl, BT*DD);
    // 1: all weight preprocessing fused
    prep_weights_kernel<<<(PW_T3 + 1023)/1024, 256>>>(
        Wq_down, Wkv_down, Wk_rope, wdnh, wdnl,
        Wq_up, Wq_rope, wquph, wqupl,
        Wk_up, Wv_up, wkvuh, wkvul,
        Wout, woh, wol);
    // 2: gate
    float* out_alpha = (out_size >= BB*TT*DD + BB*TT) ? (out + (size_t)BB*TT*DD)
                                                      : nullptr;
    alpha_kernel<<<BT, 256>>>(x, Wgate, bgate, al, out_alpha);
    // 3 (ncu slot): merged down-projection GEMM
    gemm_split<<<dim3(3072/128, BT/128), 256, GS_SMEM>>>(
        xh, xl, wdnh, wdnl, lat3, BT, 3072, DD);
    // 4-5: norms
    rmsnorm_split_kernel<<<BT, 256>>>(lat3, 3072, 0,    q_norm_w,  qlh, qll, CQQ);
    rmsnorm_split_kernel<<<BT, 256>>>(lat3, 3072, CQQ,  kv_norm_w, kvh, kvl, CKVV);
    // 6: merged up-projections (q-up 768 blocks + kv-up 1024 blocks)
    gemm_up2<<<768 + 1024, 256, GS_SMEM>>>(
        qlh, qll, wquph, wqupl, qcr,
        kvh, kvl, wkvuh, wkvul, kcv);
    // 7: assemble Q/K/V
    assemble_kernel<<<BT*NHH, 128>>>(qcr, kcv, lat3, unc,
                                     Qh, Ql, Kh, Kl, Vh, Vl);
    // 8: attention
    attn_tc_kernel<<<dim3(TT/64, BB*NHH), 256, ATTN_SMEM>>>(
        Qh, Ql, Kh, Kl, Vh, Vl, al, mgh, mgl);
    // 9: output projection
    gemm_split<<<dim3(DD/128, BT/128), 256, GS_SMEM>>>(
        mgh, mgl, woh, wol, out, BT, DD, 2048);
}

// round 14
// speedup vs baseline: 1.7449x; 1.3253x over previous
#include <cuda_runtime.h>
#include <cuda_fp16.h>
#include <math.h>
#include <stdint.h>

// ---------------- problem constants ----------------
#define BB   2
#define TT   2048
#define DD   2048
#define NHH  16
#define HDD  128
#define RR   64
#define CQQ  1536
#define CKVV 512
#define BT   (BB*TT)       // 4096
#define DQK  192           // HD + R
#define DVV  128
#define HALFW 256          // WINDOW/2
#define RSCALE 0.07216878364870323f  // 1/sqrt(192)

typedef __half fp16;

// ---------------- scratch (device globals; no runtime alloc) ----------------
__device__ float g_lat3 [(size_t)BT*3072];   // [qlat(1536) | kvlat(512) | kr(1024)]
__device__ float g_qcr  [(size_t)BT*3072];   // [qc(2048) | qr(1024)]
__device__ float g_kcv  [(size_t)BT*4096];   // [kc(2048) | vv(2048)]
__device__ float g_alpha[BT];

// attention operands fp16, head-major: Q hi-only; K,V hi+lo
__device__ fp16 g_Qh[(size_t)BB*NHH*TT*DQK];
__device__ fp16 g_Kh[(size_t)BB*NHH*TT*DQK], g_Kl[(size_t)BB*NHH*TT*DQK];
__device__ fp16 g_Vh[(size_t)BB*NHH*TT*DVV], g_Vl[(size_t)BB*NHH*TT*DVV];

// fp16 buffers: activations hi-only (A operands); weights hi+lo (B operands)
__device__ fp16 g_xh [(size_t)BT*DD];
__device__ fp16 g_qlh[(size_t)BT*CQQ];
__device__ fp16 g_kvh[(size_t)BT*CKVV];
__device__ fp16 g_mgh[(size_t)BT*NHH*HDD];
__device__ fp16 g_wdn_h [(size_t)DD*3072],   g_wdn_l [(size_t)DD*3072];
__device__ fp16 g_wqup_h[(size_t)CQQ*3072],  g_wqup_l[(size_t)CQQ*3072];
__device__ fp16 g_wkvu_h[(size_t)CKVV*4096], g_wkvu_l[(size_t)CKVV*4096];
__device__ fp16 g_wo_h  [(size_t)2048*DD],   g_wo_l  [(size_t)2048*DD];

// ---------------- ptx helpers ----------------
__device__ __forceinline__ uint32_t smem_u32(const void* p) {
    return (uint32_t)__cvta_generic_to_shared(p);
}
__device__ __forceinline__ void ldsm_x4(uint32_t* r, const void* p) {
    uint32_t a = smem_u32(p);
    asm volatile("ldmatrix.sync.aligned.m8n8.x4.shared.b16 {%0,%1,%2,%3}, [%4];"
                 : "=r"(r[0]), "=r"(r[1]), "=r"(r[2]), "=r"(r[3]) : "r"(a));
}
__device__ __forceinline__ void ldsm_x4t(uint32_t* r, const void* p) {
    uint32_t a = smem_u32(p);
    asm volatile("ldmatrix.sync.aligned.m8n8.x4.trans.shared.b16 {%0,%1,%2,%3}, [%4];"
                 : "=r"(r[0]), "=r"(r[1]), "=r"(r[2]), "=r"(r[3]) : "r"(a));
}
__device__ __forceinline__ void ldsm_x2t(uint32_t &r0, uint32_t &r1,
                                         const void* p) {
    uint32_t a = smem_u32(p);
    asm volatile("ldmatrix.sync.aligned.m8n8.x2.trans.shared.b16 {%0,%1}, [%2];"
                 : "=r"(r0), "=r"(r1) : "r"(a));
}
__device__ __forceinline__ void mma_fp16(float* c, const uint32_t* a,
                                         const uint32_t* b) {
    asm volatile(
        "mma.sync.aligned.m16n8k16.row.col.f32.f16.f16.f32 "
        "{%0,%1,%2,%3}, {%4,%5,%6,%7}, {%8,%9}, {%0,%1,%2,%3};"
        : "+f"(c[0]), "+f"(c[1]), "+f"(c[2]), "+f"(c[3])
        : "r"(a[0]), "r"(a[1]), "r"(a[2]), "r"(a[3]), "r"(b[0]), "r"(b[1]));
}
__device__ __forceinline__ void cpa16(void* s, const void* g) {
    asm volatile("cp.async.cg.shared.global [%0], [%1], 16;"
                 :: "r"(smem_u32(s)), "l"(g));
}
#define CP_COMMIT asm volatile("cp.async.commit_group;")
#define CP_WAIT0  asm volatile("cp.async.wait_group 0;")

__device__ __forceinline__ uint32_t pkh(fp16 a, fp16 b) {
    __half2 t = __halves2half2(a, b);
    return *reinterpret_cast<uint32_t*>(&t);
}

// ---------------- split helpers ----------------
__device__ __forceinline__ void store_hi4(float4 v, fp16* h, int i) {
    *(__half2*)(h + i)     = __halves2half2(__float2half(v.x), __float2half(v.y));
    *(__half2*)(h + i + 2) = __halves2half2(__float2half(v.z), __float2half(v.w));
}
__device__ __forceinline__ void store_split4(float4 v, fp16* h, fp16* l, int i) {
    fp16 h0 = __float2half(v.x), h1 = __float2half(v.y);
    fp16 h2 = __float2half(v.z), h3 = __float2half(v.w);
    *(__half2*)(h + i)     = __halves2half2(h0, h1);
    *(__half2*)(h + i + 2) = __halves2half2(h2, h3);
    *(__half2*)(l + i) = __halves2half2(
        __float2half(v.x - __half2float(h0)),
        __float2half(v.y - __half2float(h1)));
    *(__half2*)(l + i + 2) = __halves2half2(
        __float2half(v.z - __half2float(h2)),
        __float2half(v.w - __half2float(h3)));
}

// ---------------- split input activations (hi only) ----------------
__global__ __launch_bounds__(256) void split_hi_kernel(
    const float* __restrict__ s, fp16* __restrict__ h, int n)
{
    int i = (blockIdx.x * 256 + threadIdx.x) * 4;
    if (i >= n) return;
    store_hi4(*(const float4*)(s + i), h, i);
}

// ---------------- fused weight prep: merges + hi/lo splits ----------------
#define PW_T0 (DD*3072)
#define PW_T1 (PW_T0 + CQQ*3072)
#define PW_T2 (PW_T1 + CKVV*4096)
#define PW_T3 (PW_T2 + 2048*DD)

__global__ __launch_bounds__(256) void prep_weights_kernel(
    const float* __restrict__ Wq_down, const float* __restrict__ Wkv_down,
    const float* __restrict__ Wk_rope,
    fp16* __restrict__ wdnh, fp16* __restrict__ wdnl,
    const float* __restrict__ Wq_up, const float* __restrict__ Wq_rope,
    fp16* __restrict__ wquph, fp16* __restrict__ wqupl,
    const float* __restrict__ Wk_up, const float* __restrict__ Wv_up,
    fp16* __restrict__ wkvuh, fp16* __restrict__ wkvul,
    const float* __restrict__ Wout,
    fp16* __restrict__ woh, fp16* __restrict__ wol)
{
    int gi = (blockIdx.x * 256 + threadIdx.x) * 4;
    if (gi >= PW_T3) return;
    if (gi < PW_T0) {
        int i = gi;
        int k = i / 3072, n = i % 3072;
        const float* src;
        if (n < CQQ)             src = Wq_down  + (size_t)k * CQQ  + n;
        else if (n < CQQ + CKVV) src = Wkv_down + (size_t)k * CKVV + (n - CQQ);
        else                     src = Wk_rope  + (size_t)k * 1024 + (n - CQQ - CKVV);
        store_split4(*(const float4*)src, wdnh, wdnl, i);
    } else if (gi < PW_T1) {
        int i = gi - PW_T0;
        int k = i / 3072, n = i % 3072;
        const float* src = (n < 2048) ? (Wq_up + (size_t)k * 2048 + n)
                                      : (Wq_rope + (size_t)k * 1024 + (n - 2048));
        store_split4(*(const float4*)src, wquph, wqupl, i);
    } else if (gi < PW_T2) {
        int i = gi - PW_T1;
        int k = i / 4096, n = i % 4096;
        const float* src = (n < 2048) ? (Wk_up + (size_t)k * 2048 + n)
                                      : (Wv_up + (size_t)k * 2048 + (n - 2048));
        store_split4(*(const float4*)src, wkvuh, wkvul, i);
    } else {
        int i = gi - PW_T2;
        store_split4(*(const float4*)(Wout + i), woh, wol, i);
    }
}

// ---------------- fp16 2-chain TC GEMM (A hi-only, B hi+lo) ----------------
#define GS_A   (128*40)
#define GS_B   (32*136)
#define GS_STG (GS_A + 2*GS_B)
#define GS_SMEM (2*GS_STG*2)

__device__ __forceinline__ void gemm_core(
    const fp16* __restrict__ Ah,
    const fp16* __restrict__ Bh, const fp16* __restrict__ Bl,
    float* __restrict__ C, int N, int K, int bm, int bn, fp16* gsm)
{
    int tid = threadIdx.x;
    int warp = tid >> 5, lane = tid & 31;
    int wm = warp >> 2, wn = warp & 3;

    int arow = tid >> 2, ac = (tid & 3) * 8;
    int brow = tid >> 4, bc = (tid & 15) * 8;

    float acc[4][4][4];
#pragma unroll
    for (int a = 0; a < 4; a++)
#pragma unroll
        for (int b = 0; b < 4; b++)
#pragma unroll
            for (int c = 0; c < 4; c++) acc[a][b][c] = 0.f;

    int nk = K >> 5;

    auto issue = [&](int stage, int k0) {
        fp16* sA  = gsm + stage * GS_STG;
        fp16* sBh = sA + GS_A;
        fp16* sBl = sBh + GS_B;
#pragma unroll
        for (int i = 0; i < 2; i++) {
            int r = arow + i * 64;
            size_t g = (size_t)(bm * 128 + r) * K + k0 + ac;
            cpa16(&sA[r * 40 + ac], Ah + g);
        }
#pragma unroll
        for (int i = 0; i < 2; i++) {
            int r = brow + i * 16;
            size_t g = (size_t)(k0 + r) * N + bn * 128 + bc;
            cpa16(&sBh[r * 136 + bc], Bh + g);
            cpa16(&sBl[r * 136 + bc], Bl + g);
        }
    };

    issue(0, 0);
    CP_COMMIT;

    for (int it = 0; it < nk; it++) {
        CP_WAIT0;
        __syncthreads();
        if (it + 1 < nk) {
            issue((it + 1) & 1, (it + 1) << 5);
            CP_COMMIT;
        }

        fp16* sA  = gsm + (it & 1) * GS_STG;
        fp16* sBh = sA + GS_A;
        fp16* sBl = sBh + GS_B;

#pragma unroll
        for (int kh = 0; kh < 2; kh++) {
            uint32_t bhf[4][2], blf[4][2];
#pragma unroll
            for (int nt = 0; nt < 4; nt++) {
                int br = kh * 16 + (lane & 15);
                int bcl = wn * 32 + nt * 8;
                ldsm_x2t(bhf[nt][0], bhf[nt][1], &sBh[br * 136 + bcl]);
                ldsm_x2t(blf[nt][0], blf[nt][1], &sBl[br * 136 + bcl]);
            }
#pragma unroll
            for (int mt = 0; mt < 4; mt++) {
                int ar = wm * 64 + mt * 16 + (lane & 15);
                int acl = kh * 16 + (lane >> 4) * 8;
                uint32_t ah[4];
                ldsm_x4(ah, &sA[ar * 40 + acl]);
#pragma unroll
                for (int nt = 0; nt < 4; nt++) mma_fp16(acc[mt][nt], ah, bhf[nt]);
#pragma unroll
                for (int nt = 0; nt < 4; nt++) mma_fp16(acc[mt][nt], ah, blf[nt]);
            }
        }
    }

#pragma unroll
    for (int mt = 0; mt < 4; mt++) {
#pragma unroll
        for (int nt = 0; nt < 4; nt++) {
            int r0 = bm * 128 + wm * 64 + mt * 16 + (lane >> 2);
            int c0 = bn * 128 + wn * 32 + nt * 8 + (lane & 3) * 2;
            *(float2*)&C[(size_t)r0 * N + c0] =
                make_float2(acc[mt][nt][0], acc[mt][nt][1]);
            *(float2*)&C[(size_t)(r0 + 8) * N + c0] =
                make_float2(acc[mt][nt][2], acc[mt][nt][3]);
        }
    }
}

__global__ __launch_bounds__(256) void gemm_split(
    const fp16* __restrict__ Ah,
    const fp16* __restrict__ Bh, const fp16* __restrict__ Bl,
    float* __restrict__ C, int M, int N, int K)
{
    extern __shared__ __align__(16) fp16 gsm[];
    gemm_core(Ah, Bh, Bl, C, N, K, blockIdx.y, blockIdx.x, gsm);
}

__global__ __launch_bounds__(256) void gemm_up2(
    const fp16* __restrict__ qlh,
    const fp16* __restrict__ wquph, const fp16* __restrict__ wqupl,
    float* __restrict__ qcr,
    const fp16* __restrict__ kvh,
    const fp16* __restrict__ wkvuh, const fp16* __restrict__ wkvul,
    float* __restrict__ kcv)
{
    extern __shared__ __align__(16) fp16 gsm[];
    int idx = blockIdx.x;
    if (idx < 768) {
        gemm_core(qlh, wquph, wqupl, qcr, 3072, CQQ, idx / 24, idx % 24, gsm);
    } else {
        idx -= 768;
        gemm_core(kvh, wkvuh, wkvul, kcv, 4096, CKVV, idx / 32, idx % 32, gsm);
    }
}

// ---------------- RMSNorm slice -> fp16 hi-only outputs ----------------
__global__ __launch_bounds__(256) void rmsnorm_hi_kernel(
    const float* __restrict__ x, int rowstride, int off,
    const float* __restrict__ w, fp16* __restrict__ hi, int n)
{
    const float* row = x + (size_t)blockIdx.x * rowstride + off;
    float ss = 0.f;
    for (int i = threadIdx.x; i < n; i += 256) { float v = row[i]; ss += v*v; }
    __shared__ float sh[8];
    __shared__ float tot;
    int lane = threadIdx.x & 31, wp = threadIdx.x >> 5;
#pragma unroll
    for (int o = 16; o; o >>= 1) ss += __shfl_xor_sync(0xffffffffu, ss, o);
    if (lane == 0) sh[wp] = ss;
    __syncthreads();
    if (threadIdx.x == 0) {
        float s = 0.f;
        for (int i = 0; i < 8; i++) s += sh[i];
        tot = rsqrtf(s / n + 1e-6f);
    }
    __syncthreads();
    float rs = tot;
    fp16* hrow = hi + (size_t)blockIdx.x * n;
    for (int i = threadIdx.x; i < n; i += 256)
        hrow[i] = __float2half(row[i] * rs * w[i]);
}

// ---------------- gate alpha ----------------
__global__ __launch_bounds__(256) void alpha_kernel(
    const float* __restrict__ x, const float* __restrict__ wg,
    const float* __restrict__ bg, float* __restrict__ alpha,
    float* __restrict__ out_alpha)
{
    const float* row = x + (size_t)blockIdx.x * DD;
    float s = 0.f;
    for (int i = threadIdx.x; i < DD; i += 256) s += row[i] * wg[i];
    __shared__ float sh[8];
    int lane = threadIdx.x & 31, wp = threadIdx.x >> 5;
#pragma unroll
    for (int o = 16; o; o >>= 1) s += __shfl_xor_sync(0xffffffffu, s, o);
    if (lane == 0) sh[wp] = s;
    __syncthreads();
    if (threadIdx.x == 0) {
        float t = 0.f;
        for (int i = 0; i < 8; i++) t += sh[i];
        float z = t + bg[0];
        float a = 1.f / (1.f + expf(-z));
        alpha[blockIdx.x] = a;
        if (out_alpha) out_alpha[blockIdx.x] = a;
    }
}

// ---------------- assemble Q/K/V with EPE-RoPE ----------------
__global__ __launch_bounds__(128) void assemble_kernel(
    const float* __restrict__ qcr, const float* __restrict__ kcv,
    const float* __restrict__ lat3, const float* __restrict__ unc,
    fp16* __restrict__ Qh,
    fp16* __restrict__ Kh, fp16* __restrict__ Kl,
    fp16* __restrict__ Vh, fp16* __restrict__ Vl)
{
    int idx = blockIdx.x;
    int h  = idx % NHH;
    int bt = idx / NHH;
    int t  = bt % TT;
    int b  = bt / TT;
    __shared__ float cs[32], sn[32];
    int d = threadIdx.x;
    if (d < 32) {
        float u = unc[bt];
        u = fminf(fmaxf(u, 0.f), 1.f);
        float scale = 0.5f + 1.5f * u;
        float fi = (float)d / 32.0f;
        float theta = expf(-fi * logf(500000.0f));
        float fr = (float)t * theta * scale;
        cs[d] = cosf(fr);
        sn[d] = sinf(fr);
    }
    __syncthreads();
    size_t qkrow = ((size_t)(b*NHH + h))*TT + t;

    float qv0 = qcr[(size_t)bt*3072 + h*128 + d];
    float kv0 = kcv[(size_t)bt*4096 + h*128 + d];
    float vv0 = kcv[(size_t)bt*4096 + 2048 + h*128 + d];
    Qh[qkrow*DQK + d] = __float2half(qv0);
    fp16 hh;
    hh = __float2half(kv0);
    Kh[qkrow*DQK + d] = hh; Kl[qkrow*DQK + d] = __float2half(kv0 - __half2float(hh));
    hh = __float2half(vv0);
    Vh[qkrow*DVV + d] = hh; Vl[qkrow*DVV + d] = __float2half(vv0 - __half2float(hh));

    if (d < 64) {
        const float* qrp = qcr  + (size_t)bt*3072 + 2048 + h*64;
        const float* krp = lat3 + (size_t)bt*3072 + 2048 + h*64;
        float qv, kv;
        if (d < 32) {
            float c = cs[d], s = sn[d];
            qv = qrp[d]*c - qrp[d+32]*s;
            kv = krp[d]*c - krp[d+32]*s;
        } else {
            int j = d - 32;
            float c = cs[j], s = sn[j];
            qv = qrp[j+32]*c + qrp[j]*s;
            kv = krp[j+32]*c + krp[j]*s;
        }
        Qh[qkrow*DQK + 128 + d] = __float2half(qv);
        hh = __float2half(kv);
        Kh[qkrow*DQK + 128 + d] = hh;
        Kl[qkrow*DQK + 128 + d] = __float2half(kv - __half2float(hh));
    }
}

// ---------------- fp16 2-chain fused dual attention, split-key warps -------
#define KSTR 200
#define VSTR 136
#define ATTN_SMEM ((64*KSTR + 2*64*KSTR*2 + 2*64*VSTR*2) * 2)

__global__ void __launch_bounds__(256, 1) attn_tc_kernel(
    const fp16* __restrict__ Qh,
    const fp16* __restrict__ Kh, const fp16* __restrict__ Kl,
    const fp16* __restrict__ Vh, const fp16* __restrict__ Vl,
    const float* __restrict__ alpha, fp16* __restrict__ mgh)
{
    extern __shared__ __align__(16) fp16 smem[];
    fp16* sQh = smem;
    fp16* sKh = sQh + 64*KSTR;
    fp16* sKl = sKh + 2*64*KSTR;
    fp16* sVh = sKl + 2*64*KSTR;
    fp16* sVl = sVh + 2*64*VSTR;

    int tid = threadIdx.x, lane = tid & 31, warp = tid >> 5;
    int rg = warp & 3;
    int ch = warp >> 2;
    int qt = blockIdx.x * 64;
    int bh = blockIdx.y;
    int b = bh >> 4, h = bh & 15;
    size_t base = (size_t)bh * TT;

    for (int i = tid; i < 64*24; i += 256) {
        int r = i / 24, c = (i % 24) * 8;
        size_t g = (base + qt + r) * DQK + c;
        cpa16(&sQh[r*KSTR + c], Qh + g);
    }
    for (int i = tid; i < 64*24; i += 256) {
        int r = i / 24, c = (i % 24) * 8;
        size_t g = (base + r) * DQK + c;
        cpa16(&sKh[r*KSTR + c], Kh + g);
        cpa16(&sKl[r*KSTR + c], Kl + g);
    }
    for (int i = tid; i < 64*16; i += 256) {
        int r = i / 16, c = (i % 16) * 8;
        size_t g = (base + r) * DVV + c;
        cpa16(&sVh[r*VSTR + c], Vh + g);
        cpa16(&sVl[r*VSTR + c], Vl + g);
    }
    CP_COMMIT;

    int q0 = qt + 16*rg + (lane >> 2);
    int q1 = q0 + 8;
    int winlo = ((qt >> 8) << 8) - HALFW;
    if (winlo < 0) winlo = 0;

    float ob[16][4], ow[16][4];
#pragma unroll
    for (int n = 0; n < 16; n++)
#pragma unroll
        for (int j = 0; j < 4; j++) { ob[n][j] = 0.f; ow[n][j] = 0.f; }
    float m0 = -1e30f, m1 = -1e30f;
    float lb0 = 0.f, lb1 = 0.f, lw0 = 0.f, lw1 = 0.f;

    for (int t = 0; t < 32; t++) {
        int kt = t * 64;

        CP_WAIT0;
        __syncthreads();
        if (t + 1 < 32) {
            int nb = (t + 1) & 1;
            int kn = kt + 64;
            for (int i = tid; i < 64*24; i += 256) {
                int r = i / 24, c = (i % 24) * 8;
                size_t g = (base + kn + r) * DQK + c;
                cpa16(&sKh[nb*64*KSTR + r*KSTR + c], Kh + g);
                cpa16(&sKl[nb*64*KSTR + r*KSTR + c], Kl + g);
            }
            for (int i = tid; i < 64*16; i += 256) {
                int r = i / 16, c = (i % 16) * 8;
                size_t g = (base + kn + r) * DVV + c;
                cpa16(&sVh[nb*64*VSTR + r*VSTR + c], Vh + g);
                cpa16(&sVl[nb*64*VSTR + r*VSTR + c], Vl + g);
            }
            CP_COMMIT;
        }

        const fp16* bKh = sKh + (t & 1) * 64 * KSTR;
        const fp16* bVh = sVh + (t & 1) * 64 * VSTR;

        bool diag    = (kt == qt);
        bool fullwin = (kt >= winlo) && (kt < qt);

        float sacc[4][4];
#pragma unroll
        for (int n = 0; n < 4; n++)
#pragma unroll
            for (int j = 0; j < 4; j++) sacc[n][j] = 0.f;

#pragma unroll
        for (int ks = 0; ks < 12; ks++) {
            uint32_t qhf[4];
            const fp16* ap = &sQh[(16*rg + (lane & 15))*KSTR + ks*16 + (lane >> 4)*8];
            ldsm_x4(qhf, ap);
#pragma unroll
            for (int np = 0; np < 2; np++) {
                int g2 = lane >> 3;
                int krow = ch*32 + np*16 + (g2 >> 1)*8 + (lane & 7);
                int kcol = ks*16 + (g2 & 1)*8;
                const fp16* bp = &bKh[krow*KSTR + kcol];
                uint32_t khf[4], klf[4];
                ldsm_x4(khf, bp);
                ldsm_x4(klf, bp + 2*64*KSTR);
                mma_fp16(sacc[2*np],   qhf, khf);
                mma_fp16(sacc[2*np+1], qhf, khf + 2);
                mma_fp16(sacc[2*np],   qhf, klf);
                mma_fp16(sacc[2*np+1], qhf, klf + 2);
            }
        }

        float tm0 = -1e30f, tm1 = -1e30f;
#pragma unroll
        for (int n = 0; n < 4; n++) {
            tm0 = fmaxf(tm0, fmaxf(sacc[n][0], sacc[n][1]));
            tm1 = fmaxf(tm1, fmaxf(sacc[n][2], sacc[n][3]));
        }
        tm0 *= RSCALE; tm1 *= RSCALE;
        tm0 = fmaxf(tm0, __shfl_xor_sync(0xffffffffu, tm0, 1));
        tm0 = fmaxf(tm0, __shfl_xor_sync(0xffffffffu, tm0, 2));
        tm1 = fmaxf(tm1, __shfl_xor_sync(0xffffffffu, tm1, 1));
        tm1 = fmaxf(tm1, __shfl_xor_sync(0xffffffffu, tm1, 2));
        float mn0 = fmaxf(m0, tm0), mn1 = fmaxf(m1, tm1);
        float c0 = __expf(m0 - mn0), c1 = __expf(m1 - mn1);
        m0 = mn0; m1 = mn1;
        lb0 *= c0; lb1 *= c1; lw0 *= c0; lw1 *= c1;
        if (c0 < 1.f || c1 < 1.f) {
#pragma unroll
            for (int n = 0; n < 16; n++) {
                ob[n][0] *= c0; ob[n][1] *= c0; ob[n][2] *= c1; ob[n][3] *= c1;
                ow[n][0] *= c0; ow[n][1] *= c0; ow[n][2] *= c1; ow[n][3] *= c1;
            }
        }

        float sb0 = 0.f, sb1 = 0.f, sw0 = 0.f, sw1 = 0.f;
#pragma unroll
        for (int n = 0; n < 4; n++) {
            float p0 = __expf(sacc[n][0]*RSCALE - mn0);
            float p1 = __expf(sacc[n][1]*RSCALE - mn0);
            float p2 = __expf(sacc[n][2]*RSCALE - mn1);
            float p3 = __expf(sacc[n][3]*RSCALE - mn1);
            sacc[n][0] = p0; sacc[n][1] = p1; sacc[n][2] = p2; sacc[n][3] = p3;
            sb0 += p0 + p1; sb1 += p2 + p3;
            if (diag) {
                int keyc = kt + ch*32 + 8*n + 2*(lane & 3);
                sw0 += ((keyc   <= q0) ? p0 : 0.f) + ((keyc+1 <= q0) ? p1 : 0.f);
                sw1 += ((keyc   <= q1) ? p2 : 0.f) + ((keyc+1 <= q1) ? p3 : 0.f);
            }
        }
        sb0 += __shfl_xor_sync(0xffffffffu, sb0, 1); sb0 += __shfl_xor_sync(0xffffffffu, sb0, 2);
        sb1 += __shfl_xor_sync(0xffffffffu, sb1, 1); sb1 += __shfl_xor_sync(0xffffffffu, sb1, 2);
        lb0 += sb0; lb1 += sb1;
        if (fullwin) { lw0 += sb0; lw1 += sb1; }
        if (diag) {
            sw0 += __shfl_xor_sync(0xffffffffu, sw0, 1); sw0 += __shfl_xor_sync(0xffffffffu, sw0, 2);
            sw1 += __shfl_xor_sync(0xffffffffu, sw1, 1); sw1 += __shfl_xor_sync(0xffffffffu, sw1, 2);
            lw0 += sw0; lw1 += sw1;
        }

#pragma unroll
        for (int j = 0; j < 2; j++) {
            fp16 h0 = __float2half(sacc[2*j][0]),   h1 = __float2half(sacc[2*j][1]);
            fp16 h2 = __float2half(sacc[2*j][2]),   h3 = __float2half(sacc[2*j][3]);
            fp16 h4 = __float2half(sacc[2*j+1][0]), h5 = __float2half(sacc[2*j+1][1]);
            fp16 h6 = __float2half(sacc[2*j+1][2]), h7 = __float2half(sacc[2*j+1][3]);
            uint32_t ph2[4] = { pkh(h0,h1), pkh(h2,h3), pkh(h4,h5), pkh(h6,h7) };

            if (diag) {
                fp16 z = __float2half(0.f);
                int kc = kt + ch*32 + 16*j + 2*(lane & 3);
                bool a0 = kc   <= q0, a1 = kc+1 <= q0;
                bool b0m = kc  <= q1, b1m = kc+1 <= q1;
                bool a2 = kc+8 <= q0, a3 = kc+9 <= q0;
                bool b2m = kc+8 <= q1, b3m = kc+9 <= q1;
                uint32_t wh[4], xh2[4];
                wh[0] = pkh(a0?h0:z, a1?h1:z);
                wh[1] = pkh(b0m?h2:z, b1m?h3:z);
                wh[2] = pkh(a2?h4:z, a3?h5:z);
                wh[3] = pkh(b2m?h6:z, b3m?h7:z);
                xh2[0] = pkh(a0?z:h0, a1?z:h1);
                xh2[1] = pkh(b0m?z:h2, b1m?z:h3);
                xh2[2] = pkh(a2?z:h4, a3?z:h5);
                xh2[3] = pkh(b2m?z:h6, b3m?z:h7);
#pragma unroll
                for (int np = 0; np < 8; np++) {
                    int g2 = lane >> 3;
                    int vrow = ch*32 + 16*j + (g2 & 1)*8 + (lane & 7);
                    int vcol = np*16 + (g2 >> 1)*8;
                    const fp16* vp = &bVh[vrow*VSTR + vcol];
                    uint32_t vhf[4], vlf[4];
                    ldsm_x4t(vhf, vp);
                    ldsm_x4t(vlf, vp + 2*64*VSTR);
                    mma_fp16(ow[2*np],   wh, vhf);
                    mma_fp16(ow[2*np+1], wh, vhf + 2);
                    mma_fp16(ob[2*np],   xh2, vhf);
                    mma_fp16(ob[2*np+1], xh2, vhf + 2);
                    mma_fp16(ow[2*np],   wh, vlf);
                    mma_fp16(ow[2*np+1], wh, vlf + 2);
                    mma_fp16(ob[2*np],   xh2, vlf);
                    mma_fp16(ob[2*np+1], xh2, vlf + 2);
                }
            } else if (fullwin) {
#pragma unroll
                for (int np = 0; np < 8; np++) {
                    int g2 = lane >> 3;
                    int vrow = ch*32 + 16*j + (g2 & 1)*8 + (lane & 7);
                    int vcol = np*16 + (g2 >> 1)*8;
                    const fp16* vp = &bVh[vrow*VSTR + vcol];
                    uint32_t vhf[4], vlf[4];
                    ldsm_x4t(vhf, vp);
                    ldsm_x4t(vlf, vp + 2*64*VSTR);
                    mma_fp16(ow[2*np],   ph2, vhf);
                    mma_fp16(ow[2*np+1], ph2, vhf + 2);
                    mma_fp16(ow[2*np],   ph2, vlf);
                    mma_fp16(ow[2*np+1], ph2, vlf + 2);
                }
            } else {
#pragma unroll
                for (int np = 0; np < 8; np++) {
                    int g2 = lane >> 3;
                    int vrow = ch*32 + 16*j + (g2 & 1)*8 + (lane & 7);
                    int vcol = np*16 + (g2 >> 1)*8;
                    const fp16* vp = &bVh[vrow*VSTR + vcol];
                    uint32_t vhf[4], vlf[4];
                    ldsm_x4t(vhf, vp);
                    ldsm_x4t(vlf, vp + 2*64*VSTR);
                    mma_fp16(ob[2*np],   ph2, vhf);
                    mma_fp16(ob[2*np+1], ph2, vhf + 2);
                    mma_fp16(ob[2*np],   ph2, vlf);
                    mma_fp16(ob[2*np+1], ph2, vlf + 2);
                }
            }
        }
    }

    // ---- split-key merge ----
    __syncthreads();
    float* msm = (float*)smem;
    float* slot = msm + ((size_t)rg * 32 + lane) * 134;
    if (ch == 1) {
        slot[0] = m0; slot[1] = m1;
        slot[2] = lb0; slot[3] = lb1;
        slot[4] = lw0; slot[5] = lw1;
#pragma unroll
        for (int n = 0; n < 16; n++)
#pragma unroll
            for (int j = 0; j < 4; j++) {
                slot[6  + n*4 + j] = ob[n][j];
                slot[70 + n*4 + j] = ow[n][j];
            }
    }
    __syncthreads();
    if (ch == 0) {
        float mB0 = slot[0], mB1 = slot[1];
        float lbB0 = slot[2], lbB1 = slot[3];
        float lwB0 = slot[4], lwB1 = slot[5];
        float M0 = fmaxf(m0, mB0), M1 = fmaxf(m1, mB1);
        float sA0 = __expf(m0 - M0), sB0 = __expf(mB0 - M0);
        float sA1 = __expf(m1 - M1), sB1 = __expf(mB1 - M1);
        lb0 = lb0*sA0 + lbB0*sB0;  lb1 = lb1*sA1 + lbB1*sB1;
        lw0 = lw0*sA0 + lwB0*sB0;  lw1 = lw1*sA1 + lwB1*sB1;
#pragma unroll
        for (int n = 0; n < 16; n++) {
            ob[n][0] = ob[n][0]*sA0 + slot[6 + n*4 + 0]*sB0;
            ob[n][1] = ob[n][1]*sA0 + slot[6 + n*4 + 1]*sB0;
            ob[n][2] = ob[n][2]*sA1 + slot[6 + n*4 + 2]*sB1;
            ob[n][3] = ob[n][3]*sA1 + slot[6 + n*4 + 3]*sB1;
            ow[n][0] = ow[n][0]*sA0 + slot[70 + n*4 + 0]*sB0;
            ow[n][1] = ow[n][1]*sA0 + slot[70 + n*4 + 1]*sB0;
            ow[n][2] = ow[n][2]*sA1 + slot[70 + n*4 + 2]*sB1;
            ow[n][3] = ow[n][3]*sA1 + slot[70 + n*4 + 3]*sB1;
        }

        float a0 = alpha[(size_t)b*TT + q0];
        float a1 = alpha[(size_t)b*TT + q1];
        float ilb0 = 1.f/lb0, ilb1 = 1.f/lb1, ilw0 = 1.f/lw0, ilw1 = 1.f/lw1;
        size_t r0o = ((size_t)b*TT + q0)*2048 + (size_t)h*128;
        size_t r1o = ((size_t)b*TT + q1)*2048 + (size_t)h*128;
#pragma unroll
        for (int n = 0; n < 16; n++) {
            int d = 8*n + 2*(lane & 3);
            float b00 = ob[n][0] + ow[n][0], b01 = ob[n][1] + ow[n][1];
            float b10 = ob[n][2] + ow[n][2], b11 = ob[n][3] + ow[n][3];
            float o00 = a0*b00*ilb0 + (1.f-a0)*ow[n][0]*ilw0;
            float o01 = a0*b01*ilb0 + (1.f-a0)*ow[n][1]*ilw0;
            float o10 = a1*b10*ilb1 + (1.f-a1)*ow[n][2]*ilw1;
            float o11 = a1*b11*ilb1 + (1.f-a1)*ow[n][3]*ilw1;
            *(uint32_t*)(mgh + r0o + d) = pkh(__float2half(o00), __float2half(o01));
            *(uint32_t*)(mgh + r1o + d) = pkh(__float2half(o10), __float2half(o11));
        }
    }
}

// ---------------- launcher ----------------
extern "C" void kernel_launch(void* const* d_in, const int* in_sizes, int n_in,
                              void* d_out, int out_size)
{
    (void)in_sizes; (void)n_in;
    const float* x        = (const float*)d_in[0];
    const float* unc      = (const float*)d_in[1];
    const float* Wq_down  = (const float*)d_in[2];
    const float* q_norm_w = (const float*)d_in[3];
    const float* Wq_up    = (const float*)d_in[4];
    const float* Wq_rope  = (const float*)d_in[5];
    const float* Wkv_down = (const float*)d_in[6];
    const float* kv_norm_w= (const float*)d_in[7];
    const float* Wk_up    = (const float*)d_in[8];
    const float* Wv_up    = (const float*)d_in[9];
    const float* Wk_rope  = (const float*)d_in[10];
    const float* Wout     = (const float*)d_in[11];
    const float* Wgate    = (const float*)d_in[12];
    const float* bgate    = (const float*)d_in[13];
    float* out = (float*)d_out;

    float *lat3, *qcr, *kcv, *al;
    fp16 *Qh,*Kh,*Kl,*Vh,*Vl;
    fp16 *xh,*qlh,*kvh,*mgh;
    fp16 *wdnh,*wdnl,*wquph,*wqupl,*wkvuh,*wkvul,*woh,*wol;
    cudaGetSymbolAddress((void**)&lat3,  g_lat3);
    cudaGetSymbolAddress((void**)&qcr,   g_qcr);
    cudaGetSymbolAddress((void**)&kcv,   g_kcv);
    cudaGetSymbolAddress((void**)&al,    g_alpha);
    cudaGetSymbolAddress((void**)&Qh,    g_Qh);
    cudaGetSymbolAddress((void**)&Kh,    g_Kh);
    cudaGetSymbolAddress((void**)&Kl,    g_Kl);
    cudaGetSymbolAddress((void**)&Vh,    g_Vh);
    cudaGetSymbolAddress((void**)&Vl,    g_Vl);
    cudaGetSymbolAddress((void**)&xh,    g_xh);
    cudaGetSymbolAddress((void**)&qlh,   g_qlh);
    cudaGetSymbolAddress((void**)&kvh,   g_kvh);
    cudaGetSymbolAddress((void**)&mgh,   g_mgh);
    cudaGetSymbolAddress((void**)&wdnh,  g_wdn_h);
    cudaGetSymbolAddress((void**)&wdnl,  g_wdn_l);
    cudaGetSymbolAddress((void**)&wquph, g_wqup_h);
    cudaGetSymbolAddress((void**)&wqupl, g_wqup_l);
    cudaGetSymbolAddress((void**)&wkvuh, g_wkvu_h);
    cudaGetSymbolAddress((void**)&wkvul, g_wkvu_l);
    cudaGetSymbolAddress((void**)&woh,   g_wo_h);
    cudaGetSymbolAddress((void**)&wol,   g_wo_l);

    cudaFuncSetAttribute(attn_tc_kernel,
                         cudaFuncAttributeMaxDynamicSharedMemorySize, ATTN_SMEM);
    cudaFuncSetAttribute(gemm_split,
                         cudaFuncAttributeMaxDynamicSharedMemorySize, GS_SMEM);
    cudaFuncSetAttribute(gemm_up2,
                         cudaFuncAttributeMaxDynamicSharedMemorySize, GS_SMEM);

    // 0: split input activations (hi only)
    split_hi_kernel<<<(BT*DD)/1024, 256>>>(x, xh, BT*DD);
    // 1: all weight preprocessing fused
    prep_weights_kernel<<<(PW_T3 + 1023)/1024, 256>>>(
        Wq_down, Wkv_down, Wk_rope, wdnh, wdnl,
        Wq_up, Wq_rope, wquph, wqupl,
        Wk_up, Wv_up, wkvuh, wkvul,
        Wout, woh, wol);
    // 2: gate
    float* out_alpha = (out_size >= BB*TT*DD + BB*TT) ? (out + (size_t)BB*TT*DD)
                                                      : nullptr;
    alpha_kernel<<<BT, 256>>>(x, Wgate, bgate, al, out_alpha);
    // 3 (ncu slot): merged down-projection GEMM
    gemm_split<<<dim3(3072/128, BT/128), 256, GS_SMEM>>>(
        xh, wdnh, wdnl, lat3, BT, 3072, DD);
    // 4-5: norms (hi-only outputs)
    rmsnorm_hi_kernel<<<BT, 256>>>(lat3, 3072, 0,   q_norm_w,  qlh, CQQ);
    rmsnorm_hi_kernel<<<BT, 256>>>(lat3, 3072, CQQ, kv_norm_w, kvh, CKVV);
    // 6: merged up-projections
    gemm_up2<<<768 + 1024, 256, GS_SMEM>>>(
        qlh, wquph, wqupl, qcr,
        kvh, wkvuh, wkvul, kcv);
    // 7: assemble Q/K/V
    assemble_kernel<<<BT*NHH, 128>>>(qcr, kcv, lat3, unc,
                                     Qh, Kh, Kl, Vh, Vl);
    // 8: attention
    attn_tc_kernel<<<dim3(TT/64, BB*NHH), 256, ATTN_SMEM>>>(
        Qh, Kh, Kl, Vh, Vl, al, mgh);
    // 9: output projection
    gemm_split<<<dim3(DD/128, BT/128), 256, GS_SMEM>>>(
        mgh, woh, wol, out, BT, DD, 2048);
}

// round 15
// speedup vs baseline: 1.8653x; 1.0690x over previous
#include <cuda_runtime.h>
#include <cuda_fp16.h>
#include <math.h>
#include <stdint.h>

// ---------------- problem constants ----------------
#define BB   2
#define TT   2048
#define DD   2048
#define NHH  16
#define HDD  128
#define RR   64
#define CQQ  1536
#define CKVV 512
#define BT   (BB*TT)       // 4096
#define DQK  192           // HD + R
#define DVV  128
#define HALFW 256          // WINDOW/2
#define RSCALE 0.07216878364870323f  // 1/sqrt(192)

typedef __half fp16;

// ---------------- scratch (device globals; no runtime alloc) ----------------
__device__ float g_lat3 [(size_t)BT*3072];
__device__ float g_qcr  [(size_t)BT*3072];
__device__ float g_kcv  [(size_t)BT*4096];
__device__ float g_alpha[BT];

__device__ fp16 g_Qh[(size_t)BB*NHH*TT*DQK];
__device__ fp16 g_Kh[(size_t)BB*NHH*TT*DQK], g_Kl[(size_t)BB*NHH*TT*DQK];
__device__ fp16 g_Vh[(size_t)BB*NHH*TT*DVV], g_Vl[(size_t)BB*NHH*TT*DVV];

__device__ fp16 g_xh [(size_t)BT*DD];
__device__ fp16 g_qlh[(size_t)BT*CQQ];
__device__ fp16 g_kvh[(size_t)BT*CKVV];
__device__ fp16 g_mgh[(size_t)BT*NHH*HDD];
__device__ fp16 g_wdn_h [(size_t)DD*3072],   g_wdn_l [(size_t)DD*3072];
__device__ fp16 g_wqup_h[(size_t)CQQ*3072],  g_wqup_l[(size_t)CQQ*3072];
__device__ fp16 g_wkvu_h[(size_t)CKVV*4096], g_wkvu_l[(size_t)CKVV*4096];
__device__ fp16 g_wo_h  [(size_t)2048*DD];

// ---------------- ptx helpers ----------------
__device__ __forceinline__ uint32_t smem_u32(const void* p) {
    return (uint32_t)__cvta_generic_to_shared(p);
}
__device__ __forceinline__ void ldsm_x4(uint32_t* r, const void* p) {
    uint32_t a = smem_u32(p);
    asm volatile("ldmatrix.sync.aligned.m8n8.x4.shared.b16 {%0,%1,%2,%3}, [%4];"
                 : "=r"(r[0]), "=r"(r[1]), "=r"(r[2]), "=r"(r[3]) : "r"(a));
}
__device__ __forceinline__ void ldsm_x4t(uint32_t* r, const void* p) {
    uint32_t a = smem_u32(p);
    asm volatile("ldmatrix.sync.aligned.m8n8.x4.trans.shared.b16 {%0,%1,%2,%3}, [%4];"
                 : "=r"(r[0]), "=r"(r[1]), "=r"(r[2]), "=r"(r[3]) : "r"(a));
}
__device__ __forceinline__ void mma_fp16(float* c, const uint32_t* a,
                                         const uint32_t* b) {
    asm volatile(
        "mma.sync.aligned.m16n8k16.row.col.f32.f16.f16.f32 "
        "{%0,%1,%2,%3}, {%4,%5,%6,%7}, {%8,%9}, {%0,%1,%2,%3};"
        : "+f"(c[0]), "+f"(c[1]), "+f"(c[2]), "+f"(c[3])
        : "r"(a[0]), "r"(a[1]), "r"(a[2]), "r"(a[3]), "r"(b[0]), "r"(b[1]));
}
__device__ __forceinline__ void cpa16(void* s, const void* g) {
    asm volatile("cp.async.cg.shared.global [%0], [%1], 16;"
                 :: "r"(smem_u32(s)), "l"(g));
}
#define CP_COMMIT asm volatile("cp.async.commit_group;")
#define CP_WAIT0  asm volatile("cp.async.wait_group 0;")

__device__ __forceinline__ uint32_t pkh(fp16 a, fp16 b) {
    __half2 t = __halves2half2(a, b);
    return *reinterpret_cast<uint32_t*>(&t);
}

// ---------------- split helpers ----------------
__device__ __forceinline__ void store_hi4(float4 v, fp16* h, int i) {
    *(__half2*)(h + i)     = __halves2half2(__float2half(v.x), __float2half(v.y));
    *(__half2*)(h + i + 2) = __halves2half2(__float2half(v.z), __float2half(v.w));
}
__device__ __forceinline__ void store_split4(float4 v, fp16* h, fp16* l, int i) {
    fp16 h0 = __float2half(v.x), h1 = __float2half(v.y);
    fp16 h2 = __float2half(v.z), h3 = __float2half(v.w);
    *(__half2*)(h + i)     = __halves2half2(h0, h1);
    *(__half2*)(h + i + 2) = __halves2half2(h2, h3);
    *(__half2*)(l + i) = __halves2half2(
        __float2half(v.x - __half2float(h0)),
        __float2half(v.y - __half2float(h1)));
    *(__half2*)(l + i + 2) = __halves2half2(
        __float2half(v.z - __half2float(h2)),
        __float2half(v.w - __half2float(h3)));
}

// ---------------- split input activations (hi only) ----------------
__global__ __launch_bounds__(256) void split_hi_kernel(
    const float* __restrict__ s, fp16* __restrict__ h, int n)
{
    int i = (blockIdx.x * 256 + threadIdx.x) * 4;
    if (i >= n) return;
    store_hi4(*(const float4*)(s + i), h, i);
}

// ---------------- fused weight prep ----------------
#define PW_T0 (DD*3072)
#define PW_T1 (PW_T0 + CQQ*3072)
#define PW_T2 (PW_T1 + CKVV*4096)
#define PW_T3 (PW_T2 + 2048*DD)

__global__ __launch_bounds__(256) void prep_weights_kernel(
    const float* __restrict__ Wq_down, const float* __restrict__ Wkv_down,
    const float* __restrict__ Wk_rope,
    fp16* __restrict__ wdnh, fp16* __restrict__ wdnl,
    const float* __restrict__ Wq_up, const float* __restrict__ Wq_rope,
    fp16* __restrict__ wquph, fp16* __restrict__ wqupl,
    const float* __restrict__ Wk_up, const float* __restrict__ Wv_up,
    fp16* __restrict__ wkvuh, fp16* __restrict__ wkvul,
    const float* __restrict__ Wout, fp16* __restrict__ woh)
{
    int gi = (blockIdx.x * 256 + threadIdx.x) * 4;
    if (gi >= PW_T3) return;
    if (gi < PW_T0) {
        int i = gi;
        int k = i / 3072, n = i % 3072;
        const float* src;
        if (n < CQQ)             src = Wq_down  + (size_t)k * CQQ  + n;
        else if (n < CQQ + CKVV) src = Wkv_down + (size_t)k * CKVV + (n - CQQ);
        else                     src = Wk_rope  + (size_t)k * 1024 + (n - CQQ - CKVV);
        store_split4(*(const float4*)src, wdnh, wdnl, i);
    } else if (gi < PW_T1) {
        int i = gi - PW_T0;
        int k = i / 3072, n = i % 3072;
        const float* src = (n < 2048) ? (Wq_up + (size_t)k * 2048 + n)
                                      : (Wq_rope + (size_t)k * 1024 + (n - 2048));
        store_split4(*(const float4*)src, wquph, wqupl, i);
    } else if (gi < PW_T2) {
        int i = gi - PW_T1;
        int k = i / 4096, n = i % 4096;
        const float* src = (n < 2048) ? (Wk_up + (size_t)k * 2048 + n)
                                      : (Wv_up + (size_t)k * 2048 + (n - 2048));
        store_split4(*(const float4*)src, wkvuh, wkvul, i);
    } else {
        int i = gi - PW_T2;
        store_hi4(*(const float4*)(Wout + i), woh, i);
    }
}

// ---------------- fp16 TC GEMM core (A hi-only; B hi [+ optional lo]) ------
#define GS_A   (128*40)
#define GS_B   (32*136)
#define GS_STG (GS_A + 2*GS_B)
#define GS_SMEM (2*GS_STG*2)

template<bool USE_LO>
__device__ __forceinline__ void gemm_core(
    const fp16* __restrict__ Ah,
    const fp16* __restrict__ Bh, const fp16* __restrict__ Bl,
    float* __restrict__ C, int N, int K, int bm, int bn, fp16* gsm)
{
    int tid = threadIdx.x;
    int warp = tid >> 5, lane = tid & 31;
    int wm = warp >> 2, wn = warp & 3;
    int g2 = lane >> 3;

    int arow = tid >> 2, ac = (tid & 3) * 8;
    int brow = tid >> 4, bc = (tid & 15) * 8;

    float acc[4][4][4];
#pragma unroll
    for (int a = 0; a < 4; a++)
#pragma unroll
        for (int b = 0; b < 4; b++)
#pragma unroll
            for (int c = 0; c < 4; c++) acc[a][b][c] = 0.f;

    int nk = K >> 5;

    auto issue = [&](int stage, int k0) {
        fp16* sA  = gsm + stage * GS_STG;
        fp16* sBh = sA + GS_A;
        fp16* sBl = sBh + GS_B;
#pragma unroll
        for (int i = 0; i < 2; i++) {
            int r = arow + i * 64;
            size_t g = (size_t)(bm * 128 + r) * K + k0 + ac;
            cpa16(&sA[r * 40 + ac], Ah + g);
        }
#pragma unroll
        for (int i = 0; i < 2; i++) {
            int r = brow + i * 16;
            size_t g = (size_t)(k0 + r) * N + bn * 128 + bc;
            cpa16(&sBh[r * 136 + bc], Bh + g);
            if (USE_LO) cpa16(&sBl[r * 136 + bc], Bl + g);
        }
    };

    issue(0, 0);
    CP_COMMIT;

    for (int it = 0; it < nk; it++) {
        CP_WAIT0;
        __syncthreads();
        if (it + 1 < nk) {
            issue((it + 1) & 1, (it + 1) << 5);
            CP_COMMIT;
        }

        fp16* sA  = gsm + (it & 1) * GS_STG;
        fp16* sBh = sA + GS_A;

#pragma unroll
        for (int kh = 0; kh < 2; kh++) {
            // B frags via ldsm_x4t: k16 x n16 per load (same lane map as attn V)
            uint32_t bh4[2][4], bl4[2][4];
#pragma unroll
            for (int nt2 = 0; nt2 < 2; nt2++) {
                int br = kh * 16 + (g2 & 1) * 8 + (lane & 7);
                int bcl = wn * 32 + nt2 * 16 + (g2 >> 1) * 8;
                const fp16* bp = &sBh[br * 136 + bcl];
                ldsm_x4t(bh4[nt2], bp);
                if (USE_LO) ldsm_x4t(bl4[nt2], bp + GS_B);
            }
#pragma unroll
            for (int mt = 0; mt < 4; mt++) {
                int ar = wm * 64 + mt * 16 + (lane & 15);
                int acl = kh * 16 + (lane >> 4) * 8;
                uint32_t ah[4];
                ldsm_x4(ah, &sA[ar * 40 + acl]);
#pragma unroll
                for (int nt2 = 0; nt2 < 2; nt2++) {
                    mma_fp16(acc[mt][2*nt2],   ah, bh4[nt2]);
                    mma_fp16(acc[mt][2*nt2+1], ah, bh4[nt2] + 2);
                }
                if (USE_LO) {
#pragma unroll
                    for (int nt2 = 0; nt2 < 2; nt2++) {
                        mma_fp16(acc[mt][2*nt2],   ah, bl4[nt2]);
                        mma_fp16(acc[mt][2*nt2+1], ah, bl4[nt2] + 2);
                    }
                }
            }
        }
    }

#pragma unroll
    for (int mt = 0; mt < 4; mt++) {
#pragma unroll
        for (int nt = 0; nt < 4; nt++) {
            int r0 = bm * 128 + wm * 64 + mt * 16 + (lane >> 2);
            int c0 = bn * 128 + wn * 32 + nt * 8 + (lane & 3) * 2;
            *(float2*)&C[(size_t)r0 * N + c0] =
                make_float2(acc[mt][nt][0], acc[mt][nt][1]);
            *(float2*)&C[(size_t)(r0 + 8) * N + c0] =
                make_float2(acc[mt][nt][2], acc[mt][nt][3]);
        }
    }
}

__global__ __launch_bounds__(256) void gemm_split(
    const fp16* __restrict__ Ah,
    const fp16* __restrict__ Bh, const fp16* __restrict__ Bl,
    float* __restrict__ C, int M, int N, int K)
{
    extern __shared__ __align__(16) fp16 gsm[];
    gemm_core<true>(Ah, Bh, Bl, C, N, K, blockIdx.y, blockIdx.x, gsm);
}

__global__ __launch_bounds__(256) void gemm_out_hi(
    const fp16* __restrict__ Ah, const fp16* __restrict__ Bh,
    float* __restrict__ C, int M, int N, int K)
{
    extern __shared__ __align__(16) fp16 gsm[];
    gemm_core<false>(Ah, Bh, nullptr, C, N, K, blockIdx.y, blockIdx.x, gsm);
}

__global__ __launch_bounds__(256) void gemm_up2(
    const fp16* __restrict__ qlh,
    const fp16* __restrict__ wquph, const fp16* __restrict__ wqupl,
    float* __restrict__ qcr,
    const fp16* __restrict__ kvh,
    const fp16* __restrict__ wkvuh, const fp16* __restrict__ wkvul,
    float* __restrict__ kcv)
{
    extern __shared__ __align__(16) fp16 gsm[];
    int idx = blockIdx.x;
    if (idx < 768) {
        gemm_core<true>(qlh, wquph, wqupl, qcr, 3072, CQQ, idx / 24, idx % 24, gsm);
    } else {
        idx -= 768;
        gemm_core<true>(kvh, wkvuh, wkvul, kcv, 4096, CKVV, idx / 32, idx % 32, gsm);
    }
}

// ---------------- RMSNorm slice -> fp16 hi-only outputs ----------------
__global__ __launch_bounds__(256) void rmsnorm_hi_kernel(
    const float* __restrict__ x, int rowstride, int off,
    const float* __restrict__ w, fp16* __restrict__ hi, int n)
{
    const float* row = x + (size_t)blockIdx.x * rowstride + off;
    float ss = 0.f;
    for (int i = threadIdx.x; i < n; i += 256) { float v = row[i]; ss += v*v; }
    __shared__ float sh[8];
    __shared__ float tot;
    int lane = threadIdx.x & 31, wp = threadIdx.x >> 5;
#pragma unroll
    for (int o = 16; o; o >>= 1) ss += __shfl_xor_sync(0xffffffffu, ss, o);
    if (lane == 0) sh[wp] = ss;
    __syncthreads();
    if (threadIdx.x == 0) {
        float s = 0.f;
        for (int i = 0; i < 8; i++) s += sh[i];
        tot = rsqrtf(s / n + 1e-6f);
    }
    __syncthreads();
    float rs = tot;
    fp16* hrow = hi + (size_t)blockIdx.x * n;
    for (int i = threadIdx.x; i < n; i += 256)
        hrow[i] = __float2half(row[i] * rs * w[i]);
}

// ---------------- gate alpha ----------------
__global__ __launch_bounds__(256) void alpha_kernel(
    const float* __restrict__ x, const float* __restrict__ wg,
    const float* __restrict__ bg, float* __restrict__ alpha,
    float* __restrict__ out_alpha)
{
    const float* row = x + (size_t)blockIdx.x * DD;
    float s = 0.f;
    for (int i = threadIdx.x; i < DD; i += 256) s += row[i] * wg[i];
    __shared__ float sh[8];
    int lane = threadIdx.x & 31, wp = threadIdx.x >> 5;
#pragma unroll
    for (int o = 16; o; o >>= 1) s += __shfl_xor_sync(0xffffffffu, s, o);
    if (lane == 0) sh[wp] = s;
    __syncthreads();
    if (threadIdx.x == 0) {
        float t = 0.f;
        for (int i = 0; i < 8; i++) t += sh[i];
        float z = t + bg[0];
        float a = 1.f / (1.f + expf(-z));
        alpha[blockIdx.x] = a;
        if (out_alpha) out_alpha[blockIdx.x] = a;
    }
}

// ---------------- assemble Q/K/V with EPE-RoPE ----------------
__global__ __launch_bounds__(128) void assemble_kernel(
    const float* __restrict__ qcr, const float* __restrict__ kcv,
    const float* __restrict__ lat3, const float* __restrict__ unc,
    fp16* __restrict__ Qh,
    fp16* __restrict__ Kh, fp16* __restrict__ Kl,
    fp16* __restrict__ Vh, fp16* __restrict__ Vl)
{
    int idx = blockIdx.x;
    int h  = idx % NHH;
    int bt = idx / NHH;
    int t  = bt % TT;
    int b  = bt / TT;
    __shared__ float cs[32], sn[32];
    int d = threadIdx.x;
    if (d < 32) {
        float u = unc[bt];
        u = fminf(fmaxf(u, 0.f), 1.f);
        float scale = 0.5f + 1.5f * u;
        float fi = (float)d / 32.0f;
        float theta = expf(-fi * logf(500000.0f));
        float fr = (float)t * theta * scale;
        cs[d] = cosf(fr);
        sn[d] = sinf(fr);
    }
    __syncthreads();
    size_t qkrow = ((size_t)(b*NHH + h))*TT + t;

    float qv0 = qcr[(size_t)bt*3072 + h*128 + d];
    float kv0 = kcv[(size_t)bt*4096 + h*128 + d];
    float vv0 = kcv[(size_t)bt*4096 + 2048 + h*128 + d];
    Qh[qkrow*DQK + d] = __float2half(qv0);
    fp16 hh;
    hh = __float2half(kv0);
    Kh[qkrow*DQK + d] = hh; Kl[qkrow*DQK + d] = __float2half(kv0 - __half2float(hh));
    hh = __float2half(vv0);
    Vh[qkrow*DVV + d] = hh; Vl[qkrow*DVV + d] = __float2half(vv0 - __half2float(hh));

    if (d < 64) {
        const float* qrp = qcr  + (size_t)bt*3072 + 2048 + h*64;
        const float* krp = lat3 + (size_t)bt*3072 + 2048 + h*64;
        float qv, kv;
        if (d < 32) {
            float c = cs[d], s = sn[d];
            qv = qrp[d]*c - qrp[d+32]*s;
            kv = krp[d]*c - krp[d+32]*s;
        } else {
            int j = d - 32;
            float c = cs[j], s = sn[j];
            qv = qrp[j+32]*c + qrp[j]*s;
            kv = krp[j+32]*c + krp[j]*s;
        }
        Qh[qkrow*DQK + 128 + d] = __float2half(qv);
        hh = __float2half(kv);
        Kh[qkrow*DQK + 128 + d] = hh;
        Kl[qkrow*DQK + 128 + d] = __float2half(kv - __half2float(hh));
    }
}

// ---------------- fp16 2-chain fused dual attention, split-key warps -------
#define KSTR 200
#define VSTR 136
#define ATTN_SMEM ((64*KSTR + 2*64*KSTR*2 + 2*64*VSTR*2) * 2)

__global__ void __launch_bounds__(256, 1) attn_tc_kernel(
    const fp16* __restrict__ Qh,
    const fp16* __restrict__ Kh, const fp16* __restrict__ Kl,
    const fp16* __restrict__ Vh, const fp16* __restrict__ Vl,
    const float* __restrict__ alpha, fp16* __restrict__ mgh)
{
    extern __shared__ __align__(16) fp16 smem[];
    fp16* sQh = smem;
    fp16* sKh = sQh + 64*KSTR;
    fp16* sKl = sKh + 2*64*KSTR;
    fp16* sVh = sKl + 2*64*KSTR;
    fp16* sVl = sVh + 2*64*VSTR;

    int tid = threadIdx.x, lane = tid & 31, warp = tid >> 5;
    int rg = warp & 3;
    int ch = warp >> 2;
    int qt = blockIdx.x * 64;
    int bh = blockIdx.y;
    int b = bh >> 4, h = bh & 15;
    size_t base = (size_t)bh * TT;

    for (int i = tid; i < 64*24; i += 256) {
        int r = i / 24, c = (i % 24) * 8;
        size_t g = (base + qt + r) * DQK + c;
        cpa16(&sQh[r*KSTR + c], Qh + g);
    }
    for (int i = tid; i < 64*24; i += 256) {
        int r = i / 24, c = (i % 24) * 8;
        size_t g = (base + r) * DQK + c;
        cpa16(&sKh[r*KSTR + c], Kh + g);
        cpa16(&sKl[r*KSTR + c], Kl + g);
    }
    for (int i = tid; i < 64*16; i += 256) {
        int r = i / 16, c = (i % 16) * 8;
        size_t g = (base + r) * DVV + c;
        cpa16(&sVh[r*VSTR + c], Vh + g);
        cpa16(&sVl[r*VSTR + c], Vl + g);
    }
    CP_COMMIT;

    int q0 = qt + 16*rg + (lane >> 2);
    int q1 = q0 + 8;
    int winlo = ((qt >> 8) << 8) - HALFW;
    if (winlo < 0) winlo = 0;

    float ob[16][4], ow[16][4];
#pragma unroll
    for (int n = 0; n < 16; n++)
#pragma unroll
        for (int j = 0; j < 4; j++) { ob[n][j] = 0.f; ow[n][j] = 0.f; }
    float m0 = -1e30f, m1 = -1e30f;
    float lb0 = 0.f, lb1 = 0.f, lw0 = 0.f, lw1 = 0.f;

    for (int t = 0; t < 32; t++) {
        int kt = t * 64;

        CP_WAIT0;
        __syncthreads();
        if (t + 1 < 32) {
            int nb = (t + 1) & 1;
            int kn = kt + 64;
            for (int i = tid; i < 64*24; i += 256) {
                int r = i / 24, c = (i % 24) * 8;
                size_t g = (base + kn + r) * DQK + c;
                cpa16(&sKh[nb*64*KSTR + r*KSTR + c], Kh + g);
                cpa16(&sKl[nb*64*KSTR + r*KSTR + c], Kl + g);
            }
            for (int i = tid; i < 64*16; i += 256) {
                int r = i / 16, c = (i % 16) * 8;
                size_t g = (base + kn + r) * DVV + c;
                cpa16(&sVh[nb*64*VSTR + r*VSTR + c], Vh + g);
                cpa16(&sVl[nb*64*VSTR + r*VSTR + c], Vl + g);
            }
            CP_COMMIT;
        }

        const fp16* bKh = sKh + (t & 1) * 64 * KSTR;
        const fp16* bVh = sVh + (t & 1) * 64 * VSTR;

        bool diag    = (kt == qt);
        bool fullwin = (kt >= winlo) && (kt < qt);

        float sacc[4][4];
#pragma unroll
        for (int n = 0; n < 4; n++)
#pragma unroll
            for (int j = 0; j < 4; j++) sacc[n][j] = 0.f;

#pragma unroll
        for (int ks = 0; ks < 12; ks++) {
            uint32_t qhf[4];
            const fp16* ap = &sQh[(16*rg + (lane & 15))*KSTR + ks*16 + (lane >> 4)*8];
            ldsm_x4(qhf, ap);
#pragma unroll
            for (int np = 0; np < 2; np++) {
                int g2 = lane >> 3;
                int krow = ch*32 + np*16 + (g2 >> 1)*8 + (lane & 7);
                int kcol = ks*16 + (g2 & 1)*8;
                const fp16* bp = &bKh[krow*KSTR + kcol];
                uint32_t khf[4], klf[4];
                ldsm_x4(khf, bp);
                ldsm_x4(klf, bp + 2*64*KSTR);
                mma_fp16(sacc[2*np],   qhf, khf);
                mma_fp16(sacc[2*np+1], qhf, khf + 2);
                mma_fp16(sacc[2*np],   qhf, klf);
                mma_fp16(sacc[2*np+1], qhf, klf + 2);
            }
        }

        float tm0 = -1e30f, tm1 = -1e30f;
#pragma unroll
        for (int n = 0; n < 4; n++) {
            tm0 = fmaxf(tm0, fmaxf(sacc[n][0], sacc[n][1]));
            tm1 = fmaxf(tm1, fmaxf(sacc[n][2], sacc[n][3]));
        }
        tm0 *= RSCALE; tm1 *= RSCALE;
        tm0 = fmaxf(tm0, __shfl_xor_sync(0xffffffffu, tm0, 1));
        tm0 = fmaxf(tm0, __shfl_xor_sync(0xffffffffu, tm0, 2));
        tm1 = fmaxf(tm1, __shfl_xor_sync(0xffffffffu, tm1, 1));
        tm1 = fmaxf(tm1, __shfl_xor_sync(0xffffffffu, tm1, 2));
        float mn0 = fmaxf(m0, tm0), mn1 = fmaxf(m1, tm1);
        float c0 = __expf(m0 - mn0), c1 = __expf(m1 - mn1);
        m0 = mn0; m1 = mn1;
        lb0 *= c0; lb1 *= c1; lw0 *= c0; lw1 *= c1;
        if (c0 < 1.f || c1 < 1.f) {
#pragma unroll
            for (int n = 0; n < 16; n++) {
                ob[n][0] *= c0; ob[n][1] *= c0; ob[n][2] *= c1; ob[n][3] *= c1;
                ow[n][0] *= c0; ow[n][1] *= c0; ow[n][2] *= c1; ow[n][3] *= c1;
            }
        }

        float sb0 = 0.f, sb1 = 0.f, sw0 = 0.f, sw1 = 0.f;
#pragma unroll
        for (int n = 0; n < 4; n++) {
            float p0 = __expf(sacc[n][0]*RSCALE - mn0);
            float p1 = __expf(sacc[n][1]*RSCALE - mn0);
            float p2 = __expf(sacc[n][2]*RSCALE - mn1);
            float p3 = __expf(sacc[n][3]*RSCALE - mn1);
            sacc[n][0] = p0; sacc[n][1] = p1; sacc[n][2] = p2; sacc[n][3] = p3;
            sb0 += p0 + p1; sb1 += p2 + p3;
            if (diag) {
                int keyc = kt + ch*32 + 8*n + 2*(lane & 3);
                sw0 += ((keyc   <= q0) ? p0 : 0.f) + ((keyc+1 <= q0) ? p1 : 0.f);
                sw1 += ((keyc   <= q1) ? p2 : 0.f) + ((keyc+1 <= q1) ? p3 : 0.f);
            }
        }
        sb0 += __shfl_xor_sync(0xffffffffu, sb0, 1); sb0 += __shfl_xor_sync(0xffffffffu, sb0, 2);
        sb1 += __shfl_xor_sync(0xffffffffu, sb1, 1); sb1 += __shfl_xor_sync(0xffffffffu, sb1, 2);
        lb0 += sb0; lb1 += sb1;
        if (fullwin) { lw0 += sb0; lw1 += sb1; }
        if (diag) {
            sw0 += __shfl_xor_sync(0xffffffffu, sw0, 1); sw0 += __shfl_xor_sync(0xffffffffu, sw0, 2);
            sw1 += __shfl_xor_sync(0xffffffffu, sw1, 1); sw1 += __shfl_xor_sync(0xffffffffu, sw1, 2);
            lw0 += sw0; lw1 += sw1;
        }

#pragma unroll
        for (int j = 0; j < 2; j++) {
            fp16 h0 = __float2half(sacc[2*j][0]),   h1 = __float2half(sacc[2*j][1]);
            fp16 h2 = __float2half(sacc[2*j][2]),   h3 = __float2half(sacc[2*j][3]);
            fp16 h4 = __float2half(sacc[2*j+1][0]), h5 = __float2half(sacc[2*j+1][1]);
            fp16 h6 = __float2half(sacc[2*j+1][2]), h7 = __float2half(sacc[2*j+1][3]);
            uint32_t ph2[4] = { pkh(h0,h1), pkh(h2,h3), pkh(h4,h5), pkh(h6,h7) };

            if (diag) {
                fp16 z = __float2half(0.f);
                int kc = kt + ch*32 + 16*j + 2*(lane & 3);
                bool a0 = kc   <= q0, a1 = kc+1 <= q0;
                bool b0m = kc  <= q1, b1m = kc+1 <= q1;
                bool a2 = kc+8 <= q0, a3 = kc+9 <= q0;
                bool b2m = kc+8 <= q1, b3m = kc+9 <= q1;
                uint32_t wh[4], xh2[4];
                wh[0] = pkh(a0?h0:z, a1?h1:z);
                wh[1] = pkh(b0m?h2:z, b1m?h3:z);
                wh[2] = pkh(a2?h4:z, a3?h5:z);
                wh[3] = pkh(b2m?h6:z, b3m?h7:z);
                xh2[0] = pkh(a0?z:h0, a1?z:h1);
                xh2[1] = pkh(b0m?z:h2, b1m?z:h3);
                xh2[2] = pkh(a2?z:h4, a3?z:h5);
                xh2[3] = pkh(b2m?z:h6, b3m?z:h7);
#pragma unroll
                for (int np = 0; np < 8; np++) {
                    int g2 = lane >> 3;
                    int vrow = ch*32 + 16*j + (g2 & 1)*8 + (lane & 7);
                    int vcol = np*16 + (g2 >> 1)*8;
                    const fp16* vp = &bVh[vrow*VSTR + vcol];
                    uint32_t vhf[4], vlf[4];
                    ldsm_x4t(vhf, vp);
                    ldsm_x4t(vlf, vp + 2*64*VSTR);
                    mma_fp16(ow[2*np],   wh, vhf);
                    mma_fp16(ow[2*np+1], wh, vhf + 2);
                    mma_fp16(ob[2*np],   xh2, vhf);
                    mma_fp16(ob[2*np+1], xh2, vhf + 2);
                    mma_fp16(ow[2*np],   wh, vlf);
                    mma_fp16(ow[2*np+1], wh, vlf + 2);
                    mma_fp16(ob[2*np],   xh2, vlf);
                    mma_fp16(ob[2*np+1], xh2, vlf + 2);
                }
            } else if (fullwin) {
#pragma unroll
                for (int np = 0; np < 8; np++) {
                    int g2 = lane >> 3;
                    int vrow = ch*32 + 16*j + (g2 & 1)*8 + (lane & 7);
                    int vcol = np*16 + (g2 >> 1)*8;
                    const fp16* vp = &bVh[vrow*VSTR + vcol];
                    uint32_t vhf[4], vlf[4];
                    ldsm_x4t(vhf, vp);
                    ldsm_x4t(vlf, vp + 2*64*VSTR);
                    mma_fp16(ow[2*np],   ph2, vhf);
                    mma_fp16(ow[2*np+1], ph2, vhf + 2);
                    mma_fp16(ow[2*np],   ph2, vlf);
                    mma_fp16(ow[2*np+1], ph2, vlf + 2);
                }
            } else {
#pragma unroll
                for (int np = 0; np < 8; np++) {
                    int g2 = lane >> 3;
                    int vrow = ch*32 + 16*j + (g2 & 1)*8 + (lane & 7);
                    int vcol = np*16 + (g2 >> 1)*8;
                    const fp16* vp = &bVh[vrow*VSTR + vcol];
                    uint32_t vhf[4], vlf[4];
                    ldsm_x4t(vhf, vp);
                    ldsm_x4t(vlf, vp + 2*64*VSTR);
                    mma_fp16(ob[2*np],   ph2, vhf);
                    mma_fp16(ob[2*np+1], ph2, vhf + 2);
                    mma_fp16(ob[2*np],   ph2, vlf);
                    mma_fp16(ob[2*np+1], ph2, vlf + 2);
                }
            }
        }
    }

    // ---- split-key merge ----
    __syncthreads();
    float* msm = (float*)smem;
    float* slot = msm + ((size_t)rg * 32 + lane) * 134;
    if (ch == 1) {
        slot[0] = m0; slot[1] = m1;
        slot[2] = lb0; slot[3] = lb1;
        slot[4] = lw0; slot[5] = lw1;
#pragma unroll
        for (int n = 0; n < 16; n++)
#pragma unroll
            for (int j = 0; j < 4; j++) {
                slot[6  + n*4 + j] = ob[n][j];
                slot[70 + n*4 + j] = ow[n][j];
            }
    }
    __syncthreads();
    if (ch == 0) {
        float mB0 = slot[0], mB1 = slot[1];
        float lbB0 = slot[2], lbB1 = slot[3];
        float lwB0 = slot[4], lwB1 = slot[5];
        float M0 = fmaxf(m0, mB0), M1 = fmaxf(m1, mB1);
        float sA0 = __expf(m0 - M0), sB0 = __expf(mB0 - M0);
        float sA1 = __expf(m1 - M1), sB1 = __expf(mB1 - M1);
        lb0 = lb0*sA0 + lbB0*sB0;  lb1 = lb1*sA1 + lbB1*sB1;
        lw0 = lw0*sA0 + lwB0*sB0;  lw1 = lw1*sA1 + lwB1*sB1;
#pragma unroll
        for (int n = 0; n < 16; n++) {
            ob[n][0] = ob[n][0]*sA0 + slot[6 + n*4 + 0]*sB0;
            ob[n][1] = ob[n][1]*sA0 + slot[6 + n*4 + 1]*sB0;
            ob[n][2] = ob[n][2]*sA1 + slot[6 + n*4 + 2]*sB1;
            ob[n][3] = ob[n][3]*sA1 + slot[6 + n*4 + 3]*sB1;
            ow[n][0] = ow[n][0]*sA0 + slot[70 + n*4 + 0]*sB0;
            ow[n][1] = ow[n][1]*sA0 + slot[70 + n*4 + 1]*sB0;
            ow[n][2] = ow[n][2]*sA1 + slot[70 + n*4 + 2]*sB1;
            ow[n][3] = ow[n][3]*sA1 + slot[70 + n*4 + 3]*sB1;
        }

        float a0 = alpha[(size_t)b*TT + q0];
        float a1 = alpha[(size_t)b*TT + q1];
        float ilb0 = 1.f/lb0, ilb1 = 1.f/lb1, ilw0 = 1.f/lw0, ilw1 = 1.f/lw1;
        size_t r0o = ((size_t)b*TT + q0)*2048 + (size_t)h*128;
        size_t r1o = ((size_t)b*TT + q1)*2048 + (size_t)h*128;
#pragma unroll
        for (int n = 0; n < 16; n++) {
            int d = 8*n + 2*(lane & 3);
            float b00 = ob[n][0] + ow[n][0], b01 = ob[n][1] + ow[n][1];
            float b10 = ob[n][2] + ow[n][2], b11 = ob[n][3] + ow[n][3];
            float o00 = a0*b00*ilb0 + (1.f-a0)*ow[n][0]*ilw0;
            float o01 = a0*b01*ilb0 + (1.f-a0)*ow[n][1]*ilw0;
            float o10 = a1*b10*ilb1 + (1.f-a1)*ow[n][2]*ilw1;
            float o11 = a1*b11*ilb1 + (1.f-a1)*ow[n][3]*ilw1;
            *(uint32_t*)(mgh + r0o + d) = pkh(__float2half(o00), __float2half(o01));
            *(uint32_t*)(mgh + r1o + d) = pkh(__float2half(o10), __float2half(o11));
        }
    }
}

// ---------------- launcher ----------------
extern "C" void kernel_launch(void* const* d_in, const int* in_sizes, int n_in,
                              void* d_out, int out_size)
{
    (void)in_sizes; (void)n_in;
    const float* x        = (const float*)d_in[0];
    const float* unc      = (const float*)d_in[1];
    const float* Wq_down  = (const float*)d_in[2];
    const float* q_norm_w = (const float*)d_in[3];
    const float* Wq_up    = (const float*)d_in[4];
    const float* Wq_rope  = (const float*)d_in[5];
    const float* Wkv_down = (const float*)d_in[6];
    const float* kv_norm_w= (const float*)d_in[7];
    const float* Wk_up    = (const float*)d_in[8];
    const float* Wv_up    = (const float*)d_in[9];
    const float* Wk_rope  = (const float*)d_in[10];
    const float* Wout     = (const float*)d_in[11];
    const float* Wgate    = (const float*)d_in[12];
    const float* bgate    = (const float*)d_in[13];
    float* out = (float*)d_out;

    float *lat3, *qcr, *kcv, *al;
    fp16 *Qh,*Kh,*Kl,*Vh,*Vl;
    fp16 *xh,*qlh,*kvh,*mgh;
    fp16 *wdnh,*wdnl,*wquph,*wqupl,*wkvuh,*wkvul,*woh;
    cudaGetSymbolAddress((void**)&lat3,  g_lat3);
    cudaGetSymbolAddress((void**)&qcr,   g_qcr);
    cudaGetSymbolAddress((void**)&kcv,   g_kcv);
    cudaGetSymbolAddress((void**)&al,    g_alpha);
    cudaGetSymbolAddress((void**)&Qh,    g_Qh);
    cudaGetSymbolAddress((void**)&Kh,    g_Kh);
    cudaGetSymbolAddress((void**)&Kl,    g_Kl);
    cudaGetSymbolAddress((void**)&Vh,    g_Vh);
    cudaGetSymbolAddress((void**)&Vl,    g_Vl);
    cudaGetSymbolAddress((void**)&xh,    g_xh);
    cudaGetSymbolAddress((void**)&qlh,   g_qlh);
    cudaGetSymbolAddress((void**)&kvh,   g_kvh);
    cudaGetSymbolAddress((void**)&mgh,   g_mgh);
    cudaGetSymbolAddress((void**)&wdnh,  g_wdn_h);
    cudaGetSymbolAddress((void**)&wdnl,  g_wdn_l);
    cudaGetSymbolAddress((void**)&wquph, g_wqup_h);
    cudaGetSymbolAddress((void**)&wqupl, g_wqup_l);
    cudaGetSymbolAddress((void**)&wkvuh, g_wkvu_h);
    cudaGetSymbolAddress((void**)&wkvul, g_wkvu_l);
    cudaGetSymbolAddress((void**)&woh,   g_wo_h);

    cudaFuncSetAttribute(attn_tc_kernel,
                         cudaFuncAttributeMaxDynamicSharedMemorySize, ATTN_SMEM);
    cudaFuncSetAttribute(gemm_split,
                         cudaFuncAttributeMaxDynamicSharedMemorySize, GS_SMEM);
    cudaFuncSetAttribute(gemm_up2,
                         cudaFuncAttributeMaxDynamicSharedMemorySize, GS_SMEM);
    cudaFuncSetAttribute(gemm_out_hi,
                         cudaFuncAttributeMaxDynamicSharedMemorySize, GS_SMEM);

    // 0: split input activations (hi only)
    split_hi_kernel<<<(BT*DD)/1024, 256>>>(x, xh, BT*DD);
    // 1: all weight preprocessing fused
    prep_weights_kernel<<<(PW_T3 + 1023)/1024, 256>>>(
        Wq_down, Wkv_down, Wk_rope, wdnh, wdnl,
        Wq_up, Wq_rope, wquph, wqupl,
        Wk_up, Wv_up, wkvuh, wkvul,
        Wout, woh);
    // 2: gate
    float* out_alpha = (out_size >= BB*TT*DD + BB*TT) ? (out + (size_t)BB*TT*DD)
                                                      : nullptr;
    alpha_kernel<<<BT, 256>>>(x, Wgate, bgate, al, out_alpha);
    // 3 (ncu slot): merged down-projection GEMM
    gemm_split<<<dim3(3072/128, BT/128), 256, GS_SMEM>>>(
        xh, wdnh, wdnl, lat3, BT, 3072, DD);
    // 4-5: norms
    rmsnorm_hi_kernel<<<BT, 256>>>(lat3, 3072, 0,   q_norm_w,  qlh, CQQ);
    rmsnorm_hi_kernel<<<BT, 256>>>(lat3, 3072, CQQ, kv_norm_w, kvh, CKVV);
    // 6: merged up-projections
    gemm_up2<<<768 + 1024, 256, GS_SMEM>>>(
        qlh, wquph, wqupl, qcr,
        kvh, wkvuh, wkvul, kcv);
    // 7: assemble Q/K/V
    assemble_kernel<<<BT*NHH, 128>>>(qcr, kcv, lat3, unc,
                                     Qh, Kh, Kl, Vh, Vl);
    // 8: attention
    attn_tc_kernel<<<dim3(TT/64, BB*NHH), 256, ATTN_SMEM>>>(
        Qh, Kh, Kl, Vh, Vl, al, mgh);
    // 9: output projection (single-chain: Wout hi only)
    gemm_out_hi<<<dim3(DD/128, BT/128), 256, GS_SMEM>>>(
        mgh, woh, out, BT, DD, 2048);
}

// round 16
// speedup vs baseline: 2.2400x; 1.2009x over previous
#include <cuda_runtime.h>
#include <cuda_fp16.h>
#include <math.h>
#include <stdint.h>

// ---------------- problem constants ----------------
#define BB   2
#define TT   2048
#define DD   2048
#define NHH  16
#define HDD  128
#define RR   64
#define CQQ  1536
#define CKVV 512
#define BT   (BB*TT)       // 4096
#define DQK  192           // HD + R
#define DVV  128
#define HALFW 256          // WINDOW/2
#define RSCALE 0.07216878364870323f  // 1/sqrt(192)

typedef __half fp16;

// ---------------- scratch (device globals; no runtime alloc) ----------------
__device__ float g_lat3 [(size_t)BT*3072];
__device__ float g_qcr  [(size_t)BT*3072];
__device__ float g_kcv  [(size_t)BT*4096];
__device__ float g_alpha[BT];

__device__ fp16 g_Qh[(size_t)BB*NHH*TT*DQK];
__device__ fp16 g_Kh[(size_t)BB*NHH*TT*DQK];
__device__ fp16 g_Vh[(size_t)BB*NHH*TT*DVV];

__device__ fp16 g_xh [(size_t)BT*DD];
__device__ fp16 g_qlh[(size_t)BT*CQQ];
__device__ fp16 g_kvh[(size_t)BT*CKVV];
__device__ fp16 g_mgh[(size_t)BT*NHH*HDD];
__device__ fp16 g_wdn_h [(size_t)DD*3072],   g_wdn_l [(size_t)DD*3072];
__device__ fp16 g_wqup_h[(size_t)CQQ*3072],  g_wqup_l[(size_t)CQQ*3072];
__device__ fp16 g_wkvu_h[(size_t)CKVV*4096], g_wkvu_l[(size_t)CKVV*4096];
__device__ fp16 g_wo_h  [(size_t)2048*DD];

// ---------------- ptx helpers ----------------
__device__ __forceinline__ uint32_t smem_u32(const void* p) {
    return (uint32_t)__cvta_generic_to_shared(p);
}
__device__ __forceinline__ void ldsm_x4(uint32_t* r, const void* p) {
    uint32_t a = smem_u32(p);
    asm volatile("ldmatrix.sync.aligned.m8n8.x4.shared.b16 {%0,%1,%2,%3}, [%4];"
                 : "=r"(r[0]), "=r"(r[1]), "=r"(r[2]), "=r"(r[3]) : "r"(a));
}
__device__ __forceinline__ void ldsm_x4t(uint32_t* r, const void* p) {
    uint32_t a = smem_u32(p);
    asm volatile("ldmatrix.sync.aligned.m8n8.x4.trans.shared.b16 {%0,%1,%2,%3}, [%4];"
                 : "=r"(r[0]), "=r"(r[1]), "=r"(r[2]), "=r"(r[3]) : "r"(a));
}
__device__ __forceinline__ void mma_fp16(float* c, const uint32_t* a,
                                         const uint32_t* b) {
    asm volatile(
        "mma.sync.aligned.m16n8k16.row.col.f32.f16.f16.f32 "
        "{%0,%1,%2,%3}, {%4,%5,%6,%7}, {%8,%9}, {%0,%1,%2,%3};"
        : "+f"(c[0]), "+f"(c[1]), "+f"(c[2]), "+f"(c[3])
        : "r"(a[0]), "r"(a[1]), "r"(a[2]), "r"(a[3]), "r"(b[0]), "r"(b[1]));
}
__device__ __forceinline__ void cpa16(void* s, const void* g) {
    asm volatile("cp.async.cg.shared.global [%0], [%1], 16;"
                 :: "r"(smem_u32(s)), "l"(g));
}
#define CP_COMMIT asm volatile("cp.async.commit_group;")
#define CP_WAIT0  asm volatile("cp.async.wait_group 0;")

__device__ __forceinline__ uint32_t pkh(fp16 a, fp16 b) {
    __half2 t = __halves2half2(a, b);
    return *reinterpret_cast<uint32_t*>(&t);
}

// ---------------- split helpers ----------------
__device__ __forceinline__ void store_hi4(float4 v, fp16* h, int i) {
    *(__half2*)(h + i)     = __halves2half2(__float2half(v.x), __float2half(v.y));
    *(__half2*)(h + i + 2) = __halves2half2(__float2half(v.z), __float2half(v.w));
}
__device__ __forceinline__ void store_split4(float4 v, fp16* h, fp16* l, int i) {
    fp16 h0 = __float2half(v.x), h1 = __float2half(v.y);
    fp16 h2 = __float2half(v.z), h3 = __float2half(v.w);
    *(__half2*)(h + i)     = __halves2half2(h0, h1);
    *(__half2*)(h + i + 2) = __halves2half2(h2, h3);
    *(__half2*)(l + i) = __halves2half2(
        __float2half(v.x - __half2float(h0)),
        __float2half(v.y - __half2float(h1)));
    *(__half2*)(l + i + 2) = __halves2half2(
        __float2half(v.z - __half2float(h2)),
        __float2half(v.w - __half2float(h3)));
}

// ---------------- split input activations (hi only) ----------------
__global__ __launch_bounds__(256) void split_hi_kernel(
    const float* __restrict__ s, fp16* __restrict__ h, int n)
{
    int i = (blockIdx.x * 256 + threadIdx.x) * 4;
    if (i >= n) return;
    store_hi4(*(const float4*)(s + i), h, i);
}

// ---------------- fused weight prep ----------------
#define PW_T0 (DD*3072)
#define PW_T1 (PW_T0 + CQQ*3072)
#define PW_T2 (PW_T1 + CKVV*4096)
#define PW_T3 (PW_T2 + 2048*DD)

__global__ __launch_bounds__(256) void prep_weights_kernel(
    const float* __restrict__ Wq_down, const float* __restrict__ Wkv_down,
    const float* __restrict__ Wk_rope,
    fp16* __restrict__ wdnh, fp16* __restrict__ wdnl,
    const float* __restrict__ Wq_up, const float* __restrict__ Wq_rope,
    fp16* __restrict__ wquph, fp16* __restrict__ wqupl,
    const float* __restrict__ Wk_up, const float* __restrict__ Wv_up,
    fp16* __restrict__ wkvuh, fp16* __restrict__ wkvul,
    const float* __restrict__ Wout, fp16* __restrict__ woh)
{
    int gi = (blockIdx.x * 256 + threadIdx.x) * 4;
    if (gi >= PW_T3) return;
    if (gi < PW_T0) {
        int i = gi;
        int k = i / 3072, n = i % 3072;
        const float* src;
        if (n < CQQ)             src = Wq_down  + (size_t)k * CQQ  + n;
        else if (n < CQQ + CKVV) src = Wkv_down + (size_t)k * CKVV + (n - CQQ);
        else                     src = Wk_rope  + (size_t)k * 1024 + (n - CQQ - CKVV);
        store_split4(*(const float4*)src, wdnh, wdnl, i);
    } else if (gi < PW_T1) {
        int i = gi - PW_T0;
        int k = i / 3072, n = i % 3072;
        const float* src = (n < 2048) ? (Wq_up + (size_t)k * 2048 + n)
                                      : (Wq_rope + (size_t)k * 1024 + (n - 2048));
        store_split4(*(const float4*)src, wquph, wqupl, i);
    } else if (gi < PW_T2) {
        int i = gi - PW_T1;
        int k = i / 4096, n = i % 4096;
        const float* src = (n < 2048) ? (Wk_up + (size_t)k * 2048 + n)
                                      : (Wv_up + (size_t)k * 2048 + (n - 2048));
        store_split4(*(const float4*)src, wkvuh, wkvul, i);
    } else {
        int i = gi - PW_T2;
        store_hi4(*(const float4*)(Wout + i), woh, i);
    }
}

// ---------------- fp16 TC GEMM core (A hi-only; B hi [+ optional lo]) ------
#define GS_A   (128*40)
#define GS_B   (32*136)
#define GS_STG (GS_A + 2*GS_B)
#define GS_SMEM (2*GS_STG*2)

template<bool USE_LO>
__device__ __forceinline__ void gemm_core(
    const fp16* __restrict__ Ah,
    const fp16* __restrict__ Bh, const fp16* __restrict__ Bl,
    float* __restrict__ C, int N, int K, int bm, int bn, fp16* gsm)
{
    int tid = threadIdx.x;
    int warp = tid >> 5, lane = tid & 31;
    int wm = warp >> 2, wn = warp & 3;
    int g2 = lane >> 3;

    int arow = tid >> 2, ac = (tid & 3) * 8;
    int brow = tid >> 4, bc = (tid & 15) * 8;

    float acc[4][4][4];
#pragma unroll
    for (int a = 0; a < 4; a++)
#pragma unroll
        for (int b = 0; b < 4; b++)
#pragma unroll
            for (int c = 0; c < 4; c++) acc[a][b][c] = 0.f;

    int nk = K >> 5;

    auto issue = [&](int stage, int k0) {
        fp16* sA  = gsm + stage * GS_STG;
        fp16* sBh = sA + GS_A;
        fp16* sBl = sBh + GS_B;
#pragma unroll
        for (int i = 0; i < 2; i++) {
            int r = arow + i * 64;
            size_t g = (size_t)(bm * 128 + r) * K + k0 + ac;
            cpa16(&sA[r * 40 + ac], Ah + g);
        }
#pragma unroll
        for (int i = 0; i < 2; i++) {
            int r = brow + i * 16;
            size_t g = (size_t)(k0 + r) * N + bn * 128 + bc;
            cpa16(&sBh[r * 136 + bc], Bh + g);
            if (USE_LO) cpa16(&sBl[r * 136 + bc], Bl + g);
        }
    };

    issue(0, 0);
    CP_COMMIT;

    for (int it = 0; it < nk; it++) {
        CP_WAIT0;
        __syncthreads();
        if (it + 1 < nk) {
            issue((it + 1) & 1, (it + 1) << 5);
            CP_COMMIT;
        }

        fp16* sA  = gsm + (it & 1) * GS_STG;
        fp16* sBh = sA + GS_A;

#pragma unroll
        for (int kh = 0; kh < 2; kh++) {
            uint32_t bh4[2][4], bl4[2][4];
#pragma unroll
            for (int nt2 = 0; nt2 < 2; nt2++) {
                int br = kh * 16 + (g2 & 1) * 8 + (lane & 7);
                int bcl = wn * 32 + nt2 * 16 + (g2 >> 1) * 8;
                const fp16* bp = &sBh[br * 136 + bcl];
                ldsm_x4t(bh4[nt2], bp);
                if (USE_LO) ldsm_x4t(bl4[nt2], bp + GS_B);
            }
#pragma unroll
            for (int mt = 0; mt < 4; mt++) {
                int ar = wm * 64 + mt * 16 + (lane & 15);
                int acl = kh * 16 + (lane >> 4) * 8;
                uint32_t ah[4];
                ldsm_x4(ah, &sA[ar * 40 + acl]);
#pragma unroll
                for (int nt2 = 0; nt2 < 2; nt2++) {
                    mma_fp16(acc[mt][2*nt2],   ah, bh4[nt2]);
                    mma_fp16(acc[mt][2*nt2+1], ah, bh4[nt2] + 2);
                }
                if (USE_LO) {
#pragma unroll
                    for (int nt2 = 0; nt2 < 2; nt2++) {
                        mma_fp16(acc[mt][2*nt2],   ah, bl4[nt2]);
                        mma_fp16(acc[mt][2*nt2+1], ah, bl4[nt2] + 2);
                    }
                }
            }
        }
    }

#pragma unroll
    for (int mt = 0; mt < 4; mt++) {
#pragma unroll
        for (int nt = 0; nt < 4; nt++) {
            int r0 = bm * 128 + wm * 64 + mt * 16 + (lane >> 2);
            int c0 = bn * 128 + wn * 32 + nt * 8 + (lane & 3) * 2;
            *(float2*)&C[(size_t)r0 * N + c0] =
                make_float2(acc[mt][nt][0], acc[mt][nt][1]);
            *(float2*)&C[(size_t)(r0 + 8) * N + c0] =
                make_float2(acc[mt][nt][2], acc[mt][nt][3]);
        }
    }
}

__global__ __launch_bounds__(256) void gemm_split(
    const fp16* __restrict__ Ah,
    const fp16* __restrict__ Bh, const fp16* __restrict__ Bl,
    float* __restrict__ C, int M, int N, int K)
{
    extern __shared__ __align__(16) fp16 gsm[];
    gemm_core<true>(Ah, Bh, Bl, C, N, K, blockIdx.y, blockIdx.x, gsm);
}

__global__ __launch_bounds__(256) void gemm_out_hi(
    const fp16* __restrict__ Ah, const fp16* __restrict__ Bh,
    float* __restrict__ C, int M, int N, int K)
{
    extern __shared__ __align__(16) fp16 gsm[];
    gemm_core<false>(Ah, Bh, nullptr, C, N, K, blockIdx.y, blockIdx.x, gsm);
}

__global__ __launch_bounds__(256) void gemm_up2(
    const fp16* __restrict__ qlh,
    const fp16* __restrict__ wquph, const fp16* __restrict__ wqupl,
    float* __restrict__ qcr,
    const fp16* __restrict__ kvh,
    const fp16* __restrict__ wkvuh, const fp16* __restrict__ wkvul,
    float* __restrict__ kcv)
{
    extern __shared__ __align__(16) fp16 gsm[];
    int idx = blockIdx.x;
    if (idx < 768) {
        gemm_core<true>(qlh, wquph, wqupl, qcr, 3072, CQQ, idx / 24, idx % 24, gsm);
    } else {
        idx -= 768;
        gemm_core<true>(kvh, wkvuh, wkvul, kcv, 4096, CKVV, idx / 32, idx % 32, gsm);
    }
}

// ---------------- RMSNorm slice -> fp16 hi-only outputs ----------------
__global__ __launch_bounds__(256) void rmsnorm_hi_kernel(
    const float* __restrict__ x, int rowstride, int off,
    const float* __restrict__ w, fp16* __restrict__ hi, int n)
{
    const float* row = x + (size_t)blockIdx.x * rowstride + off;
    float ss = 0.f;
    for (int i = threadIdx.x; i < n; i += 256) { float v = row[i]; ss += v*v; }
    __shared__ float sh[8];
    __shared__ float tot;
    int lane = threadIdx.x & 31, wp = threadIdx.x >> 5;
#pragma unroll
    for (int o = 16; o; o >>= 1) ss += __shfl_xor_sync(0xffffffffu, ss, o);
    if (lane == 0) sh[wp] = ss;
    __syncthreads();
    if (threadIdx.x == 0) {
        float s = 0.f;
        for (int i = 0; i < 8; i++) s += sh[i];
        tot = rsqrtf(s / n + 1e-6f);
    }
    __syncthreads();
    float rs = tot;
    fp16* hrow = hi + (size_t)blockIdx.x * n;
    for (int i = threadIdx.x; i < n; i += 256)
        hrow[i] = __float2half(row[i] * rs * w[i]);
}

// ---------------- gate alpha ----------------
__global__ __launch_bounds__(256) void alpha_kernel(
    const float* __restrict__ x, const float* __restrict__ wg,
    const float* __restrict__ bg, float* __restrict__ alpha,
    float* __restrict__ out_alpha)
{
    const float* row = x + (size_t)blockIdx.x * DD;
    float s = 0.f;
    for (int i = threadIdx.x; i < DD; i += 256) s += row[i] * wg[i];
    __shared__ float sh[8];
    int lane = threadIdx.x & 31, wp = threadIdx.x >> 5;
#pragma unroll
    for (int o = 16; o; o >>= 1) s += __shfl_xor_sync(0xffffffffu, s, o);
    if (lane == 0) sh[wp] = s;
    __syncthreads();
    if (threadIdx.x == 0) {
        float t = 0.f;
        for (int i = 0; i < 8; i++) t += sh[i];
        float z = t + bg[0];
        float a = 1.f / (1.f + expf(-z));
        alpha[blockIdx.x] = a;
        if (out_alpha) out_alpha[blockIdx.x] = a;
    }
}

// ---------------- assemble Q/K/V with EPE-RoPE (fp16 hi only) --------------
__global__ __launch_bounds__(128) void assemble_kernel(
    const float* __restrict__ qcr, const float* __restrict__ kcv,
    const float* __restrict__ lat3, const float* __restrict__ unc,
    fp16* __restrict__ Qh, fp16* __restrict__ Kh, fp16* __restrict__ Vh)
{
    int idx = blockIdx.x;
    int h  = idx % NHH;
    int bt = idx / NHH;
    int t  = bt % TT;
    int b  = bt / TT;
    __shared__ float cs[32], sn[32];
    int d = threadIdx.x;
    if (d < 32) {
        float u = unc[bt];
        u = fminf(fmaxf(u, 0.f), 1.f);
        float scale = 0.5f + 1.5f * u;
        float fi = (float)d / 32.0f;
        float theta = expf(-fi * logf(500000.0f));
        float fr = (float)t * theta * scale;
        cs[d] = cosf(fr);
        sn[d] = sinf(fr);
    }
    __syncthreads();
    size_t qkrow = ((size_t)(b*NHH + h))*TT + t;

    Qh[qkrow*DQK + d] = __float2half(qcr[(size_t)bt*3072 + h*128 + d]);
    Kh[qkrow*DQK + d] = __float2half(kcv[(size_t)bt*4096 + h*128 + d]);
    Vh[qkrow*DVV + d] = __float2half(kcv[(size_t)bt*4096 + 2048 + h*128 + d]);

    if (d < 64) {
        const float* qrp = qcr  + (size_t)bt*3072 + 2048 + h*64;
        const float* krp = lat3 + (size_t)bt*3072 + 2048 + h*64;
        float qv, kv;
        if (d < 32) {
            float c = cs[d], s = sn[d];
            qv = qrp[d]*c - qrp[d+32]*s;
            kv = krp[d]*c - krp[d+32]*s;
        } else {
            int j = d - 32;
            float c = cs[j], s = sn[j];
            qv = qrp[j+32]*c + qrp[j]*s;
            kv = krp[j+32]*c + krp[j]*s;
        }
        Qh[qkrow*DQK + 128 + d] = __float2half(qv);
        Kh[qkrow*DQK + 128 + d] = __float2half(kv);
    }
}

// ---------------- fp16 single-chain fused dual attention, split-key warps --
#define KSTR 200
#define VSTR 136
#define ATTN_SMEM ((64*KSTR + 2*64*KSTR + 2*64*VSTR) * 2)

__global__ void __launch_bounds__(256, 1) attn_tc_kernel(
    const fp16* __restrict__ Qh,
    const fp16* __restrict__ Kh, const fp16* __restrict__ Vh,
    const float* __restrict__ alpha, fp16* __restrict__ mgh)
{
    extern __shared__ __align__(16) fp16 smem[];
    fp16* sQh = smem;
    fp16* sKh = sQh + 64*KSTR;
    fp16* sVh = sKh + 2*64*KSTR;

    int tid = threadIdx.x, lane = tid & 31, warp = tid >> 5;
    int rg = warp & 3;
    int ch = warp >> 2;
    int qt = blockIdx.x * 64;
    int bh = blockIdx.y;
    int b = bh >> 4, h = bh & 15;
    size_t base = (size_t)bh * TT;

    for (int i = tid; i < 64*24; i += 256) {
        int r = i / 24, c = (i % 24) * 8;
        size_t g = (base + qt + r) * DQK + c;
        cpa16(&sQh[r*KSTR + c], Qh + g);
    }
    for (int i = tid; i < 64*24; i += 256) {
        int r = i / 24, c = (i % 24) * 8;
        size_t g = (base + r) * DQK + c;
        cpa16(&sKh[r*KSTR + c], Kh + g);
    }
    for (int i = tid; i < 64*16; i += 256) {
        int r = i / 16, c = (i % 16) * 8;
        size_t g = (base + r) * DVV + c;
        cpa16(&sVh[r*VSTR + c], Vh + g);
    }
    CP_COMMIT;

    int q0 = qt + 16*rg + (lane >> 2);
    int q1 = q0 + 8;
    int winlo = ((qt >> 8) << 8) - HALFW;
    if (winlo < 0) winlo = 0;

    float ob[16][4], ow[16][4];
#pragma unroll
    for (int n = 0; n < 16; n++)
#pragma unroll
        for (int j = 0; j < 4; j++) { ob[n][j] = 0.f; ow[n][j] = 0.f; }
    float m0 = -1e30f, m1 = -1e30f;
    float lb0 = 0.f, lb1 = 0.f, lw0 = 0.f, lw1 = 0.f;

    for (int t = 0; t < 32; t++) {
        int kt = t * 64;

        CP_WAIT0;
        __syncthreads();
        if (t + 1 < 32) {
            int nb = (t + 1) & 1;
            int kn = kt + 64;
            for (int i = tid; i < 64*24; i += 256) {
                int r = i / 24, c = (i % 24) * 8;
                size_t g = (base + kn + r) * DQK + c;
                cpa16(&sKh[nb*64*KSTR + r*KSTR + c], Kh + g);
            }
            for (int i = tid; i < 64*16; i += 256) {
                int r = i / 16, c = (i % 16) * 8;
                size_t g = (base + kn + r) * DVV + c;
                cpa16(&sVh[nb*64*VSTR + r*VSTR + c], Vh + g);
            }
            CP_COMMIT;
        }

        const fp16* bKh = sKh + (t & 1) * 64 * KSTR;
        const fp16* bVh = sVh + (t & 1) * 64 * VSTR;

        bool diag    = (kt == qt);
        bool fullwin = (kt >= winlo) && (kt < qt);

        float sacc[4][4];
#pragma unroll
        for (int n = 0; n < 4; n++)
#pragma unroll
            for (int j = 0; j < 4; j++) sacc[n][j] = 0.f;

#pragma unroll
        for (int ks = 0; ks < 12; ks++) {
            uint32_t qhf[4];
            const fp16* ap = &sQh[(16*rg + (lane & 15))*KSTR + ks*16 + (lane >> 4)*8];
            ldsm_x4(qhf, ap);
#pragma unroll
            for (int np = 0; np < 2; np++) {
                int g2 = lane >> 3;
                int krow = ch*32 + np*16 + (g2 >> 1)*8 + (lane & 7);
                int kcol = ks*16 + (g2 & 1)*8;
                const fp16* bp = &bKh[krow*KSTR + kcol];
                uint32_t khf[4];
                ldsm_x4(khf, bp);
                mma_fp16(sacc[2*np],   qhf, khf);
                mma_fp16(sacc[2*np+1], qhf, khf + 2);
            }
        }

        float tm0 = -1e30f, tm1 = -1e30f;
#pragma unroll
        for (int n = 0; n < 4; n++) {
            tm0 = fmaxf(tm0, fmaxf(sacc[n][0], sacc[n][1]));
            tm1 = fmaxf(tm1, fmaxf(sacc[n][2], sacc[n][3]));
        }
        tm0 *= RSCALE; tm1 *= RSCALE;
        tm0 = fmaxf(tm0, __shfl_xor_sync(0xffffffffu, tm0, 1));
        tm0 = fmaxf(tm0, __shfl_xor_sync(0xffffffffu, tm0, 2));
        tm1 = fmaxf(tm1, __shfl_xor_sync(0xffffffffu, tm1, 1));
        tm1 = fmaxf(tm1, __shfl_xor_sync(0xffffffffu, tm1, 2));
        float mn0 = fmaxf(m0, tm0), mn1 = fmaxf(m1, tm1);
        float c0 = __expf(m0 - mn0), c1 = __expf(m1 - mn1);
        m0 = mn0; m1 = mn1;
        lb0 *= c0; lb1 *= c1; lw0 *= c0; lw1 *= c1;
        if (c0 < 1.f || c1 < 1.f) {
#pragma unroll
            for (int n = 0; n < 16; n++) {
                ob[n][0] *= c0; ob[n][1] *= c0; ob[n][2] *= c1; ob[n][3] *= c1;
                ow[n][0] *= c0; ow[n][1] *= c0; ow[n][2] *= c1; ow[n][3] *= c1;
            }
        }

        float sb0 = 0.f, sb1 = 0.f, sw0 = 0.f, sw1 = 0.f;
#pragma unroll
        for (int n = 0; n < 4; n++) {
            float p0 = __expf(sacc[n][0]*RSCALE - mn0);
            float p1 = __expf(sacc[n][1]*RSCALE - mn0);
            float p2 = __expf(sacc[n][2]*RSCALE - mn1);
            float p3 = __expf(sacc[n][3]*RSCALE - mn1);
            sacc[n][0] = p0; sacc[n][1] = p1; sacc[n][2] = p2; sacc[n][3] = p3;
            sb0 += p0 + p1; sb1 += p2 + p3;
            if (diag) {
                int keyc = kt + ch*32 + 8*n + 2*(lane & 3);
                sw0 += ((keyc   <= q0) ? p0 : 0.f) + ((keyc+1 <= q0) ? p1 : 0.f);
                sw1 += ((keyc   <= q1) ? p2 : 0.f) + ((keyc+1 <= q1) ? p3 : 0.f);
            }
        }
        sb0 += __shfl_xor_sync(0xffffffffu, sb0, 1); sb0 += __shfl_xor_sync(0xffffffffu, sb0, 2);
        sb1 += __shfl_xor_sync(0xffffffffu, sb1, 1); sb1 += __shfl_xor_sync(0xffffffffu, sb1, 2);
        lb0 += sb0; lb1 += sb1;
        if (fullwin) { lw0 += sb0; lw1 += sb1; }
        if (diag) {
            sw0 += __shfl_xor_sync(0xffffffffu, sw0, 1); sw0 += __shfl_xor_sync(0xffffffffu, sw0, 2);
            sw1 += __shfl_xor_sync(0xffffffffu, sw1, 1); sw1 += __shfl_xor_sync(0xffffffffu, sw1, 2);
            lw0 += sw0; lw1 += sw1;
        }

#pragma unroll
        for (int j = 0; j < 2; j++) {
            fp16 h0 = __float2half(sacc[2*j][0]),   h1 = __float2half(sacc[2*j][1]);
            fp16 h2 = __float2half(sacc[2*j][2]),   h3 = __float2half(sacc[2*j][3]);
            fp16 h4 = __float2half(sacc[2*j+1][0]), h5 = __float2half(sacc[2*j+1][1]);
            fp16 h6 = __float2half(sacc[2*j+1][2]), h7 = __float2half(sacc[2*j+1][3]);
            uint32_t ph2[4] = { pkh(h0,h1), pkh(h2,h3), pkh(h4,h5), pkh(h6,h7) };

            if (diag) {
                fp16 z = __float2half(0.f);
                int kc = kt + ch*32 + 16*j + 2*(lane & 3);
                bool a0 = kc   <= q0, a1 = kc+1 <= q0;
                bool b0m = kc  <= q1, b1m = kc+1 <= q1;
                bool a2 = kc+8 <= q0, a3 = kc+9 <= q0;
                bool b2m = kc+8 <= q1, b3m = kc+9 <= q1;
                uint32_t wh[4], xh2[4];
                wh[0] = pkh(a0?h0:z, a1?h1:z);
                wh[1] = pkh(b0m?h2:z, b1m?h3:z);
                wh[2] = pkh(a2?h4:z, a3?h5:z);
                wh[3] = pkh(b2m?h6:z, b3m?h7:z);
                xh2[0] = pkh(a0?z:h0, a1?z:h1);
                xh2[1] = pkh(b0m?z:h2, b1m?z:h3);
                xh2[2] = pkh(a2?z:h4, a3?z:h5);
                xh2[3] = pkh(b2m?z:h6, b3m?z:h7);
#pragma unroll
                for (int np = 0; np < 8; np++) {
                    int g2 = lane >> 3;
                    int vrow = ch*32 + 16*j + (g2 & 1)*8 + (lane & 7);
                    int vcol = np*16 + (g2 >> 1)*8;
                    const fp16* vp = &bVh[vrow*VSTR + vcol];
                    uint32_t vhf[4];
                    ldsm_x4t(vhf, vp);
                    mma_fp16(ow[2*np],   wh, vhf);
                    mma_fp16(ow[2*np+1], wh, vhf + 2);
                    mma_fp16(ob[2*np],   xh2, vhf);
                    mma_fp16(ob[2*np+1], xh2, vhf + 2);
                }
            } else if (fullwin) {
#pragma unroll
                for (int np = 0; np < 8; np++) {
                    int g2 = lane >> 3;
                    int vrow = ch*32 + 16*j + (g2 & 1)*8 + (lane & 7);
                    int vcol = np*16 + (g2 >> 1)*8;
                    const fp16* vp = &bVh[vrow*VSTR + vcol];
                    uint32_t vhf[4];
                    ldsm_x4t(vhf, vp);
                    mma_fp16(ow[2*np],   ph2, vhf);
                    mma_fp16(ow[2*np+1], ph2, vhf + 2);
                }
            } else {
#pragma unroll
                for (int np = 0; np < 8; np++) {
                    int g2 = lane >> 3;
                    int vrow = ch*32 + 16*j + (g2 & 1)*8 + (lane & 7);
                    int vcol = np*16 + (g2 >> 1)*8;
                    const fp16* vp = &bVh[vrow*VSTR + vcol];
                    uint32_t vhf[4];
                    ldsm_x4t(vhf, vp);
                    mma_fp16(ob[2*np],   ph2, vhf);
                    mma_fp16(ob[2*np+1], ph2, vhf + 2);
                }
            }
        }
    }

    // ---- split-key merge ----
    __syncthreads();
    float* msm = (float*)smem;
    float* slot = msm + ((size_t)rg * 32 + lane) * 134;
    if (ch == 1) {
        slot[0] = m0; slot[1] = m1;
        slot[2] = lb0; slot[3] = lb1;
        slot[4] = lw0; slot[5] = lw1;
#pragma unroll
        for (int n = 0; n < 16; n++)
#pragma unroll
            for (int j = 0; j < 4; j++) {
                slot[6  + n*4 + j] = ob[n][j];
                slot[70 + n*4 + j] = ow[n][j];
            }
    }
    __syncthreads();
    if (ch == 0) {
        float mB0 = slot[0], mB1 = slot[1];
        float lbB0 = slot[2], lbB1 = slot[3];
        float lwB0 = slot[4], lwB1 = slot[5];
        float M0 = fmaxf(m0, mB0), M1 = fmaxf(m1, mB1);
        float sA0 = __expf(m0 - M0), sB0 = __expf(mB0 - M0);
        float sA1 = __expf(m1 - M1), sB1 = __expf(mB1 - M1);
        lb0 = lb0*sA0 + lbB0*sB0;  lb1 = lb1*sA1 + lbB1*sB1;
        lw0 = lw0*sA0 + lwB0*sB0;  lw1 = lw1*sA1 + lwB1*sB1;
#pragma unroll
        for (int n = 0; n < 16; n++) {
            ob[n][0] = ob[n][0]*sA0 + slot[6 + n*4 + 0]*sB0;
            ob[n][1] = ob[n][1]*sA0 + slot[6 + n*4 + 1]*sB0;
            ob[n][2] = ob[n][2]*sA1 + slot[6 + n*4 + 2]*sB1;
            ob[n][3] = ob[n][3]*sA1 + slot[6 + n*4 + 3]*sB1;
            ow[n][0] = ow[n][0]*sA0 + slot[70 + n*4 + 0]*sB0;
            ow[n][1] = ow[n][1]*sA0 + slot[70 + n*4 + 1]*sB0;
            ow[n][2] = ow[n][2]*sA1 + slot[70 + n*4 + 2]*sB1;
            ow[n][3] = ow[n][3]*sA1 + slot[70 + n*4 + 3]*sB1;
        }

        float a0 = alpha[(size_t)b*TT + q0];
        float a1 = alpha[(size_t)b*TT + q1];
        float ilb0 = 1.f/lb0, ilb1 = 1.f/lb1, ilw0 = 1.f/lw0, ilw1 = 1.f/lw1;
        size_t r0o = ((size_t)b*TT + q0)*2048 + (size_t)h*128;
        size_t r1o = ((size_t)b*TT + q1)*2048 + (size_t)h*128;
#pragma unroll
        for (int n = 0; n < 16; n++) {
            int d = 8*n + 2*(lane & 3);
            float b00 = ob[n][0] + ow[n][0], b01 = ob[n][1] + ow[n][1];
            float b10 = ob[n][2] + ow[n][2], b11 = ob[n][3] + ow[n][3];
            float o00 = a0*b00*ilb0 + (1.f-a0)*ow[n][0]*ilw0;
            float o01 = a0*b01*ilb0 + (1.f-a0)*ow[n][1]*ilw0;
            float o10 = a1*b10*ilb1 + (1.f-a1)*ow[n][2]*ilw1;
            float o11 = a1*b11*ilb1 + (1.f-a1)*ow[n][3]*ilw1;
            *(uint32_t*)(mgh + r0o + d) = pkh(__float2half(o00), __float2half(o01));
            *(uint32_t*)(mgh + r1o + d) = pkh(__float2half(o10), __float2half(o11));
        }
    }
}

// ---------------- launcher ----------------
extern "C" void kernel_launch(void* const* d_in, const int* in_sizes, int n_in,
                              void* d_out, int out_size)
{
    (void)in_sizes; (void)n_in;
    const float* x        = (const float*)d_in[0];
    const float* unc      = (const float*)d_in[1];
    const float* Wq_down  = (const float*)d_in[2];
    const float* q_norm_w = (const float*)d_in[3];
    const float* Wq_up    = (const float*)d_in[4];
    const float* Wq_rope  = (const float*)d_in[5];
    const float* Wkv_down = (const float*)d_in[6];
    const float* kv_norm_w= (const float*)d_in[7];
    const float* Wk_up    = (const float*)d_in[8];
    const float* Wv_up    = (const float*)d_in[9];
    const float* Wk_rope  = (const float*)d_in[10];
    const float* Wout     = (const float*)d_in[11];
    const float* Wgate    = (const float*)d_in[12];
    const float* bgate    = (const float*)d_in[13];
    float* out = (float*)d_out;

    float *lat3, *qcr, *kcv, *al;
    fp16 *Qh,*Kh,*Vh;
    fp16 *xh,*qlh,*kvh,*mgh;
    fp16 *wdnh,*wdnl,*wquph,*wqupl,*wkvuh,*wkvul,*woh;
    cudaGetSymbolAddress((void**)&lat3,  g_lat3);
    cudaGetSymbolAddress((void**)&qcr,   g_qcr);
    cudaGetSymbolAddress((void**)&kcv,   g_kcv);
    cudaGetSymbolAddress((void**)&al,    g_alpha);
    cudaGetSymbolAddress((void**)&Qh,    g_Qh);
    cudaGetSymbolAddress((void**)&Kh,    g_Kh);
    cudaGetSymbolAddress((void**)&Vh,    g_Vh);
    cudaGetSymbolAddress((void**)&xh,    g_xh);
    cudaGetSymbolAddress((void**)&qlh,   g_qlh);
    cudaGetSymbolAddress((void**)&kvh,   g_kvh);
    cudaGetSymbolAddress((void**)&mgh,   g_mgh);
    cudaGetSymbolAddress((void**)&wdnh,  g_wdn_h);
    cudaGetSymbolAddress((void**)&wdnl,  g_wdn_l);
    cudaGetSymbolAddress((void**)&wquph, g_wqup_h);
    cudaGetSymbolAddress((void**)&wqupl, g_wqup_l);
    cudaGetSymbolAddress((void**)&wkvuh, g_wkvu_h);
    cudaGetSymbolAddress((void**)&wkvul, g_wkvu_l);
    cudaGetSymbolAddress((void**)&woh,   g_wo_h);

    cudaFuncSetAttribute(attn_tc_kernel,
                         cudaFuncAttributeMaxDynamicSharedMemorySize, ATTN_SMEM);
    cudaFuncSetAttribute(gemm_split,
                         cudaFuncAttributeMaxDynamicSharedMemorySize, GS_SMEM);
    cudaFuncSetAttribute(gemm_up2,
                         cudaFuncAttributeMaxDynamicSharedMemorySize, GS_SMEM);
    cudaFuncSetAttribute(gemm_out_hi,
                         cudaFuncAttributeMaxDynamicSharedMemorySize, GS_SMEM);

    // 0: split input activations (hi only)
    split_hi_kernel<<<(BT*DD)/1024, 256>>>(x, xh, BT*DD);
    // 1: all weight preprocessing fused
    prep_weights_kernel<<<(PW_T3 + 1023)/1024, 256>>>(
        Wq_down, Wkv_down, Wk_rope, wdnh, wdnl,
        Wq_up, Wq_rope, wquph, wqupl,
        Wk_up, Wv_up, wkvuh, wkvul,
        Wout, woh);
    // 2: gate
    float* out_alpha = (out_size >= BB*TT*DD + BB*TT) ? (out + (size_t)BB*TT*DD)
                                                      : nullptr;
    alpha_kernel<<<BT, 256>>>(x, Wgate, bgate, al, out_alpha);
    // 3 (ncu slot): merged down-projection GEMM
    gemm_split<<<dim3(3072/128, BT/128), 256, GS_SMEM>>>(
        xh, wdnh, wdnl, lat3, BT, 3072, DD);
    // 4-5: norms
    rmsnorm_hi_kernel<<<BT, 256>>>(lat3, 3072, 0,   q_norm_w,  qlh, CQQ);
    rmsnorm_hi_kernel<<<BT, 256>>>(lat3, 3072, CQQ, kv_norm_w, kvh, CKVV);
    // 6: merged up-projections
    gemm_up2<<<768 + 1024, 256, GS_SMEM>>>(
        qlh, wquph, wqupl, qcr,
        kvh, wkvuh, wkvul, kcv);
    // 7: assemble Q/K/V (fp16 hi only)
    assemble_kernel<<<BT*NHH, 128>>>(qcr, kcv, lat3, unc, Qh, Kh, Vh);
    // 8: attention (single-chain fp16, fp32 softmax/accum)
    attn_tc_kernel<<<dim3(TT/64, BB*NHH), 256, ATTN_SMEM>>>(
        Qh, Kh, Vh, al, mgh);
    // 9: output projection (single-chain: Wout hi only)
    gemm_out_hi<<<dim3(DD/128, BT/128), 256, GS_SMEM>>>(
        mgh, woh, out, BT, DD, 2048);
}

// round 17
// speedup vs baseline: 2.6983x; 1.2046x over previous
#include <cuda_runtime.h>
#include <cuda_fp16.h>
#include <math.h>
#include <stdint.h>

// ---------------- problem constants ----------------
#define BB   2
#define TT   2048
#define DD   2048
#define NHH  16
#define HDD  128
#define RR   64
#define CQQ  1536
#define CKVV 512
#define BT   (BB*TT)       // 4096
#define DQK  192           // HD + R
#define DVV  128
#define HALFW 256          // WINDOW/2
#define RSCALE 0.07216878364870323f  // 1/sqrt(192)

typedef __half fp16;

// ---------------- scratch (device globals; no runtime alloc) ----------------
__device__ float g_lat3 [(size_t)BT*3072];
__device__ float g_qcr  [(size_t)BT*3072];
__device__ float g_kcv  [(size_t)BT*4096];
__device__ float g_alpha[BT];

__device__ fp16 g_Qh[(size_t)BB*NHH*TT*DQK];
__device__ fp16 g_Kh[(size_t)BB*NHH*TT*DQK];
__device__ fp16 g_Vh[(size_t)BB*NHH*TT*DVV];

__device__ fp16 g_xh [(size_t)BT*DD];
__device__ fp16 g_qlh[(size_t)BT*CQQ];
__device__ fp16 g_kvh[(size_t)BT*CKVV];
__device__ fp16 g_mgh[(size_t)BT*NHH*HDD];
__device__ fp16 g_wdn_h [(size_t)DD*3072];
__device__ fp16 g_wqup_h[(size_t)CQQ*3072];
__device__ fp16 g_wkvu_h[(size_t)CKVV*4096];
__device__ fp16 g_wo_h  [(size_t)2048*DD];

// ---------------- ptx helpers ----------------
__device__ __forceinline__ uint32_t smem_u32(const void* p) {
    return (uint32_t)__cvta_generic_to_shared(p);
}
__device__ __forceinline__ void ldsm_x4(uint32_t* r, const void* p) {
    uint32_t a = smem_u32(p);
    asm volatile("ldmatrix.sync.aligned.m8n8.x4.shared.b16 {%0,%1,%2,%3}, [%4];"
                 : "=r"(r[0]), "=r"(r[1]), "=r"(r[2]), "=r"(r[3]) : "r"(a));
}
__device__ __forceinline__ void ldsm_x4t(uint32_t* r, const void* p) {
    uint32_t a = smem_u32(p);
    asm volatile("ldmatrix.sync.aligned.m8n8.x4.trans.shared.b16 {%0,%1,%2,%3}, [%4];"
                 : "=r"(r[0]), "=r"(r[1]), "=r"(r[2]), "=r"(r[3]) : "r"(a));
}
__device__ __forceinline__ void mma_fp16(float* c, const uint32_t* a,
                                         const uint32_t* b) {
    asm volatile(
        "mma.sync.aligned.m16n8k16.row.col.f32.f16.f16.f32 "
        "{%0,%1,%2,%3}, {%4,%5,%6,%7}, {%8,%9}, {%0,%1,%2,%3};"
        : "+f"(c[0]), "+f"(c[1]), "+f"(c[2]), "+f"(c[3])
        : "r"(a[0]), "r"(a[1]), "r"(a[2]), "r"(a[3]), "r"(b[0]), "r"(b[1]));
}
__device__ __forceinline__ void cpa16(void* s, const void* g) {
    asm volatile("cp.async.cg.shared.global [%0], [%1], 16;"
                 :: "r"(smem_u32(s)), "l"(g));
}
#define CP_COMMIT asm volatile("cp.async.commit_group;")
#define CP_WAIT0  asm volatile("cp.async.wait_group 0;")

__device__ __forceinline__ uint32_t pkh(fp16 a, fp16 b) {
    __half2 t = __halves2half2(a, b);
    return *reinterpret_cast<uint32_t*>(&t);
}

// ---------------- split helpers ----------------
__device__ __forceinline__ void store_hi4(float4 v, fp16* h, int i) {
    *(__half2*)(h + i)     = __halves2half2(__float2half(v.x), __float2half(v.y));
    *(__half2*)(h + i + 2) = __halves2half2(__float2half(v.z), __float2half(v.w));
}

// ---------------- split input activations (hi only) ----------------
__global__ __launch_bounds__(256) void split_hi_kernel(
    const float* __restrict__ s, fp16* __restrict__ h, int n)
{
    int i = (blockIdx.x * 256 + threadIdx.x) * 4;
    if (i >= n) return;
    store_hi4(*(const float4*)(s + i), h, i);
}

// ---------------- fused weight prep (all hi-only fp16) ----------------
#define PW_T0 (DD*3072)
#define PW_T1 (PW_T0 + CQQ*3072)
#define PW_T2 (PW_T1 + CKVV*4096)
#define PW_T3 (PW_T2 + 2048*DD)

__global__ __launch_bounds__(256) void prep_weights_kernel(
    const float* __restrict__ Wq_down, const float* __restrict__ Wkv_down,
    const float* __restrict__ Wk_rope, fp16* __restrict__ wdnh,
    const float* __restrict__ Wq_up, const float* __restrict__ Wq_rope,
    fp16* __restrict__ wquph,
    const float* __restrict__ Wk_up, const float* __restrict__ Wv_up,
    fp16* __restrict__ wkvuh,
    const float* __restrict__ Wout, fp16* __restrict__ woh)
{
    int gi = (blockIdx.x * 256 + threadIdx.x) * 4;
    if (gi >= PW_T3) return;
    if (gi < PW_T0) {
        int i = gi;
        int k = i / 3072, n = i % 3072;
        const float* src;
        if (n < CQQ)             src = Wq_down  + (size_t)k * CQQ  + n;
        else if (n < CQQ + CKVV) src = Wkv_down + (size_t)k * CKVV + (n - CQQ);
        else                     src = Wk_rope  + (size_t)k * 1024 + (n - CQQ - CKVV);
        store_hi4(*(const float4*)src, wdnh, i);
    } else if (gi < PW_T1) {
        int i = gi - PW_T0;
        int k = i / 3072, n = i % 3072;
        const float* src = (n < 2048) ? (Wq_up + (size_t)k * 2048 + n)
                                      : (Wq_rope + (size_t)k * 1024 + (n - 2048));
        store_hi4(*(const float4*)src, wquph, i);
    } else if (gi < PW_T2) {
        int i = gi - PW_T1;
        int k = i / 4096, n = i % 4096;
        const float* src = (n < 2048) ? (Wk_up + (size_t)k * 2048 + n)
                                      : (Wv_up + (size_t)k * 2048 + (n - 2048));
        store_hi4(*(const float4*)src, wkvuh, i);
    } else {
        int i = gi - PW_T2;
        store_hi4(*(const float4*)(Wout + i), woh, i);
    }
}

// ---------------- fp16 single-chain TC GEMM core ----------------
#define GS_A   (128*40)
#define GS_B   (32*136)
#define GS_STG (GS_A + GS_B)
#define GS_SMEM (2*GS_STG*2)

__device__ __forceinline__ void gemm_core(
    const fp16* __restrict__ Ah, const fp16* __restrict__ Bh,
    float* __restrict__ C, int N, int K, int bm, int bn, fp16* gsm)
{
    int tid = threadIdx.x;
    int warp = tid >> 5, lane = tid & 31;
    int wm = warp >> 2, wn = warp & 3;
    int g2 = lane >> 3;

    int arow = tid >> 2, ac = (tid & 3) * 8;
    int brow = tid >> 4, bc = (tid & 15) * 8;

    float acc[4][4][4];
#pragma unroll
    for (int a = 0; a < 4; a++)
#pragma unroll
        for (int b = 0; b < 4; b++)
#pragma unroll
            for (int c = 0; c < 4; c++) acc[a][b][c] = 0.f;

    int nk = K >> 5;

    auto issue = [&](int stage, int k0) {
        fp16* sA  = gsm + stage * GS_STG;
        fp16* sBh = sA + GS_A;
#pragma unroll
        for (int i = 0; i < 2; i++) {
            int r = arow + i * 64;
            size_t g = (size_t)(bm * 128 + r) * K + k0 + ac;
            cpa16(&sA[r * 40 + ac], Ah + g);
        }
#pragma unroll
        for (int i = 0; i < 2; i++) {
            int r = brow + i * 16;
            size_t g = (size_t)(k0 + r) * N + bn * 128 + bc;
            cpa16(&sBh[r * 136 + bc], Bh + g);
        }
    };

    issue(0, 0);
    CP_COMMIT;

    for (int it = 0; it < nk; it++) {
        CP_WAIT0;
        __syncthreads();
        if (it + 1 < nk) {
            issue((it + 1) & 1, (it + 1) << 5);
            CP_COMMIT;
        }

        fp16* sA  = gsm + (it & 1) * GS_STG;
        fp16* sBh = sA + GS_A;

#pragma unroll
        for (int kh = 0; kh < 2; kh++) {
            uint32_t bh4[2][4];
#pragma unroll
            for (int nt2 = 0; nt2 < 2; nt2++) {
                int br = kh * 16 + (g2 & 1) * 8 + (lane & 7);
                int bcl = wn * 32 + nt2 * 16 + (g2 >> 1) * 8;
                ldsm_x4t(bh4[nt2], &sBh[br * 136 + bcl]);
            }
#pragma unroll
            for (int mt = 0; mt < 4; mt++) {
                int ar = wm * 64 + mt * 16 + (lane & 15);
                int acl = kh * 16 + (lane >> 4) * 8;
                uint32_t ah[4];
                ldsm_x4(ah, &sA[ar * 40 + acl]);
#pragma unroll
                for (int nt2 = 0; nt2 < 2; nt2++) {
                    mma_fp16(acc[mt][2*nt2],   ah, bh4[nt2]);
                    mma_fp16(acc[mt][2*nt2+1], ah, bh4[nt2] + 2);
                }
            }
        }
    }

#pragma unroll
    for (int mt = 0; mt < 4; mt++) {
#pragma unroll
        for (int nt = 0; nt < 4; nt++) {
            int r0 = bm * 128 + wm * 64 + mt * 16 + (lane >> 2);
            int c0 = bn * 128 + wn * 32 + nt * 8 + (lane & 3) * 2;
            *(float2*)&C[(size_t)r0 * N + c0] =
                make_float2(acc[mt][nt][0], acc[mt][nt][1]);
            *(float2*)&C[(size_t)(r0 + 8) * N + c0] =
                make_float2(acc[mt][nt][2], acc[mt][nt][3]);
        }
    }
}

__global__ __launch_bounds__(256) void gemm_hi(
    const fp16* __restrict__ Ah, const fp16* __restrict__ Bh,
    float* __restrict__ C, int M, int N, int K)
{
    extern __shared__ __align__(16) fp16 gsm[];
    gemm_core(Ah, Bh, C, N, K, blockIdx.y, blockIdx.x, gsm);
}

__global__ __launch_bounds__(256) void gemm_up2(
    const fp16* __restrict__ qlh, const fp16* __restrict__ wquph,
    float* __restrict__ qcr,
    const fp16* __restrict__ kvh, const fp16* __restrict__ wkvuh,
    float* __restrict__ kcv)
{
    extern __shared__ __align__(16) fp16 gsm[];
    int idx = blockIdx.x;
    if (idx < 768) {
        gemm_core(qlh, wquph, qcr, 3072, CQQ, idx / 24, idx % 24, gsm);
    } else {
        idx -= 768;
        gemm_core(kvh, wkvuh, kcv, 4096, CKVV, idx / 32, idx % 32, gsm);
    }
}

// ---------------- RMSNorm slice -> fp16 hi-only outputs ----------------
__global__ __launch_bounds__(256) void rmsnorm_hi_kernel(
    const float* __restrict__ x, int rowstride, int off,
    const float* __restrict__ w, fp16* __restrict__ hi, int n)
{
    const float* row = x + (size_t)blockIdx.x * rowstride + off;
    float ss = 0.f;
    for (int i = threadIdx.x; i < n; i += 256) { float v = row[i]; ss += v*v; }
    __shared__ float sh[8];
    __shared__ float tot;
    int lane = threadIdx.x & 31, wp = threadIdx.x >> 5;
#pragma unroll
    for (int o = 16; o; o >>= 1) ss += __shfl_xor_sync(0xffffffffu, ss, o);
    if (lane == 0) sh[wp] = ss;
    __syncthreads();
    if (threadIdx.x == 0) {
        float s = 0.f;
        for (int i = 0; i < 8; i++) s += sh[i];
        tot = rsqrtf(s / n + 1e-6f);
    }
    __syncthreads();
    float rs = tot;
    fp16* hrow = hi + (size_t)blockIdx.x * n;
    for (int i = threadIdx.x; i < n; i += 256)
        hrow[i] = __float2half(row[i] * rs * w[i]);
}

// ---------------- gate alpha ----------------
__global__ __launch_bounds__(256) void alpha_kernel(
    const float* __restrict__ x, const float* __restrict__ wg,
    const float* __restrict__ bg, float* __restrict__ alpha,
    float* __restrict__ out_alpha)
{
    const float* row = x + (size_t)blockIdx.x * DD;
    float s = 0.f;
    for (int i = threadIdx.x; i < DD; i += 256) s += row[i] * wg[i];
    __shared__ float sh[8];
    int lane = threadIdx.x & 31, wp = threadIdx.x >> 5;
#pragma unroll
    for (int o = 16; o; o >>= 1) s += __shfl_xor_sync(0xffffffffu, s, o);
    if (lane == 0) sh[wp] = s;
    __syncthreads();
    if (threadIdx.x == 0) {
        float t = 0.f;
        for (int i = 0; i < 8; i++) t += sh[i];
        float z = t + bg[0];
        float a = 1.f / (1.f + expf(-z));
        alpha[blockIdx.x] = a;
        if (out_alpha) out_alpha[blockIdx.x] = a;
    }
}

// ---------------- assemble Q/K/V with EPE-RoPE (fp16 hi only) --------------
__global__ __launch_bounds__(128) void assemble_kernel(
    const float* __restrict__ qcr, const float* __restrict__ kcv,
    const float* __restrict__ lat3, const float* __restrict__ unc,
    fp16* __restrict__ Qh, fp16* __restrict__ Kh, fp16* __restrict__ Vh)
{
    int idx = blockIdx.x;
    int h  = idx % NHH;
    int bt = idx / NHH;
    int t  = bt % TT;
    int b  = bt / TT;
    __shared__ float cs[32], sn[32];
    int d = threadIdx.x;
    if (d < 32) {
        float u = unc[bt];
        u = fminf(fmaxf(u, 0.f), 1.f);
        float scale = 0.5f + 1.5f * u;
        float fi = (float)d / 32.0f;
        float theta = expf(-fi * logf(500000.0f));
        float fr = (float)t * theta * scale;
        cs[d] = cosf(fr);
        sn[d] = sinf(fr);
    }
    __syncthreads();
    size_t qkrow = ((size_t)(b*NHH + h))*TT + t;

    Qh[qkrow*DQK + d] = __float2half(qcr[(size_t)bt*3072 + h*128 + d]);
    Kh[qkrow*DQK + d] = __float2half(kcv[(size_t)bt*4096 + h*128 + d]);
    Vh[qkrow*DVV + d] = __float2half(kcv[(size_t)bt*4096 + 2048 + h*128 + d]);

    if (d < 64) {
        const float* qrp = qcr  + (size_t)bt*3072 + 2048 + h*64;
        const float* krp = lat3 + (size_t)bt*3072 + 2048 + h*64;
        float qv, kv;
        if (d < 32) {
            float c = cs[d], s = sn[d];
            qv = qrp[d]*c - qrp[d+32]*s;
            kv = krp[d]*c - krp[d+32]*s;
        } else {
            int j = d - 32;
            float c = cs[j], s = sn[j];
            qv = qrp[j+32]*c + qrp[j]*s;
            kv = krp[j+32]*c + krp[j]*s;
        }
        Qh[qkrow*DQK + 128 + d] = __float2half(qv);
        Kh[qkrow*DQK + 128 + d] = __float2half(kv);
    }
}

// ---------------- fp16 single-chain fused dual attention, split-key warps --
#define KSTR 200
#define VSTR 136
#define ATTN_SMEM ((64*KSTR + 2*64*KSTR + 2*64*VSTR) * 2)

__global__ void __launch_bounds__(256, 1) attn_tc_kernel(
    const fp16* __restrict__ Qh,
    const fp16* __restrict__ Kh, const fp16* __restrict__ Vh,
    const float* __restrict__ alpha, fp16* __restrict__ mgh)
{
    extern __shared__ __align__(16) fp16 smem[];
    fp16* sQh = smem;
    fp16* sKh = sQh + 64*KSTR;
    fp16* sVh = sKh + 2*64*KSTR;

    int tid = threadIdx.x, lane = tid & 31, warp = tid >> 5;
    int rg = warp & 3;
    int ch = warp >> 2;
    int qt = blockIdx.x * 64;
    int bh = blockIdx.y;
    int b = bh >> 4, h = bh & 15;
    size_t base = (size_t)bh * TT;

    for (int i = tid; i < 64*24; i += 256) {
        int r = i / 24, c = (i % 24) * 8;
        size_t g = (base + qt + r) * DQK + c;
        cpa16(&sQh[r*KSTR + c], Qh + g);
    }
    for (int i = tid; i < 64*24; i += 256) {
        int r = i / 24, c = (i % 24) * 8;
        size_t g = (base + r) * DQK + c;
        cpa16(&sKh[r*KSTR + c], Kh + g);
    }
    for (int i = tid; i < 64*16; i += 256) {
        int r = i / 16, c = (i % 16) * 8;
        size_t g = (base + r) * DVV + c;
        cpa16(&sVh[r*VSTR + c], Vh + g);
    }
    CP_COMMIT;

    int q0 = qt + 16*rg + (lane >> 2);
    int q1 = q0 + 8;
    int winlo = ((qt >> 8) << 8) - HALFW;
    if (winlo < 0) winlo = 0;

    float ob[16][4], ow[16][4];
#pragma unroll
    for (int n = 0; n < 16; n++)
#pragma unroll
        for (int j = 0; j < 4; j++) { ob[n][j] = 0.f; ow[n][j] = 0.f; }
    float m0 = -1e30f, m1 = -1e30f;
    float lb0 = 0.f, lb1 = 0.f, lw0 = 0.f, lw1 = 0.f;

    for (int t = 0; t < 32; t++) {
        int kt = t * 64;

        CP_WAIT0;
        __syncthreads();
        if (t + 1 < 32) {
            int nb = (t + 1) & 1;
            int kn = kt + 64;
            for (int i = tid; i < 64*24; i += 256) {
                int r = i / 24, c = (i % 24) * 8;
                size_t g = (base + kn + r) * DQK + c;
                cpa16(&sKh[nb*64*KSTR + r*KSTR + c], Kh + g);
            }
            for (int i = tid; i < 64*16; i += 256) {
                int r = i / 16, c = (i % 16) * 8;
                size_t g = (base + kn + r) * DVV + c;
                cpa16(&sVh[nb*64*VSTR + r*VSTR + c], Vh + g);
            }
            CP_COMMIT;
        }

        const fp16* bKh = sKh + (t & 1) * 64 * KSTR;
        const fp16* bVh = sVh + (t & 1) * 64 * VSTR;

        bool diag    = (kt == qt);
        bool fullwin = (kt >= winlo) && (kt < qt);

        float sacc[4][4];
#pragma unroll
        for (int n = 0; n < 4; n++)
#pragma unroll
            for (int j = 0; j < 4; j++) sacc[n][j] = 0.f;

#pragma unroll
        for (int ks = 0; ks < 12; ks++) {
            uint32_t qhf[4];
            const fp16* ap = &sQh[(16*rg + (lane & 15))*KSTR + ks*16 + (lane >> 4)*8];
            ldsm_x4(qhf, ap);
#pragma unroll
            for (int np = 0; np < 2; np++) {
                int g2 = lane >> 3;
                int krow = ch*32 + np*16 + (g2 >> 1)*8 + (lane & 7);
                int kcol = ks*16 + (g2 & 1)*8;
                const fp16* bp = &bKh[krow*KSTR + kcol];
                uint32_t khf[4];
                ldsm_x4(khf, bp);
                mma_fp16(sacc[2*np],   qhf, khf);
                mma_fp16(sacc[2*np+1], qhf, khf + 2);
            }
        }

        float tm0 = -1e30f, tm1 = -1e30f;
#pragma unroll
        for (int n = 0; n < 4; n++) {
            tm0 = fmaxf(tm0, fmaxf(sacc[n][0], sacc[n][1]));
            tm1 = fmaxf(tm1, fmaxf(sacc[n][2], sacc[n][3]));
        }
        tm0 *= RSCALE; tm1 *= RSCALE;
        tm0 = fmaxf(tm0, __shfl_xor_sync(0xffffffffu, tm0, 1));
        tm0 = fmaxf(tm0, __shfl_xor_sync(0xffffffffu, tm0, 2));
        tm1 = fmaxf(tm1, __shfl_xor_sync(0xffffffffu, tm1, 1));
        tm1 = fmaxf(tm1, __shfl_xor_sync(0xffffffffu, tm1, 2));
        float mn0 = fmaxf(m0, tm0), mn1 = fmaxf(m1, tm1);
        float c0 = __expf(m0 - mn0), c1 = __expf(m1 - mn1);
        m0 = mn0; m1 = mn1;
        lb0 *= c0; lb1 *= c1; lw0 *= c0; lw1 *= c1;
        if (c0 < 1.f || c1 < 1.f) {
#pragma unroll
            for (int n = 0; n < 16; n++) {
                ob[n][0] *= c0; ob[n][1] *= c0; ob[n][2] *= c1; ob[n][3] *= c1;
                ow[n][0] *= c0; ow[n][1] *= c0; ow[n][2] *= c1; ow[n][3] *= c1;
            }
        }

        float sb0 = 0.f, sb1 = 0.f, sw0 = 0.f, sw1 = 0.f;
#pragma unroll
        for (int n = 0; n < 4; n++) {
            float p0 = __expf(sacc[n][0]*RSCALE - mn0);
            float p1 = __expf(sacc[n][1]*RSCALE - mn0);
            float p2 = __expf(sacc[n][2]*RSCALE - mn1);
            float p3 = __expf(sacc[n][3]*RSCALE - mn1);
            sacc[n][0] = p0; sacc[n][1] = p1; sacc[n][2] = p2; sacc[n][3] = p3;
            sb0 += p0 + p1; sb1 += p2 + p3;
            if (diag) {
                int keyc = kt + ch*32 + 8*n + 2*(lane & 3);
                sw0 += ((keyc   <= q0) ? p0 : 0.f) + ((keyc+1 <= q0) ? p1 : 0.f);
                sw1 += ((keyc   <= q1) ? p2 : 0.f) + ((keyc+1 <= q1) ? p3 : 0.f);
            }
        }
        sb0 += __shfl_xor_sync(0xffffffffu, sb0, 1); sb0 += __shfl_xor_sync(0xffffffffu, sb0, 2);
        sb1 += __shfl_xor_sync(0xffffffffu, sb1, 1); sb1 += __shfl_xor_sync(0xffffffffu, sb1, 2);
        lb0 += sb0; lb1 += sb1;
        if (fullwin) { lw0 += sb0; lw1 += sb1; }
        if (diag) {
            sw0 += __shfl_xor_sync(0xffffffffu, sw0, 1); sw0 += __shfl_xor_sync(0xffffffffu, sw0, 2);
            sw1 += __shfl_xor_sync(0xffffffffu, sw1, 1); sw1 += __shfl_xor_sync(0xffffffffu, sw1, 2);
            lw0 += sw0; lw1 += sw1;
        }

#pragma unroll
        for (int j = 0; j < 2; j++) {
            fp16 h0 = __float2half(sacc[2*j][0]),   h1 = __float2half(sacc[2*j][1]);
            fp16 h2 = __float2half(sacc[2*j][2]),   h3 = __float2half(sacc[2*j][3]);
            fp16 h4 = __float2half(sacc[2*j+1][0]), h5 = __float2half(sacc[2*j+1][1]);
            fp16 h6 = __float2half(sacc[2*j+1][2]), h7 = __float2half(sacc[2*j+1][3]);
            uint32_t ph2[4] = { pkh(h0,h1), pkh(h2,h3), pkh(h4,h5), pkh(h6,h7) };

            if (diag) {
                fp16 z = __float2half(0.f);
                int kc = kt + ch*32 + 16*j + 2*(lane & 3);
                bool a0 = kc   <= q0, a1 = kc+1 <= q0;
                bool b0m = kc  <= q1, b1m = kc+1 <= q1;
                bool a2 = kc+8 <= q0, a3 = kc+9 <= q0;
                bool b2m = kc+8 <= q1, b3m = kc+9 <= q1;
                uint32_t wh[4], xh2[4];
                wh[0] = pkh(a0?h0:z, a1?h1:z);
                wh[1] = pkh(b0m?h2:z, b1m?h3:z);
                wh[2] = pkh(a2?h4:z, a3?h5:z);
                wh[3] = pkh(b2m?h6:z, b3m?h7:z);
                xh2[0] = pkh(a0?z:h0, a1?z:h1);
                xh2[1] = pkh(b0m?z:h2, b1m?z:h3);
                xh2[2] = pkh(a2?z:h4, a3?z:h5);
                xh2[3] = pkh(b2m?z:h6, b3m?z:h7);
#pragma unroll
                for (int np = 0; np < 8; np++) {
                    int g2 = lane >> 3;
                    int vrow = ch*32 + 16*j + (g2 & 1)*8 + (lane & 7);
                    int vcol = np*16 + (g2 >> 1)*8;
                    const fp16* vp = &bVh[vrow*VSTR + vcol];
                    uint32_t vhf[4];
                    ldsm_x4t(vhf, vp);
                    mma_fp16(ow[2*np],   wh, vhf);
                    mma_fp16(ow[2*np+1], wh, vhf + 2);
                    mma_fp16(ob[2*np],   xh2, vhf);
                    mma_fp16(ob[2*np+1], xh2, vhf + 2);
                }
            } else if (fullwin) {
#pragma unroll
                for (int np = 0; np < 8; np++) {
                    int g2 = lane >> 3;
                    int vrow = ch*32 + 16*j + (g2 & 1)*8 + (lane & 7);
                    int vcol = np*16 + (g2 >> 1)*8;
                    const fp16* vp = &bVh[vrow*VSTR + vcol];
                    uint32_t vhf[4];
                    ldsm_x4t(vhf, vp);
                    mma_fp16(ow[2*np],   ph2, vhf);
                    mma_fp16(ow[2*np+1], ph2, vhf + 2);
                }
            } else {
#pragma unroll
                for (int np = 0; np < 8; np++) {
                    int g2 = lane >> 3;
                    int vrow = ch*32 + 16*j + (g2 & 1)*8 + (lane & 7);
                    int vcol = np*16 + (g2 >> 1)*8;
                    const fp16* vp = &bVh[vrow*VSTR + vcol];
                    uint32_t vhf[4];
                    ldsm_x4t(vhf, vp);
                    mma_fp16(ob[2*np],   ph2, vhf);
                    mma_fp16(ob[2*np+1], ph2, vhf + 2);
                }
            }
        }
    }

    // ---- split-key merge ----
    __syncthreads();
    float* msm = (float*)smem;
    float* slot = msm + ((size_t)rg * 32 + lane) * 134;
    if (ch == 1) {
        slot[0] = m0; slot[1] = m1;
        slot[2] = lb0; slot[3] = lb1;
        slot[4] = lw0; slot[5] = lw1;
#pragma unroll
        for (int n = 0; n < 16; n++)
#pragma unroll
            for (int j = 0; j < 4; j++) {
                slot[6  + n*4 + j] = ob[n][j];
                slot[70 + n*4 + j] = ow[n][j];
            }
    }
    __syncthreads();
    if (ch == 0) {
        float mB0 = slot[0], mB1 = slot[1];
        float lbB0 = slot[2], lbB1 = slot[3];
        float lwB0 = slot[4], lwB1 = slot[5];
        float M0 = fmaxf(m0, mB0), M1 = fmaxf(m1, mB1);
        float sA0 = __expf(m0 - M0), sB0 = __expf(mB0 - M0);
        float sA1 = __expf(m1 - M1), sB1 = __expf(mB1 - M1);
        lb0 = lb0*sA0 + lbB0*sB0;  lb1 = lb1*sA1 + lbB1*sB1;
        lw0 = lw0*sA0 + lwB0*sB0;  lw1 = lw1*sA1 + lwB1*sB1;
#pragma unroll
        for (int n = 0; n < 16; n++) {
            ob[n][0] = ob[n][0]*sA0 + slot[6 + n*4 + 0]*sB0;
            ob[n][1] = ob[n][1]*sA0 + slot[6 + n*4 + 1]*sB0;
            ob[n][2] = ob[n][2]*sA1 + slot[6 + n*4 + 2]*sB1;
            ob[n][3] = ob[n][3]*sA1 + slot[6 + n*4 + 3]*sB1;
            ow[n][0] = ow[n][0]*sA0 + slot[70 + n*4 + 0]*sB0;
            ow[n][1] = ow[n][1]*sA0 + slot[70 + n*4 + 1]*sB0;
            ow[n][2] = ow[n][2]*sA1 + slot[70 + n*4 + 2]*sB1;
            ow[n][3] = ow[n][3]*sA1 + slot[70 + n*4 + 3]*sB1;
        }

        float a0 = alpha[(size_t)b*TT + q0];
        float a1 = alpha[(size_t)b*TT + q1];
        float ilb0 = 1.f/lb0, ilb1 = 1.f/lb1, ilw0 = 1.f/lw0, ilw1 = 1.f/lw1;
        size_t r0o = ((size_t)b*TT + q0)*2048 + (size_t)h*128;
        size_t r1o = ((size_t)b*TT + q1)*2048 + (size_t)h*128;
#pragma unroll
        for (int n = 0; n < 16; n++) {
            int d = 8*n + 2*(lane & 3);
            float b00 = ob[n][0] + ow[n][0], b01 = ob[n][1] + ow[n][1];
            float b10 = ob[n][2] + ow[n][2], b11 = ob[n][3] + ow[n][3];
            float o00 = a0*b00*ilb0 + (1.f-a0)*ow[n][0]*ilw0;
            float o01 = a0*b01*ilb0 + (1.f-a0)*ow[n][1]*ilw0;
            float o10 = a1*b10*ilb1 + (1.f-a1)*ow[n][2]*ilw1;
            float o11 = a1*b11*ilb1 + (1.f-a1)*ow[n][3]*ilw1;
            *(uint32_t*)(mgh + r0o + d) = pkh(__float2half(o00), __float2half(o01));
            *(uint32_t*)(mgh + r1o + d) = pkh(__float2half(o10), __float2half(o11));
        }
    }
}

// ---------------- launcher ----------------
extern "C" void kernel_launch(void* const* d_in, const int* in_sizes, int n_in,
                              void* d_out, int out_size)
{
    (void)in_sizes; (void)n_in;
    const float* x        = (const float*)d_in[0];
    const float* unc      = (const float*)d_in[1];
    const float* Wq_down  = (const float*)d_in[2];
    const float* q_norm_w = (const float*)d_in[3];
    const float* Wq_up    = (const float*)d_in[4];
    const float* Wq_rope  = (const float*)d_in[5];
    const float* Wkv_down = (const float*)d_in[6];
    const float* kv_norm_w= (const float*)d_in[7];
    const float* Wk_up    = (const float*)d_in[8];
    const float* Wv_up    = (const float*)d_in[9];
    const float* Wk_rope  = (const float*)d_in[10];
    const float* Wout     = (const float*)d_in[11];
    const float* Wgate    = (const float*)d_in[12];
    const float* bgate    = (const float*)d_in[13];
    float* out = (float*)d_out;

    float *lat3, *qcr, *kcv, *al;
    fp16 *Qh,*Kh,*Vh;
    fp16 *xh,*qlh,*kvh,*mgh;
    fp16 *wdnh,*wquph,*wkvuh,*woh;
    cudaGetSymbolAddress((void**)&lat3,  g_lat3);
    cudaGetSymbolAddress((void**)&qcr,   g_qcr);
    cudaGetSymbolAddress((void**)&kcv,   g_kcv);
    cudaGetSymbolAddress((void**)&al,    g_alpha);
    cudaGetSymbolAddress((void**)&Qh,    g_Qh);
    cudaGetSymbolAddress((void**)&Kh,    g_Kh);
    cudaGetSymbolAddress((void**)&Vh,    g_Vh);
    cudaGetSymbolAddress((void**)&xh,    g_xh);
    cudaGetSymbolAddress((void**)&qlh,   g_qlh);
    cudaGetSymbolAddress((void**)&kvh,   g_kvh);
    cudaGetSymbolAddress((void**)&mgh,   g_mgh);
    cudaGetSymbolAddress((void**)&wdnh,  g_wdn_h);
    cudaGetSymbolAddress((void**)&wquph, g_wqup_h);
    cudaGetSymbolAddress((void**)&wkvuh, g_wkvu_h);
    cudaGetSymbolAddress((void**)&woh,   g_wo_h);

    cudaFuncSetAttribute(attn_tc_kernel,
                         cudaFuncAttributeMaxDynamicSharedMemorySize, ATTN_SMEM);
    cudaFuncSetAttribute(gemm_hi,
                         cudaFuncAttributeMaxDynamicSharedMemorySize, GS_SMEM);
    cudaFuncSetAttribute(gemm_up2,
                         cudaFuncAttributeMaxDynamicSharedMemorySize, GS_SMEM);

    // 0: split input activations (hi only)
    split_hi_kernel<<<(BT*DD)/1024, 256>>>(x, xh, BT*DD);
    // 1: all weight preprocessing fused (hi only)
    prep_weights_kernel<<<(PW_T3 + 1023)/1024, 256>>>(
        Wq_down, Wkv_down, Wk_rope, wdnh,
        Wq_up, Wq_rope, wquph,
        Wk_up, Wv_up, wkvuh,
        Wout, woh);
    // 2: gate
    float* out_alpha = (out_size >= BB*TT*DD + BB*TT) ? (out + (size_t)BB*TT*DD)
                                                      : nullptr;
    alpha_kernel<<<BT, 256>>>(x, Wgate, bgate, al, out_alpha);
    // 3 (ncu slot): merged down-projection GEMM (single-chain)
    gemm_hi<<<dim3(3072/128, BT/128), 256, GS_SMEM>>>(
        xh, wdnh, lat3, BT, 3072, DD);
    // 4-5: norms
    rmsnorm_hi_kernel<<<BT, 256>>>(lat3, 3072, 0,   q_norm_w,  qlh, CQQ);
    rmsnorm_hi_kernel<<<BT, 256>>>(lat3, 3072, CQQ, kv_norm_w, kvh, CKVV);
    // 6: merged up-projections (single-chain)
    gemm_up2<<<768 + 1024, 256, GS_SMEM>>>(
        qlh, wquph, qcr, kvh, wkvuh, kcv);
    // 7: assemble Q/K/V
    assemble_kernel<<<BT*NHH, 128>>>(qcr, kcv, lat3, unc, Qh, Kh, Vh);
    // 8: attention
    attn_tc_kernel<<<dim3(TT/64, BB*NHH), 256, ATTN_SMEM>>>(
        Qh, Kh, Vh, al, mgh);
    // 9: output projection (single-chain)
    gemm_hi<<<dim3(DD/128, BT/128), 256, GS_SMEM>>>(
        mgh, woh, out, BT, DD, 2048);
}